// round 1
// baseline (speedup 1.0000x reference)
#include <cuda_runtime.h>

#define BATCH 2
#define SEQ 2048
#define EMBED 2048
#define NHEADS 32
#define NKV 8
#define HDIM 64
#define KVDIM (NKV*HDIM)   // 512

// Scratch (no allocations allowed)
__device__ float g_Q[(size_t)BATCH*SEQ*EMBED];
__device__ float g_K[(size_t)BATCH*SEQ*KVDIM];
__device__ float g_V[(size_t)BATCH*SEQ*KVDIM];
__device__ float g_O[(size_t)BATCH*SEQ*EMBED];

// ---------------------------------------------------------------------------
// C[M,N] = A[M,K] * B[N,K]^T   (both row-major, K-major => "TN" gemm)
// 128x128 tile, BK=16, 256 threads, 8x8 per-thread microtile.
// ---------------------------------------------------------------------------
__global__ __launch_bounds__(256) void sgemm_tn(const float* __restrict__ A,
                                                const float* __restrict__ B,
                                                float* __restrict__ C,
                                                int M, int N, int K)
{
    __shared__ float As[16][132];
    __shared__ float Bs[16][132];

    const int bm = blockIdx.y * 128;
    const int bn = blockIdx.x * 128;
    const int tid = threadIdx.x;
    const int tm = (tid / 16) * 8;
    const int tn = (tid % 16) * 8;

    float acc[8][8];
#pragma unroll
    for (int i = 0; i < 8; i++)
#pragma unroll
        for (int j = 0; j < 8; j++) acc[i][j] = 0.f;

    const float* Aptr = A + (size_t)bm * K;
    const float* Bptr = B + (size_t)bn * K;

    for (int k0 = 0; k0 < K; k0 += 16) {
        // 128 rows x 16 cols per tile = 512 float4 loads, 2 per thread
#pragma unroll
        for (int i = tid; i < 512; i += 256) {
            int r = i >> 2;
            int c = i & 3;
            float4 va = *(const float4*)(Aptr + (size_t)r * K + k0 + c * 4);
            As[c*4+0][r] = va.x; As[c*4+1][r] = va.y;
            As[c*4+2][r] = va.z; As[c*4+3][r] = va.w;
            float4 vb = *(const float4*)(Bptr + (size_t)r * K + k0 + c * 4);
            Bs[c*4+0][r] = vb.x; Bs[c*4+1][r] = vb.y;
            Bs[c*4+2][r] = vb.z; Bs[c*4+3][r] = vb.w;
        }
        __syncthreads();

#pragma unroll
        for (int kk = 0; kk < 16; kk++) {
            float ra[8], rb[8];
            *(float4*)&ra[0] = *(const float4*)&As[kk][tm];
            *(float4*)&ra[4] = *(const float4*)&As[kk][tm + 4];
            *(float4*)&rb[0] = *(const float4*)&Bs[kk][tn];
            *(float4*)&rb[4] = *(const float4*)&Bs[kk][tn + 4];
#pragma unroll
            for (int i = 0; i < 8; i++)
#pragma unroll
                for (int j = 0; j < 8; j++)
                    acc[i][j] += ra[i] * rb[j];
        }
        __syncthreads();
    }

#pragma unroll
    for (int i = 0; i < 8; i++) {
        float* crow = C + (size_t)(bm + tm + i) * N + bn + tn;
        *(float4*)(crow)     = make_float4(acc[i][0], acc[i][1], acc[i][2], acc[i][3]);
        *(float4*)(crow + 4) = make_float4(acc[i][4], acc[i][5], acc[i][6], acc[i][7]);
    }
}

// ---------------------------------------------------------------------------
// In-place RoPE on [B,S,nheads,64] buffer. One thread per (b,s,h,d<32) pair.
// out[d]    = x[d]*cos[d]    - x[d+32]*sin[d]
// out[d+32] = x[d+32]*cos[d+32] + x[d]*sin[d+32]
// ---------------------------------------------------------------------------
__global__ void rope_kernel(float* __restrict__ buf,
                            const float* __restrict__ cosv,
                            const float* __restrict__ sinv,
                            int nheads)
{
    int i = blockIdx.x * blockDim.x + threadIdx.x;
    int total = BATCH * SEQ * nheads * 32;
    if (i >= total) return;
    int d = i & 31;
    int h = (i >> 5) % nheads;
    int s = (i / (32 * nheads)) % SEQ;
    int b = i / (32 * nheads * SEQ);

    float* p = buf + (((size_t)b * SEQ + s) * nheads + h) * HDIM;
    float c0 = cosv[s * HDIM + d];
    float c1 = cosv[s * HDIM + d + 32];
    float s0 = sinv[s * HDIM + d];
    float s1 = sinv[s * HDIM + d + 32];
    float x0 = p[d];
    float x1 = p[d + 32];
    p[d]      = x0 * c0 - x1 * s0;
    p[d + 32] = x1 * c1 + x0 * s1;
}

// ---------------------------------------------------------------------------
// Causal flash attention, GQA (4 q-heads per kv-head).
// 1 block = 128 query rows of one (b,h). 1 thread = 1 query row.
// q row + O accumulator in registers; K/V tiles (64x64) in smem,
// read warp-broadcast (all lanes share key index n) -> conflict-free.
// ---------------------------------------------------------------------------
__global__ __launch_bounds__(128) void attn_kernel(const float* __restrict__ Q,
                                                   const float* __restrict__ K,
                                                   const float* __restrict__ V,
                                                   float* __restrict__ O)
{
    __shared__ float Ks[64][64];
    __shared__ float Vs[64][64];

    const int tid = threadIdx.x;
    const int q0  = blockIdx.x * 128;
    const int h   = blockIdx.y;
    const int b   = blockIdx.z;
    const int kvh = h >> 2;          // N_REP = 4, repeat_interleave
    const int qi  = q0 + tid;

    const float4* qptr = (const float4*)(Q + (((size_t)b * SEQ + qi) * NHEADS + h) * HDIM);
    float4 qv[16];
#pragma unroll
    for (int i = 0; i < 16; i++) qv[i] = qptr[i];

    float4 av[16];
#pragma unroll
    for (int i = 0; i < 16; i++) av[i] = make_float4(0.f, 0.f, 0.f, 0.f);

    float mi = -1e30f, li = 0.f;

    const int nkb = q0 / 64 + 2;   // key tiles covering keys <= q0+127
    for (int kb = 0; kb < nkb; kb++) {
        const float* kbase = K + (((size_t)b * SEQ + kb * 64) * NKV + kvh) * HDIM;
        const float* vbase = V + (((size_t)b * SEQ + kb * 64) * NKV + kvh) * HDIM;
#pragma unroll
        for (int i = tid; i < 64 * 16; i += 128) {
            int r = i >> 4;
            int c = i & 15;
            ((float4*)Ks[r])[c] = ((const float4*)(kbase + (size_t)r * KVDIM))[c];
            ((float4*)Vs[r])[c] = ((const float4*)(vbase + (size_t)r * KVDIM))[c];
        }
        __syncthreads();

#pragma unroll 1
        for (int n0 = 0; n0 < 64; n0 += 16) {
            float pk[16];
            float cmax = -1e30f;
#pragma unroll
            for (int j = 0; j < 16; j++) {
                const int kidx = kb * 64 + n0 + j;
                const float4* kr = (const float4*)Ks[n0 + j];
                float4 a4 = make_float4(0.f, 0.f, 0.f, 0.f);
#pragma unroll
                for (int k4 = 0; k4 < 16; k4++) {
                    float4 kk4 = kr[k4];
                    a4.x += qv[k4].x * kk4.x;
                    a4.y += qv[k4].y * kk4.y;
                    a4.z += qv[k4].z * kk4.z;
                    a4.w += qv[k4].w * kk4.w;
                }
                float sc = (a4.x + a4.y + a4.z + a4.w) * 0.125f;  // 1/sqrt(64)
                sc = (kidx <= qi) ? sc : -1e30f;
                pk[j] = sc;
                cmax = fmaxf(cmax, sc);
            }
            float mnew  = fmaxf(mi, cmax);
            float scale = __expf(mi - mnew);
            float psum  = 0.f;
#pragma unroll
            for (int j = 0; j < 16; j++) {
                pk[j] = __expf(pk[j] - mnew);
                psum += pk[j];
            }
            li = li * scale + psum;
#pragma unroll
            for (int i = 0; i < 16; i++) {
                av[i].x *= scale; av[i].y *= scale;
                av[i].z *= scale; av[i].w *= scale;
            }
#pragma unroll
            for (int j = 0; j < 16; j++) {
                const float4* vr = (const float4*)Vs[n0 + j];
                const float p = pk[j];
#pragma unroll
                for (int k4 = 0; k4 < 16; k4++) {
                    float4 v4 = vr[k4];
                    av[k4].x += p * v4.x;
                    av[k4].y += p * v4.y;
                    av[k4].z += p * v4.z;
                    av[k4].w += p * v4.w;
                }
            }
            mi = mnew;
        }
        __syncthreads();
    }

    const float inv = 1.f / li;
    float4* optr = (float4*)(O + (((size_t)b * SEQ + qi) * NHEADS + h) * HDIM);
#pragma unroll
    for (int i = 0; i < 16; i++)
        optr[i] = make_float4(av[i].x * inv, av[i].y * inv, av[i].z * inv, av[i].w * inv);
}

// ---------------------------------------------------------------------------
extern "C" void kernel_launch(void* const* d_in, const int* in_sizes, int n_in,
                              void* d_out, int out_size)
{
    const float* x    = (const float*)d_in[0];
    const float* fcos = (const float*)d_in[1];
    const float* fsin = (const float*)d_in[2];
    const float* wq   = (const float*)d_in[3];
    const float* wk   = (const float*)d_in[4];
    const float* wv   = (const float*)d_in[5];
    const float* wo   = (const float*)d_in[6];
    float* out = (float*)d_out;

    float *Qp, *Kp, *Vp, *Op;
    cudaGetSymbolAddress((void**)&Qp, g_Q);
    cudaGetSymbolAddress((void**)&Kp, g_K);
    cudaGetSymbolAddress((void**)&Vp, g_V);
    cudaGetSymbolAddress((void**)&Op, g_O);

    const int M = BATCH * SEQ;

    // QKV projections: y = x @ W^T
    sgemm_tn<<<dim3(EMBED / 128, M / 128), 256>>>(x, wq, Qp, M, EMBED, EMBED);
    sgemm_tn<<<dim3(KVDIM / 128, M / 128), 256>>>(x, wk, Kp, M, KVDIM, EMBED);
    sgemm_tn<<<dim3(KVDIM / 128, M / 128), 256>>>(x, wv, Vp, M, KVDIM, EMBED);

    // RoPE on Q (32 heads) and K (8 kv heads)
    int tq = BATCH * SEQ * NHEADS * 32;
    rope_kernel<<<(tq + 255) / 256, 256>>>(Qp, fcos, fsin, NHEADS);
    int tk = BATCH * SEQ * NKV * 32;
    rope_kernel<<<(tk + 255) / 256, 256>>>(Kp, fcos, fsin, NKV);

    // Causal GQA flash attention -> g_O in (b, s, h*d) layout
    attn_kernel<<<dim3(SEQ / 128, NHEADS, BATCH), 128>>>(Qp, Kp, Vp, Op);

    // Output projection
    sgemm_tn<<<dim3(EMBED / 128, M / 128), 256>>>(Op, wo, out, M, EMBED, EMBED);
}

// round 3
// speedup vs baseline: 1.3793x; 1.3793x over previous
#include <cuda_runtime.h>
#include <cuda_bf16.h>
#include <cstdint>

#define BATCH 2
#define SEQ 2048
#define EMBED 2048
#define NHEADS 32
#define NKV 8
#define HDIM 64
#define KVDIM (NKV*HDIM)   // 512

// fp32 scratch
__device__ float g_Q[(size_t)BATCH*SEQ*EMBED];
__device__ float g_K[(size_t)BATCH*SEQ*KVDIM];
__device__ float g_V[(size_t)BATCH*SEQ*KVDIM];
__device__ float g_O[(size_t)BATCH*SEQ*EMBED];

// bf16 hi/lo pool
#define N_X   (size_t)8388608    // 2*2048*2048
#define N_WQ  (size_t)4194304
#define N_WK  (size_t)1048576
#define N_WV  (size_t)1048576
#define N_WO  (size_t)4194304
#define OFF_XH  (size_t)0
#define OFF_XL  (OFF_XH + N_X)
#define OFF_WQH (OFF_XL + N_X)
#define OFF_WQL (OFF_WQH + N_WQ)
#define OFF_WKH (OFF_WQL + N_WQ)
#define OFF_WKL (OFF_WKH + N_WK)
#define OFF_WVH (OFF_WKL + N_WK)
#define OFF_WVL (OFF_WVH + N_WV)
#define OFF_WOH (OFF_WVL + N_WV)
#define OFF_WOL (OFF_WOH + N_WO)
#define OFF_OH  (OFF_WOL + N_WO)
#define OFF_OL  (OFF_OH + N_X)
#define POOL_SZ (OFF_OL + N_X)
__device__ __nv_bfloat16 g_bf[POOL_SZ];

// ---------------------------------------------------------------------------
// fp32 -> (bf16 hi, bf16 lo) split prepass. n4 = elements/4.
// ---------------------------------------------------------------------------
__global__ void split_kernel(const float* __restrict__ in,
                             __nv_bfloat16* __restrict__ hi,
                             __nv_bfloat16* __restrict__ lo, int n4)
{
    int i = blockIdx.x * blockDim.x + threadIdx.x;
    if (i >= n4) return;
    float4 v = ((const float4*)in)[i];
    __nv_bfloat16 h0 = __float2bfloat16_rn(v.x);
    __nv_bfloat16 h1 = __float2bfloat16_rn(v.y);
    __nv_bfloat16 h2 = __float2bfloat16_rn(v.z);
    __nv_bfloat16 h3 = __float2bfloat16_rn(v.w);
    __nv_bfloat16 l0 = __float2bfloat16_rn(v.x - __bfloat162float(h0));
    __nv_bfloat16 l1 = __float2bfloat16_rn(v.y - __bfloat162float(h1));
    __nv_bfloat16 l2 = __float2bfloat16_rn(v.z - __bfloat162float(h2));
    __nv_bfloat16 l3 = __float2bfloat16_rn(v.w - __bfloat162float(h3));
    uint2 uh, ul;
    uh.x = (uint32_t)__bfloat16_as_ushort(h0) | ((uint32_t)__bfloat16_as_ushort(h1) << 16);
    uh.y = (uint32_t)__bfloat16_as_ushort(h2) | ((uint32_t)__bfloat16_as_ushort(h3) << 16);
    ul.x = (uint32_t)__bfloat16_as_ushort(l0) | ((uint32_t)__bfloat16_as_ushort(l1) << 16);
    ul.y = (uint32_t)__bfloat16_as_ushort(l2) | ((uint32_t)__bfloat16_as_ushort(l3) << 16);
    ((uint2*)hi)[i] = uh;
    ((uint2*)lo)[i] = ul;
}

// ---------------------------------------------------------------------------
// bf16x3 MMA GEMM:  C[M,N] = A[M,K] * B[N,K]^T, fp32 out.
// A,B given as bf16 hi/lo pairs. Block 128x128, BK=32, 256 thr,
// warp tile 64x32 (warps 2x4), mma.sync m16n8k16 + ldmatrix.
// ---------------------------------------------------------------------------
#define PITCH 40   // bf16 elems per smem row (80B) -> conflict-free LDSM

__device__ __forceinline__ uint32_t smem_u32(const void* p) {
    uint32_t a;
    asm("{ .reg .u64 t; cvta.to.shared.u64 t, %1; cvt.u32.u64 %0, t; }"
        : "=r"(a) : "l"(p));
    return a;
}

#define LDSM4(R0,R1,R2,R3,ADDR) \
    asm volatile("ldmatrix.sync.aligned.m8n8.x4.shared.b16 {%0,%1,%2,%3}, [%4];" \
                 : "=r"(R0), "=r"(R1), "=r"(R2), "=r"(R3) : "r"(ADDR))

#define MMA16816(C, A, B0, B1) \
    asm volatile("mma.sync.aligned.m16n8k16.row.col.f32.bf16.bf16.f32 " \
                 "{%0,%1,%2,%3}, {%4,%5,%6,%7}, {%8,%9}, {%0,%1,%2,%3};" \
                 : "+f"((C)[0]), "+f"((C)[1]), "+f"((C)[2]), "+f"((C)[3]) \
                 : "r"((A)[0]), "r"((A)[1]), "r"((A)[2]), "r"((A)[3]), \
                   "r"(B0), "r"(B1))

__global__ __launch_bounds__(256, 1)
void gemm_mma(const __nv_bfloat16* __restrict__ Ah, const __nv_bfloat16* __restrict__ Al,
              const __nv_bfloat16* __restrict__ Bh, const __nv_bfloat16* __restrict__ Bl,
              float* __restrict__ C, int M, int N, int K)
{
    __shared__ __align__(16) __nv_bfloat16 sm[4][128 * PITCH]; // Ah, Al, Bh, Bl

    const int tid  = threadIdx.x;
    const int wid  = tid >> 5;
    const int lane = tid & 31;
    const int wm   = wid >> 2;      // 0..1 -> rows wm*64
    const int wn   = wid & 3;       // 0..3 -> cols wn*32

    const int bm = blockIdx.y * 128;
    const int bn = blockIdx.x * 128;

    const uint32_t uAh = smem_u32(sm[0]);
    const uint32_t uAl = smem_u32(sm[1]);
    const uint32_t uBh = smem_u32(sm[2]);
    const uint32_t uBl = smem_u32(sm[3]);

    // ldmatrix per-lane element offsets (in bf16 elems)
    const int aoff = (wm * 64 + (lane & 15)) * PITCH + ((lane >> 4) << 3);
    const int boff = (wn * 32 + ((lane >> 4) << 3) + (lane & 7)) * PITCH + (((lane >> 3) & 1) << 3);

    // gmem->smem: 512 16B-chunks per array, 2 per thread
    const int r0 = (tid + 0)   >> 2, c0 = ((tid + 0)   & 3) << 3;
    const int r1 = (tid + 256) >> 2, c1 = ((tid + 256) & 3) << 3;

    float c[4][4][4];
#pragma unroll
    for (int a = 0; a < 4; a++)
#pragma unroll
        for (int b = 0; b < 4; b++)
#pragma unroll
            for (int d = 0; d < 4; d++) c[a][b][d] = 0.f;

    const int nk = K >> 5;
#pragma unroll 1
    for (int kt = 0; kt < nk; kt++) {
        const int k0 = kt << 5;
        {
            const __nv_bfloat16* gA0h = Ah + (size_t)(bm + r0) * K + k0 + c0;
            const __nv_bfloat16* gA1h = Ah + (size_t)(bm + r1) * K + k0 + c1;
            const __nv_bfloat16* gA0l = Al + (size_t)(bm + r0) * K + k0 + c0;
            const __nv_bfloat16* gA1l = Al + (size_t)(bm + r1) * K + k0 + c1;
            const __nv_bfloat16* gB0h = Bh + (size_t)(bn + r0) * K + k0 + c0;
            const __nv_bfloat16* gB1h = Bh + (size_t)(bn + r1) * K + k0 + c1;
            const __nv_bfloat16* gB0l = Bl + (size_t)(bn + r0) * K + k0 + c0;
            const __nv_bfloat16* gB1l = Bl + (size_t)(bn + r1) * K + k0 + c1;
            *(uint4*)&sm[0][r0 * PITCH + c0] = *(const uint4*)gA0h;
            *(uint4*)&sm[0][r1 * PITCH + c1] = *(const uint4*)gA1h;
            *(uint4*)&sm[1][r0 * PITCH + c0] = *(const uint4*)gA0l;
            *(uint4*)&sm[1][r1 * PITCH + c1] = *(const uint4*)gA1l;
            *(uint4*)&sm[2][r0 * PITCH + c0] = *(const uint4*)gB0h;
            *(uint4*)&sm[2][r1 * PITCH + c1] = *(const uint4*)gB1h;
            *(uint4*)&sm[3][r0 * PITCH + c0] = *(const uint4*)gB0l;
            *(uint4*)&sm[3][r1 * PITCH + c1] = *(const uint4*)gB1l;
        }
        __syncthreads();

#pragma unroll
        for (int kk = 0; kk < 32; kk += 16) {
            uint32_t ah[4][4], al[4][4], bh[4][2], bl[4][2];
#pragma unroll
            for (int ms = 0; ms < 4; ms++) {
                LDSM4(ah[ms][0], ah[ms][1], ah[ms][2], ah[ms][3],
                      uAh + 2 * (aoff + ms * 16 * PITCH + kk));
                LDSM4(al[ms][0], al[ms][1], al[ms][2], al[ms][3],
                      uAl + 2 * (aoff + ms * 16 * PITCH + kk));
            }
#pragma unroll
            for (int g = 0; g < 2; g++) {
                uint32_t t0, t1, t2, t3;
                LDSM4(t0, t1, t2, t3, uBh + 2 * (boff + g * 16 * PITCH + kk));
                bh[2*g][0] = t0; bh[2*g][1] = t1; bh[2*g+1][0] = t2; bh[2*g+1][1] = t3;
                LDSM4(t0, t1, t2, t3, uBl + 2 * (boff + g * 16 * PITCH + kk));
                bl[2*g][0] = t0; bl[2*g][1] = t1; bl[2*g+1][0] = t2; bl[2*g+1][1] = t3;
            }
#pragma unroll
            for (int ms = 0; ms < 4; ms++)
#pragma unroll
                for (int ng = 0; ng < 4; ng++) {
                    MMA16816(c[ms][ng], ah[ms], bh[ng][0], bh[ng][1]);
                    MMA16816(c[ms][ng], ah[ms], bl[ng][0], bl[ng][1]);
                    MMA16816(c[ms][ng], al[ms], bh[ng][0], bh[ng][1]);
                }
        }
        __syncthreads();
    }

    // epilogue
#pragma unroll
    for (int ms = 0; ms < 4; ms++) {
        const int row = bm + wm * 64 + ms * 16 + (lane >> 2);
#pragma unroll
        for (int ng = 0; ng < 4; ng++) {
            const int col = bn + wn * 32 + ng * 8 + (lane & 3) * 2;
            *(float2*)(C + (size_t)row * N + col)       = make_float2(c[ms][ng][0], c[ms][ng][1]);
            *(float2*)(C + (size_t)(row + 8) * N + col) = make_float2(c[ms][ng][2], c[ms][ng][3]);
        }
    }
}

// ---------------------------------------------------------------------------
// In-place RoPE on [B,S,nheads,64] buffer.
// ---------------------------------------------------------------------------
__global__ void rope_kernel(float* __restrict__ buf,
                            const float* __restrict__ cosv,
                            const float* __restrict__ sinv,
                            int nheads)
{
    int i = blockIdx.x * blockDim.x + threadIdx.x;
    int total = BATCH * SEQ * nheads * 32;
    if (i >= total) return;
    int d = i & 31;
    int h = (i >> 5) % nheads;
    int s = (i / (32 * nheads)) % SEQ;
    int b = i / (32 * nheads * SEQ);

    float* p = buf + (((size_t)b * SEQ + s) * nheads + h) * HDIM;
    float c0 = cosv[s * HDIM + d];
    float c1 = cosv[s * HDIM + d + 32];
    float s0 = sinv[s * HDIM + d];
    float s1 = sinv[s * HDIM + d + 32];
    float x0 = p[d];
    float x1 = p[d + 32];
    p[d]      = x0 * c0 - x1 * s0;
    p[d + 32] = x1 * c1 + x0 * s1;
}

// ---------------------------------------------------------------------------
// Causal flash attention, GQA (4 q-heads per kv-head). 1 thread = 1 query row.
// ---------------------------------------------------------------------------
__global__ __launch_bounds__(128) void attn_kernel(const float* __restrict__ Q,
                                                   const float* __restrict__ K,
                                                   const float* __restrict__ V,
                                                   float* __restrict__ O)
{
    __shared__ float Ks[64][64];
    __shared__ float Vs[64][64];

    const int tid = threadIdx.x;
    const int q0  = blockIdx.x * 128;
    const int h   = blockIdx.y;
    const int b   = blockIdx.z;
    const int kvh = h >> 2;
    const int qi  = q0 + tid;

    const float4* qptr = (const float4*)(Q + (((size_t)b * SEQ + qi) * NHEADS + h) * HDIM);
    float4 qv[16];
#pragma unroll
    for (int i = 0; i < 16; i++) qv[i] = qptr[i];

    float4 av[16];
#pragma unroll
    for (int i = 0; i < 16; i++) av[i] = make_float4(0.f, 0.f, 0.f, 0.f);

    float mi = -1e30f, li = 0.f;

    const int nkb = q0 / 64 + 2;
    for (int kb = 0; kb < nkb; kb++) {
        const float* kbase = K + (((size_t)b * SEQ + kb * 64) * NKV + kvh) * HDIM;
        const float* vbase = V + (((size_t)b * SEQ + kb * 64) * NKV + kvh) * HDIM;
#pragma unroll
        for (int i = tid; i < 64 * 16; i += 128) {
            int r = i >> 4;
            int c = i & 15;
            ((float4*)Ks[r])[c] = ((const float4*)(kbase + (size_t)r * KVDIM))[c];
            ((float4*)Vs[r])[c] = ((const float4*)(vbase + (size_t)r * KVDIM))[c];
        }
        __syncthreads();

#pragma unroll 1
        for (int n0 = 0; n0 < 64; n0 += 16) {
            float pk[16];
            float cmax = -1e30f;
#pragma unroll
            for (int j = 0; j < 16; j++) {
                const int kidx = kb * 64 + n0 + j;
                const float4* kr = (const float4*)Ks[n0 + j];
                float4 a4 = make_float4(0.f, 0.f, 0.f, 0.f);
#pragma unroll
                for (int k4 = 0; k4 < 16; k4++) {
                    float4 kk4 = kr[k4];
                    a4.x += qv[k4].x * kk4.x;
                    a4.y += qv[k4].y * kk4.y;
                    a4.z += qv[k4].z * kk4.z;
                    a4.w += qv[k4].w * kk4.w;
                }
                float sc = (a4.x + a4.y + a4.z + a4.w) * 0.125f;
                sc = (kidx <= qi) ? sc : -1e30f;
                pk[j] = sc;
                cmax = fmaxf(cmax, sc);
            }
            float mnew  = fmaxf(mi, cmax);
            float scale = __expf(mi - mnew);
            float psum  = 0.f;
#pragma unroll
            for (int j = 0; j < 16; j++) {
                pk[j] = __expf(pk[j] - mnew);
                psum += pk[j];
            }
            li = li * scale + psum;
#pragma unroll
            for (int i = 0; i < 16; i++) {
                av[i].x *= scale; av[i].y *= scale;
                av[i].z *= scale; av[i].w *= scale;
            }
#pragma unroll
            for (int j = 0; j < 16; j++) {
                const float4* vr = (const float4*)Vs[n0 + j];
                const float p = pk[j];
#pragma unroll
                for (int k4 = 0; k4 < 16; k4++) {
                    float4 v4 = vr[k4];
                    av[k4].x += p * v4.x;
                    av[k4].y += p * v4.y;
                    av[k4].z += p * v4.z;
                    av[k4].w += p * v4.w;
                }
            }
            mi = mnew;
        }
        __syncthreads();
    }

    const float inv = 1.f / li;
    float4* optr = (float4*)(O + (((size_t)b * SEQ + qi) * NHEADS + h) * HDIM);
#pragma unroll
    for (int i = 0; i < 16; i++)
        optr[i] = make_float4(av[i].x * inv, av[i].y * inv, av[i].z * inv, av[i].w * inv);
}

// ---------------------------------------------------------------------------
extern "C" void kernel_launch(void* const* d_in, const int* in_sizes, int n_in,
                              void* d_out, int out_size)
{
    const float* x    = (const float*)d_in[0];
    const float* fcos = (const float*)d_in[1];
    const float* fsin = (const float*)d_in[2];
    const float* wq   = (const float*)d_in[3];
    const float* wk   = (const float*)d_in[4];
    const float* wv   = (const float*)d_in[5];
    const float* wo   = (const float*)d_in[6];
    float* out = (float*)d_out;

    float *Qp, *Kp, *Vp, *Op;
    __nv_bfloat16* bf;
    cudaGetSymbolAddress((void**)&Qp, g_Q);
    cudaGetSymbolAddress((void**)&Kp, g_K);
    cudaGetSymbolAddress((void**)&Vp, g_V);
    cudaGetSymbolAddress((void**)&Op, g_O);
    cudaGetSymbolAddress((void**)&bf, g_bf);

    const int M = BATCH * SEQ;

    // fp32 -> bf16 hi/lo prepass
    split_kernel<<<(int)(N_X/4 + 255) / 256, 256>>>(x,  bf + OFF_XH,  bf + OFF_XL,  (int)(N_X/4));
    split_kernel<<<(int)(N_WQ/4 + 255) / 256, 256>>>(wq, bf + OFF_WQH, bf + OFF_WQL, (int)(N_WQ/4));
    split_kernel<<<(int)(N_WK/4 + 255) / 256, 256>>>(wk, bf + OFF_WKH, bf + OFF_WKL, (int)(N_WK/4));
    split_kernel<<<(int)(N_WV/4 + 255) / 256, 256>>>(wv, bf + OFF_WVH, bf + OFF_WVL, (int)(N_WV/4));
    split_kernel<<<(int)(N_WO/4 + 255) / 256, 256>>>(wo, bf + OFF_WOH, bf + OFF_WOL, (int)(N_WO/4));

    // QKV projections
    gemm_mma<<<dim3(EMBED / 128, M / 128), 256>>>(bf + OFF_XH, bf + OFF_XL,
                                                  bf + OFF_WQH, bf + OFF_WQL, Qp, M, EMBED, EMBED);
    gemm_mma<<<dim3(KVDIM / 128, M / 128), 256>>>(bf + OFF_XH, bf + OFF_XL,
                                                  bf + OFF_WKH, bf + OFF_WKL, Kp, M, KVDIM, EMBED);
    gemm_mma<<<dim3(KVDIM / 128, M / 128), 256>>>(bf + OFF_XH, bf + OFF_XL,
                                                  bf + OFF_WVH, bf + OFF_WVL, Vp, M, KVDIM, EMBED);

    // RoPE
    int tq = BATCH * SEQ * NHEADS * 32;
    rope_kernel<<<(tq + 255) / 256, 256>>>(Qp, fcos, fsin, NHEADS);
    int tk = BATCH * SEQ * NKV * 32;
    rope_kernel<<<(tk + 255) / 256, 256>>>(Kp, fcos, fsin, NKV);

    // Attention
    attn_kernel<<<dim3(SEQ / 128, NHEADS, BATCH), 128>>>(Qp, Kp, Vp, Op);

    // Output projection
    split_kernel<<<(int)(N_X/4 + 255) / 256, 256>>>(Op, bf + OFF_OH, bf + OFF_OL, (int)(N_X/4));
    gemm_mma<<<dim3(EMBED / 128, M / 128), 256>>>(bf + OFF_OH, bf + OFF_OL,
                                                  bf + OFF_WOH, bf + OFF_WOL, out, M, EMBED, EMBED);
}

// round 4
// speedup vs baseline: 2.2679x; 1.6443x over previous
#include <cuda_runtime.h>
#include <cuda_bf16.h>
#include <cstdint>

#define BATCH 2
#define SEQ 2048
#define EMBED 2048
#define NHEADS 32
#define NKV 8
#define HDIM 64
#define KVDIM (NKV*HDIM)   // 512

// fp32 scratch
__device__ float g_Q[(size_t)BATCH*SEQ*EMBED];
__device__ float g_K[(size_t)BATCH*SEQ*KVDIM];
__device__ float g_V[(size_t)BATCH*SEQ*KVDIM];
__device__ float g_O[(size_t)BATCH*SEQ*EMBED];

// bf16 hi/lo pool
#define N_X   (size_t)8388608    // 2*2048*2048
#define N_WQ  (size_t)4194304
#define N_WK  (size_t)1048576
#define N_WV  (size_t)1048576
#define N_WO  (size_t)4194304
#define OFF_XH  (size_t)0
#define OFF_XL  (OFF_XH + N_X)
#define OFF_WQH (OFF_XL + N_X)
#define OFF_WQL (OFF_WQH + N_WQ)
#define OFF_WKH (OFF_WQL + N_WQ)
#define OFF_WKL (OFF_WKH + N_WK)
#define OFF_WVH (OFF_WKL + N_WK)
#define OFF_WVL (OFF_WVH + N_WV)
#define OFF_WOH (OFF_WVL + N_WV)
#define OFF_WOL (OFF_WOH + N_WO)
#define OFF_OH  (OFF_WOL + N_WO)
#define OFF_OL  (OFF_OH + N_X)
#define POOL_SZ (OFF_OL + N_X)
__device__ __nv_bfloat16 g_bf[POOL_SZ];

// ============================ common helpers ===============================
__device__ __forceinline__ uint32_t smem_u32(const void* p) {
    uint32_t a;
    asm("{ .reg .u64 t; cvta.to.shared.u64 t, %1; cvt.u32.u64 %0, t; }"
        : "=r"(a) : "l"(p));
    return a;
}

#define LDSM4(R0,R1,R2,R3,ADDR) \
    asm volatile("ldmatrix.sync.aligned.m8n8.x4.shared.b16 {%0,%1,%2,%3}, [%4];" \
                 : "=r"(R0), "=r"(R1), "=r"(R2), "=r"(R3) : "r"(ADDR))

#define MMA16816(C, A, B0, B1) \
    asm volatile("mma.sync.aligned.m16n8k16.row.col.f32.bf16.bf16.f32 " \
                 "{%0,%1,%2,%3}, {%4,%5,%6,%7}, {%8,%9}, {%0,%1,%2,%3};" \
                 : "+f"((C)[0]), "+f"((C)[1]), "+f"((C)[2]), "+f"((C)[3]) \
                 : "r"((A)[0]), "r"((A)[1]), "r"((A)[2]), "r"((A)[3]), \
                   "r"(B0), "r"(B1))

__device__ __forceinline__ uint32_t pack_bf16x2(float lo, float hi) {
    uint32_t d;
    asm("cvt.rn.bf16x2.f32 %0, %1, %2;" : "=r"(d) : "f"(hi), "f"(lo));
    return d;
}

__device__ __forceinline__ void split4(float4 v, uint2& uh, uint2& ul) {
    __nv_bfloat16 h0 = __float2bfloat16_rn(v.x);
    __nv_bfloat16 h1 = __float2bfloat16_rn(v.y);
    __nv_bfloat16 h2 = __float2bfloat16_rn(v.z);
    __nv_bfloat16 h3 = __float2bfloat16_rn(v.w);
    __nv_bfloat16 l0 = __float2bfloat16_rn(v.x - __bfloat162float(h0));
    __nv_bfloat16 l1 = __float2bfloat16_rn(v.y - __bfloat162float(h1));
    __nv_bfloat16 l2 = __float2bfloat16_rn(v.z - __bfloat162float(h2));
    __nv_bfloat16 l3 = __float2bfloat16_rn(v.w - __bfloat162float(h3));
    uh.x = (uint32_t)__bfloat16_as_ushort(h0) | ((uint32_t)__bfloat16_as_ushort(h1) << 16);
    uh.y = (uint32_t)__bfloat16_as_ushort(h2) | ((uint32_t)__bfloat16_as_ushort(h3) << 16);
    ul.x = (uint32_t)__bfloat16_as_ushort(l0) | ((uint32_t)__bfloat16_as_ushort(l1) << 16);
    ul.y = (uint32_t)__bfloat16_as_ushort(l2) | ((uint32_t)__bfloat16_as_ushort(l3) << 16);
}

// ---------------------------------------------------------------------------
// fp32 -> (bf16 hi, bf16 lo) split prepass. n4 = elements/4.
// ---------------------------------------------------------------------------
__global__ void split_kernel(const float* __restrict__ in,
                             __nv_bfloat16* __restrict__ hi,
                             __nv_bfloat16* __restrict__ lo, int n4)
{
    int i = blockIdx.x * blockDim.x + threadIdx.x;
    if (i >= n4) return;
    float4 v = ((const float4*)in)[i];
    uint2 uh, ul;
    split4(v, uh, ul);
    ((uint2*)hi)[i] = uh;
    ((uint2*)lo)[i] = ul;
}

// ---------------------------------------------------------------------------
// bf16x3 MMA GEMM:  C[M,N] = A[M,K] * B[N,K]^T, fp32 out.
// ---------------------------------------------------------------------------
#define PITCH 40   // bf16 elems per smem row (80B) -> conflict-free LDSM

__global__ __launch_bounds__(256, 1)
void gemm_mma(const __nv_bfloat16* __restrict__ Ah, const __nv_bfloat16* __restrict__ Al,
              const __nv_bfloat16* __restrict__ Bh, const __nv_bfloat16* __restrict__ Bl,
              float* __restrict__ C, int M, int N, int K)
{
    __shared__ __align__(16) __nv_bfloat16 sm[4][128 * PITCH]; // Ah, Al, Bh, Bl

    const int tid  = threadIdx.x;
    const int wid  = tid >> 5;
    const int lane = tid & 31;
    const int wm   = wid >> 2;
    const int wn   = wid & 3;

    const int bm = blockIdx.y * 128;
    const int bn = blockIdx.x * 128;

    const uint32_t uAh = smem_u32(sm[0]);
    const uint32_t uAl = smem_u32(sm[1]);
    const uint32_t uBh = smem_u32(sm[2]);
    const uint32_t uBl = smem_u32(sm[3]);

    const int aoff = (wm * 64 + (lane & 15)) * PITCH + ((lane >> 4) << 3);
    const int boff = (wn * 32 + ((lane >> 4) << 3) + (lane & 7)) * PITCH + (((lane >> 3) & 1) << 3);

    const int r0 = (tid + 0)   >> 2, c0 = ((tid + 0)   & 3) << 3;
    const int r1 = (tid + 256) >> 2, c1 = ((tid + 256) & 3) << 3;

    float c[4][4][4];
#pragma unroll
    for (int a = 0; a < 4; a++)
#pragma unroll
        for (int b = 0; b < 4; b++)
#pragma unroll
            for (int d = 0; d < 4; d++) c[a][b][d] = 0.f;

    const int nk = K >> 5;
#pragma unroll 1
    for (int kt = 0; kt < nk; kt++) {
        const int k0 = kt << 5;
        {
            *(uint4*)&sm[0][r0 * PITCH + c0] = *(const uint4*)(Ah + (size_t)(bm + r0) * K + k0 + c0);
            *(uint4*)&sm[0][r1 * PITCH + c1] = *(const uint4*)(Ah + (size_t)(bm + r1) * K + k0 + c1);
            *(uint4*)&sm[1][r0 * PITCH + c0] = *(const uint4*)(Al + (size_t)(bm + r0) * K + k0 + c0);
            *(uint4*)&sm[1][r1 * PITCH + c1] = *(const uint4*)(Al + (size_t)(bm + r1) * K + k0 + c1);
            *(uint4*)&sm[2][r0 * PITCH + c0] = *(const uint4*)(Bh + (size_t)(bn + r0) * K + k0 + c0);
            *(uint4*)&sm[2][r1 * PITCH + c1] = *(const uint4*)(Bh + (size_t)(bn + r1) * K + k0 + c1);
            *(uint4*)&sm[3][r0 * PITCH + c0] = *(const uint4*)(Bl + (size_t)(bn + r0) * K + k0 + c0);
            *(uint4*)&sm[3][r1 * PITCH + c1] = *(const uint4*)(Bl + (size_t)(bn + r1) * K + k0 + c1);
        }
        __syncthreads();

#pragma unroll
        for (int kk = 0; kk < 32; kk += 16) {
            uint32_t ah[4][4], al[4][4], bh[4][2], bl[4][2];
#pragma unroll
            for (int ms = 0; ms < 4; ms++) {
                LDSM4(ah[ms][0], ah[ms][1], ah[ms][2], ah[ms][3],
                      uAh + 2 * (aoff + ms * 16 * PITCH + kk));
                LDSM4(al[ms][0], al[ms][1], al[ms][2], al[ms][3],
                      uAl + 2 * (aoff + ms * 16 * PITCH + kk));
            }
#pragma unroll
            for (int g = 0; g < 2; g++) {
                uint32_t t0, t1, t2, t3;
                LDSM4(t0, t1, t2, t3, uBh + 2 * (boff + g * 16 * PITCH + kk));
                bh[2*g][0] = t0; bh[2*g][1] = t1; bh[2*g+1][0] = t2; bh[2*g+1][1] = t3;
                LDSM4(t0, t1, t2, t3, uBl + 2 * (boff + g * 16 * PITCH + kk));
                bl[2*g][0] = t0; bl[2*g][1] = t1; bl[2*g+1][0] = t2; bl[2*g+1][1] = t3;
            }
#pragma unroll
            for (int ms = 0; ms < 4; ms++)
#pragma unroll
                for (int ng = 0; ng < 4; ng++) {
                    MMA16816(c[ms][ng], ah[ms], bh[ng][0], bh[ng][1]);
                    MMA16816(c[ms][ng], ah[ms], bl[ng][0], bl[ng][1]);
                    MMA16816(c[ms][ng], al[ms], bh[ng][0], bh[ng][1]);
                }
        }
        __syncthreads();
    }

#pragma unroll
    for (int ms = 0; ms < 4; ms++) {
        const int row = bm + wm * 64 + ms * 16 + (lane >> 2);
#pragma unroll
        for (int ng = 0; ng < 4; ng++) {
            const int col = bn + wn * 32 + ng * 8 + (lane & 3) * 2;
            *(float2*)(C + (size_t)row * N + col)       = make_float2(c[ms][ng][0], c[ms][ng][1]);
            *(float2*)(C + (size_t)(row + 8) * N + col) = make_float2(c[ms][ng][2], c[ms][ng][3]);
        }
    }
}

// ---------------------------------------------------------------------------
// In-place RoPE on [B,S,nheads,64] buffer.
// ---------------------------------------------------------------------------
__global__ void rope_kernel(float* __restrict__ buf,
                            const float* __restrict__ cosv,
                            const float* __restrict__ sinv,
                            int nheads)
{
    int i = blockIdx.x * blockDim.x + threadIdx.x;
    int total = BATCH * SEQ * nheads * 32;
    if (i >= total) return;
    int d = i & 31;
    int h = (i >> 5) % nheads;
    int s = (i / (32 * nheads)) % SEQ;
    int b = i / (32 * nheads * SEQ);

    float* p = buf + (((size_t)b * SEQ + s) * nheads + h) * HDIM;
    float c0 = cosv[s * HDIM + d];
    float c1 = cosv[s * HDIM + d + 32];
    float s0 = sinv[s * HDIM + d];
    float s1 = sinv[s * HDIM + d + 32];
    float x0 = p[d];
    float x1 = p[d + 32];
    p[d]      = x0 * c0 - x1 * s0;
    p[d + 32] = x1 * c1 + x0 * s1;
}

// ---------------------------------------------------------------------------
// Tensor-core causal flash attention (FA2 style), GQA 4:1.
// Block: 128 q-rows of one (b,h). 8 warps x 16 rows. 64-key blocks.
// QK^T: bf16x3 (Qh*Kh + Qh*Kl + Ql*Kh); PV: Ph*Vh + Ph*Vl + Pl*Vh.
// ---------------------------------------------------------------------------
#define APITCH 72   // bf16 elems per smem row (144B) -> conflict-free LDSM

__global__ __launch_bounds__(256, 1)
void attn_mma(const float* __restrict__ Q, const float* __restrict__ K,
              const float* __restrict__ V, float* __restrict__ O)
{
    __shared__ __align__(16) __nv_bfloat16 smh[128 * APITCH];
    __shared__ __align__(16) __nv_bfloat16 sml[128 * APITCH];

    const int tid  = threadIdx.x;
    const int wid  = tid >> 5;
    const int lane = tid & 31;
    const int t = blockIdx.x;
    const int h = blockIdx.y;
    const int b = blockIdx.z;
    const int kvh = h >> 2;

    const uint32_t uH = smem_u32(smh);
    const uint32_t uL = smem_u32(sml);

    // ---- stage Q (128x64 fp32 -> bf16 hi/lo smem), then ldmatrix frags ----
    {
        const int qrow = tid >> 1;
        const int qcol = (tid & 1) * 32;
        const float4* qg = (const float4*)(Q +
            (((size_t)b * SEQ + t * 128 + qrow) * NHEADS + h) * HDIM + qcol);
#pragma unroll
        for (int i = 0; i < 8; i++) {
            uint2 uh, ul;
            split4(qg[i], uh, ul);
            *(uint2*)&smh[qrow * APITCH + qcol + i * 4] = uh;
            *(uint2*)&sml[qrow * APITCH + qcol + i * 4] = ul;
        }
    }
    __syncthreads();

    uint32_t qh[4][4], ql[4][4];
    {
        const int aoff = (wid * 16 + (lane & 15)) * APITCH + ((lane >> 4) << 3);
#pragma unroll
        for (int kk = 0; kk < 4; kk++) {
            LDSM4(qh[kk][0], qh[kk][1], qh[kk][2], qh[kk][3], uH + 2 * (aoff + kk * 16));
            LDSM4(ql[kk][0], ql[kk][1], ql[kk][2], ql[kk][3], uL + 2 * (aoff + kk * 16));
        }
    }
    __syncthreads();

    float o[8][4];
#pragma unroll
    for (int nt = 0; nt < 8; nt++)
#pragma unroll
        for (int e = 0; e < 4; e++) o[nt][e] = 0.f;
    float mi0 = -1e30f, mi1 = -1e30f, li0 = 0.f, li1 = 0.f;

    const int row0 = t * 128 + wid * 16 + (lane >> 2);
    const int row1 = row0 + 8;

    const int nkb = 2 * t + 2;
    for (int kb = 0; kb < nkb; kb++) {
        // ---- load + convert K (rows 0..63) and V^T (rows 64..127) ----
        {
            const int key = tid >> 2;
            const int dbase = (tid & 3) * 16;
            const float4* kg = (const float4*)(K +
                (((size_t)b * SEQ + kb * 64 + key) * NKV + kvh) * HDIM + dbase);
#pragma unroll
            for (int i = 0; i < 4; i++) {
                uint2 uh, ul;
                split4(kg[i], uh, ul);
                *(uint2*)&smh[key * APITCH + dbase + i * 4] = uh;
                *(uint2*)&sml[key * APITCH + dbase + i * 4] = ul;
            }
        }
        {
            const int key = tid & 63;
            const int dbase = (tid >> 6) * 16;
            const float4* vg = (const float4*)(V +
                (((size_t)b * SEQ + kb * 64 + key) * NKV + kvh) * HDIM + dbase);
#pragma unroll
            for (int i = 0; i < 4; i++) {
                float4 v = vg[i];
                float vv[4] = {v.x, v.y, v.z, v.w};
#pragma unroll
                for (int e = 0; e < 4; e++) {
                    __nv_bfloat16 hh = __float2bfloat16_rn(vv[e]);
                    __nv_bfloat16 ll = __float2bfloat16_rn(vv[e] - __bfloat162float(hh));
                    const int d = dbase + i * 4 + e;
                    smh[(64 + d) * APITCH + key] = hh;
                    sml[(64 + d) * APITCH + key] = ll;
                }
            }
        }
        __syncthreads();

        // ---- S = Q K^T (bf16x3) ----
        float s[8][4];
#pragma unroll
        for (int nt = 0; nt < 8; nt++)
#pragma unroll
            for (int e = 0; e < 4; e++) s[nt][e] = 0.f;

#pragma unroll
        for (int kk = 0; kk < 4; kk++) {
            uint32_t bh[8][2], bl[8][2];
#pragma unroll
            for (int g = 0; g < 4; g++) {
                const int off = (g * 16 + ((lane >> 4) << 3) + (lane & 7)) * APITCH
                              + (((lane >> 3) & 1) << 3) + kk * 16;
                uint32_t t0, t1, t2, t3;
                LDSM4(t0, t1, t2, t3, uH + 2 * off);
                bh[2*g][0] = t0; bh[2*g][1] = t1; bh[2*g+1][0] = t2; bh[2*g+1][1] = t3;
                LDSM4(t0, t1, t2, t3, uL + 2 * off);
                bl[2*g][0] = t0; bl[2*g][1] = t1; bl[2*g+1][0] = t2; bl[2*g+1][1] = t3;
            }
#pragma unroll
            for (int nt = 0; nt < 8; nt++) {
                MMA16816(s[nt], qh[kk], bh[nt][0], bh[nt][1]);
                MMA16816(s[nt], qh[kk], bl[nt][0], bl[nt][1]);
                MMA16816(s[nt], ql[kk], bh[nt][0], bh[nt][1]);
            }
        }

        // scale + causal mask
        const bool diag = (kb >= 2 * t);
#pragma unroll
        for (int nt = 0; nt < 8; nt++) {
            const int col = kb * 64 + nt * 8 + (lane & 3) * 2;
            s[nt][0] *= 0.125f; s[nt][1] *= 0.125f;
            s[nt][2] *= 0.125f; s[nt][3] *= 0.125f;
            if (diag) {
                if (col > row0)     s[nt][0] = -1e30f;
                if (col + 1 > row0) s[nt][1] = -1e30f;
                if (col > row1)     s[nt][2] = -1e30f;
                if (col + 1 > row1) s[nt][3] = -1e30f;
            }
        }

        // ---- online softmax ----
        float bm0 = -1e30f, bm1 = -1e30f;
#pragma unroll
        for (int nt = 0; nt < 8; nt++) {
            bm0 = fmaxf(bm0, fmaxf(s[nt][0], s[nt][1]));
            bm1 = fmaxf(bm1, fmaxf(s[nt][2], s[nt][3]));
        }
        bm0 = fmaxf(bm0, __shfl_xor_sync(0xffffffffu, bm0, 1));
        bm0 = fmaxf(bm0, __shfl_xor_sync(0xffffffffu, bm0, 2));
        bm1 = fmaxf(bm1, __shfl_xor_sync(0xffffffffu, bm1, 1));
        bm1 = fmaxf(bm1, __shfl_xor_sync(0xffffffffu, bm1, 2));

        const float mn0 = fmaxf(mi0, bm0);
        const float mn1 = fmaxf(mi1, bm1);
        const float sc0 = __expf(mi0 - mn0);
        const float sc1 = __expf(mi1 - mn1);

        float ls0 = 0.f, ls1 = 0.f;
#pragma unroll
        for (int nt = 0; nt < 8; nt++) {
            s[nt][0] = __expf(s[nt][0] - mn0);
            s[nt][1] = __expf(s[nt][1] - mn0);
            s[nt][2] = __expf(s[nt][2] - mn1);
            s[nt][3] = __expf(s[nt][3] - mn1);
            ls0 += s[nt][0] + s[nt][1];
            ls1 += s[nt][2] + s[nt][3];
        }
        ls0 += __shfl_xor_sync(0xffffffffu, ls0, 1);
        ls0 += __shfl_xor_sync(0xffffffffu, ls0, 2);
        ls1 += __shfl_xor_sync(0xffffffffu, ls1, 1);
        ls1 += __shfl_xor_sync(0xffffffffu, ls1, 2);

        li0 = li0 * sc0 + ls0;
        li1 = li1 * sc1 + ls1;
        mi0 = mn0; mi1 = mn1;

#pragma unroll
        for (int nt = 0; nt < 8; nt++) {
            o[nt][0] *= sc0; o[nt][1] *= sc0;
            o[nt][2] *= sc1; o[nt][3] *= sc1;
        }

        // ---- pack P to bf16 hi/lo fragments ----
        uint32_t ph[8][2], pl[8][2];
#pragma unroll
        for (int nt = 0; nt < 8; nt++) {
            uint32_t u0 = pack_bf16x2(s[nt][0], s[nt][1]);
            uint32_t u1 = pack_bf16x2(s[nt][2], s[nt][3]);
            ph[nt][0] = u0; ph[nt][1] = u1;
            float l00 = s[nt][0] - __uint_as_float(u0 << 16);
            float l01 = s[nt][1] - __uint_as_float(u0 & 0xffff0000u);
            float l10 = s[nt][2] - __uint_as_float(u1 << 16);
            float l11 = s[nt][3] - __uint_as_float(u1 & 0xffff0000u);
            pl[nt][0] = pack_bf16x2(l00, l01);
            pl[nt][1] = pack_bf16x2(l10, l11);
        }

        // ---- O += P V ----
#pragma unroll
        for (int kk = 0; kk < 4; kk++) {
            uint32_t vh[8][2], vl[8][2];
#pragma unroll
            for (int g = 0; g < 4; g++) {
                const int off = (64 + g * 16 + ((lane >> 4) << 3) + (lane & 7)) * APITCH
                              + (((lane >> 3) & 1) << 3) + kk * 16;
                uint32_t t0, t1, t2, t3;
                LDSM4(t0, t1, t2, t3, uH + 2 * off);
                vh[2*g][0] = t0; vh[2*g][1] = t1; vh[2*g+1][0] = t2; vh[2*g+1][1] = t3;
                LDSM4(t0, t1, t2, t3, uL + 2 * off);
                vl[2*g][0] = t0; vl[2*g][1] = t1; vl[2*g+1][0] = t2; vl[2*g+1][1] = t3;
            }
            uint32_t ah[4] = {ph[2*kk][0], ph[2*kk][1], ph[2*kk+1][0], ph[2*kk+1][1]};
            uint32_t al[4] = {pl[2*kk][0], pl[2*kk][1], pl[2*kk+1][0], pl[2*kk+1][1]};
#pragma unroll
            for (int nt = 0; nt < 8; nt++) {
                MMA16816(o[nt], ah, vh[nt][0], vh[nt][1]);
                MMA16816(o[nt], ah, vl[nt][0], vl[nt][1]);
                MMA16816(o[nt], al, vh[nt][0], vh[nt][1]);
            }
        }
        __syncthreads();
    }

    // ---- finalize ----
    const float inv0 = 1.f / li0;
    const float inv1 = 1.f / li1;
    float* o0 = O + (((size_t)b * SEQ + row0) * NHEADS + h) * HDIM;
    float* o1 = O + (((size_t)b * SEQ + row1) * NHEADS + h) * HDIM;
#pragma unroll
    for (int nt = 0; nt < 8; nt++) {
        const int col = nt * 8 + (lane & 3) * 2;
        *(float2*)(o0 + col) = make_float2(o[nt][0] * inv0, o[nt][1] * inv0);
        *(float2*)(o1 + col) = make_float2(o[nt][2] * inv1, o[nt][3] * inv1);
    }
}

// ---------------------------------------------------------------------------
extern "C" void kernel_launch(void* const* d_in, const int* in_sizes, int n_in,
                              void* d_out, int out_size)
{
    const float* x    = (const float*)d_in[0];
    const float* fcos = (const float*)d_in[1];
    const float* fsin = (const float*)d_in[2];
    const float* wq   = (const float*)d_in[3];
    const float* wk   = (const float*)d_in[4];
    const float* wv   = (const float*)d_in[5];
    const float* wo   = (const float*)d_in[6];
    float* out = (float*)d_out;

    float *Qp, *Kp, *Vp, *Op;
    __nv_bfloat16* bf;
    cudaGetSymbolAddress((void**)&Qp, g_Q);
    cudaGetSymbolAddress((void**)&Kp, g_K);
    cudaGetSymbolAddress((void**)&Vp, g_V);
    cudaGetSymbolAddress((void**)&Op, g_O);
    cudaGetSymbolAddress((void**)&bf, g_bf);

    const int M = BATCH * SEQ;

    // fp32 -> bf16 hi/lo prepass
    split_kernel<<<(int)(N_X/4 + 255) / 256, 256>>>(x,  bf + OFF_XH,  bf + OFF_XL,  (int)(N_X/4));
    split_kernel<<<(int)(N_WQ/4 + 255) / 256, 256>>>(wq, bf + OFF_WQH, bf + OFF_WQL, (int)(N_WQ/4));
    split_kernel<<<(int)(N_WK/4 + 255) / 256, 256>>>(wk, bf + OFF_WKH, bf + OFF_WKL, (int)(N_WK/4));
    split_kernel<<<(int)(N_WV/4 + 255) / 256, 256>>>(wv, bf + OFF_WVH, bf + OFF_WVL, (int)(N_WV/4));
    split_kernel<<<(int)(N_WO/4 + 255) / 256, 256>>>(wo, bf + OFF_WOH, bf + OFF_WOL, (int)(N_WO/4));

    // QKV projections
    gemm_mma<<<dim3(EMBED / 128, M / 128), 256>>>(bf + OFF_XH, bf + OFF_XL,
                                                  bf + OFF_WQH, bf + OFF_WQL, Qp, M, EMBED, EMBED);
    gemm_mma<<<dim3(KVDIM / 128, M / 128), 256>>>(bf + OFF_XH, bf + OFF_XL,
                                                  bf + OFF_WKH, bf + OFF_WKL, Kp, M, KVDIM, EMBED);
    gemm_mma<<<dim3(KVDIM / 128, M / 128), 256>>>(bf + OFF_XH, bf + OFF_XL,
                                                  bf + OFF_WVH, bf + OFF_WVL, Vp, M, KVDIM, EMBED);

    // RoPE
    int tq = BATCH * SEQ * NHEADS * 32;
    rope_kernel<<<(tq + 255) / 256, 256>>>(Qp, fcos, fsin, NHEADS);
    int tk = BATCH * SEQ * NKV * 32;
    rope_kernel<<<(tk + 255) / 256, 256>>>(Kp, fcos, fsin, NKV);

    // Tensor-core causal GQA flash attention
    attn_mma<<<dim3(SEQ / 128, NHEADS, BATCH), 256>>>(Qp, Kp, Vp, Op);

    // Output projection
    split_kernel<<<(int)(N_X/4 + 255) / 256, 256>>>(Op, bf + OFF_OH, bf + OFF_OL, (int)(N_X/4));
    gemm_mma<<<dim3(EMBED / 128, M / 128), 256>>>(bf + OFF_OH, bf + OFF_OL,
                                                  bf + OFF_WOH, bf + OFF_WOL, out, M, EMBED, EMBED);
}

// round 5
// speedup vs baseline: 3.1734x; 1.3992x over previous
#include <cuda_runtime.h>
#include <cuda_bf16.h>
#include <cstdint>

#define BATCH 2
#define SEQ 2048
#define EMBED 2048
#define NHEADS 32
#define NKV 8
#define HDIM 64
#define KVDIM (NKV*HDIM)   // 512

// fp32 scratch (gemm outputs)
__device__ float g_Q[(size_t)BATCH*SEQ*EMBED];
__device__ float g_K[(size_t)BATCH*SEQ*KVDIM];
__device__ float g_V[(size_t)BATCH*SEQ*KVDIM];

// bf16 hi/lo pool (gemm operands)
#define N_X   (size_t)8388608    // 2*2048*2048
#define N_WQ  (size_t)4194304
#define N_WK  (size_t)1048576
#define N_WV  (size_t)1048576
#define N_WO  (size_t)4194304
#define OFF_XH  (size_t)0
#define OFF_XL  (OFF_XH + N_X)
#define OFF_WQH (OFF_XL + N_X)
#define OFF_WQL (OFF_WQH + N_WQ)
#define OFF_WKH (OFF_WQL + N_WQ)
#define OFF_WKL (OFF_WKH + N_WK)
#define OFF_WVH (OFF_WKL + N_WK)
#define OFF_WVL (OFF_WVH + N_WV)
#define OFF_WOH (OFF_WVL + N_WV)
#define OFF_WOL (OFF_WOH + N_WO)
#define OFF_OH  (OFF_WOL + N_WO)
#define OFF_OL  (OFF_OH + N_X)
#define POOL_SZ (OFF_OL + N_X)
__device__ __nv_bfloat16 g_bf[POOL_SZ];

// bf16 attention operands
__device__ __nv_bfloat16 g_Qh[(size_t)BATCH*NHEADS*SEQ*HDIM];
__device__ __nv_bfloat16 g_Ql[(size_t)BATCH*NHEADS*SEQ*HDIM];
__device__ __nv_bfloat16 g_Kh[(size_t)BATCH*NKV*SEQ*HDIM];
__device__ __nv_bfloat16 g_Kl[(size_t)BATCH*NKV*SEQ*HDIM];
__device__ __nv_bfloat16 g_Vth[(size_t)BATCH*NKV*HDIM*SEQ];
__device__ __nv_bfloat16 g_Vtl[(size_t)BATCH*NKV*HDIM*SEQ];

// ============================ helpers ======================================
__device__ __forceinline__ uint32_t smem_u32(const void* p) {
    uint32_t a;
    asm("{ .reg .u64 t; cvta.to.shared.u64 t, %1; cvt.u32.u64 %0, t; }"
        : "=r"(a) : "l"(p));
    return a;
}

#define LDSM4(R0,R1,R2,R3,ADDR) \
    asm volatile("ldmatrix.sync.aligned.m8n8.x4.shared.b16 {%0,%1,%2,%3}, [%4];" \
                 : "=r"(R0), "=r"(R1), "=r"(R2), "=r"(R3) : "r"(ADDR))

#define MMA16816(C, A, B0, B1) \
    asm volatile("mma.sync.aligned.m16n8k16.row.col.f32.bf16.bf16.f32 " \
                 "{%0,%1,%2,%3}, {%4,%5,%6,%7}, {%8,%9}, {%0,%1,%2,%3};" \
                 : "+f"((C)[0]), "+f"((C)[1]), "+f"((C)[2]), "+f"((C)[3]) \
                 : "r"((A)[0]), "r"((A)[1]), "r"((A)[2]), "r"((A)[3]), \
                   "r"(B0), "r"(B1))

#define CP16(DST, SRC) \
    asm volatile("cp.async.cg.shared.global [%0], [%1], 16;" :: "r"(DST), "l"(SRC))
#define CP_COMMIT() asm volatile("cp.async.commit_group;")
#define CP_WAIT0()  asm volatile("cp.async.wait_group 0;")
#define CP_WAIT1()  asm volatile("cp.async.wait_group 1;")

__device__ __forceinline__ uint32_t pack_bf16x2(float lo, float hi) {
    uint32_t d;
    asm("cvt.rn.bf16x2.f32 %0, %1, %2;" : "=r"(d) : "f"(hi), "f"(lo));
    return d;
}

__device__ __forceinline__ void split4(float4 v, uint2& uh, uint2& ul) {
    __nv_bfloat16 h0 = __float2bfloat16_rn(v.x);
    __nv_bfloat16 h1 = __float2bfloat16_rn(v.y);
    __nv_bfloat16 h2 = __float2bfloat16_rn(v.z);
    __nv_bfloat16 h3 = __float2bfloat16_rn(v.w);
    __nv_bfloat16 l0 = __float2bfloat16_rn(v.x - __bfloat162float(h0));
    __nv_bfloat16 l1 = __float2bfloat16_rn(v.y - __bfloat162float(h1));
    __nv_bfloat16 l2 = __float2bfloat16_rn(v.z - __bfloat162float(h2));
    __nv_bfloat16 l3 = __float2bfloat16_rn(v.w - __bfloat162float(h3));
    uh.x = (uint32_t)__bfloat16_as_ushort(h0) | ((uint32_t)__bfloat16_as_ushort(h1) << 16);
    uh.y = (uint32_t)__bfloat16_as_ushort(h2) | ((uint32_t)__bfloat16_as_ushort(h3) << 16);
    ul.x = (uint32_t)__bfloat16_as_ushort(l0) | ((uint32_t)__bfloat16_as_ushort(l1) << 16);
    ul.y = (uint32_t)__bfloat16_as_ushort(l2) | ((uint32_t)__bfloat16_as_ushort(l3) << 16);
}

// ---------------------------------------------------------------------------
// fp32 -> (bf16 hi, bf16 lo) split prepass.
// ---------------------------------------------------------------------------
__global__ void split_kernel(const float* __restrict__ in,
                             __nv_bfloat16* __restrict__ hi,
                             __nv_bfloat16* __restrict__ lo, int n4)
{
    int i = blockIdx.x * blockDim.x + threadIdx.x;
    if (i >= n4) return;
    float4 v = ((const float4*)in)[i];
    uint2 uh, ul;
    split4(v, uh, ul);
    ((uint2*)hi)[i] = uh;
    ((uint2*)lo)[i] = ul;
}

// ---------------------------------------------------------------------------
// bf16x3 MMA GEMM, 3-stage cp.async pipeline.
// C[M,N] = A[M,K] * B[N,K]^T, fp32 out. Block 128x128, BK=32, 256 thr.
// ---------------------------------------------------------------------------
#define PITCH 40
#define G_ARR (128*PITCH)            // elems per array
#define G_STG (4*G_ARR)              // elems per stage
#define G_STG_B (G_STG*2)            // bytes per stage
#define G_SMEM (3*G_STG_B)           // 122880 B

__global__ __launch_bounds__(256, 1)
void gemm_mma(const __nv_bfloat16* __restrict__ Ah, const __nv_bfloat16* __restrict__ Al,
              const __nv_bfloat16* __restrict__ Bh, const __nv_bfloat16* __restrict__ Bl,
              float* __restrict__ C, int M, int N, int K)
{
    extern __shared__ __align__(16) char dsm_raw[];
    const uint32_t sbase = smem_u32(dsm_raw);

    const int tid  = threadIdx.x;
    const int wid  = tid >> 5;
    const int lane = tid & 31;
    const int wm   = wid >> 2;
    const int wn   = wid & 3;

    const int bm = blockIdx.y * 128;
    const int bn = blockIdx.x * 128;

    const int aoff = (wm * 64 + (lane & 15)) * PITCH + ((lane >> 4) << 3);
    const int boff = (wn * 32 + ((lane >> 4) << 3) + (lane & 7)) * PITCH + (((lane >> 3) & 1) << 3);

    const int nk = K >> 5;

    auto load_stage = [&](int kt, int stage) {
        const int k0 = kt << 5;
        const uint32_t sb = sbase + stage * G_STG_B;
#pragma unroll
        for (int q = 0; q < 8; q++) {
            int i = tid + q * 256;
            int a = i >> 9;
            int j = i & 511;
            int r = j >> 2;
            int cc = (j & 3) << 3;
            const __nv_bfloat16* g;
            if (a == 0)      g = Ah + (size_t)(bm + r) * K + k0 + cc;
            else if (a == 1) g = Al + (size_t)(bm + r) * K + k0 + cc;
            else if (a == 2) g = Bh + (size_t)(bn + r) * K + k0 + cc;
            else             g = Bl + (size_t)(bn + r) * K + k0 + cc;
            CP16(sb + (a * G_ARR + r * PITCH + cc) * 2, g);
        }
        CP_COMMIT();
    };

    float c[4][4][4];
#pragma unroll
    for (int a = 0; a < 4; a++)
#pragma unroll
        for (int b = 0; b < 4; b++)
#pragma unroll
            for (int d = 0; d < 4; d++) c[a][b][d] = 0.f;

    load_stage(0, 0);
    if (nk > 1) load_stage(1, 1);

#pragma unroll 1
    for (int kt = 0; kt < nk; kt++) {
        if (kt + 1 < nk) { CP_WAIT1(); } else { CP_WAIT0(); }
        __syncthreads();

        const uint32_t sb = sbase + (kt % 3) * G_STG_B;
        const uint32_t uAh = sb;
        const uint32_t uAl = sb + G_ARR * 2;
        const uint32_t uBh = sb + 2 * G_ARR * 2;
        const uint32_t uBl = sb + 3 * G_ARR * 2;

#pragma unroll
        for (int kk = 0; kk < 32; kk += 16) {
            uint32_t ah[4][4], al[4][4], bh[4][2], bl[4][2];
#pragma unroll
            for (int ms = 0; ms < 4; ms++) {
                LDSM4(ah[ms][0], ah[ms][1], ah[ms][2], ah[ms][3],
                      uAh + 2 * (aoff + ms * 16 * PITCH + kk));
                LDSM4(al[ms][0], al[ms][1], al[ms][2], al[ms][3],
                      uAl + 2 * (aoff + ms * 16 * PITCH + kk));
            }
#pragma unroll
            for (int g = 0; g < 2; g++) {
                uint32_t t0, t1, t2, t3;
                LDSM4(t0, t1, t2, t3, uBh + 2 * (boff + g * 16 * PITCH + kk));
                bh[2*g][0] = t0; bh[2*g][1] = t1; bh[2*g+1][0] = t2; bh[2*g+1][1] = t3;
                LDSM4(t0, t1, t2, t3, uBl + 2 * (boff + g * 16 * PITCH + kk));
                bl[2*g][0] = t0; bl[2*g][1] = t1; bl[2*g+1][0] = t2; bl[2*g+1][1] = t3;
            }
#pragma unroll
            for (int ms = 0; ms < 4; ms++)
#pragma unroll
                for (int ng = 0; ng < 4; ng++) {
                    MMA16816(c[ms][ng], ah[ms], bh[ng][0], bh[ng][1]);
                    MMA16816(c[ms][ng], ah[ms], bl[ng][0], bl[ng][1]);
                    MMA16816(c[ms][ng], al[ms], bh[ng][0], bh[ng][1]);
                }
        }

        if (kt + 2 < nk) load_stage(kt + 2, (kt + 2) % 3);
        __syncthreads();
    }

#pragma unroll
    for (int ms = 0; ms < 4; ms++) {
        const int row = bm + wm * 64 + ms * 16 + (lane >> 2);
#pragma unroll
        for (int ng = 0; ng < 4; ng++) {
            const int col = bn + wn * 32 + ng * 8 + (lane & 3) * 2;
            *(float2*)(C + (size_t)row * N + col)       = make_float2(c[ms][ng][0], c[ms][ng][1]);
            *(float2*)(C + (size_t)(row + 8) * N + col) = make_float2(c[ms][ng][2], c[ms][ng][3]);
        }
    }
}

// ---------------------------------------------------------------------------
// Fused RoPE + bf16 hi/lo split.  In: fp32 [b,s,nheads,64].
// Out: bf16 hi/lo [b,nheads,s,64].
// ---------------------------------------------------------------------------
__global__ void rope_split(const float* __restrict__ buf,
                           const float* __restrict__ cosv,
                           const float* __restrict__ sinv,
                           __nv_bfloat16* __restrict__ oh,
                           __nv_bfloat16* __restrict__ ol, int nheads)
{
    int i = blockIdx.x * blockDim.x + threadIdx.x;
    int total = BATCH * SEQ * nheads * 32;
    if (i >= total) return;
    int d = i & 31;
    int h = (i >> 5) % nheads;
    int s = (i / (32 * nheads)) % SEQ;
    int b = i / (32 * nheads * SEQ);

    const float* p = buf + (((size_t)b * SEQ + s) * nheads + h) * HDIM;
    float c0 = cosv[s * HDIM + d];
    float c1 = cosv[s * HDIM + d + 32];
    float s0 = sinv[s * HDIM + d];
    float s1 = sinv[s * HDIM + d + 32];
    float x0 = p[d];
    float x1 = p[d + 32];
    float y0 = x0 * c0 - x1 * s0;
    float y1 = x1 * c1 + x0 * s1;

    size_t o = (((size_t)b * nheads + h) * SEQ + s) * HDIM;
    __nv_bfloat16 h0 = __float2bfloat16_rn(y0);
    __nv_bfloat16 h1 = __float2bfloat16_rn(y1);
    oh[o + d]      = h0;
    oh[o + d + 32] = h1;
    ol[o + d]      = __float2bfloat16_rn(y0 - __bfloat162float(h0));
    ol[o + d + 32] = __float2bfloat16_rn(y1 - __bfloat162float(h1));
}

// ---------------------------------------------------------------------------
// V fp32 [b,s,8,64] -> V^T bf16 hi/lo [b,kvh,d,s]  (64x64 smem tile transpose)
// ---------------------------------------------------------------------------
__global__ __launch_bounds__(256) void split_v_t(const float* __restrict__ V,
                                                 __nv_bfloat16* __restrict__ vth,
                                                 __nv_bfloat16* __restrict__ vtl)
{
    __shared__ __nv_bfloat16 th[64][68];
    __shared__ __nv_bfloat16 tl[64][68];
    const int s0  = blockIdx.x * 64;
    const int kvh = blockIdx.y;
    const int b   = blockIdx.z;

    {
        const int r  = threadIdx.x >> 2;
        const int cb = (threadIdx.x & 3) * 16;
        const float4* g = (const float4*)(V + (((size_t)b * SEQ + s0 + r) * NKV + kvh) * HDIM + cb);
#pragma unroll
        for (int i = 0; i < 4; i++) {
            float4 v = g[i];
            float vv[4] = {v.x, v.y, v.z, v.w};
#pragma unroll
            for (int e = 0; e < 4; e++) {
                int d = cb + i * 4 + e;
                __nv_bfloat16 hh = __float2bfloat16_rn(vv[e]);
                th[d][r] = hh;
                tl[d][r] = __float2bfloat16_rn(vv[e] - __bfloat162float(hh));
            }
        }
    }
    __syncthreads();
    {
        const int d  = threadIdx.x >> 2;
        const int sc = (threadIdx.x & 3) * 16;
        size_t obase = (((size_t)b * NKV + kvh) * HDIM + d) * SEQ + s0 + sc;
        uint2 a0 = *(uint2*)&th[d][sc];
        uint2 a1 = *(uint2*)&th[d][sc + 4];
        uint2 a2 = *(uint2*)&th[d][sc + 8];
        uint2 a3 = *(uint2*)&th[d][sc + 12];
        *(uint4*)(vth + obase)     = make_uint4(a0.x, a0.y, a1.x, a1.y);
        *(uint4*)(vth + obase + 8) = make_uint4(a2.x, a2.y, a3.x, a3.y);
        a0 = *(uint2*)&tl[d][sc];
        a1 = *(uint2*)&tl[d][sc + 4];
        a2 = *(uint2*)&tl[d][sc + 8];
        a3 = *(uint2*)&tl[d][sc + 12];
        *(uint4*)(vtl + obase)     = make_uint4(a0.x, a0.y, a1.x, a1.y);
        *(uint4*)(vtl + obase + 8) = make_uint4(a2.x, a2.y, a3.x, a3.y);
    }
}

// ---------------------------------------------------------------------------
// Tensor-core causal flash attention, all-bf16 operands, 2-stage cp.async.
// Inputs: Qh/Ql [b,h,s,d], Kh/Kl [b,kvh,s,d], Vth/Vtl [b,kvh,d,s].
// Output: bf16 hi/lo [b,s,h,d] (= [M,2048] for the O-projection).
// ---------------------------------------------------------------------------
#define APITCH 72
#define A_ARR (64*APITCH)            // elems per K/V array
#define A_STG (4*A_ARR)
#define A_STG_B (A_STG*2)            // 36864 B
#define A_SMEM (2*A_STG_B)           // 73728 B

__global__ __launch_bounds__(256, 1)
void attn_mma(const __nv_bfloat16* __restrict__ Qh, const __nv_bfloat16* __restrict__ Ql,
              const __nv_bfloat16* __restrict__ Kh, const __nv_bfloat16* __restrict__ Kl,
              const __nv_bfloat16* __restrict__ Vth, const __nv_bfloat16* __restrict__ Vtl,
              __nv_bfloat16* __restrict__ Oh, __nv_bfloat16* __restrict__ Ol)
{
    extern __shared__ __align__(16) char dsm_raw[];
    const uint32_t sbase = smem_u32(dsm_raw);

    const int tid  = threadIdx.x;
    const int wid  = tid >> 5;
    const int lane = tid & 31;
    const int t = blockIdx.x;
    const int h = blockIdx.y;
    const int b = blockIdx.z;
    const int kvh = h >> 2;

    // ---- stage Q (bf16, [b,h,s,d]) and extract fragments ----
    {
        const size_t qbase = (((size_t)b * NHEADS + h) * SEQ + (size_t)t * 128) * HDIM;
#pragma unroll
        for (int q = 0; q < 8; q++) {
            int i = tid + q * 256;
            int a = i >> 10;
            int j = i & 1023;
            int r = j >> 3;
            int cc = (j & 7) << 3;
            const __nv_bfloat16* g = (a ? Ql : Qh) + qbase + (size_t)r * HDIM + cc;
            CP16(sbase + (a * 128 * APITCH + r * APITCH + cc) * 2, g);
        }
        CP_COMMIT();
        CP_WAIT0();
    }
    __syncthreads();

    uint32_t qh[4][4], ql[4][4];
    {
        const uint32_t uQh = sbase;
        const uint32_t uQl = sbase + 128 * APITCH * 2;
        const int aoff = (wid * 16 + (lane & 15)) * APITCH + ((lane >> 4) << 3);
#pragma unroll
        for (int kk = 0; kk < 4; kk++) {
            LDSM4(qh[kk][0], qh[kk][1], qh[kk][2], qh[kk][3], uQh + 2 * (aoff + kk * 16));
            LDSM4(ql[kk][0], ql[kk][1], ql[kk][2], ql[kk][3], uQl + 2 * (aoff + kk * 16));
        }
    }
    __syncthreads();

    const size_t kbase = ((size_t)b * NKV + kvh) * SEQ * HDIM;
    const size_t vbase = ((size_t)b * NKV + kvh) * HDIM * SEQ;

    auto load_kv = [&](int kb, int stage) {
        const uint32_t sb = sbase + stage * A_STG_B;
#pragma unroll
        for (int q = 0; q < 8; q++) {
            int i = tid + q * 256;
            int a = i >> 9;
            int j = i & 511;
            int r = j >> 3;
            int cc = (j & 7) << 3;
            const __nv_bfloat16* g;
            if (a == 0)      g = Kh  + kbase + (size_t)(kb * 64 + r) * HDIM + cc;
            else if (a == 1) g = Kl  + kbase + (size_t)(kb * 64 + r) * HDIM + cc;
            else if (a == 2) g = Vth + vbase + (size_t)r * SEQ + kb * 64 + cc;
            else             g = Vtl + vbase + (size_t)r * SEQ + kb * 64 + cc;
            CP16(sb + (a * A_ARR + r * APITCH + cc) * 2, g);
        }
        CP_COMMIT();
    };

    float o[8][4];
#pragma unroll
    for (int nt = 0; nt < 8; nt++)
#pragma unroll
        for (int e = 0; e < 4; e++) o[nt][e] = 0.f;
    float mi0 = -1e30f, mi1 = -1e30f, li0 = 0.f, li1 = 0.f;

    const int row0 = t * 128 + wid * 16 + (lane >> 2);
    const int row1 = row0 + 8;

    const int nkb = 2 * t + 2;
    load_kv(0, 0);

#pragma unroll 1
    for (int kb = 0; kb < nkb; kb++) {
        if (kb + 1 < nkb) {
            load_kv(kb + 1, (kb + 1) & 1);
            CP_WAIT1();
        } else {
            CP_WAIT0();
        }
        __syncthreads();

        const uint32_t sb = sbase + (kb & 1) * A_STG_B;
        const uint32_t uKh = sb;
        const uint32_t uKl = sb + A_ARR * 2;
        const uint32_t uVh = sb + 2 * A_ARR * 2;
        const uint32_t uVl = sb + 3 * A_ARR * 2;

        // ---- S = Q K^T (bf16x3) ----
        float s[8][4];
#pragma unroll
        for (int nt = 0; nt < 8; nt++)
#pragma unroll
            for (int e = 0; e < 4; e++) s[nt][e] = 0.f;

#pragma unroll
        for (int kk = 0; kk < 4; kk++) {
            uint32_t bh[8][2], bl[8][2];
#pragma unroll
            for (int g = 0; g < 4; g++) {
                const int off = (g * 16 + ((lane >> 4) << 3) + (lane & 7)) * APITCH
                              + (((lane >> 3) & 1) << 3) + kk * 16;
                uint32_t t0, t1, t2, t3;
                LDSM4(t0, t1, t2, t3, uKh + 2 * off);
                bh[2*g][0] = t0; bh[2*g][1] = t1; bh[2*g+1][0] = t2; bh[2*g+1][1] = t3;
                LDSM4(t0, t1, t2, t3, uKl + 2 * off);
                bl[2*g][0] = t0; bl[2*g][1] = t1; bl[2*g+1][0] = t2; bl[2*g+1][1] = t3;
            }
#pragma unroll
            for (int nt = 0; nt < 8; nt++) {
                MMA16816(s[nt], qh[kk], bh[nt][0], bh[nt][1]);
                MMA16816(s[nt], qh[kk], bl[nt][0], bl[nt][1]);
                MMA16816(s[nt], ql[kk], bh[nt][0], bh[nt][1]);
            }
        }

        // scale + causal mask
        const bool diag = (kb >= 2 * t);
#pragma unroll
        for (int nt = 0; nt < 8; nt++) {
            const int col = kb * 64 + nt * 8 + (lane & 3) * 2;
            s[nt][0] *= 0.125f; s[nt][1] *= 0.125f;
            s[nt][2] *= 0.125f; s[nt][3] *= 0.125f;
            if (diag) {
                if (col > row0)     s[nt][0] = -1e30f;
                if (col + 1 > row0) s[nt][1] = -1e30f;
                if (col > row1)     s[nt][2] = -1e30f;
                if (col + 1 > row1) s[nt][3] = -1e30f;
            }
        }

        // ---- online softmax ----
        float bm0 = -1e30f, bm1 = -1e30f;
#pragma unroll
        for (int nt = 0; nt < 8; nt++) {
            bm0 = fmaxf(bm0, fmaxf(s[nt][0], s[nt][1]));
            bm1 = fmaxf(bm1, fmaxf(s[nt][2], s[nt][3]));
        }
        bm0 = fmaxf(bm0, __shfl_xor_sync(0xffffffffu, bm0, 1));
        bm0 = fmaxf(bm0, __shfl_xor_sync(0xffffffffu, bm0, 2));
        bm1 = fmaxf(bm1, __shfl_xor_sync(0xffffffffu, bm1, 1));
        bm1 = fmaxf(bm1, __shfl_xor_sync(0xffffffffu, bm1, 2));

        const float mn0 = fmaxf(mi0, bm0);
        const float mn1 = fmaxf(mi1, bm1);
        const float sc0 = __expf(mi0 - mn0);
        const float sc1 = __expf(mi1 - mn1);

        float ls0 = 0.f, ls1 = 0.f;
#pragma unroll
        for (int nt = 0; nt < 8; nt++) {
            s[nt][0] = __expf(s[nt][0] - mn0);
            s[nt][1] = __expf(s[nt][1] - mn0);
            s[nt][2] = __expf(s[nt][2] - mn1);
            s[nt][3] = __expf(s[nt][3] - mn1);
            ls0 += s[nt][0] + s[nt][1];
            ls1 += s[nt][2] + s[nt][3];
        }
        ls0 += __shfl_xor_sync(0xffffffffu, ls0, 1);
        ls0 += __shfl_xor_sync(0xffffffffu, ls0, 2);
        ls1 += __shfl_xor_sync(0xffffffffu, ls1, 1);
        ls1 += __shfl_xor_sync(0xffffffffu, ls1, 2);

        li0 = li0 * sc0 + ls0;
        li1 = li1 * sc1 + ls1;
        mi0 = mn0; mi1 = mn1;

#pragma unroll
        for (int nt = 0; nt < 8; nt++) {
            o[nt][0] *= sc0; o[nt][1] *= sc0;
            o[nt][2] *= sc1; o[nt][3] *= sc1;
        }

        // ---- pack P to bf16 hi/lo fragments ----
        uint32_t ph[8][2], pl[8][2];
#pragma unroll
        for (int nt = 0; nt < 8; nt++) {
            uint32_t u0 = pack_bf16x2(s[nt][0], s[nt][1]);
            uint32_t u1 = pack_bf16x2(s[nt][2], s[nt][3]);
            ph[nt][0] = u0; ph[nt][1] = u1;
            float l00 = s[nt][0] - __uint_as_float(u0 << 16);
            float l01 = s[nt][1] - __uint_as_float(u0 & 0xffff0000u);
            float l10 = s[nt][2] - __uint_as_float(u1 << 16);
            float l11 = s[nt][3] - __uint_as_float(u1 & 0xffff0000u);
            pl[nt][0] = pack_bf16x2(l00, l01);
            pl[nt][1] = pack_bf16x2(l10, l11);
        }

        // ---- O += P V ----
#pragma unroll
        for (int kk = 0; kk < 4; kk++) {
            uint32_t vh[8][2], vl[8][2];
#pragma unroll
            for (int g = 0; g < 4; g++) {
                const int off = (g * 16 + ((lane >> 4) << 3) + (lane & 7)) * APITCH
                              + (((lane >> 3) & 1) << 3) + kk * 16;
                uint32_t t0, t1, t2, t3;
                LDSM4(t0, t1, t2, t3, uVh + 2 * off);
                vh[2*g][0] = t0; vh[2*g][1] = t1; vh[2*g+1][0] = t2; vh[2*g+1][1] = t3;
                LDSM4(t0, t1, t2, t3, uVl + 2 * off);
                vl[2*g][0] = t0; vl[2*g][1] = t1; vl[2*g+1][0] = t2; vl[2*g+1][1] = t3;
            }
            uint32_t ah[4] = {ph[2*kk][0], ph[2*kk][1], ph[2*kk+1][0], ph[2*kk+1][1]};
            uint32_t al[4] = {pl[2*kk][0], pl[2*kk][1], pl[2*kk+1][0], pl[2*kk+1][1]};
#pragma unroll
            for (int nt = 0; nt < 8; nt++) {
                MMA16816(o[nt], ah, vh[nt][0], vh[nt][1]);
                MMA16816(o[nt], ah, vl[nt][0], vl[nt][1]);
                MMA16816(o[nt], al, vh[nt][0], vh[nt][1]);
            }
        }
        __syncthreads();
    }

    // ---- finalize: write bf16 hi/lo output ([b,s,h,d] = [M,2048]) ----
    const float inv0 = 1.f / li0;
    const float inv1 = 1.f / li1;
    const size_t o0 = (((size_t)b * SEQ + row0) * NHEADS + h) * HDIM;
    const size_t o1 = (((size_t)b * SEQ + row1) * NHEADS + h) * HDIM;
#pragma unroll
    for (int nt = 0; nt < 8; nt++) {
        const int col = nt * 8 + (lane & 3) * 2;
        float a0 = o[nt][0] * inv0, a1 = o[nt][1] * inv0;
        float b0 = o[nt][2] * inv1, b1 = o[nt][3] * inv1;
        uint32_t uh0 = pack_bf16x2(a0, a1);
        uint32_t uh1 = pack_bf16x2(b0, b1);
        uint32_t ul0 = pack_bf16x2(a0 - __uint_as_float(uh0 << 16),
                                   a1 - __uint_as_float(uh0 & 0xffff0000u));
        uint32_t ul1 = pack_bf16x2(b0 - __uint_as_float(uh1 << 16),
                                   b1 - __uint_as_float(uh1 & 0xffff0000u));
        *(uint32_t*)(Oh + o0 + col) = uh0;
        *(uint32_t*)(Ol + o0 + col) = ul0;
        *(uint32_t*)(Oh + o1 + col) = uh1;
        *(uint32_t*)(Ol + o1 + col) = ul1;
    }
}

// ---------------------------------------------------------------------------
extern "C" void kernel_launch(void* const* d_in, const int* in_sizes, int n_in,
                              void* d_out, int out_size)
{
    const float* x    = (const float*)d_in[0];
    const float* fcos = (const float*)d_in[1];
    const float* fsin = (const float*)d_in[2];
    const float* wq   = (const float*)d_in[3];
    const float* wk   = (const float*)d_in[4];
    const float* wv   = (const float*)d_in[5];
    const float* wo   = (const float*)d_in[6];
    float* out = (float*)d_out;

    float *Qp, *Kp, *Vp;
    __nv_bfloat16 *bf, *qh, *ql, *kh, *kl, *vth, *vtl;
    cudaGetSymbolAddress((void**)&Qp, g_Q);
    cudaGetSymbolAddress((void**)&Kp, g_K);
    cudaGetSymbolAddress((void**)&Vp, g_V);
    cudaGetSymbolAddress((void**)&bf, g_bf);
    cudaGetSymbolAddress((void**)&qh, g_Qh);
    cudaGetSymbolAddress((void**)&ql, g_Ql);
    cudaGetSymbolAddress((void**)&kh, g_Kh);
    cudaGetSymbolAddress((void**)&kl, g_Kl);
    cudaGetSymbolAddress((void**)&vth, g_Vth);
    cudaGetSymbolAddress((void**)&vtl, g_Vtl);

    cudaFuncSetAttribute(gemm_mma, cudaFuncAttributeMaxDynamicSharedMemorySize, G_SMEM);
    cudaFuncSetAttribute(attn_mma, cudaFuncAttributeMaxDynamicSharedMemorySize, A_SMEM);

    const int M = BATCH * SEQ;

    // fp32 -> bf16 hi/lo prepass
    split_kernel<<<(int)(N_X/4 + 255) / 256, 256>>>(x,  bf + OFF_XH,  bf + OFF_XL,  (int)(N_X/4));
    split_kernel<<<(int)(N_WQ/4 + 255) / 256, 256>>>(wq, bf + OFF_WQH, bf + OFF_WQL, (int)(N_WQ/4));
    split_kernel<<<(int)(N_WK/4 + 255) / 256, 256>>>(wk, bf + OFF_WKH, bf + OFF_WKL, (int)(N_WK/4));
    split_kernel<<<(int)(N_WV/4 + 255) / 256, 256>>>(wv, bf + OFF_WVH, bf + OFF_WVL, (int)(N_WV/4));
    split_kernel<<<(int)(N_WO/4 + 255) / 256, 256>>>(wo, bf + OFF_WOH, bf + OFF_WOL, (int)(N_WO/4));

    // QKV projections (fp32 out)
    gemm_mma<<<dim3(EMBED / 128, M / 128), 256, G_SMEM>>>(bf + OFF_XH, bf + OFF_XL,
                                                          bf + OFF_WQH, bf + OFF_WQL, Qp, M, EMBED, EMBED);
    gemm_mma<<<dim3(KVDIM / 128, M / 128), 256, G_SMEM>>>(bf + OFF_XH, bf + OFF_XL,
                                                          bf + OFF_WKH, bf + OFF_WKL, Kp, M, KVDIM, EMBED);
    gemm_mma<<<dim3(KVDIM / 128, M / 128), 256, G_SMEM>>>(bf + OFF_XH, bf + OFF_XL,
                                                          bf + OFF_WVH, bf + OFF_WVL, Vp, M, KVDIM, EMBED);

    // RoPE + split to attention layouts
    int tq = BATCH * SEQ * NHEADS * 32;
    rope_split<<<(tq + 255) / 256, 256>>>(Qp, fcos, fsin, qh, ql, NHEADS);
    int tk = BATCH * SEQ * NKV * 32;
    rope_split<<<(tk + 255) / 256, 256>>>(Kp, fcos, fsin, kh, kl, NKV);
    split_v_t<<<dim3(SEQ / 64, NKV, BATCH), 256>>>(Vp, vth, vtl);

    // Tensor-core causal GQA flash attention (bf16 in/out)
    attn_mma<<<dim3(SEQ / 128, NHEADS, BATCH), 256, A_SMEM>>>(qh, ql, kh, kl, vth, vtl,
                                                              bf + OFF_OH, bf + OFF_OL);

    // Output projection
    gemm_mma<<<dim3(EMBED / 128, M / 128), 256, G_SMEM>>>(bf + OFF_OH, bf + OFF_OL,
                                                          bf + OFF_WOH, bf + OFF_WOL, out, M, EMBED, EMBED);
}

// round 6
// speedup vs baseline: 3.2287x; 1.0174x over previous
#include <cuda_runtime.h>
#include <cuda_bf16.h>
#include <cstdint>

#define BATCH 2
#define SEQ 2048
#define EMBED 2048
#define NHEADS 32
#define NKV 8
#define HDIM 64
#define KVDIM (NKV*HDIM)   // 512

// fp32 scratch (gemm outputs)
__device__ float g_Q[(size_t)BATCH*SEQ*EMBED];
__device__ float g_K[(size_t)BATCH*SEQ*KVDIM];
__device__ float g_V[(size_t)BATCH*SEQ*KVDIM];

// bf16 hi/lo pool (gemm operands)
#define N_X   (size_t)8388608    // 2*2048*2048
#define N_WQ  (size_t)4194304
#define N_WK  (size_t)1048576
#define N_WV  (size_t)1048576
#define N_WO  (size_t)4194304
#define OFF_XH  (size_t)0
#define OFF_XL  (OFF_XH + N_X)
#define OFF_WQH (OFF_XL + N_X)
#define OFF_WQL (OFF_WQH + N_WQ)
#define OFF_WKH (OFF_WQL + N_WQ)
#define OFF_WKL (OFF_WKH + N_WK)
#define OFF_WVH (OFF_WKL + N_WK)
#define OFF_WVL (OFF_WVH + N_WV)
#define OFF_WOH (OFF_WVL + N_WV)
#define OFF_WOL (OFF_WOH + N_WO)
#define OFF_OH  (OFF_WOL + N_WO)
#define OFF_OL  (OFF_OH + N_X)
#define POOL_SZ (OFF_OL + N_X)
__device__ __nv_bfloat16 g_bf[POOL_SZ];

// bf16 attention operands
__device__ __nv_bfloat16 g_Qh[(size_t)BATCH*NHEADS*SEQ*HDIM];
__device__ __nv_bfloat16 g_Ql[(size_t)BATCH*NHEADS*SEQ*HDIM];
__device__ __nv_bfloat16 g_Kh[(size_t)BATCH*NKV*SEQ*HDIM];
__device__ __nv_bfloat16 g_Kl[(size_t)BATCH*NKV*SEQ*HDIM];
__device__ __nv_bfloat16 g_Vth[(size_t)BATCH*NKV*HDIM*SEQ];
__device__ __nv_bfloat16 g_Vtl[(size_t)BATCH*NKV*HDIM*SEQ];

// ============================ helpers ======================================
__device__ __forceinline__ uint32_t smem_u32(const void* p) {
    uint32_t a;
    asm("{ .reg .u64 t; cvta.to.shared.u64 t, %1; cvt.u32.u64 %0, t; }"
        : "=r"(a) : "l"(p));
    return a;
}

#define LDSM4(R0,R1,R2,R3,ADDR) \
    asm volatile("ldmatrix.sync.aligned.m8n8.x4.shared.b16 {%0,%1,%2,%3}, [%4];" \
                 : "=r"(R0), "=r"(R1), "=r"(R2), "=r"(R3) : "r"(ADDR))

#define MMA16816(C, A, B0, B1) \
    asm volatile("mma.sync.aligned.m16n8k16.row.col.f32.bf16.bf16.f32 " \
                 "{%0,%1,%2,%3}, {%4,%5,%6,%7}, {%8,%9}, {%0,%1,%2,%3};" \
                 : "+f"((C)[0]), "+f"((C)[1]), "+f"((C)[2]), "+f"((C)[3]) \
                 : "r"((A)[0]), "r"((A)[1]), "r"((A)[2]), "r"((A)[3]), \
                   "r"(B0), "r"(B1))

#define CP16(DST, SRC) \
    asm volatile("cp.async.cg.shared.global [%0], [%1], 16;" :: "r"(DST), "l"(SRC))
#define CP_COMMIT() asm volatile("cp.async.commit_group;")
#define CP_WAIT0()  asm volatile("cp.async.wait_group 0;")
#define CP_WAIT1()  asm volatile("cp.async.wait_group 1;")

__device__ __forceinline__ uint32_t pack_bf16x2(float lo, float hi) {
    uint32_t d;
    asm("cvt.rn.bf16x2.f32 %0, %1, %2;" : "=r"(d) : "f"(hi), "f"(lo));
    return d;
}

__device__ __forceinline__ void split4(float4 v, uint2& uh, uint2& ul) {
    __nv_bfloat16 h0 = __float2bfloat16_rn(v.x);
    __nv_bfloat16 h1 = __float2bfloat16_rn(v.y);
    __nv_bfloat16 h2 = __float2bfloat16_rn(v.z);
    __nv_bfloat16 h3 = __float2bfloat16_rn(v.w);
    __nv_bfloat16 l0 = __float2bfloat16_rn(v.x - __bfloat162float(h0));
    __nv_bfloat16 l1 = __float2bfloat16_rn(v.y - __bfloat162float(h1));
    __nv_bfloat16 l2 = __float2bfloat16_rn(v.z - __bfloat162float(h2));
    __nv_bfloat16 l3 = __float2bfloat16_rn(v.w - __bfloat162float(h3));
    uh.x = (uint32_t)__bfloat16_as_ushort(h0) | ((uint32_t)__bfloat16_as_ushort(h1) << 16);
    uh.y = (uint32_t)__bfloat16_as_ushort(h2) | ((uint32_t)__bfloat16_as_ushort(h3) << 16);
    ul.x = (uint32_t)__bfloat16_as_ushort(l0) | ((uint32_t)__bfloat16_as_ushort(l1) << 16);
    ul.y = (uint32_t)__bfloat16_as_ushort(l2) | ((uint32_t)__bfloat16_as_ushort(l3) << 16);
}

// ---------------------------------------------------------------------------
// One-shot split prepass: x, wq, wk, wv, wo -> bf16 hi/lo pool.
// Index space is in float4 quads.
// ---------------------------------------------------------------------------
#define Q_X  (int)(N_X/4)     // 2097152
#define Q_WQ (int)(N_WQ/4)    // 1048576
#define Q_WK (int)(N_WK/4)    // 262144
#define Q_WV (int)(N_WV/4)
#define Q_WO (int)(N_WO/4)
#define Q_TOT (Q_X + Q_WQ + Q_WK + Q_WV + Q_WO)   // 4718592

__global__ void split_all(const float* __restrict__ x,  const float* __restrict__ wq,
                          const float* __restrict__ wk, const float* __restrict__ wv,
                          const float* __restrict__ wo, __nv_bfloat16* __restrict__ bf)
{
    int i = blockIdx.x * blockDim.x + threadIdx.x;
    const float* src; size_t dh, dl; int j;
    if (i < Q_X)                        { src = x;  j = i;                     dh = OFF_XH;  dl = OFF_XL; }
    else if (i < Q_X + Q_WQ)            { src = wq; j = i - Q_X;               dh = OFF_WQH; dl = OFF_WQL; }
    else if (i < Q_X + Q_WQ + Q_WK)     { src = wk; j = i - Q_X - Q_WQ;        dh = OFF_WKH; dl = OFF_WKL; }
    else if (i < Q_X + Q_WQ + Q_WK + Q_WV) { src = wv; j = i - Q_X - Q_WQ - Q_WK; dh = OFF_WVH; dl = OFF_WVL; }
    else if (i < Q_TOT)                 { src = wo; j = i - Q_X - Q_WQ - Q_WK - Q_WV; dh = OFF_WOH; dl = OFF_WOL; }
    else return;
    float4 v = ((const float4*)src)[j];
    uint2 uh, ul;
    split4(v, uh, ul);
    ((uint2*)(bf + dh))[j] = uh;
    ((uint2*)(bf + dl))[j] = ul;
}

// ---------------------------------------------------------------------------
// bf16x3 MMA GEMM, 3-stage cp.async pipeline.
// C[M,N] = A[M,K] * B[N,K]^T, fp32 out. Block 128x128, BK=32, 256 thr.
// ---------------------------------------------------------------------------
#define PITCH 40
#define G_ARR (128*PITCH)
#define G_STG (4*G_ARR)
#define G_STG_B (G_STG*2)
#define G_SMEM (3*G_STG_B)           // 122880 B

__global__ __launch_bounds__(256, 1)
void gemm_mma(const __nv_bfloat16* __restrict__ Ah, const __nv_bfloat16* __restrict__ Al,
              const __nv_bfloat16* __restrict__ Bh, const __nv_bfloat16* __restrict__ Bl,
              float* __restrict__ C, int M, int N, int K)
{
    extern __shared__ __align__(16) char dsm_raw[];
    const uint32_t sbase = smem_u32(dsm_raw);

    const int tid  = threadIdx.x;
    const int wid  = tid >> 5;
    const int lane = tid & 31;
    const int wm   = wid >> 2;
    const int wn   = wid & 3;

    const int bm = blockIdx.y * 128;
    const int bn = blockIdx.x * 128;

    const int aoff = (wm * 64 + (lane & 15)) * PITCH + ((lane >> 4) << 3);
    const int boff = (wn * 32 + ((lane >> 4) << 3) + (lane & 7)) * PITCH + (((lane >> 3) & 1) << 3);

    const int nk = K >> 5;

    auto load_stage = [&](int kt, int stage) {
        const int k0 = kt << 5;
        const uint32_t sb = sbase + stage * G_STG_B;
#pragma unroll
        for (int q = 0; q < 8; q++) {
            int i = tid + q * 256;
            int a = i >> 9;
            int j = i & 511;
            int r = j >> 2;
            int cc = (j & 3) << 3;
            const __nv_bfloat16* g;
            if (a == 0)      g = Ah + (size_t)(bm + r) * K + k0 + cc;
            else if (a == 1) g = Al + (size_t)(bm + r) * K + k0 + cc;
            else if (a == 2) g = Bh + (size_t)(bn + r) * K + k0 + cc;
            else             g = Bl + (size_t)(bn + r) * K + k0 + cc;
            CP16(sb + (a * G_ARR + r * PITCH + cc) * 2, g);
        }
        CP_COMMIT();
    };

    float c[4][4][4];
#pragma unroll
    for (int a = 0; a < 4; a++)
#pragma unroll
        for (int b = 0; b < 4; b++)
#pragma unroll
            for (int d = 0; d < 4; d++) c[a][b][d] = 0.f;

    load_stage(0, 0);
    if (nk > 1) load_stage(1, 1);

#pragma unroll 1
    for (int kt = 0; kt < nk; kt++) {
        if (kt + 1 < nk) { CP_WAIT1(); } else { CP_WAIT0(); }
        __syncthreads();

        const uint32_t sb = sbase + (kt % 3) * G_STG_B;
        const uint32_t uAh = sb;
        const uint32_t uAl = sb + G_ARR * 2;
        const uint32_t uBh = sb + 2 * G_ARR * 2;
        const uint32_t uBl = sb + 3 * G_ARR * 2;

#pragma unroll
        for (int kk = 0; kk < 32; kk += 16) {
            uint32_t ah[4][4], al[4][4], bh[4][2], bl[4][2];
#pragma unroll
            for (int ms = 0; ms < 4; ms++) {
                LDSM4(ah[ms][0], ah[ms][1], ah[ms][2], ah[ms][3],
                      uAh + 2 * (aoff + ms * 16 * PITCH + kk));
                LDSM4(al[ms][0], al[ms][1], al[ms][2], al[ms][3],
                      uAl + 2 * (aoff + ms * 16 * PITCH + kk));
            }
#pragma unroll
            for (int g = 0; g < 2; g++) {
                uint32_t t0, t1, t2, t3;
                LDSM4(t0, t1, t2, t3, uBh + 2 * (boff + g * 16 * PITCH + kk));
                bh[2*g][0] = t0; bh[2*g][1] = t1; bh[2*g+1][0] = t2; bh[2*g+1][1] = t3;
                LDSM4(t0, t1, t2, t3, uBl + 2 * (boff + g * 16 * PITCH + kk));
                bl[2*g][0] = t0; bl[2*g][1] = t1; bl[2*g+1][0] = t2; bl[2*g+1][1] = t3;
            }
#pragma unroll
            for (int ms = 0; ms < 4; ms++)
#pragma unroll
                for (int ng = 0; ng < 4; ng++) {
                    MMA16816(c[ms][ng], ah[ms], bh[ng][0], bh[ng][1]);
                    MMA16816(c[ms][ng], ah[ms], bl[ng][0], bl[ng][1]);
                    MMA16816(c[ms][ng], al[ms], bh[ng][0], bh[ng][1]);
                }
        }

        if (kt + 2 < nk) load_stage(kt + 2, (kt + 2) % 3);
        __syncthreads();
    }

#pragma unroll
    for (int ms = 0; ms < 4; ms++) {
        const int row = bm + wm * 64 + ms * 16 + (lane >> 2);
#pragma unroll
        for (int ng = 0; ng < 4; ng++) {
            const int col = bn + wn * 32 + ng * 8 + (lane & 3) * 2;
            *(float2*)(C + (size_t)row * N + col)       = make_float2(c[ms][ng][0], c[ms][ng][1]);
            *(float2*)(C + (size_t)(row + 8) * N + col) = make_float2(c[ms][ng][2], c[ms][ng][3]);
        }
    }
}

// ---------------------------------------------------------------------------
// Fused RoPE + split for BOTH Q and K in one launch.
// Q: fp32 [b,s,32,64] -> bf16 hi/lo [b,32,s,64]
// K: fp32 [b,s,8,64]  -> bf16 hi/lo [b,8,s,64]
// ---------------------------------------------------------------------------
#define TQ_ITEMS (BATCH*SEQ*NHEADS*32)   // 4194304
#define TK_ITEMS (BATCH*SEQ*NKV*32)      // 1048576

__global__ void rope_all(const float* __restrict__ Qf, const float* __restrict__ Kf,
                         const float* __restrict__ cosv, const float* __restrict__ sinv,
                         __nv_bfloat16* __restrict__ qh, __nv_bfloat16* __restrict__ ql,
                         __nv_bfloat16* __restrict__ kh, __nv_bfloat16* __restrict__ kl)
{
    int i = blockIdx.x * blockDim.x + threadIdx.x;
    const float* buf; __nv_bfloat16 *oh, *ol; int nheads, j;
    if (i < TQ_ITEMS) { buf = Qf; oh = qh; ol = ql; nheads = NHEADS; j = i; }
    else if (i < TQ_ITEMS + TK_ITEMS) { buf = Kf; oh = kh; ol = kl; nheads = NKV; j = i - TQ_ITEMS; }
    else return;

    int d = j & 31;
    int h = (j >> 5) % nheads;
    int s = (j / (32 * nheads)) % SEQ;
    int b = j / (32 * nheads * SEQ);

    const float* p = buf + (((size_t)b * SEQ + s) * nheads + h) * HDIM;
    float c0 = cosv[s * HDIM + d];
    float c1 = cosv[s * HDIM + d + 32];
    float s0 = sinv[s * HDIM + d];
    float s1 = sinv[s * HDIM + d + 32];
    float x0 = p[d];
    float x1 = p[d + 32];
    float y0 = x0 * c0 - x1 * s0;
    float y1 = x1 * c1 + x0 * s1;

    size_t o = (((size_t)b * nheads + h) * SEQ + s) * HDIM;
    __nv_bfloat16 h0 = __float2bfloat16_rn(y0);
    __nv_bfloat16 h1 = __float2bfloat16_rn(y1);
    oh[o + d]      = h0;
    oh[o + d + 32] = h1;
    ol[o + d]      = __float2bfloat16_rn(y0 - __bfloat162float(h0));
    ol[o + d + 32] = __float2bfloat16_rn(y1 - __bfloat162float(h1));
}

// ---------------------------------------------------------------------------
// V fp32 [b,s,8,64] -> V^T bf16 hi/lo [b,kvh,d,s]  (64x64 smem tile transpose)
// ---------------------------------------------------------------------------
__global__ __launch_bounds__(256) void split_v_t(const float* __restrict__ V,
                                                 __nv_bfloat16* __restrict__ vth,
                                                 __nv_bfloat16* __restrict__ vtl)
{
    __shared__ __nv_bfloat16 th[64][68];
    __shared__ __nv_bfloat16 tl[64][68];
    const int s0  = blockIdx.x * 64;
    const int kvh = blockIdx.y;
    const int b   = blockIdx.z;

    {
        const int r  = threadIdx.x >> 2;
        const int cb = (threadIdx.x & 3) * 16;
        const float4* g = (const float4*)(V + (((size_t)b * SEQ + s0 + r) * NKV + kvh) * HDIM + cb);
#pragma unroll
        for (int i = 0; i < 4; i++) {
            float4 v = g[i];
            float vv[4] = {v.x, v.y, v.z, v.w};
#pragma unroll
            for (int e = 0; e < 4; e++) {
                int d = cb + i * 4 + e;
                __nv_bfloat16 hh = __float2bfloat16_rn(vv[e]);
                th[d][r] = hh;
                tl[d][r] = __float2bfloat16_rn(vv[e] - __bfloat162float(hh));
            }
        }
    }
    __syncthreads();
    {
        const int d  = threadIdx.x >> 2;
        const int sc = (threadIdx.x & 3) * 16;
        size_t obase = (((size_t)b * NKV + kvh) * HDIM + d) * SEQ + s0 + sc;
        uint2 a0 = *(uint2*)&th[d][sc];
        uint2 a1 = *(uint2*)&th[d][sc + 4];
        uint2 a2 = *(uint2*)&th[d][sc + 8];
        uint2 a3 = *(uint2*)&th[d][sc + 12];
        *(uint4*)(vth + obase)     = make_uint4(a0.x, a0.y, a1.x, a1.y);
        *(uint4*)(vth + obase + 8) = make_uint4(a2.x, a2.y, a3.x, a3.y);
        a0 = *(uint2*)&tl[d][sc];
        a1 = *(uint2*)&tl[d][sc + 4];
        a2 = *(uint2*)&tl[d][sc + 8];
        a3 = *(uint2*)&tl[d][sc + 12];
        *(uint4*)(vtl + obase)     = make_uint4(a0.x, a0.y, a1.x, a1.y);
        *(uint4*)(vtl + obase + 8) = make_uint4(a2.x, a2.y, a3.x, a3.y);
    }
}

// ---------------------------------------------------------------------------
// Tensor-core causal flash attention, all-bf16 operands, 2-stage cp.async.
// Work-balanced: largest-t CTAs launch first. Softmax in exp2 domain.
// ---------------------------------------------------------------------------
#define APITCH 72
#define A_ARR (64*APITCH)
#define A_STG (4*A_ARR)
#define A_STG_B (A_STG*2)            // 36864 B
#define A_SMEM (2*A_STG_B)           // 73728 B
#define SCALE_LOG2 0.18033688011112042f   // log2(e)/8

__global__ __launch_bounds__(256, 1)
void attn_mma(const __nv_bfloat16* __restrict__ Qh, const __nv_bfloat16* __restrict__ Ql,
              const __nv_bfloat16* __restrict__ Kh, const __nv_bfloat16* __restrict__ Kl,
              const __nv_bfloat16* __restrict__ Vth, const __nv_bfloat16* __restrict__ Vtl,
              __nv_bfloat16* __restrict__ Oh, __nv_bfloat16* __restrict__ Ol)
{
    extern __shared__ __align__(16) char dsm_raw[];
    const uint32_t sbase = smem_u32(dsm_raw);

    const int tid  = threadIdx.x;
    const int wid  = tid >> 5;
    const int lane = tid & 31;
    const int t = (int)gridDim.x - 1 - (int)blockIdx.x;   // largest tiles first
    const int h = blockIdx.y;
    const int b = blockIdx.z;
    const int kvh = h >> 2;

    // ---- stage Q and extract fragments ----
    {
        const size_t qbase = (((size_t)b * NHEADS + h) * SEQ + (size_t)t * 128) * HDIM;
#pragma unroll
        for (int q = 0; q < 8; q++) {
            int i = tid + q * 256;
            int a = i >> 10;
            int j = i & 1023;
            int r = j >> 3;
            int cc = (j & 7) << 3;
            const __nv_bfloat16* g = (a ? Ql : Qh) + qbase + (size_t)r * HDIM + cc;
            CP16(sbase + (a * 128 * APITCH + r * APITCH + cc) * 2, g);
        }
        CP_COMMIT();
        CP_WAIT0();
    }
    __syncthreads();

    uint32_t qh[4][4], ql[4][4];
    {
        const uint32_t uQh = sbase;
        const uint32_t uQl = sbase + 128 * APITCH * 2;
        const int aoff = (wid * 16 + (lane & 15)) * APITCH + ((lane >> 4) << 3);
#pragma unroll
        for (int kk = 0; kk < 4; kk++) {
            LDSM4(qh[kk][0], qh[kk][1], qh[kk][2], qh[kk][3], uQh + 2 * (aoff + kk * 16));
            LDSM4(ql[kk][0], ql[kk][1], ql[kk][2], ql[kk][3], uQl + 2 * (aoff + kk * 16));
        }
    }
    __syncthreads();

    const size_t kbase = ((size_t)b * NKV + kvh) * SEQ * HDIM;
    const size_t vbase = ((size_t)b * NKV + kvh) * HDIM * SEQ;

    auto load_kv = [&](int kb, int stage) {
        const uint32_t sb = sbase + stage * A_STG_B;
#pragma unroll
        for (int q = 0; q < 8; q++) {
            int i = tid + q * 256;
            int a = i >> 9;
            int j = i & 511;
            int r = j >> 3;
            int cc = (j & 7) << 3;
            const __nv_bfloat16* g;
            if (a == 0)      g = Kh  + kbase + (size_t)(kb * 64 + r) * HDIM + cc;
            else if (a == 1) g = Kl  + kbase + (size_t)(kb * 64 + r) * HDIM + cc;
            else if (a == 2) g = Vth + vbase + (size_t)r * SEQ + kb * 64 + cc;
            else             g = Vtl + vbase + (size_t)r * SEQ + kb * 64 + cc;
            CP16(sb + (a * A_ARR + r * APITCH + cc) * 2, g);
        }
        CP_COMMIT();
    };

    float o[8][4];
#pragma unroll
    for (int nt = 0; nt < 8; nt++)
#pragma unroll
        for (int e = 0; e < 4; e++) o[nt][e] = 0.f;
    float mi0 = -1e30f, mi1 = -1e30f, li0 = 0.f, li1 = 0.f;

    const int row0 = t * 128 + wid * 16 + (lane >> 2);
    const int row1 = row0 + 8;

    const int nkb = 2 * t + 2;
    load_kv(0, 0);

#pragma unroll 1
    for (int kb = 0; kb < nkb; kb++) {
        if (kb + 1 < nkb) {
            load_kv(kb + 1, (kb + 1) & 1);
            CP_WAIT1();
        } else {
            CP_WAIT0();
        }
        __syncthreads();

        const uint32_t sb = sbase + (kb & 1) * A_STG_B;
        const uint32_t uKh = sb;
        const uint32_t uKl = sb + A_ARR * 2;
        const uint32_t uVh = sb + 2 * A_ARR * 2;
        const uint32_t uVl = sb + 3 * A_ARR * 2;

        // ---- S = Q K^T (bf16x3) ----
        float s[8][4];
#pragma unroll
        for (int nt = 0; nt < 8; nt++)
#pragma unroll
            for (int e = 0; e < 4; e++) s[nt][e] = 0.f;

#pragma unroll
        for (int kk = 0; kk < 4; kk++) {
            uint32_t bh[8][2], bl[8][2];
#pragma unroll
            for (int g = 0; g < 4; g++) {
                const int off = (g * 16 + ((lane >> 4) << 3) + (lane & 7)) * APITCH
                              + (((lane >> 3) & 1) << 3) + kk * 16;
                uint32_t t0, t1, t2, t3;
                LDSM4(t0, t1, t2, t3, uKh + 2 * off);
                bh[2*g][0] = t0; bh[2*g][1] = t1; bh[2*g+1][0] = t2; bh[2*g+1][1] = t3;
                LDSM4(t0, t1, t2, t3, uKl + 2 * off);
                bl[2*g][0] = t0; bl[2*g][1] = t1; bl[2*g+1][0] = t2; bl[2*g+1][1] = t3;
            }
#pragma unroll
            for (int nt = 0; nt < 8; nt++) {
                MMA16816(s[nt], qh[kk], bh[nt][0], bh[nt][1]);
                MMA16816(s[nt], qh[kk], bl[nt][0], bl[nt][1]);
                MMA16816(s[nt], ql[kk], bh[nt][0], bh[nt][1]);
            }
        }

        // scale (exp2 domain) + causal mask
        const bool diag = (kb >= 2 * t);
#pragma unroll
        for (int nt = 0; nt < 8; nt++) {
            const int col = kb * 64 + nt * 8 + (lane & 3) * 2;
            s[nt][0] *= SCALE_LOG2; s[nt][1] *= SCALE_LOG2;
            s[nt][2] *= SCALE_LOG2; s[nt][3] *= SCALE_LOG2;
            if (diag) {
                if (col > row0)     s[nt][0] = -1e30f;
                if (col + 1 > row0) s[nt][1] = -1e30f;
                if (col > row1)     s[nt][2] = -1e30f;
                if (col + 1 > row1) s[nt][3] = -1e30f;
            }
        }

        // ---- online softmax (base 2) ----
        float bm0 = -1e30f, bm1 = -1e30f;
#pragma unroll
        for (int nt = 0; nt < 8; nt++) {
            bm0 = fmaxf(bm0, fmaxf(s[nt][0], s[nt][1]));
            bm1 = fmaxf(bm1, fmaxf(s[nt][2], s[nt][3]));
        }
        bm0 = fmaxf(bm0, __shfl_xor_sync(0xffffffffu, bm0, 1));
        bm0 = fmaxf(bm0, __shfl_xor_sync(0xffffffffu, bm0, 2));
        bm1 = fmaxf(bm1, __shfl_xor_sync(0xffffffffu, bm1, 1));
        bm1 = fmaxf(bm1, __shfl_xor_sync(0xffffffffu, bm1, 2));

        const float mn0 = fmaxf(mi0, bm0);
        const float mn1 = fmaxf(mi1, bm1);
        const float sc0 = exp2f(mi0 - mn0);
        const float sc1 = exp2f(mi1 - mn1);

        float ls0 = 0.f, ls1 = 0.f;
#pragma unroll
        for (int nt = 0; nt < 8; nt++) {
            s[nt][0] = exp2f(s[nt][0] - mn0);
            s[nt][1] = exp2f(s[nt][1] - mn0);
            s[nt][2] = exp2f(s[nt][2] - mn1);
            s[nt][3] = exp2f(s[nt][3] - mn1);
            ls0 += s[nt][0] + s[nt][1];
            ls1 += s[nt][2] + s[nt][3];
        }
        ls0 += __shfl_xor_sync(0xffffffffu, ls0, 1);
        ls0 += __shfl_xor_sync(0xffffffffu, ls0, 2);
        ls1 += __shfl_xor_sync(0xffffffffu, ls1, 1);
        ls1 += __shfl_xor_sync(0xffffffffu, ls1, 2);

        li0 = li0 * sc0 + ls0;
        li1 = li1 * sc1 + ls1;
        mi0 = mn0; mi1 = mn1;

#pragma unroll
        for (int nt = 0; nt < 8; nt++) {
            o[nt][0] *= sc0; o[nt][1] *= sc0;
            o[nt][2] *= sc1; o[nt][3] *= sc1;
        }

        // ---- pack P to bf16 hi/lo fragments ----
        uint32_t ph[8][2], pl[8][2];
#pragma unroll
        for (int nt = 0; nt < 8; nt++) {
            uint32_t u0 = pack_bf16x2(s[nt][0], s[nt][1]);
            uint32_t u1 = pack_bf16x2(s[nt][2], s[nt][3]);
            ph[nt][0] = u0; ph[nt][1] = u1;
            float l00 = s[nt][0] - __uint_as_float(u0 << 16);
            float l01 = s[nt][1] - __uint_as_float(u0 & 0xffff0000u);
            float l10 = s[nt][2] - __uint_as_float(u1 << 16);
            float l11 = s[nt][3] - __uint_as_float(u1 & 0xffff0000u);
            pl[nt][0] = pack_bf16x2(l00, l01);
            pl[nt][1] = pack_bf16x2(l10, l11);
        }

        // ---- O += P V ----
#pragma unroll
        for (int kk = 0; kk < 4; kk++) {
            uint32_t vh[8][2], vl[8][2];
#pragma unroll
            for (int g = 0; g < 4; g++) {
                const int off = (g * 16 + ((lane >> 4) << 3) + (lane & 7)) * APITCH
                              + (((lane >> 3) & 1) << 3) + kk * 16;
                uint32_t t0, t1, t2, t3;
                LDSM4(t0, t1, t2, t3, uVh + 2 * off);
                vh[2*g][0] = t0; vh[2*g][1] = t1; vh[2*g+1][0] = t2; vh[2*g+1][1] = t3;
                LDSM4(t0, t1, t2, t3, uVl + 2 * off);
                vl[2*g][0] = t0; vl[2*g][1] = t1; vl[2*g+1][0] = t2; vl[2*g+1][1] = t3;
            }
            uint32_t ah[4] = {ph[2*kk][0], ph[2*kk][1], ph[2*kk+1][0], ph[2*kk+1][1]};
            uint32_t al[4] = {pl[2*kk][0], pl[2*kk][1], pl[2*kk+1][0], pl[2*kk+1][1]};
#pragma unroll
            for (int nt = 0; nt < 8; nt++) {
                MMA16816(o[nt], ah, vh[nt][0], vh[nt][1]);
                MMA16816(o[nt], ah, vl[nt][0], vl[nt][1]);
                MMA16816(o[nt], al, vh[nt][0], vh[nt][1]);
            }
        }
        __syncthreads();
    }

    // ---- finalize: write bf16 hi/lo output ([b,s,h,d] = [M,2048]) ----
    const float inv0 = 1.f / li0;
    const float inv1 = 1.f / li1;
    const size_t o0 = (((size_t)b * SEQ + row0) * NHEADS + h) * HDIM;
    const size_t o1 = (((size_t)b * SEQ + row1) * NHEADS + h) * HDIM;
#pragma unroll
    for (int nt = 0; nt < 8; nt++) {
        const int col = nt * 8 + (lane & 3) * 2;
        float a0 = o[nt][0] * inv0, a1 = o[nt][1] * inv0;
        float b0 = o[nt][2] * inv1, b1 = o[nt][3] * inv1;
        uint32_t uh0 = pack_bf16x2(a0, a1);
        uint32_t uh1 = pack_bf16x2(b0, b1);
        uint32_t ul0 = pack_bf16x2(a0 - __uint_as_float(uh0 << 16),
                                   a1 - __uint_as_float(uh0 & 0xffff0000u));
        uint32_t ul1 = pack_bf16x2(b0 - __uint_as_float(uh1 << 16),
                                   b1 - __uint_as_float(uh1 & 0xffff0000u));
        *(uint32_t*)(Oh + o0 + col) = uh0;
        *(uint32_t*)(Ol + o0 + col) = ul0;
        *(uint32_t*)(Oh + o1 + col) = uh1;
        *(uint32_t*)(Ol + o1 + col) = ul1;
    }
}

// ---------------------------------------------------------------------------
extern "C" void kernel_launch(void* const* d_in, const int* in_sizes, int n_in,
                              void* d_out, int out_size)
{
    const float* x    = (const float*)d_in[0];
    const float* fcos = (const float*)d_in[1];
    const float* fsin = (const float*)d_in[2];
    const float* wq   = (const float*)d_in[3];
    const float* wk   = (const float*)d_in[4];
    const float* wv   = (const float*)d_in[5];
    const float* wo   = (const float*)d_in[6];
    float* out = (float*)d_out;

    float *Qp, *Kp, *Vp;
    __nv_bfloat16 *bf, *qh, *ql, *kh, *kl, *vth, *vtl;
    cudaGetSymbolAddress((void**)&Qp, g_Q);
    cudaGetSymbolAddress((void**)&Kp, g_K);
    cudaGetSymbolAddress((void**)&Vp, g_V);
    cudaGetSymbolAddress((void**)&bf, g_bf);
    cudaGetSymbolAddress((void**)&qh, g_Qh);
    cudaGetSymbolAddress((void**)&ql, g_Ql);
    cudaGetSymbolAddress((void**)&kh, g_Kh);
    cudaGetSymbolAddress((void**)&kl, g_Kl);
    cudaGetSymbolAddress((void**)&vth, g_Vth);
    cudaGetSymbolAddress((void**)&vtl, g_Vtl);

    cudaFuncSetAttribute(gemm_mma, cudaFuncAttributeMaxDynamicSharedMemorySize, G_SMEM);
    cudaFuncSetAttribute(attn_mma, cudaFuncAttributeMaxDynamicSharedMemorySize, A_SMEM);

    const int M = BATCH * SEQ;

    // #0: one-shot fp32 -> bf16 hi/lo prepass (x + all weights)
    split_all<<<(Q_TOT + 255) / 256, 256>>>(x, wq, wk, wv, wo, bf);

    // #1, #2: K and V projections
    gemm_mma<<<dim3(KVDIM / 128, M / 128), 256, G_SMEM>>>(bf + OFF_XH, bf + OFF_XL,
                                                          bf + OFF_WKH, bf + OFF_WKL, Kp, M, KVDIM, EMBED);
    gemm_mma<<<dim3(KVDIM / 128, M / 128), 256, G_SMEM>>>(bf + OFF_XH, bf + OFF_XL,
                                                          bf + OFF_WVH, bf + OFF_WVL, Vp, M, KVDIM, EMBED);

    // #3: Q projection (profiled launch slot)
    gemm_mma<<<dim3(EMBED / 128, M / 128), 256, G_SMEM>>>(bf + OFF_XH, bf + OFF_XL,
                                                          bf + OFF_WQH, bf + OFF_WQL, Qp, M, EMBED, EMBED);

    // #4: RoPE + split for Q and K (one launch)
    rope_all<<<(TQ_ITEMS + TK_ITEMS + 255) / 256, 256>>>(Qp, Kp, fcos, fsin, qh, ql, kh, kl);

    // #5: V transpose + split
    split_v_t<<<dim3(SEQ / 64, NKV, BATCH), 256>>>(Vp, vth, vtl);

    // #6: tensor-core causal GQA flash attention (bf16 in/out)
    attn_mma<<<dim3(SEQ / 128, NHEADS, BATCH), 256, A_SMEM>>>(qh, ql, kh, kl, vth, vtl,
                                                              bf + OFF_OH, bf + OFF_OL);

    // #7: output projection
    gemm_mma<<<dim3(EMBED / 128, M / 128), 256, G_SMEM>>>(bf + OFF_OH, bf + OFF_OL,
                                                          bf + OFF_WOH, bf + OFF_WOL, out, M, EMBED, EMBED);
}

// round 7
// speedup vs baseline: 3.2709x; 1.0131x over previous
#include <cuda_runtime.h>
#include <cuda_bf16.h>
#include <cstdint>

#define BATCH 2
#define SEQ 2048
#define EMBED 2048
#define NHEADS 32
#define NKV 8
#define HDIM 64
#define KVDIM (NKV*HDIM)   // 512

// fp32 scratch (gemm outputs)
__device__ float g_Q[(size_t)BATCH*SEQ*EMBED];
__device__ float g_K[(size_t)BATCH*SEQ*KVDIM];
__device__ float g_V[(size_t)BATCH*SEQ*KVDIM];

// bf16 hi/lo pool (gemm operands)
#define N_X   (size_t)8388608    // 2*2048*2048
#define N_WQ  (size_t)4194304
#define N_WK  (size_t)1048576
#define N_WV  (size_t)1048576
#define N_WO  (size_t)4194304
#define OFF_XH  (size_t)0
#define OFF_XL  (OFF_XH + N_X)
#define OFF_WQH (OFF_XL + N_X)
#define OFF_WQL (OFF_WQH + N_WQ)
#define OFF_WKH (OFF_WQL + N_WQ)
#define OFF_WKL (OFF_WKH + N_WK)
#define OFF_WVH (OFF_WKL + N_WK)
#define OFF_WVL (OFF_WVH + N_WV)
#define OFF_WOH (OFF_WVL + N_WV)
#define OFF_WOL (OFF_WOH + N_WO)
#define OFF_OH  (OFF_WOL + N_WO)
#define OFF_OL  (OFF_OH + N_X)
#define POOL_SZ (OFF_OL + N_X)
__device__ __nv_bfloat16 g_bf[POOL_SZ];

// bf16 attention operands
__device__ __nv_bfloat16 g_Qh[(size_t)BATCH*NHEADS*SEQ*HDIM];
__device__ __nv_bfloat16 g_Ql[(size_t)BATCH*NHEADS*SEQ*HDIM];
__device__ __nv_bfloat16 g_Kh[(size_t)BATCH*NKV*SEQ*HDIM];
__device__ __nv_bfloat16 g_Kl[(size_t)BATCH*NKV*SEQ*HDIM];
__device__ __nv_bfloat16 g_Vth[(size_t)BATCH*NKV*HDIM*SEQ];
__device__ __nv_bfloat16 g_Vtl[(size_t)BATCH*NKV*HDIM*SEQ];

// ============================ helpers ======================================
__device__ __forceinline__ uint32_t smem_u32(const void* p) {
    uint32_t a;
    asm("{ .reg .u64 t; cvta.to.shared.u64 t, %1; cvt.u32.u64 %0, t; }"
        : "=r"(a) : "l"(p));
    return a;
}

#define LDSM4(R0,R1,R2,R3,ADDR) \
    asm volatile("ldmatrix.sync.aligned.m8n8.x4.shared.b16 {%0,%1,%2,%3}, [%4];" \
                 : "=r"(R0), "=r"(R1), "=r"(R2), "=r"(R3) : "r"(ADDR))

#define MMA16816(C, A, B0, B1) \
    asm volatile("mma.sync.aligned.m16n8k16.row.col.f32.bf16.bf16.f32 " \
                 "{%0,%1,%2,%3}, {%4,%5,%6,%7}, {%8,%9}, {%0,%1,%2,%3};" \
                 : "+f"((C)[0]), "+f"((C)[1]), "+f"((C)[2]), "+f"((C)[3]) \
                 : "r"((A)[0]), "r"((A)[1]), "r"((A)[2]), "r"((A)[3]), \
                   "r"(B0), "r"(B1))

#define CP16(DST, SRC) \
    asm volatile("cp.async.cg.shared.global [%0], [%1], 16;" :: "r"(DST), "l"(SRC))
#define CP_COMMIT() asm volatile("cp.async.commit_group;")
#define CP_WAIT0()  asm volatile("cp.async.wait_group 0;")
#define CP_WAIT1()  asm volatile("cp.async.wait_group 1;")

__device__ __forceinline__ uint32_t pack_bf16x2(float lo, float hi) {
    uint32_t d;
    asm("cvt.rn.bf16x2.f32 %0, %1, %2;" : "=r"(d) : "f"(hi), "f"(lo));
    return d;
}

__device__ __forceinline__ void split4(float4 v, uint2& uh, uint2& ul) {
    __nv_bfloat16 h0 = __float2bfloat16_rn(v.x);
    __nv_bfloat16 h1 = __float2bfloat16_rn(v.y);
    __nv_bfloat16 h2 = __float2bfloat16_rn(v.z);
    __nv_bfloat16 h3 = __float2bfloat16_rn(v.w);
    __nv_bfloat16 l0 = __float2bfloat16_rn(v.x - __bfloat162float(h0));
    __nv_bfloat16 l1 = __float2bfloat16_rn(v.y - __bfloat162float(h1));
    __nv_bfloat16 l2 = __float2bfloat16_rn(v.z - __bfloat162float(h2));
    __nv_bfloat16 l3 = __float2bfloat16_rn(v.w - __bfloat162float(h3));
    uh.x = (uint32_t)__bfloat16_as_ushort(h0) | ((uint32_t)__bfloat16_as_ushort(h1) << 16);
    uh.y = (uint32_t)__bfloat16_as_ushort(h2) | ((uint32_t)__bfloat16_as_ushort(h3) << 16);
    ul.x = (uint32_t)__bfloat16_as_ushort(l0) | ((uint32_t)__bfloat16_as_ushort(l1) << 16);
    ul.y = (uint32_t)__bfloat16_as_ushort(l2) | ((uint32_t)__bfloat16_as_ushort(l3) << 16);
}

// ---------------------------------------------------------------------------
// One-shot split prepass: x, wq, wk, wv, wo -> bf16 hi/lo pool.
// ---------------------------------------------------------------------------
#define Q_X  (int)(N_X/4)
#define Q_WQ (int)(N_WQ/4)
#define Q_WK (int)(N_WK/4)
#define Q_WV (int)(N_WV/4)
#define Q_WO (int)(N_WO/4)
#define Q_TOT (Q_X + Q_WQ + Q_WK + Q_WV + Q_WO)

__global__ void split_all(const float* __restrict__ x,  const float* __restrict__ wq,
                          const float* __restrict__ wk, const float* __restrict__ wv,
                          const float* __restrict__ wo, __nv_bfloat16* __restrict__ bf)
{
    int i = blockIdx.x * blockDim.x + threadIdx.x;
    const float* src; size_t dh, dl; int j;
    if (i < Q_X)                        { src = x;  j = i;                     dh = OFF_XH;  dl = OFF_XL; }
    else if (i < Q_X + Q_WQ)            { src = wq; j = i - Q_X;               dh = OFF_WQH; dl = OFF_WQL; }
    else if (i < Q_X + Q_WQ + Q_WK)     { src = wk; j = i - Q_X - Q_WQ;        dh = OFF_WKH; dl = OFF_WKL; }
    else if (i < Q_X + Q_WQ + Q_WK + Q_WV) { src = wv; j = i - Q_X - Q_WQ - Q_WK; dh = OFF_WVH; dl = OFF_WVL; }
    else if (i < Q_TOT)                 { src = wo; j = i - Q_X - Q_WQ - Q_WK - Q_WV; dh = OFF_WOH; dl = OFF_WOL; }
    else return;
    float4 v = ((const float4*)src)[j];
    uint2 uh, ul;
    split4(v, uh, ul);
    ((uint2*)(bf + dh))[j] = uh;
    ((uint2*)(bf + dl))[j] = ul;
}

// ---------------------------------------------------------------------------
// bf16x3 MMA GEMM, 3-stage cp.async pipeline, 512 threads (16 warps).
// C[M,N] = A[M,K] * B[N,K]^T. Block 128x128, BK=32, warp tile 32x32.
// grid.z selects (B, C) pair: B += z*bstride, C = z ? C1 : C0.
// ---------------------------------------------------------------------------
#define PITCH 40
#define G_ARR (128*PITCH)
#define G_STG (4*G_ARR)
#define G_STG_B (G_STG*2)
#define G_SMEM (3*G_STG_B)           // 122880 B

__global__ __launch_bounds__(512, 1)
void gemm_mma(const __nv_bfloat16* __restrict__ Ah, const __nv_bfloat16* __restrict__ Al,
              const __nv_bfloat16* __restrict__ Bh0, const __nv_bfloat16* __restrict__ Bl0,
              size_t bstride, float* __restrict__ C0, float* __restrict__ C1,
              int M, int N, int K)
{
    extern __shared__ __align__(16) char dsm_raw[];
    const uint32_t sbase = smem_u32(dsm_raw);

    const int tid  = threadIdx.x;
    const int wid  = tid >> 5;
    const int lane = tid & 31;
    const int wm   = wid >> 2;      // 0..3 -> rows wm*32
    const int wn   = wid & 3;       // 0..3 -> cols wn*32

    const int bm = blockIdx.y * 128;
    const int bn = blockIdx.x * 128;

    const __nv_bfloat16* Bh = Bh0 + (size_t)blockIdx.z * bstride;
    const __nv_bfloat16* Bl = Bl0 + (size_t)blockIdx.z * bstride;
    float* C = blockIdx.z ? C1 : C0;

    const int aoff = (wm * 32 + (lane & 15)) * PITCH + ((lane >> 4) << 3);
    const int boff = (wn * 32 + ((lane >> 4) << 3) + (lane & 7)) * PITCH + (((lane >> 3) & 1) << 3);

    const int nk = K >> 5;

    auto load_stage = [&](int kt, int stage) {
        const int k0 = kt << 5;
        const uint32_t sb = sbase + stage * G_STG_B;
#pragma unroll
        for (int q = 0; q < 4; q++) {
            int i = tid + q * 512;
            int a = i >> 9;
            int j = i & 511;
            int r = j >> 2;
            int cc = (j & 3) << 3;
            const __nv_bfloat16* g;
            if (a == 0)      g = Ah + (size_t)(bm + r) * K + k0 + cc;
            else if (a == 1) g = Al + (size_t)(bm + r) * K + k0 + cc;
            else if (a == 2) g = Bh + (size_t)(bn + r) * K + k0 + cc;
            else             g = Bl + (size_t)(bn + r) * K + k0 + cc;
            CP16(sb + (a * G_ARR + r * PITCH + cc) * 2, g);
        }
        CP_COMMIT();
    };

    float c[2][4][4];
#pragma unroll
    for (int a = 0; a < 2; a++)
#pragma unroll
        for (int b = 0; b < 4; b++)
#pragma unroll
            for (int d = 0; d < 4; d++) c[a][b][d] = 0.f;

    load_stage(0, 0);
    if (nk > 1) load_stage(1, 1);

#pragma unroll 1
    for (int kt = 0; kt < nk; kt++) {
        if (kt + 1 < nk) { CP_WAIT1(); } else { CP_WAIT0(); }
        __syncthreads();

        const uint32_t sb = sbase + (kt % 3) * G_STG_B;
        const uint32_t uAh = sb;
        const uint32_t uAl = sb + G_ARR * 2;
        const uint32_t uBh = sb + 2 * G_ARR * 2;
        const uint32_t uBl = sb + 3 * G_ARR * 2;

#pragma unroll
        for (int kk = 0; kk < 32; kk += 16) {
            uint32_t ah[2][4], al[2][4], bh[4][2], bl[4][2];
#pragma unroll
            for (int ms = 0; ms < 2; ms++) {
                LDSM4(ah[ms][0], ah[ms][1], ah[ms][2], ah[ms][3],
                      uAh + 2 * (aoff + ms * 16 * PITCH + kk));
                LDSM4(al[ms][0], al[ms][1], al[ms][2], al[ms][3],
                      uAl + 2 * (aoff + ms * 16 * PITCH + kk));
            }
#pragma unroll
            for (int g = 0; g < 2; g++) {
                uint32_t t0, t1, t2, t3;
                LDSM4(t0, t1, t2, t3, uBh + 2 * (boff + g * 16 * PITCH + kk));
                bh[2*g][0] = t0; bh[2*g][1] = t1; bh[2*g+1][0] = t2; bh[2*g+1][1] = t3;
                LDSM4(t0, t1, t2, t3, uBl + 2 * (boff + g * 16 * PITCH + kk));
                bl[2*g][0] = t0; bl[2*g][1] = t1; bl[2*g+1][0] = t2; bl[2*g+1][1] = t3;
            }
#pragma unroll
            for (int ms = 0; ms < 2; ms++)
#pragma unroll
                for (int ng = 0; ng < 4; ng++) {
                    MMA16816(c[ms][ng], ah[ms], bh[ng][0], bh[ng][1]);
                    MMA16816(c[ms][ng], ah[ms], bl[ng][0], bl[ng][1]);
                    MMA16816(c[ms][ng], al[ms], bh[ng][0], bh[ng][1]);
                }
        }

        if (kt + 2 < nk) load_stage(kt + 2, (kt + 2) % 3);
        __syncthreads();
    }

#pragma unroll
    for (int ms = 0; ms < 2; ms++) {
        const int row = bm + wm * 32 + ms * 16 + (lane >> 2);
#pragma unroll
        for (int ng = 0; ng < 4; ng++) {
            const int col = bn + wn * 32 + ng * 8 + (lane & 3) * 2;
            *(float2*)(C + (size_t)row * N + col)       = make_float2(c[ms][ng][0], c[ms][ng][1]);
            *(float2*)(C + (size_t)(row + 8) * N + col) = make_float2(c[ms][ng][2], c[ms][ng][3]);
        }
    }
}

// ---------------------------------------------------------------------------
// Fused RoPE + split for BOTH Q and K in one launch.
// ---------------------------------------------------------------------------
#define TQ_ITEMS (BATCH*SEQ*NHEADS*32)
#define TK_ITEMS (BATCH*SEQ*NKV*32)

__global__ void rope_all(const float* __restrict__ Qf, const float* __restrict__ Kf,
                         const float* __restrict__ cosv, const float* __restrict__ sinv,
                         __nv_bfloat16* __restrict__ qh, __nv_bfloat16* __restrict__ ql,
                         __nv_bfloat16* __restrict__ kh, __nv_bfloat16* __restrict__ kl)
{
    int i = blockIdx.x * blockDim.x + threadIdx.x;
    const float* buf; __nv_bfloat16 *oh, *ol; int nheads, j;
    if (i < TQ_ITEMS) { buf = Qf; oh = qh; ol = ql; nheads = NHEADS; j = i; }
    else if (i < TQ_ITEMS + TK_ITEMS) { buf = Kf; oh = kh; ol = kl; nheads = NKV; j = i - TQ_ITEMS; }
    else return;

    int d = j & 31;
    int h = (j >> 5) % nheads;
    int s = (j / (32 * nheads)) % SEQ;
    int b = j / (32 * nheads * SEQ);

    const float* p = buf + (((size_t)b * SEQ + s) * nheads + h) * HDIM;
    float c0 = cosv[s * HDIM + d];
    float c1 = cosv[s * HDIM + d + 32];
    float s0 = sinv[s * HDIM + d];
    float s1 = sinv[s * HDIM + d + 32];
    float x0 = p[d];
    float x1 = p[d + 32];
    float y0 = x0 * c0 - x1 * s0;
    float y1 = x1 * c1 + x0 * s1;

    size_t o = (((size_t)b * nheads + h) * SEQ + s) * HDIM;
    __nv_bfloat16 h0 = __float2bfloat16_rn(y0);
    __nv_bfloat16 h1 = __float2bfloat16_rn(y1);
    oh[o + d]      = h0;
    oh[o + d + 32] = h1;
    ol[o + d]      = __float2bfloat16_rn(y0 - __bfloat162float(h0));
    ol[o + d + 32] = __float2bfloat16_rn(y1 - __bfloat162float(h1));
}

// ---------------------------------------------------------------------------
// V fp32 [b,s,8,64] -> V^T bf16 hi/lo [b,kvh,d,s]
// ---------------------------------------------------------------------------
__global__ __launch_bounds__(256) void split_v_t(const float* __restrict__ V,
                                                 __nv_bfloat16* __restrict__ vth,
                                                 __nv_bfloat16* __restrict__ vtl)
{
    __shared__ __nv_bfloat16 th[64][68];
    __shared__ __nv_bfloat16 tl[64][68];
    const int s0  = blockIdx.x * 64;
    const int kvh = blockIdx.y;
    const int b   = blockIdx.z;

    {
        const int r  = threadIdx.x >> 2;
        const int cb = (threadIdx.x & 3) * 16;
        const float4* g = (const float4*)(V + (((size_t)b * SEQ + s0 + r) * NKV + kvh) * HDIM + cb);
#pragma unroll
        for (int i = 0; i < 4; i++) {
            float4 v = g[i];
            float vv[4] = {v.x, v.y, v.z, v.w};
#pragma unroll
            for (int e = 0; e < 4; e++) {
                int d = cb + i * 4 + e;
                __nv_bfloat16 hh = __float2bfloat16_rn(vv[e]);
                th[d][r] = hh;
                tl[d][r] = __float2bfloat16_rn(vv[e] - __bfloat162float(hh));
            }
        }
    }
    __syncthreads();
    {
        const int d  = threadIdx.x >> 2;
        const int sc = (threadIdx.x & 3) * 16;
        size_t obase = (((size_t)b * NKV + kvh) * HDIM + d) * SEQ + s0 + sc;
        uint2 a0 = *(uint2*)&th[d][sc];
        uint2 a1 = *(uint2*)&th[d][sc + 4];
        uint2 a2 = *(uint2*)&th[d][sc + 8];
        uint2 a3 = *(uint2*)&th[d][sc + 12];
        *(uint4*)(vth + obase)     = make_uint4(a0.x, a0.y, a1.x, a1.y);
        *(uint4*)(vth + obase + 8) = make_uint4(a2.x, a2.y, a3.x, a3.y);
        a0 = *(uint2*)&tl[d][sc];
        a1 = *(uint2*)&tl[d][sc + 4];
        a2 = *(uint2*)&tl[d][sc + 8];
        a3 = *(uint2*)&tl[d][sc + 12];
        *(uint4*)(vtl + obase)     = make_uint4(a0.x, a0.y, a1.x, a1.y);
        *(uint4*)(vtl + obase + 8) = make_uint4(a2.x, a2.y, a3.x, a3.y);
    }
}

// ---------------------------------------------------------------------------
// Tensor-core causal flash attention, all-bf16 operands, 2-stage cp.async.
// ---------------------------------------------------------------------------
#define APITCH 72
#define A_ARR (64*APITCH)
#define A_STG (4*A_ARR)
#define A_STG_B (A_STG*2)
#define A_SMEM (2*A_STG_B)           // 73728 B
#define SCALE_LOG2 0.18033688011112042f   // log2(e)/8

__global__ __launch_bounds__(256, 1)
void attn_mma(const __nv_bfloat16* __restrict__ Qh, const __nv_bfloat16* __restrict__ Ql,
              const __nv_bfloat16* __restrict__ Kh, const __nv_bfloat16* __restrict__ Kl,
              const __nv_bfloat16* __restrict__ Vth, const __nv_bfloat16* __restrict__ Vtl,
              __nv_bfloat16* __restrict__ Oh, __nv_bfloat16* __restrict__ Ol)
{
    extern __shared__ __align__(16) char dsm_raw[];
    const uint32_t sbase = smem_u32(dsm_raw);

    const int tid  = threadIdx.x;
    const int wid  = tid >> 5;
    const int lane = tid & 31;
    const int t = (int)gridDim.x - 1 - (int)blockIdx.x;
    const int h = blockIdx.y;
    const int b = blockIdx.z;
    const int kvh = h >> 2;

    {
        const size_t qbase = (((size_t)b * NHEADS + h) * SEQ + (size_t)t * 128) * HDIM;
#pragma unroll
        for (int q = 0; q < 8; q++) {
            int i = tid + q * 256;
            int a = i >> 10;
            int j = i & 1023;
            int r = j >> 3;
            int cc = (j & 7) << 3;
            const __nv_bfloat16* g = (a ? Ql : Qh) + qbase + (size_t)r * HDIM + cc;
            CP16(sbase + (a * 128 * APITCH + r * APITCH + cc) * 2, g);
        }
        CP_COMMIT();
        CP_WAIT0();
    }
    __syncthreads();

    uint32_t qh[4][4], ql[4][4];
    {
        const uint32_t uQh = sbase;
        const uint32_t uQl = sbase + 128 * APITCH * 2;
        const int aoff = (wid * 16 + (lane & 15)) * APITCH + ((lane >> 4) << 3);
#pragma unroll
        for (int kk = 0; kk < 4; kk++) {
            LDSM4(qh[kk][0], qh[kk][1], qh[kk][2], qh[kk][3], uQh + 2 * (aoff + kk * 16));
            LDSM4(ql[kk][0], ql[kk][1], ql[kk][2], ql[kk][3], uQl + 2 * (aoff + kk * 16));
        }
    }
    __syncthreads();

    const size_t kbase = ((size_t)b * NKV + kvh) * SEQ * HDIM;
    const size_t vbase = ((size_t)b * NKV + kvh) * HDIM * SEQ;

    auto load_kv = [&](int kb, int stage) {
        const uint32_t sb = sbase + stage * A_STG_B;
#pragma unroll
        for (int q = 0; q < 8; q++) {
            int i = tid + q * 256;
            int a = i >> 9;
            int j = i & 511;
            int r = j >> 3;
            int cc = (j & 7) << 3;
            const __nv_bfloat16* g;
            if (a == 0)      g = Kh  + kbase + (size_t)(kb * 64 + r) * HDIM + cc;
            else if (a == 1) g = Kl  + kbase + (size_t)(kb * 64 + r) * HDIM + cc;
            else if (a == 2) g = Vth + vbase + (size_t)r * SEQ + kb * 64 + cc;
            else             g = Vtl + vbase + (size_t)r * SEQ + kb * 64 + cc;
            CP16(sb + (a * A_ARR + r * APITCH + cc) * 2, g);
        }
        CP_COMMIT();
    };

    float o[8][4];
#pragma unroll
    for (int nt = 0; nt < 8; nt++)
#pragma unroll
        for (int e = 0; e < 4; e++) o[nt][e] = 0.f;
    float mi0 = -1e30f, mi1 = -1e30f, li0 = 0.f, li1 = 0.f;

    const int row0 = t * 128 + wid * 16 + (lane >> 2);
    const int row1 = row0 + 8;

    const int nkb = 2 * t + 2;
    load_kv(0, 0);

#pragma unroll 1
    for (int kb = 0; kb < nkb; kb++) {
        if (kb + 1 < nkb) {
            load_kv(kb + 1, (kb + 1) & 1);
            CP_WAIT1();
        } else {
            CP_WAIT0();
        }
        __syncthreads();

        const uint32_t sb = sbase + (kb & 1) * A_STG_B;
        const uint32_t uKh = sb;
        const uint32_t uKl = sb + A_ARR * 2;
        const uint32_t uVh = sb + 2 * A_ARR * 2;
        const uint32_t uVl = sb + 3 * A_ARR * 2;

        float s[8][4];
#pragma unroll
        for (int nt = 0; nt < 8; nt++)
#pragma unroll
            for (int e = 0; e < 4; e++) s[nt][e] = 0.f;

#pragma unroll
        for (int kk = 0; kk < 4; kk++) {
            uint32_t bh[8][2], bl[8][2];
#pragma unroll
            for (int g = 0; g < 4; g++) {
                const int off = (g * 16 + ((lane >> 4) << 3) + (lane & 7)) * APITCH
                              + (((lane >> 3) & 1) << 3) + kk * 16;
                uint32_t t0, t1, t2, t3;
                LDSM4(t0, t1, t2, t3, uKh + 2 * off);
                bh[2*g][0] = t0; bh[2*g][1] = t1; bh[2*g+1][0] = t2; bh[2*g+1][1] = t3;
                LDSM4(t0, t1, t2, t3, uKl + 2 * off);
                bl[2*g][0] = t0; bl[2*g][1] = t1; bl[2*g+1][0] = t2; bl[2*g+1][1] = t3;
            }
#pragma unroll
            for (int nt = 0; nt < 8; nt++) {
                MMA16816(s[nt], qh[kk], bh[nt][0], bh[nt][1]);
                MMA16816(s[nt], qh[kk], bl[nt][0], bl[nt][1]);
                MMA16816(s[nt], ql[kk], bh[nt][0], bh[nt][1]);
            }
        }

        const bool diag = (kb >= 2 * t);
#pragma unroll
        for (int nt = 0; nt < 8; nt++) {
            const int col = kb * 64 + nt * 8 + (lane & 3) * 2;
            s[nt][0] *= SCALE_LOG2; s[nt][1] *= SCALE_LOG2;
            s[nt][2] *= SCALE_LOG2; s[nt][3] *= SCALE_LOG2;
            if (diag) {
                if (col > row0)     s[nt][0] = -1e30f;
                if (col + 1 > row0) s[nt][1] = -1e30f;
                if (col > row1)     s[nt][2] = -1e30f;
                if (col + 1 > row1) s[nt][3] = -1e30f;
            }
        }

        float bm0 = -1e30f, bm1 = -1e30f;
#pragma unroll
        for (int nt = 0; nt < 8; nt++) {
            bm0 = fmaxf(bm0, fmaxf(s[nt][0], s[nt][1]));
            bm1 = fmaxf(bm1, fmaxf(s[nt][2], s[nt][3]));
        }
        bm0 = fmaxf(bm0, __shfl_xor_sync(0xffffffffu, bm0, 1));
        bm0 = fmaxf(bm0, __shfl_xor_sync(0xffffffffu, bm0, 2));
        bm1 = fmaxf(bm1, __shfl_xor_sync(0xffffffffu, bm1, 1));
        bm1 = fmaxf(bm1, __shfl_xor_sync(0xffffffffu, bm1, 2));

        const float mn0 = fmaxf(mi0, bm0);
        const float mn1 = fmaxf(mi1, bm1);
        const float sc0 = exp2f(mi0 - mn0);
        const float sc1 = exp2f(mi1 - mn1);

        float ls0 = 0.f, ls1 = 0.f;
#pragma unroll
        for (int nt = 0; nt < 8; nt++) {
            s[nt][0] = exp2f(s[nt][0] - mn0);
            s[nt][1] = exp2f(s[nt][1] - mn0);
            s[nt][2] = exp2f(s[nt][2] - mn1);
            s[nt][3] = exp2f(s[nt][3] - mn1);
            ls0 += s[nt][0] + s[nt][1];
            ls1 += s[nt][2] + s[nt][3];
        }
        ls0 += __shfl_xor_sync(0xffffffffu, ls0, 1);
        ls0 += __shfl_xor_sync(0xffffffffu, ls0, 2);
        ls1 += __shfl_xor_sync(0xffffffffu, ls1, 1);
        ls1 += __shfl_xor_sync(0xffffffffu, ls1, 2);

        li0 = li0 * sc0 + ls0;
        li1 = li1 * sc1 + ls1;
        mi0 = mn0; mi1 = mn1;

#pragma unroll
        for (int nt = 0; nt < 8; nt++) {
            o[nt][0] *= sc0; o[nt][1] *= sc0;
            o[nt][2] *= sc1; o[nt][3] *= sc1;
        }

        uint32_t ph[8][2], pl[8][2];
#pragma unroll
        for (int nt = 0; nt < 8; nt++) {
            uint32_t u0 = pack_bf16x2(s[nt][0], s[nt][1]);
            uint32_t u1 = pack_bf16x2(s[nt][2], s[nt][3]);
            ph[nt][0] = u0; ph[nt][1] = u1;
            float l00 = s[nt][0] - __uint_as_float(u0 << 16);
            float l01 = s[nt][1] - __uint_as_float(u0 & 0xffff0000u);
            float l10 = s[nt][2] - __uint_as_float(u1 << 16);
            float l11 = s[nt][3] - __uint_as_float(u1 & 0xffff0000u);
            pl[nt][0] = pack_bf16x2(l00, l01);
            pl[nt][1] = pack_bf16x2(l10, l11);
        }

#pragma unroll
        for (int kk = 0; kk < 4; kk++) {
            uint32_t vh[8][2], vl[8][2];
#pragma unroll
            for (int g = 0; g < 4; g++) {
                const int off = (g * 16 + ((lane >> 4) << 3) + (lane & 7)) * APITCH
                              + (((lane >> 3) & 1) << 3) + kk * 16;
                uint32_t t0, t1, t2, t3;
                LDSM4(t0, t1, t2, t3, uVh + 2 * off);
                vh[2*g][0] = t0; vh[2*g][1] = t1; vh[2*g+1][0] = t2; vh[2*g+1][1] = t3;
                LDSM4(t0, t1, t2, t3, uVl + 2 * off);
                vl[2*g][0] = t0; vl[2*g][1] = t1; vl[2*g+1][0] = t2; vl[2*g+1][1] = t3;
            }
            uint32_t ah[4] = {ph[2*kk][0], ph[2*kk][1], ph[2*kk+1][0], ph[2*kk+1][1]};
            uint32_t al[4] = {pl[2*kk][0], pl[2*kk][1], pl[2*kk+1][0], pl[2*kk+1][1]};
#pragma unroll
            for (int nt = 0; nt < 8; nt++) {
                MMA16816(o[nt], ah, vh[nt][0], vh[nt][1]);
                MMA16816(o[nt], ah, vl[nt][0], vl[nt][1]);
                MMA16816(o[nt], al, vh[nt][0], vh[nt][1]);
            }
        }
        __syncthreads();
    }

    const float inv0 = 1.f / li0;
    const float inv1 = 1.f / li1;
    const size_t o0 = (((size_t)b * SEQ + row0) * NHEADS + h) * HDIM;
    const size_t o1 = (((size_t)b * SEQ + row1) * NHEADS + h) * HDIM;
#pragma unroll
    for (int nt = 0; nt < 8; nt++) {
        const int col = nt * 8 + (lane & 3) * 2;
        float a0 = o[nt][0] * inv0, a1 = o[nt][1] * inv0;
        float b0 = o[nt][2] * inv1, b1 = o[nt][3] * inv1;
        uint32_t uh0 = pack_bf16x2(a0, a1);
        uint32_t uh1 = pack_bf16x2(b0, b1);
        uint32_t ul0 = pack_bf16x2(a0 - __uint_as_float(uh0 << 16),
                                   a1 - __uint_as_float(uh0 & 0xffff0000u));
        uint32_t ul1 = pack_bf16x2(b0 - __uint_as_float(uh1 << 16),
                                   b1 - __uint_as_float(uh1 & 0xffff0000u));
        *(uint32_t*)(Oh + o0 + col) = uh0;
        *(uint32_t*)(Ol + o0 + col) = ul0;
        *(uint32_t*)(Oh + o1 + col) = uh1;
        *(uint32_t*)(Ol + o1 + col) = ul1;
    }
}

// ---------------------------------------------------------------------------
extern "C" void kernel_launch(void* const* d_in, const int* in_sizes, int n_in,
                              void* d_out, int out_size)
{
    const float* x    = (const float*)d_in[0];
    const float* fcos = (const float*)d_in[1];
    const float* fsin = (const float*)d_in[2];
    const float* wq   = (const float*)d_in[3];
    const float* wk   = (const float*)d_in[4];
    const float* wv   = (const float*)d_in[5];
    const float* wo   = (const float*)d_in[6];
    float* out = (float*)d_out;

    float *Qp, *Kp, *Vp;
    __nv_bfloat16 *bf, *qh, *ql, *kh, *kl, *vth, *vtl;
    cudaGetSymbolAddress((void**)&Qp, g_Q);
    cudaGetSymbolAddress((void**)&Kp, g_K);
    cudaGetSymbolAddress((void**)&Vp, g_V);
    cudaGetSymbolAddress((void**)&bf, g_bf);
    cudaGetSymbolAddress((void**)&qh, g_Qh);
    cudaGetSymbolAddress((void**)&ql, g_Ql);
    cudaGetSymbolAddress((void**)&kh, g_Kh);
    cudaGetSymbolAddress((void**)&kl, g_Kl);
    cudaGetSymbolAddress((void**)&vth, g_Vth);
    cudaGetSymbolAddress((void**)&vtl, g_Vtl);

    cudaFuncSetAttribute(gemm_mma, cudaFuncAttributeMaxDynamicSharedMemorySize, G_SMEM);
    cudaFuncSetAttribute(attn_mma, cudaFuncAttributeMaxDynamicSharedMemorySize, A_SMEM);

    const int M = BATCH * SEQ;

    // #0: one-shot fp32 -> bf16 hi/lo prepass
    split_all<<<(Q_TOT + 255) / 256, 256>>>(x, wq, wk, wv, wo, bf);

    // #1: K and V projections fused (grid.z picks weight/output)
    gemm_mma<<<dim3(KVDIM / 128, M / 128, 2), 512, G_SMEM>>>(
        bf + OFF_XH, bf + OFF_XL, bf + OFF_WKH, bf + OFF_WKL,
        (size_t)(2 * N_WK), Kp, Vp, M, KVDIM, EMBED);

    // #2: Q projection
    gemm_mma<<<dim3(EMBED / 128, M / 128, 1), 512, G_SMEM>>>(
        bf + OFF_XH, bf + OFF_XL, bf + OFF_WQH, bf + OFF_WQL,
        (size_t)0, Qp, Qp, M, EMBED, EMBED);

    // #3: RoPE + split for Q and K
    rope_all<<<(TQ_ITEMS + TK_ITEMS + 255) / 256, 256>>>(Qp, Kp, fcos, fsin, qh, ql, kh, kl);

    // #4: V transpose + split
    split_v_t<<<dim3(SEQ / 64, NKV, BATCH), 256>>>(Vp, vth, vtl);

    // #5: tensor-core causal GQA flash attention
    attn_mma<<<dim3(SEQ / 128, NHEADS, BATCH), 256, A_SMEM>>>(qh, ql, kh, kl, vth, vtl,
                                                              bf + OFF_OH, bf + OFF_OL);

    // #6: output projection
    gemm_mma<<<dim3(EMBED / 128, M / 128, 1), 512, G_SMEM>>>(
        bf + OFF_OH, bf + OFF_OL, bf + OFF_WOH, bf + OFF_WOL,
        (size_t)0, out, out, M, EMBED, EMBED);
}

// round 8
// speedup vs baseline: 3.5738x; 1.0926x over previous
#include <cuda_runtime.h>
#include <cuda_bf16.h>
#include <cstdint>

#define BATCH 2
#define SEQ 2048
#define EMBED 2048
#define NHEADS 32
#define NKV 8
#define HDIM 64
#define KVDIM (NKV*HDIM)   // 512

// fp32 scratch (gemm outputs)
__device__ float g_Q[(size_t)BATCH*SEQ*EMBED];
__device__ float g_K[(size_t)BATCH*SEQ*KVDIM];
__device__ float g_V[(size_t)BATCH*SEQ*KVDIM];

// bf16 hi/lo pool (gemm operands)
#define N_X   (size_t)8388608    // 2*2048*2048
#define N_WQ  (size_t)4194304
#define N_WK  (size_t)1048576
#define N_WV  (size_t)1048576
#define N_WO  (size_t)4194304
#define OFF_XH  (size_t)0
#define OFF_XL  (OFF_XH + N_X)
#define OFF_WQH (OFF_XL + N_X)
#define OFF_WQL (OFF_WQH + N_WQ)
#define OFF_WKH (OFF_WQL + N_WQ)
#define OFF_WKL (OFF_WKH + N_WK)
#define OFF_WVH (OFF_WKL + N_WK)
#define OFF_WVL (OFF_WVH + N_WV)
#define OFF_WOH (OFF_WVL + N_WV)
#define OFF_WOL (OFF_WOH + N_WO)
#define OFF_OH  (OFF_WOL + N_WO)
#define OFF_OL  (OFF_OH + N_X)
#define POOL_SZ (OFF_OL + N_X)
__device__ __nv_bfloat16 g_bf[POOL_SZ];

// bf16 attention operands
__device__ __nv_bfloat16 g_Qh[(size_t)BATCH*NHEADS*SEQ*HDIM];
__device__ __nv_bfloat16 g_Ql[(size_t)BATCH*NHEADS*SEQ*HDIM];
__device__ __nv_bfloat16 g_Kh[(size_t)BATCH*NKV*SEQ*HDIM];
__device__ __nv_bfloat16 g_Kl[(size_t)BATCH*NKV*SEQ*HDIM];
__device__ __nv_bfloat16 g_Vth[(size_t)BATCH*NKV*HDIM*SEQ];
__device__ __nv_bfloat16 g_Vtl[(size_t)BATCH*NKV*HDIM*SEQ];

// ============================ helpers ======================================
__device__ __forceinline__ uint32_t smem_u32(const void* p) {
    uint32_t a;
    asm("{ .reg .u64 t; cvta.to.shared.u64 t, %1; cvt.u32.u64 %0, t; }"
        : "=r"(a) : "l"(p));
    return a;
}

#define LDSM4(R0,R1,R2,R3,ADDR) \
    asm volatile("ldmatrix.sync.aligned.m8n8.x4.shared.b16 {%0,%1,%2,%3}, [%4];" \
                 : "=r"(R0), "=r"(R1), "=r"(R2), "=r"(R3) : "r"(ADDR))

#define MMA16816(C, A, B0, B1) \
    asm volatile("mma.sync.aligned.m16n8k16.row.col.f32.bf16.bf16.f32 " \
                 "{%0,%1,%2,%3}, {%4,%5,%6,%7}, {%8,%9}, {%0,%1,%2,%3};" \
                 : "+f"((C)[0]), "+f"((C)[1]), "+f"((C)[2]), "+f"((C)[3]) \
                 : "r"((A)[0]), "r"((A)[1]), "r"((A)[2]), "r"((A)[3]), \
                   "r"(B0), "r"(B1))

#define CP16(DST, SRC) \
    asm volatile("cp.async.cg.shared.global [%0], [%1], 16;" :: "r"(DST), "l"(SRC))
#define CP_COMMIT() asm volatile("cp.async.commit_group;")
#define CP_WAIT0()  asm volatile("cp.async.wait_group 0;")
#define CP_WAIT1()  asm volatile("cp.async.wait_group 1;")

__device__ __forceinline__ uint32_t pack_bf16x2(float lo, float hi) {
    uint32_t d;
    asm("cvt.rn.bf16x2.f32 %0, %1, %2;" : "=r"(d) : "f"(hi), "f"(lo));
    return d;
}

__device__ __forceinline__ void split4(float4 v, uint2& uh, uint2& ul) {
    __nv_bfloat16 h0 = __float2bfloat16_rn(v.x);
    __nv_bfloat16 h1 = __float2bfloat16_rn(v.y);
    __nv_bfloat16 h2 = __float2bfloat16_rn(v.z);
    __nv_bfloat16 h3 = __float2bfloat16_rn(v.w);
    __nv_bfloat16 l0 = __float2bfloat16_rn(v.x - __bfloat162float(h0));
    __nv_bfloat16 l1 = __float2bfloat16_rn(v.y - __bfloat162float(h1));
    __nv_bfloat16 l2 = __float2bfloat16_rn(v.z - __bfloat162float(h2));
    __nv_bfloat16 l3 = __float2bfloat16_rn(v.w - __bfloat162float(h3));
    uh.x = (uint32_t)__bfloat16_as_ushort(h0) | ((uint32_t)__bfloat16_as_ushort(h1) << 16);
    uh.y = (uint32_t)__bfloat16_as_ushort(h2) | ((uint32_t)__bfloat16_as_ushort(h3) << 16);
    ul.x = (uint32_t)__bfloat16_as_ushort(l0) | ((uint32_t)__bfloat16_as_ushort(l1) << 16);
    ul.y = (uint32_t)__bfloat16_as_ushort(l2) | ((uint32_t)__bfloat16_as_ushort(l3) << 16);
}

// ---------------------------------------------------------------------------
// One-shot split prepass.
// ---------------------------------------------------------------------------
#define Q_X  (int)(N_X/4)
#define Q_WQ (int)(N_WQ/4)
#define Q_WK (int)(N_WK/4)
#define Q_WV (int)(N_WV/4)
#define Q_WO (int)(N_WO/4)
#define Q_TOT (Q_X + Q_WQ + Q_WK + Q_WV + Q_WO)

__global__ void split_all(const float* __restrict__ x,  const float* __restrict__ wq,
                          const float* __restrict__ wk, const float* __restrict__ wv,
                          const float* __restrict__ wo, __nv_bfloat16* __restrict__ bf)
{
    int i = blockIdx.x * blockDim.x + threadIdx.x;
    const float* src; size_t dh, dl; int j;
    if (i < Q_X)                        { src = x;  j = i;                     dh = OFF_XH;  dl = OFF_XL; }
    else if (i < Q_X + Q_WQ)            { src = wq; j = i - Q_X;               dh = OFF_WQH; dl = OFF_WQL; }
    else if (i < Q_X + Q_WQ + Q_WK)     { src = wk; j = i - Q_X - Q_WQ;        dh = OFF_WKH; dl = OFF_WKL; }
    else if (i < Q_X + Q_WQ + Q_WK + Q_WV) { src = wv; j = i - Q_X - Q_WQ - Q_WK; dh = OFF_WVH; dl = OFF_WVL; }
    else if (i < Q_TOT)                 { src = wo; j = i - Q_X - Q_WQ - Q_WK - Q_WV; dh = OFF_WOH; dl = OFF_WOL; }
    else return;
    float4 v = ((const float4*)src)[j];
    uint2 uh, ul;
    split4(v, uh, ul);
    ((uint2*)(bf + dh))[j] = uh;
    ((uint2*)(bf + dl))[j] = ul;
}

// ---------------------------------------------------------------------------
// bf16x3 MMA GEMM: block tile 128x256, BK=32, 512 threads (16 warps),
// warp tile 32x64, 3-stage cp.async pipeline.
// C[M,N] = A[M,K] * B[N,K]^T. grid.z selects (B, C) pair.
// ---------------------------------------------------------------------------
#define PITCH 40
#define GA_ELE (128*PITCH)           // 5120 elems per A array
#define GB_ELE (256*PITCH)           // 10240 elems per B array
#define G_STG_E (2*GA_ELE + 2*GB_ELE) // 30720 elems per stage
#define G_STG_B (G_STG_E*2)           // 61440 B
#define G_SMEM (3*G_STG_B)            // 184320 B

__global__ __launch_bounds__(512, 1)
void gemm_mma(const __nv_bfloat16* __restrict__ Ah, const __nv_bfloat16* __restrict__ Al,
              const __nv_bfloat16* __restrict__ Bh0, const __nv_bfloat16* __restrict__ Bl0,
              size_t bstride, float* __restrict__ C0, float* __restrict__ C1,
              int M, int N, int K)
{
    extern __shared__ __align__(16) char dsm_raw[];
    const uint32_t sbase = smem_u32(dsm_raw);

    const int tid  = threadIdx.x;
    const int wid  = tid >> 5;
    const int lane = tid & 31;
    const int wm   = wid >> 2;      // 0..3 -> rows wm*32
    const int wn   = wid & 3;       // 0..3 -> cols wn*64

    const int bm = blockIdx.y * 128;
    const int bn = blockIdx.x * 256;

    const __nv_bfloat16* Bh = Bh0 + (size_t)blockIdx.z * bstride;
    const __nv_bfloat16* Bl = Bl0 + (size_t)blockIdx.z * bstride;
    float* C = blockIdx.z ? C1 : C0;

    const int aoff = (wm * 32 + (lane & 15)) * PITCH + ((lane >> 4) << 3);
    // boff for group g (g=0..3 covers n-frags 2g, 2g+1)
    const int bofflane = (((lane >> 4) << 3) + (lane & 7)) * PITCH + (((lane >> 3) & 1) << 3);

    const int nk = K >> 5;

    auto load_stage = [&](int kt, int stage) {
        const int k0 = kt << 5;
        const uint32_t sb = sbase + stage * G_STG_B;
#pragma unroll
        for (int q = 0; q < 6; q++) {
            int c = tid + q * 512;            // 0..3071
            const __nv_bfloat16* g;
            uint32_t dst;
            if (c < 1024) {                   // A arrays
                int arr = c >> 9;             // 0:Ah 1:Al
                int j = c & 511;
                int r = j >> 2;
                int col = (j & 3) << 3;
                g = (arr ? Al : Ah) + (size_t)(bm + r) * K + k0 + col;
                dst = sb + (arr * GA_ELE + r * PITCH + col) * 2;
            } else {                          // B arrays
                int cb = c - 1024;
                int arr = cb >> 10;           // 0:Bh 1:Bl
                int j = cb & 1023;
                int r = j >> 2;
                int col = (j & 3) << 3;
                g = (arr ? Bl : Bh) + (size_t)(bn + r) * K + k0 + col;
                dst = sb + (2 * GA_ELE + arr * GB_ELE + r * PITCH + col) * 2;
            }
            CP16(dst, g);
        }
        CP_COMMIT();
    };

    float c[2][8][4];
#pragma unroll
    for (int a = 0; a < 2; a++)
#pragma unroll
        for (int b = 0; b < 8; b++)
#pragma unroll
            for (int d = 0; d < 4; d++) c[a][b][d] = 0.f;

    load_stage(0, 0);
    if (nk > 1) load_stage(1, 1);

#pragma unroll 1
    for (int kt = 0; kt < nk; kt++) {
        if (kt + 1 < nk) { CP_WAIT1(); } else { CP_WAIT0(); }
        __syncthreads();

        const uint32_t sb = sbase + (kt % 3) * G_STG_B;
        const uint32_t uAh = sb;
        const uint32_t uAl = sb + GA_ELE * 2;
        const uint32_t uBh = sb + 2 * GA_ELE * 2;
        const uint32_t uBl = sb + (2 * GA_ELE + GB_ELE) * 2;

#pragma unroll
        for (int kk = 0; kk < 32; kk += 16) {
            uint32_t ah[2][4], al[2][4], bh[8][2], bl[8][2];
#pragma unroll
            for (int ms = 0; ms < 2; ms++) {
                LDSM4(ah[ms][0], ah[ms][1], ah[ms][2], ah[ms][3],
                      uAh + 2 * (aoff + ms * 16 * PITCH + kk));
                LDSM4(al[ms][0], al[ms][1], al[ms][2], al[ms][3],
                      uAl + 2 * (aoff + ms * 16 * PITCH + kk));
            }
#pragma unroll
            for (int g = 0; g < 4; g++) {
                const int off = (wn * 64 + g * 16) * PITCH + bofflane + kk;
                uint32_t t0, t1, t2, t3;
                LDSM4(t0, t1, t2, t3, uBh + 2 * off);
                bh[2*g][0] = t0; bh[2*g][1] = t1; bh[2*g+1][0] = t2; bh[2*g+1][1] = t3;
                LDSM4(t0, t1, t2, t3, uBl + 2 * off);
                bl[2*g][0] = t0; bl[2*g][1] = t1; bl[2*g+1][0] = t2; bl[2*g+1][1] = t3;
            }
#pragma unroll
            for (int ms = 0; ms < 2; ms++)
#pragma unroll
                for (int ng = 0; ng < 8; ng++) {
                    MMA16816(c[ms][ng], ah[ms], bh[ng][0], bh[ng][1]);
                    MMA16816(c[ms][ng], ah[ms], bl[ng][0], bl[ng][1]);
                    MMA16816(c[ms][ng], al[ms], bh[ng][0], bh[ng][1]);
                }
        }

        if (kt + 2 < nk) load_stage(kt + 2, (kt + 2) % 3);
        __syncthreads();
    }

#pragma unroll
    for (int ms = 0; ms < 2; ms++) {
        const int row = bm + wm * 32 + ms * 16 + (lane >> 2);
#pragma unroll
        for (int ng = 0; ng < 8; ng++) {
            const int col = bn + wn * 64 + ng * 8 + (lane & 3) * 2;
            *(float2*)(C + (size_t)row * N + col)       = make_float2(c[ms][ng][0], c[ms][ng][1]);
            *(float2*)(C + (size_t)(row + 8) * N + col) = make_float2(c[ms][ng][2], c[ms][ng][3]);
        }
    }
}

// ---------------------------------------------------------------------------
// Fused RoPE + split for BOTH Q and K in one launch.
// ---------------------------------------------------------------------------
#define TQ_ITEMS (BATCH*SEQ*NHEADS*32)
#define TK_ITEMS (BATCH*SEQ*NKV*32)

__global__ void rope_all(const float* __restrict__ Qf, const float* __restrict__ Kf,
                         const float* __restrict__ cosv, const float* __restrict__ sinv,
                         __nv_bfloat16* __restrict__ qh, __nv_bfloat16* __restrict__ ql,
                         __nv_bfloat16* __restrict__ kh, __nv_bfloat16* __restrict__ kl)
{
    int i = blockIdx.x * blockDim.x + threadIdx.x;
    const float* buf; __nv_bfloat16 *oh, *ol; int nheads, j;
    if (i < TQ_ITEMS) { buf = Qf; oh = qh; ol = ql; nheads = NHEADS; j = i; }
    else if (i < TQ_ITEMS + TK_ITEMS) { buf = Kf; oh = kh; ol = kl; nheads = NKV; j = i - TQ_ITEMS; }
    else return;

    int d = j & 31;
    int h = (j >> 5) % nheads;
    int s = (j / (32 * nheads)) % SEQ;
    int b = j / (32 * nheads * SEQ);

    const float* p = buf + (((size_t)b * SEQ + s) * nheads + h) * HDIM;
    float c0 = cosv[s * HDIM + d];
    float c1 = cosv[s * HDIM + d + 32];
    float s0 = sinv[s * HDIM + d];
    float s1 = sinv[s * HDIM + d + 32];
    float x0 = p[d];
    float x1 = p[d + 32];
    float y0 = x0 * c0 - x1 * s0;
    float y1 = x1 * c1 + x0 * s1;

    size_t o = (((size_t)b * nheads + h) * SEQ + s) * HDIM;
    __nv_bfloat16 h0 = __float2bfloat16_rn(y0);
    __nv_bfloat16 h1 = __float2bfloat16_rn(y1);
    oh[o + d]      = h0;
    oh[o + d + 32] = h1;
    ol[o + d]      = __float2bfloat16_rn(y0 - __bfloat162float(h0));
    ol[o + d + 32] = __float2bfloat16_rn(y1 - __bfloat162float(h1));
}

// ---------------------------------------------------------------------------
// V fp32 [b,s,8,64] -> V^T bf16 hi/lo [b,kvh,d,s]
// ---------------------------------------------------------------------------
__global__ __launch_bounds__(256) void split_v_t(const float* __restrict__ V,
                                                 __nv_bfloat16* __restrict__ vth,
                                                 __nv_bfloat16* __restrict__ vtl)
{
    __shared__ __nv_bfloat16 th[64][68];
    __shared__ __nv_bfloat16 tl[64][68];
    const int s0  = blockIdx.x * 64;
    const int kvh = blockIdx.y;
    const int b   = blockIdx.z;

    {
        const int r  = threadIdx.x >> 2;
        const int cb = (threadIdx.x & 3) * 16;
        const float4* g = (const float4*)(V + (((size_t)b * SEQ + s0 + r) * NKV + kvh) * HDIM + cb);
#pragma unroll
        for (int i = 0; i < 4; i++) {
            float4 v = g[i];
            float vv[4] = {v.x, v.y, v.z, v.w};
#pragma unroll
            for (int e = 0; e < 4; e++) {
                int d = cb + i * 4 + e;
                __nv_bfloat16 hh = __float2bfloat16_rn(vv[e]);
                th[d][r] = hh;
                tl[d][r] = __float2bfloat16_rn(vv[e] - __bfloat162float(hh));
            }
        }
    }
    __syncthreads();
    {
        const int d  = threadIdx.x >> 2;
        const int sc = (threadIdx.x & 3) * 16;
        size_t obase = (((size_t)b * NKV + kvh) * HDIM + d) * SEQ + s0 + sc;
        uint2 a0 = *(uint2*)&th[d][sc];
        uint2 a1 = *(uint2*)&th[d][sc + 4];
        uint2 a2 = *(uint2*)&th[d][sc + 8];
        uint2 a3 = *(uint2*)&th[d][sc + 12];
        *(uint4*)(vth + obase)     = make_uint4(a0.x, a0.y, a1.x, a1.y);
        *(uint4*)(vth + obase + 8) = make_uint4(a2.x, a2.y, a3.x, a3.y);
        a0 = *(uint2*)&tl[d][sc];
        a1 = *(uint2*)&tl[d][sc + 4];
        a2 = *(uint2*)&tl[d][sc + 8];
        a3 = *(uint2*)&tl[d][sc + 12];
        *(uint4*)(vtl + obase)     = make_uint4(a0.x, a0.y, a1.x, a1.y);
        *(uint4*)(vtl + obase + 8) = make_uint4(a2.x, a2.y, a3.x, a3.y);
    }
}

// ---------------------------------------------------------------------------
// Tensor-core causal flash attention, all-bf16 operands, 2-stage cp.async.
// ---------------------------------------------------------------------------
#define APITCH 72
#define A_ARR (64*APITCH)
#define A_STG (4*A_ARR)
#define A_STG_B (A_STG*2)
#define A_SMEM (2*A_STG_B)           // 73728 B
#define SCALE_LOG2 0.18033688011112042f   // log2(e)/8

__global__ __launch_bounds__(256, 1)
void attn_mma(const __nv_bfloat16* __restrict__ Qh, const __nv_bfloat16* __restrict__ Ql,
              const __nv_bfloat16* __restrict__ Kh, const __nv_bfloat16* __restrict__ Kl,
              const __nv_bfloat16* __restrict__ Vth, const __nv_bfloat16* __restrict__ Vtl,
              __nv_bfloat16* __restrict__ Oh, __nv_bfloat16* __restrict__ Ol)
{
    extern __shared__ __align__(16) char dsm_raw[];
    const uint32_t sbase = smem_u32(dsm_raw);

    const int tid  = threadIdx.x;
    const int wid  = tid >> 5;
    const int lane = tid & 31;
    const int t = (int)gridDim.x - 1 - (int)blockIdx.x;
    const int h = blockIdx.y;
    const int b = blockIdx.z;
    const int kvh = h >> 2;

    {
        const size_t qbase = (((size_t)b * NHEADS + h) * SEQ + (size_t)t * 128) * HDIM;
#pragma unroll
        for (int q = 0; q < 8; q++) {
            int i = tid + q * 256;
            int a = i >> 10;
            int j = i & 1023;
            int r = j >> 3;
            int cc = (j & 7) << 3;
            const __nv_bfloat16* g = (a ? Ql : Qh) + qbase + (size_t)r * HDIM + cc;
            CP16(sbase + (a * 128 * APITCH + r * APITCH + cc) * 2, g);
        }
        CP_COMMIT();
        CP_WAIT0();
    }
    __syncthreads();

    uint32_t qh[4][4], ql[4][4];
    {
        const uint32_t uQh = sbase;
        const uint32_t uQl = sbase + 128 * APITCH * 2;
        const int aoff = (wid * 16 + (lane & 15)) * APITCH + ((lane >> 4) << 3);
#pragma unroll
        for (int kk = 0; kk < 4; kk++) {
            LDSM4(qh[kk][0], qh[kk][1], qh[kk][2], qh[kk][3], uQh + 2 * (aoff + kk * 16));
            LDSM4(ql[kk][0], ql[kk][1], ql[kk][2], ql[kk][3], uQl + 2 * (aoff + kk * 16));
        }
    }
    __syncthreads();

    const size_t kbase = ((size_t)b * NKV + kvh) * SEQ * HDIM;
    const size_t vbase = ((size_t)b * NKV + kvh) * HDIM * SEQ;

    auto load_kv = [&](int kb, int stage) {
        const uint32_t sb = sbase + stage * A_STG_B;
#pragma unroll
        for (int q = 0; q < 8; q++) {
            int i = tid + q * 256;
            int a = i >> 9;
            int j = i & 511;
            int r = j >> 3;
            int cc = (j & 7) << 3;
            const __nv_bfloat16* g;
            if (a == 0)      g = Kh  + kbase + (size_t)(kb * 64 + r) * HDIM + cc;
            else if (a == 1) g = Kl  + kbase + (size_t)(kb * 64 + r) * HDIM + cc;
            else if (a == 2) g = Vth + vbase + (size_t)r * SEQ + kb * 64 + cc;
            else             g = Vtl + vbase + (size_t)r * SEQ + kb * 64 + cc;
            CP16(sb + (a * A_ARR + r * APITCH + cc) * 2, g);
        }
        CP_COMMIT();
    };

    float o[8][4];
#pragma unroll
    for (int nt = 0; nt < 8; nt++)
#pragma unroll
        for (int e = 0; e < 4; e++) o[nt][e] = 0.f;
    float mi0 = -1e30f, mi1 = -1e30f, li0 = 0.f, li1 = 0.f;

    const int row0 = t * 128 + wid * 16 + (lane >> 2);
    const int row1 = row0 + 8;

    const int nkb = 2 * t + 2;
    load_kv(0, 0);

#pragma unroll 1
    for (int kb = 0; kb < nkb; kb++) {
        if (kb + 1 < nkb) {
            load_kv(kb + 1, (kb + 1) & 1);
            CP_WAIT1();
        } else {
            CP_WAIT0();
        }
        __syncthreads();

        const uint32_t sb = sbase + (kb & 1) * A_STG_B;
        const uint32_t uKh = sb;
        const uint32_t uKl = sb + A_ARR * 2;
        const uint32_t uVh = sb + 2 * A_ARR * 2;
        const uint32_t uVl = sb + 3 * A_ARR * 2;

        float s[8][4];
#pragma unroll
        for (int nt = 0; nt < 8; nt++)
#pragma unroll
            for (int e = 0; e < 4; e++) s[nt][e] = 0.f;

#pragma unroll
        for (int kk = 0; kk < 4; kk++) {
            uint32_t bh[8][2], bl[8][2];
#pragma unroll
            for (int g = 0; g < 4; g++) {
                const int off = (g * 16 + ((lane >> 4) << 3) + (lane & 7)) * APITCH
                              + (((lane >> 3) & 1) << 3) + kk * 16;
                uint32_t t0, t1, t2, t3;
                LDSM4(t0, t1, t2, t3, uKh + 2 * off);
                bh[2*g][0] = t0; bh[2*g][1] = t1; bh[2*g+1][0] = t2; bh[2*g+1][1] = t3;
                LDSM4(t0, t1, t2, t3, uKl + 2 * off);
                bl[2*g][0] = t0; bl[2*g][1] = t1; bl[2*g+1][0] = t2; bl[2*g+1][1] = t3;
            }
#pragma unroll
            for (int nt = 0; nt < 8; nt++) {
                MMA16816(s[nt], qh[kk], bh[nt][0], bh[nt][1]);
                MMA16816(s[nt], qh[kk], bl[nt][0], bl[nt][1]);
                MMA16816(s[nt], ql[kk], bh[nt][0], bh[nt][1]);
            }
        }

        const bool diag = (kb >= 2 * t);
#pragma unroll
        for (int nt = 0; nt < 8; nt++) {
            const int col = kb * 64 + nt * 8 + (lane & 3) * 2;
            s[nt][0] *= SCALE_LOG2; s[nt][1] *= SCALE_LOG2;
            s[nt][2] *= SCALE_LOG2; s[nt][3] *= SCALE_LOG2;
            if (diag) {
                if (col > row0)     s[nt][0] = -1e30f;
                if (col + 1 > row0) s[nt][1] = -1e30f;
                if (col > row1)     s[nt][2] = -1e30f;
                if (col + 1 > row1) s[nt][3] = -1e30f;
            }
        }

        float bm0 = -1e30f, bm1 = -1e30f;
#pragma unroll
        for (int nt = 0; nt < 8; nt++) {
            bm0 = fmaxf(bm0, fmaxf(s[nt][0], s[nt][1]));
            bm1 = fmaxf(bm1, fmaxf(s[nt][2], s[nt][3]));
        }
        bm0 = fmaxf(bm0, __shfl_xor_sync(0xffffffffu, bm0, 1));
        bm0 = fmaxf(bm0, __shfl_xor_sync(0xffffffffu, bm0, 2));
        bm1 = fmaxf(bm1, __shfl_xor_sync(0xffffffffu, bm1, 1));
        bm1 = fmaxf(bm1, __shfl_xor_sync(0xffffffffu, bm1, 2));

        const float mn0 = fmaxf(mi0, bm0);
        const float mn1 = fmaxf(mi1, bm1);
        const float sc0 = exp2f(mi0 - mn0);
        const float sc1 = exp2f(mi1 - mn1);

        float ls0 = 0.f, ls1 = 0.f;
#pragma unroll
        for (int nt = 0; nt < 8; nt++) {
            s[nt][0] = exp2f(s[nt][0] - mn0);
            s[nt][1] = exp2f(s[nt][1] - mn0);
            s[nt][2] = exp2f(s[nt][2] - mn1);
            s[nt][3] = exp2f(s[nt][3] - mn1);
            ls0 += s[nt][0] + s[nt][1];
            ls1 += s[nt][2] + s[nt][3];
        }
        ls0 += __shfl_xor_sync(0xffffffffu, ls0, 1);
        ls0 += __shfl_xor_sync(0xffffffffu, ls0, 2);
        ls1 += __shfl_xor_sync(0xffffffffu, ls1, 1);
        ls1 += __shfl_xor_sync(0xffffffffu, ls1, 2);

        li0 = li0 * sc0 + ls0;
        li1 = li1 * sc1 + ls1;
        mi0 = mn0; mi1 = mn1;

#pragma unroll
        for (int nt = 0; nt < 8; nt++) {
            o[nt][0] *= sc0; o[nt][1] *= sc0;
            o[nt][2] *= sc1; o[nt][3] *= sc1;
        }

        uint32_t ph[8][2], pl[8][2];
#pragma unroll
        for (int nt = 0; nt < 8; nt++) {
            uint32_t u0 = pack_bf16x2(s[nt][0], s[nt][1]);
            uint32_t u1 = pack_bf16x2(s[nt][2], s[nt][3]);
            ph[nt][0] = u0; ph[nt][1] = u1;
            float l00 = s[nt][0] - __uint_as_float(u0 << 16);
            float l01 = s[nt][1] - __uint_as_float(u0 & 0xffff0000u);
            float l10 = s[nt][2] - __uint_as_float(u1 << 16);
            float l11 = s[nt][3] - __uint_as_float(u1 & 0xffff0000u);
            pl[nt][0] = pack_bf16x2(l00, l01);
            pl[nt][1] = pack_bf16x2(l10, l11);
        }

#pragma unroll
        for (int kk = 0; kk < 4; kk++) {
            uint32_t vh[8][2], vl[8][2];
#pragma unroll
            for (int g = 0; g < 4; g++) {
                const int off = (g * 16 + ((lane >> 4) << 3) + (lane & 7)) * APITCH
                              + (((lane >> 3) & 1) << 3) + kk * 16;
                uint32_t t0, t1, t2, t3;
                LDSM4(t0, t1, t2, t3, uVh + 2 * off);
                vh[2*g][0] = t0; vh[2*g][1] = t1; vh[2*g+1][0] = t2; vh[2*g+1][1] = t3;
                LDSM4(t0, t1, t2, t3, uVl + 2 * off);
                vl[2*g][0] = t0; vl[2*g][1] = t1; vl[2*g+1][0] = t2; vl[2*g+1][1] = t3;
            }
            uint32_t ah[4] = {ph[2*kk][0], ph[2*kk][1], ph[2*kk+1][0], ph[2*kk+1][1]};
            uint32_t al[4] = {pl[2*kk][0], pl[2*kk][1], pl[2*kk+1][0], pl[2*kk+1][1]};
#pragma unroll
            for (int nt = 0; nt < 8; nt++) {
                MMA16816(o[nt], ah, vh[nt][0], vh[nt][1]);
                MMA16816(o[nt], ah, vl[nt][0], vl[nt][1]);
                MMA16816(o[nt], al, vh[nt][0], vh[nt][1]);
            }
        }
        __syncthreads();
    }

    const float inv0 = 1.f / li0;
    const float inv1 = 1.f / li1;
    const size_t o0 = (((size_t)b * SEQ + row0) * NHEADS + h) * HDIM;
    const size_t o1 = (((size_t)b * SEQ + row1) * NHEADS + h) * HDIM;
#pragma unroll
    for (int nt = 0; nt < 8; nt++) {
        const int col = nt * 8 + (lane & 3) * 2;
        float a0 = o[nt][0] * inv0, a1 = o[nt][1] * inv0;
        float b0 = o[nt][2] * inv1, b1 = o[nt][3] * inv1;
        uint32_t uh0 = pack_bf16x2(a0, a1);
        uint32_t uh1 = pack_bf16x2(b0, b1);
        uint32_t ul0 = pack_bf16x2(a0 - __uint_as_float(uh0 << 16),
                                   a1 - __uint_as_float(uh0 & 0xffff0000u));
        uint32_t ul1 = pack_bf16x2(b0 - __uint_as_float(uh1 << 16),
                                   b1 - __uint_as_float(uh1 & 0xffff0000u));
        *(uint32_t*)(Oh + o0 + col) = uh0;
        *(uint32_t*)(Ol + o0 + col) = ul0;
        *(uint32_t*)(Oh + o1 + col) = uh1;
        *(uint32_t*)(Ol + o1 + col) = ul1;
    }
}

// ---------------------------------------------------------------------------
extern "C" void kernel_launch(void* const* d_in, const int* in_sizes, int n_in,
                              void* d_out, int out_size)
{
    const float* x    = (const float*)d_in[0];
    const float* fcos = (const float*)d_in[1];
    const float* fsin = (const float*)d_in[2];
    const float* wq   = (const float*)d_in[3];
    const float* wk   = (const float*)d_in[4];
    const float* wv   = (const float*)d_in[5];
    const float* wo   = (const float*)d_in[6];
    float* out = (float*)d_out;

    float *Qp, *Kp, *Vp;
    __nv_bfloat16 *bf, *qh, *ql, *kh, *kl, *vth, *vtl;
    cudaGetSymbolAddress((void**)&Qp, g_Q);
    cudaGetSymbolAddress((void**)&Kp, g_K);
    cudaGetSymbolAddress((void**)&Vp, g_V);
    cudaGetSymbolAddress((void**)&bf, g_bf);
    cudaGetSymbolAddress((void**)&qh, g_Qh);
    cudaGetSymbolAddress((void**)&ql, g_Ql);
    cudaGetSymbolAddress((void**)&kh, g_Kh);
    cudaGetSymbolAddress((void**)&kl, g_Kl);
    cudaGetSymbolAddress((void**)&vth, g_Vth);
    cudaGetSymbolAddress((void**)&vtl, g_Vtl);

    cudaFuncSetAttribute(gemm_mma, cudaFuncAttributeMaxDynamicSharedMemorySize, G_SMEM);
    cudaFuncSetAttribute(attn_mma, cudaFuncAttributeMaxDynamicSharedMemorySize, A_SMEM);

    const int M = BATCH * SEQ;

    // #0: one-shot fp32 -> bf16 hi/lo prepass
    split_all<<<(Q_TOT + 255) / 256, 256>>>(x, wq, wk, wv, wo, bf);

    // #1: K and V projections fused (grid.z picks weight/output)
    gemm_mma<<<dim3(KVDIM / 256, M / 128, 2), 512, G_SMEM>>>(
        bf + OFF_XH, bf + OFF_XL, bf + OFF_WKH, bf + OFF_WKL,
        (size_t)(2 * N_WK), Kp, Vp, M, KVDIM, EMBED);

    // #2: Q projection
    gemm_mma<<<dim3(EMBED / 256, M / 128, 1), 512, G_SMEM>>>(
        bf + OFF_XH, bf + OFF_XL, bf + OFF_WQH, bf + OFF_WQL,
        (size_t)0, Qp, Qp, M, EMBED, EMBED);

    // #3: RoPE + split for Q and K
    rope_all<<<(TQ_ITEMS + TK_ITEMS + 255) / 256, 256>>>(Qp, Kp, fcos, fsin, qh, ql, kh, kl);

    // #4: V transpose + split
    split_v_t<<<dim3(SEQ / 64, NKV, BATCH), 256>>>(Vp, vth, vtl);

    // #5: tensor-core causal GQA flash attention
    attn_mma<<<dim3(SEQ / 128, NHEADS, BATCH), 256, A_SMEM>>>(qh, ql, kh, kl, vth, vtl,
                                                              bf + OFF_OH, bf + OFF_OL);

    // #6: output projection
    gemm_mma<<<dim3(EMBED / 256, M / 128, 1), 512, G_SMEM>>>(
        bf + OFF_OH, bf + OFF_OL, bf + OFF_WOH, bf + OFF_WOL,
        (size_t)0, out, out, M, EMBED, EMBED);
}

// round 9
// speedup vs baseline: 4.3172x; 1.2080x over previous
#include <cuda_runtime.h>
#include <cuda_bf16.h>
#include <cuda_fp16.h>
#include <cstdint>

#define BATCH 2
#define SEQ 2048
#define EMBED 2048
#define NHEADS 32
#define NKV 8
#define HDIM 64
#define KVDIM (NKV*HDIM)   // 512

// fp32 scratch (gemm outputs)
__device__ float g_Q[(size_t)BATCH*SEQ*EMBED];
__device__ float g_K[(size_t)BATCH*SEQ*KVDIM];
__device__ float g_V[(size_t)BATCH*SEQ*KVDIM];

// fp16 pool (gemm operands): activations single, weights hi/lo
#define N_X   (size_t)8388608    // 2*2048*2048
#define N_WQ  (size_t)4194304
#define N_WK  (size_t)1048576
#define N_WV  (size_t)1048576
#define N_WO  (size_t)4194304
#define OFF_XS  (size_t)0
#define OFF_WQH (OFF_XS + N_X)
#define OFF_WQL (OFF_WQH + N_WQ)
#define OFF_WKH (OFF_WQL + N_WQ)
#define OFF_WKL (OFF_WKH + N_WK)
#define OFF_WVH (OFF_WKL + N_WK)
#define OFF_WVL (OFF_WVH + N_WV)
#define OFF_WOH (OFF_WVL + N_WV)
#define OFF_WOL (OFF_WOH + N_WO)
#define OFF_OS  (OFF_WOL + N_WO)
#define POOL_SZ (OFF_OS + N_X)
__device__ __half g_hf[POOL_SZ];

// bf16 attention operands (attention stays bf16x3)
__device__ __nv_bfloat16 g_Qh[(size_t)BATCH*NHEADS*SEQ*HDIM];
__device__ __nv_bfloat16 g_Ql[(size_t)BATCH*NHEADS*SEQ*HDIM];
__device__ __nv_bfloat16 g_Kh[(size_t)BATCH*NKV*SEQ*HDIM];
__device__ __nv_bfloat16 g_Kl[(size_t)BATCH*NKV*SEQ*HDIM];
__device__ __nv_bfloat16 g_Vth[(size_t)BATCH*NKV*HDIM*SEQ];
__device__ __nv_bfloat16 g_Vtl[(size_t)BATCH*NKV*HDIM*SEQ];

// ============================ helpers ======================================
__device__ __forceinline__ uint32_t smem_u32(const void* p) {
    uint32_t a;
    asm("{ .reg .u64 t; cvta.to.shared.u64 t, %1; cvt.u32.u64 %0, t; }"
        : "=r"(a) : "l"(p));
    return a;
}

#define LDSM4(R0,R1,R2,R3,ADDR) \
    asm volatile("ldmatrix.sync.aligned.m8n8.x4.shared.b16 {%0,%1,%2,%3}, [%4];" \
                 : "=r"(R0), "=r"(R1), "=r"(R2), "=r"(R3) : "r"(ADDR))

// bf16 MMA (attention)
#define MMA16816(C, A, B0, B1) \
    asm volatile("mma.sync.aligned.m16n8k16.row.col.f32.bf16.bf16.f32 " \
                 "{%0,%1,%2,%3}, {%4,%5,%6,%7}, {%8,%9}, {%0,%1,%2,%3};" \
                 : "+f"((C)[0]), "+f"((C)[1]), "+f"((C)[2]), "+f"((C)[3]) \
                 : "r"((A)[0]), "r"((A)[1]), "r"((A)[2]), "r"((A)[3]), \
                   "r"(B0), "r"(B1))

// fp16 MMA (gemms)
#define MMA16816F(C, A, B0, B1) \
    asm volatile("mma.sync.aligned.m16n8k16.row.col.f32.f16.f16.f32 " \
                 "{%0,%1,%2,%3}, {%4,%5,%6,%7}, {%8,%9}, {%0,%1,%2,%3};" \
                 : "+f"((C)[0]), "+f"((C)[1]), "+f"((C)[2]), "+f"((C)[3]) \
                 : "r"((A)[0]), "r"((A)[1]), "r"((A)[2]), "r"((A)[3]), \
                   "r"(B0), "r"(B1))

#define CP16(DST, SRC) \
    asm volatile("cp.async.cg.shared.global [%0], [%1], 16;" :: "r"(DST), "l"(SRC))
#define CP_COMMIT() asm volatile("cp.async.commit_group;")
#define CP_WAIT0()  asm volatile("cp.async.wait_group 0;")
#define CP_WAIT1()  asm volatile("cp.async.wait_group 1;")

__device__ __forceinline__ uint32_t pack_bf16x2(float lo, float hi) {
    uint32_t d;
    asm("cvt.rn.bf16x2.f32 %0, %1, %2;" : "=r"(d) : "f"(hi), "f"(lo));
    return d;
}
__device__ __forceinline__ uint32_t pack_f16x2(float lo, float hi) {
    uint32_t d;
    asm("cvt.rn.f16x2.f32 %0, %1, %2;" : "=r"(d) : "f"(hi), "f"(lo));
    return d;
}

// ---------------------------------------------------------------------------
// One-shot prepass: x -> fp16 single; weights -> fp16 hi/lo.
// ---------------------------------------------------------------------------
#define Q_X  (int)(N_X/4)
#define Q_WQ (int)(N_WQ/4)
#define Q_WK (int)(N_WK/4)
#define Q_WV (int)(N_WV/4)
#define Q_WO (int)(N_WO/4)
#define Q_TOT (Q_X + Q_WQ + Q_WK + Q_WV + Q_WO)

__global__ void split_all(const float* __restrict__ x,  const float* __restrict__ wq,
                          const float* __restrict__ wk, const float* __restrict__ wv,
                          const float* __restrict__ wo, __half* __restrict__ hf)
{
    int i = blockIdx.x * blockDim.x + threadIdx.x;
    if (i >= Q_TOT) return;
    if (i < Q_X) {
        float4 v = ((const float4*)x)[i];
        uint2 u;
        u.x = pack_f16x2(v.x, v.y);
        u.y = pack_f16x2(v.z, v.w);
        ((uint2*)(hf + OFF_XS))[i] = u;
        return;
    }
    const float* src; size_t dh, dl; int j;
    if (i < Q_X + Q_WQ)                    { src = wq; j = i - Q_X;                   dh = OFF_WQH; dl = OFF_WQL; }
    else if (i < Q_X + Q_WQ + Q_WK)        { src = wk; j = i - Q_X - Q_WQ;            dh = OFF_WKH; dl = OFF_WKL; }
    else if (i < Q_X + Q_WQ + Q_WK + Q_WV) { src = wv; j = i - Q_X - Q_WQ - Q_WK;     dh = OFF_WVH; dl = OFF_WVL; }
    else                                   { src = wo; j = i - Q_X - Q_WQ - Q_WK - Q_WV; dh = OFF_WOH; dl = OFF_WOL; }
    float4 v = ((const float4*)src)[j];
    __half h0 = __float2half_rn(v.x);
    __half h1 = __float2half_rn(v.y);
    __half h2 = __float2half_rn(v.z);
    __half h3 = __float2half_rn(v.w);
    __half l0 = __float2half_rn(v.x - __half2float(h0));
    __half l1 = __float2half_rn(v.y - __half2float(h1));
    __half l2 = __float2half_rn(v.z - __half2float(h2));
    __half l3 = __float2half_rn(v.w - __half2float(h3));
    uint2 uh, ul;
    uh.x = (uint32_t)__half_as_ushort(h0) | ((uint32_t)__half_as_ushort(h1) << 16);
    uh.y = (uint32_t)__half_as_ushort(h2) | ((uint32_t)__half_as_ushort(h3) << 16);
    ul.x = (uint32_t)__half_as_ushort(l0) | ((uint32_t)__half_as_ushort(l1) << 16);
    ul.y = (uint32_t)__half_as_ushort(l2) | ((uint32_t)__half_as_ushort(l3) << 16);
    ((uint2*)(hf + dh))[j] = uh;
    ((uint2*)(hf + dl))[j] = ul;
}

// ---------------------------------------------------------------------------
// fp16 2-term MMA GEMM: C = A(single) * [Bh + Bl]^T.
// Block 128x256, BK=32, 512 threads, warp tile 32x64, 3-stage cp.async.
// ---------------------------------------------------------------------------
#define PITCH 40
#define GA_ELE (128*PITCH)            // A single array
#define GB_ELE (256*PITCH)            // per B array
#define G_STG_E (GA_ELE + 2*GB_ELE)   // 25600 elems
#define G_STG_B (G_STG_E*2)           // 51200 B
#define G_SMEM (3*G_STG_B)            // 153600 B

__global__ __launch_bounds__(512, 1)
void gemm_mma(const __half* __restrict__ As,
              const __half* __restrict__ Bh0, const __half* __restrict__ Bl0,
              size_t bstride, float* __restrict__ C0, float* __restrict__ C1,
              int M, int N, int K)
{
    extern __shared__ __align__(16) char dsm_raw[];
    const uint32_t sbase = smem_u32(dsm_raw);

    const int tid  = threadIdx.x;
    const int wid  = tid >> 5;
    const int lane = tid & 31;
    const int wm   = wid >> 2;      // 0..3 -> rows wm*32
    const int wn   = wid & 3;       // 0..3 -> cols wn*64

    const int bm = blockIdx.y * 128;
    const int bn = blockIdx.x * 256;

    const __half* Bh = Bh0 + (size_t)blockIdx.z * bstride;
    const __half* Bl = Bl0 + (size_t)blockIdx.z * bstride;
    float* C = blockIdx.z ? C1 : C0;

    const int aoff = (wm * 32 + (lane & 15)) * PITCH + ((lane >> 4) << 3);
    const int bofflane = (((lane >> 4) << 3) + (lane & 7)) * PITCH + (((lane >> 3) & 1) << 3);

    const int nk = K >> 5;

    auto load_stage = [&](int kt, int stage) {
        const int k0 = kt << 5;
        const uint32_t sb = sbase + stage * G_STG_B;
#pragma unroll
        for (int q = 0; q < 5; q++) {
            int c = tid + q * 512;            // 0..2559
            const __half* g;
            uint32_t dst;
            if (c < 512) {                    // A single
                int r = c >> 2;
                int col = (c & 3) << 3;
                g = As + (size_t)(bm + r) * K + k0 + col;
                dst = sb + (r * PITCH + col) * 2;
            } else {                          // B arrays
                int cb = c - 512;
                int arr = cb >> 10;           // 0:Bh 1:Bl
                int j = cb & 1023;
                int r = j >> 2;
                int col = (j & 3) << 3;
                g = (arr ? Bl : Bh) + (size_t)(bn + r) * K + k0 + col;
                dst = sb + (GA_ELE + arr * GB_ELE + r * PITCH + col) * 2;
            }
            CP16(dst, g);
        }
        CP_COMMIT();
    };

    float c[2][8][4];
#pragma unroll
    for (int a = 0; a < 2; a++)
#pragma unroll
        for (int b = 0; b < 8; b++)
#pragma unroll
            for (int d = 0; d < 4; d++) c[a][b][d] = 0.f;

    load_stage(0, 0);
    if (nk > 1) load_stage(1, 1);

#pragma unroll 1
    for (int kt = 0; kt < nk; kt++) {
        if (kt + 1 < nk) { CP_WAIT1(); } else { CP_WAIT0(); }
        __syncthreads();

        const uint32_t sb = sbase + (kt % 3) * G_STG_B;
        const uint32_t uAs = sb;
        const uint32_t uBh = sb + GA_ELE * 2;
        const uint32_t uBl = sb + (GA_ELE + GB_ELE) * 2;

#pragma unroll
        for (int kk = 0; kk < 32; kk += 16) {
            uint32_t as[2][4], bh[8][2], bl[8][2];
#pragma unroll
            for (int ms = 0; ms < 2; ms++) {
                LDSM4(as[ms][0], as[ms][1], as[ms][2], as[ms][3],
                      uAs + 2 * (aoff + ms * 16 * PITCH + kk));
            }
#pragma unroll
            for (int g = 0; g < 4; g++) {
                const int off = (wn * 64 + g * 16) * PITCH + bofflane + kk;
                uint32_t t0, t1, t2, t3;
                LDSM4(t0, t1, t2, t3, uBh + 2 * off);
                bh[2*g][0] = t0; bh[2*g][1] = t1; bh[2*g+1][0] = t2; bh[2*g+1][1] = t3;
                LDSM4(t0, t1, t2, t3, uBl + 2 * off);
                bl[2*g][0] = t0; bl[2*g][1] = t1; bl[2*g+1][0] = t2; bl[2*g+1][1] = t3;
            }
#pragma unroll
            for (int ms = 0; ms < 2; ms++)
#pragma unroll
                for (int ng = 0; ng < 8; ng++) {
                    MMA16816F(c[ms][ng], as[ms], bh[ng][0], bh[ng][1]);
                    MMA16816F(c[ms][ng], as[ms], bl[ng][0], bl[ng][1]);
                }
        }

        if (kt + 2 < nk) load_stage(kt + 2, (kt + 2) % 3);
        __syncthreads();
    }

#pragma unroll
    for (int ms = 0; ms < 2; ms++) {
        const int row = bm + wm * 32 + ms * 16 + (lane >> 2);
#pragma unroll
        for (int ng = 0; ng < 8; ng++) {
            const int col = bn + wn * 64 + ng * 8 + (lane & 3) * 2;
            *(float2*)(C + (size_t)row * N + col)       = make_float2(c[ms][ng][0], c[ms][ng][1]);
            *(float2*)(C + (size_t)(row + 8) * N + col) = make_float2(c[ms][ng][2], c[ms][ng][3]);
        }
    }
}

// ---------------------------------------------------------------------------
// Fused RoPE + bf16 hi/lo split for Q and K.
// ---------------------------------------------------------------------------
#define TQ_ITEMS (BATCH*SEQ*NHEADS*32)
#define TK_ITEMS (BATCH*SEQ*NKV*32)

__global__ void rope_all(const float* __restrict__ Qf, const float* __restrict__ Kf,
                         const float* __restrict__ cosv, const float* __restrict__ sinv,
                         __nv_bfloat16* __restrict__ qh, __nv_bfloat16* __restrict__ ql,
                         __nv_bfloat16* __restrict__ kh, __nv_bfloat16* __restrict__ kl)
{
    int i = blockIdx.x * blockDim.x + threadIdx.x;
    const float* buf; __nv_bfloat16 *oh, *ol; int nheads, j;
    if (i < TQ_ITEMS) { buf = Qf; oh = qh; ol = ql; nheads = NHEADS; j = i; }
    else if (i < TQ_ITEMS + TK_ITEMS) { buf = Kf; oh = kh; ol = kl; nheads = NKV; j = i - TQ_ITEMS; }
    else return;

    int d = j & 31;
    int h = (j >> 5) % nheads;
    int s = (j / (32 * nheads)) % SEQ;
    int b = j / (32 * nheads * SEQ);

    const float* p = buf + (((size_t)b * SEQ + s) * nheads + h) * HDIM;
    float c0 = cosv[s * HDIM + d];
    float c1 = cosv[s * HDIM + d + 32];
    float s0 = sinv[s * HDIM + d];
    float s1 = sinv[s * HDIM + d + 32];
    float x0 = p[d];
    float x1 = p[d + 32];
    float y0 = x0 * c0 - x1 * s0;
    float y1 = x1 * c1 + x0 * s1;

    size_t o = (((size_t)b * nheads + h) * SEQ + s) * HDIM;
    __nv_bfloat16 h0 = __float2bfloat16_rn(y0);
    __nv_bfloat16 h1 = __float2bfloat16_rn(y1);
    oh[o + d]      = h0;
    oh[o + d + 32] = h1;
    ol[o + d]      = __float2bfloat16_rn(y0 - __bfloat162float(h0));
    ol[o + d + 32] = __float2bfloat16_rn(y1 - __bfloat162float(h1));
}

// ---------------------------------------------------------------------------
// V fp32 [b,s,8,64] -> V^T bf16 hi/lo [b,kvh,d,s]
// ---------------------------------------------------------------------------
__global__ __launch_bounds__(256) void split_v_t(const float* __restrict__ V,
                                                 __nv_bfloat16* __restrict__ vth,
                                                 __nv_bfloat16* __restrict__ vtl)
{
    __shared__ __nv_bfloat16 th[64][68];
    __shared__ __nv_bfloat16 tl[64][68];
    const int s0  = blockIdx.x * 64;
    const int kvh = blockIdx.y;
    const int b   = blockIdx.z;

    {
        const int r  = threadIdx.x >> 2;
        const int cb = (threadIdx.x & 3) * 16;
        const float4* g = (const float4*)(V + (((size_t)b * SEQ + s0 + r) * NKV + kvh) * HDIM + cb);
#pragma unroll
        for (int i = 0; i < 4; i++) {
            float4 v = g[i];
            float vv[4] = {v.x, v.y, v.z, v.w};
#pragma unroll
            for (int e = 0; e < 4; e++) {
                int d = cb + i * 4 + e;
                __nv_bfloat16 hh = __float2bfloat16_rn(vv[e]);
                th[d][r] = hh;
                tl[d][r] = __float2bfloat16_rn(vv[e] - __bfloat162float(hh));
            }
        }
    }
    __syncthreads();
    {
        const int d  = threadIdx.x >> 2;
        const int sc = (threadIdx.x & 3) * 16;
        size_t obase = (((size_t)b * NKV + kvh) * HDIM + d) * SEQ + s0 + sc;
        uint2 a0 = *(uint2*)&th[d][sc];
        uint2 a1 = *(uint2*)&th[d][sc + 4];
        uint2 a2 = *(uint2*)&th[d][sc + 8];
        uint2 a3 = *(uint2*)&th[d][sc + 12];
        *(uint4*)(vth + obase)     = make_uint4(a0.x, a0.y, a1.x, a1.y);
        *(uint4*)(vth + obase + 8) = make_uint4(a2.x, a2.y, a3.x, a3.y);
        a0 = *(uint2*)&tl[d][sc];
        a1 = *(uint2*)&tl[d][sc + 4];
        a2 = *(uint2*)&tl[d][sc + 8];
        a3 = *(uint2*)&tl[d][sc + 12];
        *(uint4*)(vtl + obase)     = make_uint4(a0.x, a0.y, a1.x, a1.y);
        *(uint4*)(vtl + obase + 8) = make_uint4(a2.x, a2.y, a3.x, a3.y);
    }
}

// ---------------------------------------------------------------------------
// Tensor-core causal flash attention (bf16x3), output fp16 single.
// ---------------------------------------------------------------------------
#define APITCH 72
#define A_ARR (64*APITCH)
#define A_STG (4*A_ARR)
#define A_STG_B (A_STG*2)
#define A_SMEM (2*A_STG_B)           // 73728 B
#define SCALE_LOG2 0.18033688011112042f   // log2(e)/8

__global__ __launch_bounds__(256, 1)
void attn_mma(const __nv_bfloat16* __restrict__ Qh, const __nv_bfloat16* __restrict__ Ql,
              const __nv_bfloat16* __restrict__ Kh, const __nv_bfloat16* __restrict__ Kl,
              const __nv_bfloat16* __restrict__ Vth, const __nv_bfloat16* __restrict__ Vtl,
              __half* __restrict__ Os)
{
    extern __shared__ __align__(16) char dsm_raw[];
    const uint32_t sbase = smem_u32(dsm_raw);

    const int tid  = threadIdx.x;
    const int wid  = tid >> 5;
    const int lane = tid & 31;
    const int t = (int)gridDim.x - 1 - (int)blockIdx.x;
    const int h = blockIdx.y;
    const int b = blockIdx.z;
    const int kvh = h >> 2;

    {
        const size_t qbase = (((size_t)b * NHEADS + h) * SEQ + (size_t)t * 128) * HDIM;
#pragma unroll
        for (int q = 0; q < 8; q++) {
            int i = tid + q * 256;
            int a = i >> 10;
            int j = i & 1023;
            int r = j >> 3;
            int cc = (j & 7) << 3;
            const __nv_bfloat16* g = (a ? Ql : Qh) + qbase + (size_t)r * HDIM + cc;
            CP16(sbase + (a * 128 * APITCH + r * APITCH + cc) * 2, g);
        }
        CP_COMMIT();
        CP_WAIT0();
    }
    __syncthreads();

    uint32_t qh[4][4], ql[4][4];
    {
        const uint32_t uQh = sbase;
        const uint32_t uQl = sbase + 128 * APITCH * 2;
        const int aoff = (wid * 16 + (lane & 15)) * APITCH + ((lane >> 4) << 3);
#pragma unroll
        for (int kk = 0; kk < 4; kk++) {
            LDSM4(qh[kk][0], qh[kk][1], qh[kk][2], qh[kk][3], uQh + 2 * (aoff + kk * 16));
            LDSM4(ql[kk][0], ql[kk][1], ql[kk][2], ql[kk][3], uQl + 2 * (aoff + kk * 16));
        }
    }
    __syncthreads();

    const size_t kbase = ((size_t)b * NKV + kvh) * SEQ * HDIM;
    const size_t vbase = ((size_t)b * NKV + kvh) * HDIM * SEQ;

    auto load_kv = [&](int kb, int stage) {
        const uint32_t sb = sbase + stage * A_STG_B;
#pragma unroll
        for (int q = 0; q < 8; q++) {
            int i = tid + q * 256;
            int a = i >> 9;
            int j = i & 511;
            int r = j >> 3;
            int cc = (j & 7) << 3;
            const __nv_bfloat16* g;
            if (a == 0)      g = Kh  + kbase + (size_t)(kb * 64 + r) * HDIM + cc;
            else if (a == 1) g = Kl  + kbase + (size_t)(kb * 64 + r) * HDIM + cc;
            else if (a == 2) g = Vth + vbase + (size_t)r * SEQ + kb * 64 + cc;
            else             g = Vtl + vbase + (size_t)r * SEQ + kb * 64 + cc;
            CP16(sb + (a * A_ARR + r * APITCH + cc) * 2, g);
        }
        CP_COMMIT();
    };

    float o[8][4];
#pragma unroll
    for (int nt = 0; nt < 8; nt++)
#pragma unroll
        for (int e = 0; e < 4; e++) o[nt][e] = 0.f;
    float mi0 = -1e30f, mi1 = -1e30f, li0 = 0.f, li1 = 0.f;

    const int row0 = t * 128 + wid * 16 + (lane >> 2);
    const int row1 = row0 + 8;

    const int nkb = 2 * t + 2;
    load_kv(0, 0);

#pragma unroll 1
    for (int kb = 0; kb < nkb; kb++) {
        if (kb + 1 < nkb) {
            load_kv(kb + 1, (kb + 1) & 1);
            CP_WAIT1();
        } else {
            CP_WAIT0();
        }
        __syncthreads();

        const uint32_t sb = sbase + (kb & 1) * A_STG_B;
        const uint32_t uKh = sb;
        const uint32_t uKl = sb + A_ARR * 2;
        const uint32_t uVh = sb + 2 * A_ARR * 2;
        const uint32_t uVl = sb + 3 * A_ARR * 2;

        float s[8][4];
#pragma unroll
        for (int nt = 0; nt < 8; nt++)
#pragma unroll
            for (int e = 0; e < 4; e++) s[nt][e] = 0.f;

#pragma unroll
        for (int kk = 0; kk < 4; kk++) {
            uint32_t bh[8][2], bl[8][2];
#pragma unroll
            for (int g = 0; g < 4; g++) {
                const int off = (g * 16 + ((lane >> 4) << 3) + (lane & 7)) * APITCH
                              + (((lane >> 3) & 1) << 3) + kk * 16;
                uint32_t t0, t1, t2, t3;
                LDSM4(t0, t1, t2, t3, uKh + 2 * off);
                bh[2*g][0] = t0; bh[2*g][1] = t1; bh[2*g+1][0] = t2; bh[2*g+1][1] = t3;
                LDSM4(t0, t1, t2, t3, uKl + 2 * off);
                bl[2*g][0] = t0; bl[2*g][1] = t1; bl[2*g+1][0] = t2; bl[2*g+1][1] = t3;
            }
#pragma unroll
            for (int nt = 0; nt < 8; nt++) {
                MMA16816(s[nt], qh[kk], bh[nt][0], bh[nt][1]);
                MMA16816(s[nt], qh[kk], bl[nt][0], bl[nt][1]);
                MMA16816(s[nt], ql[kk], bh[nt][0], bh[nt][1]);
            }
        }

        const bool diag = (kb >= 2 * t);
#pragma unroll
        for (int nt = 0; nt < 8; nt++) {
            const int col = kb * 64 + nt * 8 + (lane & 3) * 2;
            s[nt][0] *= SCALE_LOG2; s[nt][1] *= SCALE_LOG2;
            s[nt][2] *= SCALE_LOG2; s[nt][3] *= SCALE_LOG2;
            if (diag) {
                if (col > row0)     s[nt][0] = -1e30f;
                if (col + 1 > row0) s[nt][1] = -1e30f;
                if (col > row1)     s[nt][2] = -1e30f;
                if (col + 1 > row1) s[nt][3] = -1e30f;
            }
        }

        float bm0 = -1e30f, bm1 = -1e30f;
#pragma unroll
        for (int nt = 0; nt < 8; nt++) {
            bm0 = fmaxf(bm0, fmaxf(s[nt][0], s[nt][1]));
            bm1 = fmaxf(bm1, fmaxf(s[nt][2], s[nt][3]));
        }
        bm0 = fmaxf(bm0, __shfl_xor_sync(0xffffffffu, bm0, 1));
        bm0 = fmaxf(bm0, __shfl_xor_sync(0xffffffffu, bm0, 2));
        bm1 = fmaxf(bm1, __shfl_xor_sync(0xffffffffu, bm1, 1));
        bm1 = fmaxf(bm1, __shfl_xor_sync(0xffffffffu, bm1, 2));

        const float mn0 = fmaxf(mi0, bm0);
        const float mn1 = fmaxf(mi1, bm1);
        const float sc0 = exp2f(mi0 - mn0);
        const float sc1 = exp2f(mi1 - mn1);

        float ls0 = 0.f, ls1 = 0.f;
#pragma unroll
        for (int nt = 0; nt < 8; nt++) {
            s[nt][0] = exp2f(s[nt][0] - mn0);
            s[nt][1] = exp2f(s[nt][1] - mn0);
            s[nt][2] = exp2f(s[nt][2] - mn1);
            s[nt][3] = exp2f(s[nt][3] - mn1);
            ls0 += s[nt][0] + s[nt][1];
            ls1 += s[nt][2] + s[nt][3];
        }
        ls0 += __shfl_xor_sync(0xffffffffu, ls0, 1);
        ls0 += __shfl_xor_sync(0xffffffffu, ls0, 2);
        ls1 += __shfl_xor_sync(0xffffffffu, ls1, 1);
        ls1 += __shfl_xor_sync(0xffffffffu, ls1, 2);

        li0 = li0 * sc0 + ls0;
        li1 = li1 * sc1 + ls1;
        mi0 = mn0; mi1 = mn1;

#pragma unroll
        for (int nt = 0; nt < 8; nt++) {
            o[nt][0] *= sc0; o[nt][1] *= sc0;
            o[nt][2] *= sc1; o[nt][3] *= sc1;
        }

        uint32_t ph[8][2], pl[8][2];
#pragma unroll
        for (int nt = 0; nt < 8; nt++) {
            uint32_t u0 = pack_bf16x2(s[nt][0], s[nt][1]);
            uint32_t u1 = pack_bf16x2(s[nt][2], s[nt][3]);
            ph[nt][0] = u0; ph[nt][1] = u1;
            float l00 = s[nt][0] - __uint_as_float(u0 << 16);
            float l01 = s[nt][1] - __uint_as_float(u0 & 0xffff0000u);
            float l10 = s[nt][2] - __uint_as_float(u1 << 16);
            float l11 = s[nt][3] - __uint_as_float(u1 & 0xffff0000u);
            pl[nt][0] = pack_bf16x2(l00, l01);
            pl[nt][1] = pack_bf16x2(l10, l11);
        }

#pragma unroll
        for (int kk = 0; kk < 4; kk++) {
            uint32_t vh[8][2], vl[8][2];
#pragma unroll
            for (int g = 0; g < 4; g++) {
                const int off = (g * 16 + ((lane >> 4) << 3) + (lane & 7)) * APITCH
                              + (((lane >> 3) & 1) << 3) + kk * 16;
                uint32_t t0, t1, t2, t3;
                LDSM4(t0, t1, t2, t3, uVh + 2 * off);
                vh[2*g][0] = t0; vh[2*g][1] = t1; vh[2*g+1][0] = t2; vh[2*g+1][1] = t3;
                LDSM4(t0, t1, t2, t3, uVl + 2 * off);
                vl[2*g][0] = t0; vl[2*g][1] = t1; vl[2*g+1][0] = t2; vl[2*g+1][1] = t3;
            }
            uint32_t ah[4] = {ph[2*kk][0], ph[2*kk][1], ph[2*kk+1][0], ph[2*kk+1][1]};
            uint32_t al[4] = {pl[2*kk][0], pl[2*kk][1], pl[2*kk+1][0], pl[2*kk+1][1]};
#pragma unroll
            for (int nt = 0; nt < 8; nt++) {
                MMA16816(o[nt], ah, vh[nt][0], vh[nt][1]);
                MMA16816(o[nt], ah, vl[nt][0], vl[nt][1]);
                MMA16816(o[nt], al, vh[nt][0], vh[nt][1]);
            }
        }
        __syncthreads();
    }

    // ---- finalize: write fp16 single output ([b,s,h,d] = [M,2048]) ----
    const float inv0 = 1.f / li0;
    const float inv1 = 1.f / li1;
    const size_t o0 = (((size_t)b * SEQ + row0) * NHEADS + h) * HDIM;
    const size_t o1 = (((size_t)b * SEQ + row1) * NHEADS + h) * HDIM;
#pragma unroll
    for (int nt = 0; nt < 8; nt++) {
        const int col = nt * 8 + (lane & 3) * 2;
        *(uint32_t*)(Os + o0 + col) = pack_f16x2(o[nt][0] * inv0, o[nt][1] * inv0);
        *(uint32_t*)(Os + o1 + col) = pack_f16x2(o[nt][2] * inv1, o[nt][3] * inv1);
    }
}

// ---------------------------------------------------------------------------
extern "C" void kernel_launch(void* const* d_in, const int* in_sizes, int n_in,
                              void* d_out, int out_size)
{
    const float* x    = (const float*)d_in[0];
    const float* fcos = (const float*)d_in[1];
    const float* fsin = (const float*)d_in[2];
    const float* wq   = (const float*)d_in[3];
    const float* wk   = (const float*)d_in[4];
    const float* wv   = (const float*)d_in[5];
    const float* wo   = (const float*)d_in[6];
    float* out = (float*)d_out;

    float *Qp, *Kp, *Vp;
    __half* hf;
    __nv_bfloat16 *qh, *ql, *kh, *kl, *vth, *vtl;
    cudaGetSymbolAddress((void**)&Qp, g_Q);
    cudaGetSymbolAddress((void**)&Kp, g_K);
    cudaGetSymbolAddress((void**)&Vp, g_V);
    cudaGetSymbolAddress((void**)&hf, g_hf);
    cudaGetSymbolAddress((void**)&qh, g_Qh);
    cudaGetSymbolAddress((void**)&ql, g_Ql);
    cudaGetSymbolAddress((void**)&kh, g_Kh);
    cudaGetSymbolAddress((void**)&kl, g_Kl);
    cudaGetSymbolAddress((void**)&vth, g_Vth);
    cudaGetSymbolAddress((void**)&vtl, g_Vtl);

    cudaFuncSetAttribute(gemm_mma, cudaFuncAttributeMaxDynamicSharedMemorySize, G_SMEM);
    cudaFuncSetAttribute(attn_mma, cudaFuncAttributeMaxDynamicSharedMemorySize, A_SMEM);

    const int M = BATCH * SEQ;

    // #0: prepass (x -> fp16 single; weights -> fp16 hi/lo)
    split_all<<<(Q_TOT + 255) / 256, 256>>>(x, wq, wk, wv, wo, hf);

    // #1: K and V projections fused (grid.z picks weight/output)
    gemm_mma<<<dim3(KVDIM / 256, M / 128, 2), 512, G_SMEM>>>(
        hf + OFF_XS, hf + OFF_WKH, hf + OFF_WKL,
        (size_t)(2 * N_WK), Kp, Vp, M, KVDIM, EMBED);

    // #2: Q projection
    gemm_mma<<<dim3(EMBED / 256, M / 128, 1), 512, G_SMEM>>>(
        hf + OFF_XS, hf + OFF_WQH, hf + OFF_WQL,
        (size_t)0, Qp, Qp, M, EMBED, EMBED);

    // #3: RoPE + split for Q and K
    rope_all<<<(TQ_ITEMS + TK_ITEMS + 255) / 256, 256>>>(Qp, Kp, fcos, fsin, qh, ql, kh, kl);

    // #4: V transpose + split
    split_v_t<<<dim3(SEQ / 64, NKV, BATCH), 256>>>(Vp, vth, vtl);

    // #5: tensor-core causal GQA flash attention (fp16 single out)
    attn_mma<<<dim3(SEQ / 128, NHEADS, BATCH), 256, A_SMEM>>>(qh, ql, kh, kl, vth, vtl,
                                                              hf + OFF_OS);

    // #6: output projection (A = attention output fp16)
    gemm_mma<<<dim3(EMBED / 256, M / 128, 1), 512, G_SMEM>>>(
        hf + OFF_OS, hf + OFF_WOH, hf + OFF_WOL,
        (size_t)0, out, out, M, EMBED, EMBED);
}

// round 11
// speedup vs baseline: 4.5016x; 1.0427x over previous
#include <cuda_runtime.h>
#include <cuda_bf16.h>
#include <cuda_fp16.h>
#include <cstdint>

#define BATCH 2
#define SEQ 2048
#define EMBED 2048
#define NHEADS 32
#define NKV 8
#define HDIM 64
#define KVDIM (NKV*HDIM)   // 512

// fp32 scratch (gemm outputs)
__device__ float g_Q[(size_t)BATCH*SEQ*EMBED];
__device__ float g_K[(size_t)BATCH*SEQ*KVDIM];
__device__ float g_V[(size_t)BATCH*SEQ*KVDIM];

// fp16 pool (gemm operands): activations single, weights hi/lo
#define N_X   (size_t)8388608    // 2*2048*2048
#define N_WQ  (size_t)4194304
#define N_WK  (size_t)1048576
#define N_WV  (size_t)1048576
#define N_WO  (size_t)4194304
#define OFF_XS  (size_t)0
#define OFF_WQH (OFF_XS + N_X)
#define OFF_WQL (OFF_WQH + N_WQ)
#define OFF_WKH (OFF_WQL + N_WQ)
#define OFF_WKL (OFF_WKH + N_WK)
#define OFF_WVH (OFF_WKL + N_WK)
#define OFF_WVL (OFF_WVH + N_WV)
#define OFF_WOH (OFF_WVL + N_WV)
#define OFF_WOL (OFF_WOH + N_WO)
#define OFF_OS  (OFF_WOL + N_WO)
#define POOL_SZ (OFF_OS + N_X)
__device__ __half g_hf[POOL_SZ];

// attention operands: Q/K bf16 hi/lo, V^T single fp16
__device__ __nv_bfloat16 g_Qh[(size_t)BATCH*NHEADS*SEQ*HDIM];
__device__ __nv_bfloat16 g_Ql[(size_t)BATCH*NHEADS*SEQ*HDIM];
__device__ __nv_bfloat16 g_Kh[(size_t)BATCH*NKV*SEQ*HDIM];
__device__ __nv_bfloat16 g_Kl[(size_t)BATCH*NKV*SEQ*HDIM];
__device__ __half        g_Vts[(size_t)BATCH*NKV*HDIM*SEQ];

// ============================ helpers ======================================
__device__ __forceinline__ uint32_t smem_u32(const void* p) {
    uint32_t a;
    asm("{ .reg .u64 t; cvta.to.shared.u64 t, %1; cvt.u32.u64 %0, t; }"
        : "=r"(a) : "l"(p));
    return a;
}

#define LDSM4(R0,R1,R2,R3,ADDR) \
    asm volatile("ldmatrix.sync.aligned.m8n8.x4.shared.b16 {%0,%1,%2,%3}, [%4];" \
                 : "=r"(R0), "=r"(R1), "=r"(R2), "=r"(R3) : "r"(ADDR))

// bf16 MMA (attention QK)
#define MMA16816(C, A, B0, B1) \
    asm volatile("mma.sync.aligned.m16n8k16.row.col.f32.bf16.bf16.f32 " \
                 "{%0,%1,%2,%3}, {%4,%5,%6,%7}, {%8,%9}, {%0,%1,%2,%3};" \
                 : "+f"((C)[0]), "+f"((C)[1]), "+f"((C)[2]), "+f"((C)[3]) \
                 : "r"((A)[0]), "r"((A)[1]), "r"((A)[2]), "r"((A)[3]), \
                   "r"(B0), "r"(B1))

// fp16 MMA (gemms + PV)
#define MMA16816F(C, A, B0, B1) \
    asm volatile("mma.sync.aligned.m16n8k16.row.col.f32.f16.f16.f32 " \
                 "{%0,%1,%2,%3}, {%4,%5,%6,%7}, {%8,%9}, {%0,%1,%2,%3};" \
                 : "+f"((C)[0]), "+f"((C)[1]), "+f"((C)[2]), "+f"((C)[3]) \
                 : "r"((A)[0]), "r"((A)[1]), "r"((A)[2]), "r"((A)[3]), \
                   "r"(B0), "r"(B1))

#define CP16(DST, SRC) \
    asm volatile("cp.async.cg.shared.global [%0], [%1], 16;" :: "r"(DST), "l"(SRC))
#define CP_COMMIT() asm volatile("cp.async.commit_group;")
#define CP_WAIT0()  asm volatile("cp.async.wait_group 0;")
#define CP_WAIT1()  asm volatile("cp.async.wait_group 1;")

__device__ __forceinline__ uint32_t pack_bf16x2(float lo, float hi) {
    uint32_t d;
    asm("cvt.rn.bf16x2.f32 %0, %1, %2;" : "=r"(d) : "f"(hi), "f"(lo));
    return d;
}
__device__ __forceinline__ uint32_t pack_f16x2(float lo, float hi) {
    uint32_t d;
    asm("cvt.rn.f16x2.f32 %0, %1, %2;" : "=r"(d) : "f"(hi), "f"(lo));
    return d;
}

// ---------------------------------------------------------------------------
// One-shot prepass: x -> fp16 single; weights -> fp16 hi/lo.
// ---------------------------------------------------------------------------
#define Q_X  (int)(N_X/4)
#define Q_WQ (int)(N_WQ/4)
#define Q_WK (int)(N_WK/4)
#define Q_WV (int)(N_WV/4)
#define Q_WO (int)(N_WO/4)
#define Q_TOT (Q_X + Q_WQ + Q_WK + Q_WV + Q_WO)

__global__ void split_all(const float* __restrict__ x,  const float* __restrict__ wq,
                          const float* __restrict__ wk, const float* __restrict__ wv,
                          const float* __restrict__ wo, __half* __restrict__ hf)
{
    int i = blockIdx.x * blockDim.x + threadIdx.x;
    if (i >= Q_TOT) return;
    if (i < Q_X) {
        float4 v = ((const float4*)x)[i];
        uint2 u;
        u.x = pack_f16x2(v.x, v.y);
        u.y = pack_f16x2(v.z, v.w);
        ((uint2*)(hf + OFF_XS))[i] = u;
        return;
    }
    const float* src; size_t dh, dl; int j;
    if (i < Q_X + Q_WQ)                    { src = wq; j = i - Q_X;                   dh = OFF_WQH; dl = OFF_WQL; }
    else if (i < Q_X + Q_WQ + Q_WK)        { src = wk; j = i - Q_X - Q_WQ;            dh = OFF_WKH; dl = OFF_WKL; }
    else if (i < Q_X + Q_WQ + Q_WK + Q_WV) { src = wv; j = i - Q_X - Q_WQ - Q_WK;     dh = OFF_WVH; dl = OFF_WVL; }
    else                                   { src = wo; j = i - Q_X - Q_WQ - Q_WK - Q_WV; dh = OFF_WOH; dl = OFF_WOL; }
    float4 v = ((const float4*)src)[j];
    __half h0 = __float2half_rn(v.x);
    __half h1 = __float2half_rn(v.y);
    __half h2 = __float2half_rn(v.z);
    __half h3 = __float2half_rn(v.w);
    __half l0 = __float2half_rn(v.x - __half2float(h0));
    __half l1 = __float2half_rn(v.y - __half2float(h1));
    __half l2 = __float2half_rn(v.z - __half2float(h2));
    __half l3 = __float2half_rn(v.w - __half2float(h3));
    uint2 uh, ul;
    uh.x = (uint32_t)__half_as_ushort(h0) | ((uint32_t)__half_as_ushort(h1) << 16);
    uh.y = (uint32_t)__half_as_ushort(h2) | ((uint32_t)__half_as_ushort(h3) << 16);
    ul.x = (uint32_t)__half_as_ushort(l0) | ((uint32_t)__half_as_ushort(l1) << 16);
    ul.y = (uint32_t)__half_as_ushort(l2) | ((uint32_t)__half_as_ushort(l3) << 16);
    ((uint2*)(hf + dh))[j] = uh;
    ((uint2*)(hf + dl))[j] = ul;
}

// ---------------------------------------------------------------------------
// fp16 2-term MMA GEMM: C = A(single) * [Bh + Bl]^T.
// Block 128x256, BK=64, 512 threads, warp tile 32x64, 2-stage cp.async.
// ---------------------------------------------------------------------------
#define GPITCH 72
#define GA_ELE (128*GPITCH)           // 9216
#define GB_ELE (256*GPITCH)           // 18432
#define G_STG_E (GA_ELE + 2*GB_ELE)   // 46080 elems
#define G_STG_B (G_STG_E*2)           // 92160 B
#define G_SMEM (2*G_STG_B)            // 184320 B

__global__ __launch_bounds__(512, 1)
void gemm_mma(const __half* __restrict__ As,
              const __half* __restrict__ Bh0, const __half* __restrict__ Bl0,
              size_t bstride, float* __restrict__ C0, float* __restrict__ C1,
              int M, int N, int K)
{
    extern __shared__ __align__(16) char dsm_raw[];
    const uint32_t sbase = smem_u32(dsm_raw);

    const int tid  = threadIdx.x;
    const int wid  = tid >> 5;
    const int lane = tid & 31;
    const int wm   = wid >> 2;      // 0..3 -> rows wm*32
    const int wn   = wid & 3;       // 0..3 -> cols wn*64

    const int bm = blockIdx.y * 128;
    const int bn = blockIdx.x * 256;

    const __half* Bh = Bh0 + (size_t)blockIdx.z * bstride;
    const __half* Bl = Bl0 + (size_t)blockIdx.z * bstride;
    float* C = blockIdx.z ? C1 : C0;

    const int aoff = (wm * 32 + (lane & 15)) * GPITCH + ((lane >> 4) << 3);
    const int bofflane = (((lane >> 4) << 3) + (lane & 7)) * GPITCH + (((lane >> 3) & 1) << 3);

    const int nk = K >> 6;

    auto load_stage = [&](int kt, int stage) {
        const int k0 = kt << 6;
        const uint32_t sb = sbase + stage * G_STG_B;
#pragma unroll
        for (int q = 0; q < 10; q++) {        // 5120 chunks total (FIXED: was 9)
            int c = tid + q * 512;            // 0..5119
            const __half* g;
            uint32_t dst;
            if (c < 1024) {                   // A single: 128 rows x 8 chunks
                int r = c >> 3;
                int col = (c & 7) << 3;
                g = As + (size_t)(bm + r) * K + k0 + col;
                dst = sb + (r * GPITCH + col) * 2;
            } else {                          // B arrays: 2 x 256 rows x 8 chunks
                int cb = c - 1024;
                int arr = cb >> 11;           // 0:Bh 1:Bl
                int j = cb & 2047;
                int r = j >> 3;
                int col = (j & 7) << 3;
                g = (arr ? Bl : Bh) + (size_t)(bn + r) * K + k0 + col;
                dst = sb + (GA_ELE + arr * GB_ELE + r * GPITCH + col) * 2;
            }
            CP16(dst, g);
        }
        CP_COMMIT();
    };

    float c[2][8][4];
#pragma unroll
    for (int a = 0; a < 2; a++)
#pragma unroll
        for (int b = 0; b < 8; b++)
#pragma unroll
            for (int d = 0; d < 4; d++) c[a][b][d] = 0.f;

    load_stage(0, 0);

#pragma unroll 1
    for (int kt = 0; kt < nk; kt++) {
        if (kt + 1 < nk) {
            load_stage(kt + 1, (kt + 1) & 1);
            CP_WAIT1();
        } else {
            CP_WAIT0();
        }
        __syncthreads();

        const uint32_t sb = sbase + (kt & 1) * G_STG_B;
        const uint32_t uAs = sb;
        const uint32_t uBh = sb + GA_ELE * 2;
        const uint32_t uBl = sb + (GA_ELE + GB_ELE) * 2;

#pragma unroll
        for (int kk = 0; kk < 64; kk += 16) {
            uint32_t as[2][4], bh[8][2], bl[8][2];
#pragma unroll
            for (int ms = 0; ms < 2; ms++) {
                LDSM4(as[ms][0], as[ms][1], as[ms][2], as[ms][3],
                      uAs + 2 * (aoff + ms * 16 * GPITCH + kk));
            }
#pragma unroll
            for (int g = 0; g < 4; g++) {
                const int off = (wn * 64 + g * 16) * GPITCH + bofflane + kk;
                uint32_t t0, t1, t2, t3;
                LDSM4(t0, t1, t2, t3, uBh + 2 * off);
                bh[2*g][0] = t0; bh[2*g][1] = t1; bh[2*g+1][0] = t2; bh[2*g+1][1] = t3;
                LDSM4(t0, t1, t2, t3, uBl + 2 * off);
                bl[2*g][0] = t0; bl[2*g][1] = t1; bl[2*g+1][0] = t2; bl[2*g+1][1] = t3;
            }
#pragma unroll
            for (int ms = 0; ms < 2; ms++)
#pragma unroll
                for (int ng = 0; ng < 8; ng++) {
                    MMA16816F(c[ms][ng], as[ms], bh[ng][0], bh[ng][1]);
                    MMA16816F(c[ms][ng], as[ms], bl[ng][0], bl[ng][1]);
                }
        }
        __syncthreads();
    }

#pragma unroll
    for (int ms = 0; ms < 2; ms++) {
        const int row = bm + wm * 32 + ms * 16 + (lane >> 2);
#pragma unroll
        for (int ng = 0; ng < 8; ng++) {
            const int col = bn + wn * 64 + ng * 8 + (lane & 3) * 2;
            *(float2*)(C + (size_t)row * N + col)       = make_float2(c[ms][ng][0], c[ms][ng][1]);
            *(float2*)(C + (size_t)(row + 8) * N + col) = make_float2(c[ms][ng][2], c[ms][ng][3]);
        }
    }
}

// ---------------------------------------------------------------------------
// Fused RoPE + bf16 hi/lo split for Q and K.
// ---------------------------------------------------------------------------
#define TQ_ITEMS (BATCH*SEQ*NHEADS*32)
#define TK_ITEMS (BATCH*SEQ*NKV*32)

__global__ void rope_all(const float* __restrict__ Qf, const float* __restrict__ Kf,
                         const float* __restrict__ cosv, const float* __restrict__ sinv,
                         __nv_bfloat16* __restrict__ qh, __nv_bfloat16* __restrict__ ql,
                         __nv_bfloat16* __restrict__ kh, __nv_bfloat16* __restrict__ kl)
{
    int i = blockIdx.x * blockDim.x + threadIdx.x;
    const float* buf; __nv_bfloat16 *oh, *ol; int nheads, j;
    if (i < TQ_ITEMS) { buf = Qf; oh = qh; ol = ql; nheads = NHEADS; j = i; }
    else if (i < TQ_ITEMS + TK_ITEMS) { buf = Kf; oh = kh; ol = kl; nheads = NKV; j = i - TQ_ITEMS; }
    else return;

    int d = j & 31;
    int h = (j >> 5) % nheads;
    int s = (j / (32 * nheads)) % SEQ;
    int b = j / (32 * nheads * SEQ);

    const float* p = buf + (((size_t)b * SEQ + s) * nheads + h) * HDIM;
    float c0 = cosv[s * HDIM + d];
    float c1 = cosv[s * HDIM + d + 32];
    float s0 = sinv[s * HDIM + d];
    float s1 = sinv[s * HDIM + d + 32];
    float x0 = p[d];
    float x1 = p[d + 32];
    float y0 = x0 * c0 - x1 * s0;
    float y1 = x1 * c1 + x0 * s1;

    size_t o = (((size_t)b * nheads + h) * SEQ + s) * HDIM;
    __nv_bfloat16 h0 = __float2bfloat16_rn(y0);
    __nv_bfloat16 h1 = __float2bfloat16_rn(y1);
    oh[o + d]      = h0;
    oh[o + d + 32] = h1;
    ol[o + d]      = __float2bfloat16_rn(y0 - __bfloat162float(h0));
    ol[o + d + 32] = __float2bfloat16_rn(y1 - __bfloat162float(h1));
}

// ---------------------------------------------------------------------------
// V fp32 [b,s,8,64] -> V^T single fp16 [b,kvh,d,s]
// ---------------------------------------------------------------------------
__global__ __launch_bounds__(256) void split_v_t(const float* __restrict__ V,
                                                 __half* __restrict__ vts)
{
    __shared__ __half th[64][68];
    const int s0  = blockIdx.x * 64;
    const int kvh = blockIdx.y;
    const int b   = blockIdx.z;

    {
        const int r  = threadIdx.x >> 2;
        const int cb = (threadIdx.x & 3) * 16;
        const float4* g = (const float4*)(V + (((size_t)b * SEQ + s0 + r) * NKV + kvh) * HDIM + cb);
#pragma unroll
        for (int i = 0; i < 4; i++) {
            float4 v = g[i];
            th[cb + i * 4 + 0][r] = __float2half_rn(v.x);
            th[cb + i * 4 + 1][r] = __float2half_rn(v.y);
            th[cb + i * 4 + 2][r] = __float2half_rn(v.z);
            th[cb + i * 4 + 3][r] = __float2half_rn(v.w);
        }
    }
    __syncthreads();
    {
        const int d  = threadIdx.x >> 2;
        const int sc = (threadIdx.x & 3) * 16;
        size_t obase = (((size_t)b * NKV + kvh) * HDIM + d) * SEQ + s0 + sc;
        uint2 a0 = *(uint2*)&th[d][sc];
        uint2 a1 = *(uint2*)&th[d][sc + 4];
        uint2 a2 = *(uint2*)&th[d][sc + 8];
        uint2 a3 = *(uint2*)&th[d][sc + 12];
        *(uint4*)(vts + obase)     = make_uint4(a0.x, a0.y, a1.x, a1.y);
        *(uint4*)(vts + obase + 8) = make_uint4(a2.x, a2.y, a3.x, a3.y);
    }
}

// ---------------------------------------------------------------------------
// Tensor-core causal flash attention: QK bf16x3, PV single fp16 x fp16.
// K bf16 hi/lo + V^T fp16 staged via 2-stage cp.async.
// ---------------------------------------------------------------------------
#define APITCH 72
#define A_ARR (64*APITCH)             // 4608 elems
#define A_STG_E (3*A_ARR)             // Kh, Kl, Vs
#define A_STG_B (A_STG_E*2)           // 27648 B
#define A_SMEM (2*A_STG_B)            // 55296 B  (Q staging needs 36864 <= this)
#define SCALE_LOG2 0.18033688011112042f   // log2(e)/8

__global__ __launch_bounds__(256, 1)
void attn_mma(const __nv_bfloat16* __restrict__ Qh, const __nv_bfloat16* __restrict__ Ql,
              const __nv_bfloat16* __restrict__ Kh, const __nv_bfloat16* __restrict__ Kl,
              const __half* __restrict__ Vts, __half* __restrict__ Os)
{
    extern __shared__ __align__(16) char dsm_raw[];
    const uint32_t sbase = smem_u32(dsm_raw);

    const int tid  = threadIdx.x;
    const int wid  = tid >> 5;
    const int lane = tid & 31;
    const int t = (int)gridDim.x - 1 - (int)blockIdx.x;
    const int h = blockIdx.y;
    const int b = blockIdx.z;
    const int kvh = h >> 2;

    // ---- stage Q (bf16 hi/lo) and extract fragments ----
    {
        const size_t qbase = (((size_t)b * NHEADS + h) * SEQ + (size_t)t * 128) * HDIM;
#pragma unroll
        for (int q = 0; q < 8; q++) {
            int i = tid + q * 256;
            int a = i >> 10;
            int j = i & 1023;
            int r = j >> 3;
            int cc = (j & 7) << 3;
            const __nv_bfloat16* g = (a ? Ql : Qh) + qbase + (size_t)r * HDIM + cc;
            CP16(sbase + (a * 128 * APITCH + r * APITCH + cc) * 2, g);
        }
        CP_COMMIT();
        CP_WAIT0();
    }
    __syncthreads();

    uint32_t qh[4][4], ql[4][4];
    {
        const uint32_t uQh = sbase;
        const uint32_t uQl = sbase + 128 * APITCH * 2;
        const int aoff = (wid * 16 + (lane & 15)) * APITCH + ((lane >> 4) << 3);
#pragma unroll
        for (int kk = 0; kk < 4; kk++) {
            LDSM4(qh[kk][0], qh[kk][1], qh[kk][2], qh[kk][3], uQh + 2 * (aoff + kk * 16));
            LDSM4(ql[kk][0], ql[kk][1], ql[kk][2], ql[kk][3], uQl + 2 * (aoff + kk * 16));
        }
    }
    __syncthreads();

    const size_t kbase = ((size_t)b * NKV + kvh) * SEQ * HDIM;
    const size_t vbase = ((size_t)b * NKV + kvh) * HDIM * SEQ;

    auto load_kv = [&](int kb, int stage) {
        const uint32_t sb = sbase + stage * A_STG_B;
#pragma unroll
        for (int q = 0; q < 6; q++) {
            int i = tid + q * 256;            // 0..1535
            int a = i >> 9;                   // 0:Kh 1:Kl 2:Vs
            int j = i & 511;
            int r = j >> 3;
            int cc = (j & 7) << 3;
            uint32_t dst = sb + (a * A_ARR + r * APITCH + cc) * 2;
            if (a == 0)      CP16(dst, Kh  + kbase + (size_t)(kb * 64 + r) * HDIM + cc);
            else if (a == 1) CP16(dst, Kl  + kbase + (size_t)(kb * 64 + r) * HDIM + cc);
            else             CP16(dst, Vts + vbase + (size_t)r * SEQ + kb * 64 + cc);
        }
        CP_COMMIT();
    };

    float o[8][4];
#pragma unroll
    for (int nt = 0; nt < 8; nt++)
#pragma unroll
        for (int e = 0; e < 4; e++) o[nt][e] = 0.f;
    float mi0 = -1e30f, mi1 = -1e30f, li0 = 0.f, li1 = 0.f;

    const int row0 = t * 128 + wid * 16 + (lane >> 2);
    const int row1 = row0 + 8;

    const int nkb = 2 * t + 2;
    load_kv(0, 0);

#pragma unroll 1
    for (int kb = 0; kb < nkb; kb++) {
        if (kb + 1 < nkb) {
            load_kv(kb + 1, (kb + 1) & 1);
            CP_WAIT1();
        } else {
            CP_WAIT0();
        }
        __syncthreads();

        const uint32_t sb = sbase + (kb & 1) * A_STG_B;
        const uint32_t uKh = sb;
        const uint32_t uKl = sb + A_ARR * 2;
        const uint32_t uVs = sb + 2 * A_ARR * 2;

        // ---- S = Q K^T (bf16x3) ----
        float s[8][4];
#pragma unroll
        for (int nt = 0; nt < 8; nt++)
#pragma unroll
            for (int e = 0; e < 4; e++) s[nt][e] = 0.f;

#pragma unroll
        for (int kk = 0; kk < 4; kk++) {
            uint32_t bh[8][2], bl[8][2];
#pragma unroll
            for (int g = 0; g < 4; g++) {
                const int off = (g * 16 + ((lane >> 4) << 3) + (lane & 7)) * APITCH
                              + (((lane >> 3) & 1) << 3) + kk * 16;
                uint32_t t0, t1, t2, t3;
                LDSM4(t0, t1, t2, t3, uKh + 2 * off);
                bh[2*g][0] = t0; bh[2*g][1] = t1; bh[2*g+1][0] = t2; bh[2*g+1][1] = t3;
                LDSM4(t0, t1, t2, t3, uKl + 2 * off);
                bl[2*g][0] = t0; bl[2*g][1] = t1; bl[2*g+1][0] = t2; bl[2*g+1][1] = t3;
            }
#pragma unroll
            for (int nt = 0; nt < 8; nt++) {
                MMA16816(s[nt], qh[kk], bh[nt][0], bh[nt][1]);
                MMA16816(s[nt], qh[kk], bl[nt][0], bl[nt][1]);
                MMA16816(s[nt], ql[kk], bh[nt][0], bh[nt][1]);
            }
        }

        const bool diag = (kb >= 2 * t);
#pragma unroll
        for (int nt = 0; nt < 8; nt++) {
            const int col = kb * 64 + nt * 8 + (lane & 3) * 2;
            s[nt][0] *= SCALE_LOG2; s[nt][1] *= SCALE_LOG2;
            s[nt][2] *= SCALE_LOG2; s[nt][3] *= SCALE_LOG2;
            if (diag) {
                if (col > row0)     s[nt][0] = -1e30f;
                if (col + 1 > row0) s[nt][1] = -1e30f;
                if (col > row1)     s[nt][2] = -1e30f;
                if (col + 1 > row1) s[nt][3] = -1e30f;
            }
        }

        float bm0 = -1e30f, bm1 = -1e30f;
#pragma unroll
        for (int nt = 0; nt < 8; nt++) {
            bm0 = fmaxf(bm0, fmaxf(s[nt][0], s[nt][1]));
            bm1 = fmaxf(bm1, fmaxf(s[nt][2], s[nt][3]));
        }
        bm0 = fmaxf(bm0, __shfl_xor_sync(0xffffffffu, bm0, 1));
        bm0 = fmaxf(bm0, __shfl_xor_sync(0xffffffffu, bm0, 2));
        bm1 = fmaxf(bm1, __shfl_xor_sync(0xffffffffu, bm1, 1));
        bm1 = fmaxf(bm1, __shfl_xor_sync(0xffffffffu, bm1, 2));

        const float mn0 = fmaxf(mi0, bm0);
        const float mn1 = fmaxf(mi1, bm1);
        const float sc0 = exp2f(mi0 - mn0);
        const float sc1 = exp2f(mi1 - mn1);

        float ls0 = 0.f, ls1 = 0.f;
#pragma unroll
        for (int nt = 0; nt < 8; nt++) {
            s[nt][0] = exp2f(s[nt][0] - mn0);
            s[nt][1] = exp2f(s[nt][1] - mn0);
            s[nt][2] = exp2f(s[nt][2] - mn1);
            s[nt][3] = exp2f(s[nt][3] - mn1);
            ls0 += s[nt][0] + s[nt][1];
            ls1 += s[nt][2] + s[nt][3];
        }
        ls0 += __shfl_xor_sync(0xffffffffu, ls0, 1);
        ls0 += __shfl_xor_sync(0xffffffffu, ls0, 2);
        ls1 += __shfl_xor_sync(0xffffffffu, ls1, 1);
        ls1 += __shfl_xor_sync(0xffffffffu, ls1, 2);

        li0 = li0 * sc0 + ls0;
        li1 = li1 * sc1 + ls1;
        mi0 = mn0; mi1 = mn1;

#pragma unroll
        for (int nt = 0; nt < 8; nt++) {
            o[nt][0] *= sc0; o[nt][1] *= sc0;
            o[nt][2] *= sc1; o[nt][3] *= sc1;
        }

        // ---- pack P to single fp16 fragments ----
        uint32_t ps[8][2];
#pragma unroll
        for (int nt = 0; nt < 8; nt++) {
            ps[nt][0] = pack_f16x2(s[nt][0], s[nt][1]);
            ps[nt][1] = pack_f16x2(s[nt][2], s[nt][3]);
        }

        // ---- O += P V (single fp16 term) ----
#pragma unroll
        for (int kk = 0; kk < 4; kk++) {
            uint32_t vs[8][2];
#pragma unroll
            for (int g = 0; g < 4; g++) {
                const int off = (g * 16 + ((lane >> 4) << 3) + (lane & 7)) * APITCH
                              + (((lane >> 3) & 1) << 3) + kk * 16;
                uint32_t t0, t1, t2, t3;
                LDSM4(t0, t1, t2, t3, uVs + 2 * off);
                vs[2*g][0] = t0; vs[2*g][1] = t1; vs[2*g+1][0] = t2; vs[2*g+1][1] = t3;
            }
            uint32_t ap[4] = {ps[2*kk][0], ps[2*kk][1], ps[2*kk+1][0], ps[2*kk+1][1]};
#pragma unroll
            for (int nt = 0; nt < 8; nt++) {
                MMA16816F(o[nt], ap, vs[nt][0], vs[nt][1]);
            }
        }
        __syncthreads();
    }

    // ---- finalize: write fp16 single output ([b,s,h,d] = [M,2048]) ----
    const float inv0 = 1.f / li0;
    const float inv1 = 1.f / li1;
    const size_t o0 = (((size_t)b * SEQ + row0) * NHEADS + h) * HDIM;
    const size_t o1 = (((size_t)b * SEQ + row1) * NHEADS + h) * HDIM;
#pragma unroll
    for (int nt = 0; nt < 8; nt++) {
        const int col = nt * 8 + (lane & 3) * 2;
        *(uint32_t*)(Os + o0 + col) = pack_f16x2(o[nt][0] * inv0, o[nt][1] * inv0);
        *(uint32_t*)(Os + o1 + col) = pack_f16x2(o[nt][2] * inv1, o[nt][3] * inv1);
    }
}

// ---------------------------------------------------------------------------
extern "C" void kernel_launch(void* const* d_in, const int* in_sizes, int n_in,
                              void* d_out, int out_size)
{
    const float* x    = (const float*)d_in[0];
    const float* fcos = (const float*)d_in[1];
    const float* fsin = (const float*)d_in[2];
    const float* wq   = (const float*)d_in[3];
    const float* wk   = (const float*)d_in[4];
    const float* wv   = (const float*)d_in[5];
    const float* wo   = (const float*)d_in[6];
    float* out = (float*)d_out;

    float *Qp, *Kp, *Vp;
    __half *hf, *vts;
    __nv_bfloat16 *qh, *ql, *kh, *kl;
    cudaGetSymbolAddress((void**)&Qp, g_Q);
    cudaGetSymbolAddress((void**)&Kp, g_K);
    cudaGetSymbolAddress((void**)&Vp, g_V);
    cudaGetSymbolAddress((void**)&hf, g_hf);
    cudaGetSymbolAddress((void**)&qh, g_Qh);
    cudaGetSymbolAddress((void**)&ql, g_Ql);
    cudaGetSymbolAddress((void**)&kh, g_Kh);
    cudaGetSymbolAddress((void**)&kl, g_Kl);
    cudaGetSymbolAddress((void**)&vts, g_Vts);

    cudaFuncSetAttribute(gemm_mma, cudaFuncAttributeMaxDynamicSharedMemorySize, G_SMEM);
    cudaFuncSetAttribute(attn_mma, cudaFuncAttributeMaxDynamicSharedMemorySize, A_SMEM);

    const int M = BATCH * SEQ;

    // #0: prepass (x -> fp16 single; weights -> fp16 hi/lo)
    split_all<<<(Q_TOT + 255) / 256, 256>>>(x, wq, wk, wv, wo, hf);

    // #1: K and V projections fused
    gemm_mma<<<dim3(KVDIM / 256, M / 128, 2), 512, G_SMEM>>>(
        hf + OFF_XS, hf + OFF_WKH, hf + OFF_WKL,
        (size_t)(2 * N_WK), Kp, Vp, M, KVDIM, EMBED);

    // #2: V transpose (single fp16)
    split_v_t<<<dim3(SEQ / 64, NKV, BATCH), 256>>>(Vp, vts);

    // #3: Q projection  (ncu-profiled launch slot)
    gemm_mma<<<dim3(EMBED / 256, M / 128, 1), 512, G_SMEM>>>(
        hf + OFF_XS, hf + OFF_WQH, hf + OFF_WQL,
        (size_t)0, Qp, Qp, M, EMBED, EMBED);

    // #4: RoPE + split for Q and K
    rope_all<<<(TQ_ITEMS + TK_ITEMS + 255) / 256, 256>>>(Qp, Kp, fcos, fsin, qh, ql, kh, kl);

    // #5: tensor-core causal GQA flash attention
    attn_mma<<<dim3(SEQ / 128, NHEADS, BATCH), 256, A_SMEM>>>(qh, ql, kh, kl, vts,
                                                              hf + OFF_OS);

    // #6: output projection
    gemm_mma<<<dim3(EMBED / 256, M / 128, 1), 512, G_SMEM>>>(
        hf + OFF_OS, hf + OFF_WOH, hf + OFF_WOL,
        (size_t)0, out, out, M, EMBED, EMBED);
}

// round 12
// speedup vs baseline: 4.8453x; 1.0764x over previous
#include <cuda_runtime.h>
#include <cuda_bf16.h>
#include <cuda_fp16.h>
#include <cstdint>

#define BATCH 2
#define SEQ 2048
#define EMBED 2048
#define NHEADS 32
#define NKV 8
#define HDIM 64
#define KVDIM (NKV*HDIM)   // 512

// fp32 scratch (gemm outputs)
__device__ float g_Q[(size_t)BATCH*SEQ*EMBED];
__device__ float g_K[(size_t)BATCH*SEQ*KVDIM];
__device__ float g_V[(size_t)BATCH*SEQ*KVDIM];

// fp16 pool (gemm operands): activations single, weights hi/lo
#define N_X   (size_t)8388608    // 2*2048*2048
#define N_WQ  (size_t)4194304
#define N_WK  (size_t)1048576
#define N_WV  (size_t)1048576
#define N_WO  (size_t)4194304
#define OFF_XS  (size_t)0
#define OFF_WQH (OFF_XS + N_X)
#define OFF_WQL (OFF_WQH + N_WQ)
#define OFF_WKH (OFF_WQL + N_WQ)
#define OFF_WKL (OFF_WKH + N_WK)
#define OFF_WVH (OFF_WKL + N_WK)
#define OFF_WVL (OFF_WVH + N_WV)
#define OFF_WOH (OFF_WVL + N_WV)
#define OFF_WOL (OFF_WOH + N_WO)
#define OFF_OS  (OFF_WOL + N_WO)
#define POOL_SZ (OFF_OS + N_X)
__device__ __half g_hf[POOL_SZ];

// attention operands: all fp16. Q single, K hi/lo, V^T single.
__device__ __half g_Qs[(size_t)BATCH*NHEADS*SEQ*HDIM];
__device__ __half g_Kh[(size_t)BATCH*NKV*SEQ*HDIM];
__device__ __half g_Kl[(size_t)BATCH*NKV*SEQ*HDIM];
__device__ __half g_Vts[(size_t)BATCH*NKV*HDIM*SEQ];

// ============================ helpers ======================================
__device__ __forceinline__ uint32_t smem_u32(const void* p) {
    uint32_t a;
    asm("{ .reg .u64 t; cvta.to.shared.u64 t, %1; cvt.u32.u64 %0, t; }"
        : "=r"(a) : "l"(p));
    return a;
}

#define LDSM4(R0,R1,R2,R3,ADDR) \
    asm volatile("ldmatrix.sync.aligned.m8n8.x4.shared.b16 {%0,%1,%2,%3}, [%4];" \
                 : "=r"(R0), "=r"(R1), "=r"(R2), "=r"(R3) : "r"(ADDR))

// fp16 MMA (everything)
#define MMA16816F(C, A, B0, B1) \
    asm volatile("mma.sync.aligned.m16n8k16.row.col.f32.f16.f16.f32 " \
                 "{%0,%1,%2,%3}, {%4,%5,%6,%7}, {%8,%9}, {%0,%1,%2,%3};" \
                 : "+f"((C)[0]), "+f"((C)[1]), "+f"((C)[2]), "+f"((C)[3]) \
                 : "r"((A)[0]), "r"((A)[1]), "r"((A)[2]), "r"((A)[3]), \
                   "r"(B0), "r"(B1))

#define CP16(DST, SRC) \
    asm volatile("cp.async.cg.shared.global [%0], [%1], 16;" :: "r"(DST), "l"(SRC))
#define CP_COMMIT() asm volatile("cp.async.commit_group;")
#define CP_WAIT0()  asm volatile("cp.async.wait_group 0;")
#define CP_WAIT1()  asm volatile("cp.async.wait_group 1;")

__device__ __forceinline__ uint32_t pack_f16x2(float lo, float hi) {
    uint32_t d;
    asm("cvt.rn.f16x2.f32 %0, %1, %2;" : "=r"(d) : "f"(hi), "f"(lo));
    return d;
}

// ---------------------------------------------------------------------------
// One-shot prepass: x -> fp16 single; weights -> fp16 hi/lo.
// ---------------------------------------------------------------------------
#define Q_X  (int)(N_X/4)
#define Q_WQ (int)(N_WQ/4)
#define Q_WK (int)(N_WK/4)
#define Q_WV (int)(N_WV/4)
#define Q_WO (int)(N_WO/4)
#define Q_TOT (Q_X + Q_WQ + Q_WK + Q_WV + Q_WO)

__global__ void split_all(const float* __restrict__ x,  const float* __restrict__ wq,
                          const float* __restrict__ wk, const float* __restrict__ wv,
                          const float* __restrict__ wo, __half* __restrict__ hf)
{
    int i = blockIdx.x * blockDim.x + threadIdx.x;
    if (i >= Q_TOT) return;
    if (i < Q_X) {
        float4 v = ((const float4*)x)[i];
        uint2 u;
        u.x = pack_f16x2(v.x, v.y);
        u.y = pack_f16x2(v.z, v.w);
        ((uint2*)(hf + OFF_XS))[i] = u;
        return;
    }
    const float* src; size_t dh, dl; int j;
    if (i < Q_X + Q_WQ)                    { src = wq; j = i - Q_X;                   dh = OFF_WQH; dl = OFF_WQL; }
    else if (i < Q_X + Q_WQ + Q_WK)        { src = wk; j = i - Q_X - Q_WQ;            dh = OFF_WKH; dl = OFF_WKL; }
    else if (i < Q_X + Q_WQ + Q_WK + Q_WV) { src = wv; j = i - Q_X - Q_WQ - Q_WK;     dh = OFF_WVH; dl = OFF_WVL; }
    else                                   { src = wo; j = i - Q_X - Q_WQ - Q_WK - Q_WV; dh = OFF_WOH; dl = OFF_WOL; }
    float4 v = ((const float4*)src)[j];
    __half h0 = __float2half_rn(v.x);
    __half h1 = __float2half_rn(v.y);
    __half h2 = __float2half_rn(v.z);
    __half h3 = __float2half_rn(v.w);
    __half l0 = __float2half_rn(v.x - __half2float(h0));
    __half l1 = __float2half_rn(v.y - __half2float(h1));
    __half l2 = __float2half_rn(v.z - __half2float(h2));
    __half l3 = __float2half_rn(v.w - __half2float(h3));
    uint2 uh, ul;
    uh.x = (uint32_t)__half_as_ushort(h0) | ((uint32_t)__half_as_ushort(h1) << 16);
    uh.y = (uint32_t)__half_as_ushort(h2) | ((uint32_t)__half_as_ushort(h3) << 16);
    ul.x = (uint32_t)__half_as_ushort(l0) | ((uint32_t)__half_as_ushort(l1) << 16);
    ul.y = (uint32_t)__half_as_ushort(l2) | ((uint32_t)__half_as_ushort(l3) << 16);
    ((uint2*)(hf + dh))[j] = uh;
    ((uint2*)(hf + dl))[j] = ul;
}

// ---------------------------------------------------------------------------
// fp16 2-term MMA GEMM: C = A(single) * [Bh + Bl]^T.
// Block 128x128, BK=64, 256 threads, warp tile 32x64, 2-stage cp.async,
// 2 CTAs/SM (smem 108 KB, regs <= 128).
// ---------------------------------------------------------------------------
#define GPITCH 72
#define GA_ELE (128*GPITCH)           // 9216
#define GB_ELE (128*GPITCH)           // 9216 per B array
#define G_STG_E (GA_ELE + 2*GB_ELE)   // 27648 elems
#define G_STG_B (G_STG_E*2)           // 55296 B
#define G_SMEM (2*G_STG_B)            // 110592 B

__global__ __launch_bounds__(256, 2)
void gemm_mma(const __half* __restrict__ As,
              const __half* __restrict__ Bh0, const __half* __restrict__ Bl0,
              size_t bstride, float* __restrict__ C0, float* __restrict__ C1,
              int M, int N, int K)
{
    extern __shared__ __align__(16) char dsm_raw[];
    const uint32_t sbase = smem_u32(dsm_raw);

    const int tid  = threadIdx.x;
    const int wid  = tid >> 5;
    const int lane = tid & 31;
    const int wm   = wid >> 1;      // 0..3 -> rows wm*32
    const int wn   = wid & 1;       // 0..1 -> cols wn*64

    const int bm = blockIdx.y * 128;
    const int bn = blockIdx.x * 128;

    const __half* Bh = Bh0 + (size_t)blockIdx.z * bstride;
    const __half* Bl = Bl0 + (size_t)blockIdx.z * bstride;
    float* C = blockIdx.z ? C1 : C0;

    const int aoff = (wm * 32 + (lane & 15)) * GPITCH + ((lane >> 4) << 3);
    const int bofflane = (((lane >> 4) << 3) + (lane & 7)) * GPITCH + (((lane >> 3) & 1) << 3);

    const int nk = K >> 6;

    auto load_stage = [&](int kt, int stage) {
        const int k0 = kt << 6;
        const uint32_t sb = sbase + stage * G_STG_B;
#pragma unroll
        for (int q = 0; q < 12; q++) {        // 3072 chunks total
            int c = tid + q * 256;            // 0..3071
            const __half* g;
            uint32_t dst;
            if (c < 1024) {                   // A: 128 rows x 8 chunks
                int r = c >> 3;
                int col = (c & 7) << 3;
                g = As + (size_t)(bm + r) * K + k0 + col;
                dst = sb + (r * GPITCH + col) * 2;
            } else {                          // B arrays: 2 x 128 rows x 8 chunks
                int cb = c - 1024;
                int arr = cb >> 10;           // 0:Bh 1:Bl
                int j = cb & 1023;
                int r = j >> 3;
                int col = (j & 7) << 3;
                g = (arr ? Bl : Bh) + (size_t)(bn + r) * K + k0 + col;
                dst = sb + (GA_ELE + arr * GB_ELE + r * GPITCH + col) * 2;
            }
            CP16(dst, g);
        }
        CP_COMMIT();
    };

    float c[2][8][4];
#pragma unroll
    for (int a = 0; a < 2; a++)
#pragma unroll
        for (int b = 0; b < 8; b++)
#pragma unroll
            for (int d = 0; d < 4; d++) c[a][b][d] = 0.f;

    load_stage(0, 0);

#pragma unroll 1
    for (int kt = 0; kt < nk; kt++) {
        if (kt + 1 < nk) {
            load_stage(kt + 1, (kt + 1) & 1);
            CP_WAIT1();
        } else {
            CP_WAIT0();
        }
        __syncthreads();

        const uint32_t sb = sbase + (kt & 1) * G_STG_B;
        const uint32_t uAs = sb;
        const uint32_t uBh = sb + GA_ELE * 2;
        const uint32_t uBl = sb + (GA_ELE + GB_ELE) * 2;

#pragma unroll
        for (int kk = 0; kk < 64; kk += 16) {
            uint32_t as[2][4], bh[8][2], bl[8][2];
#pragma unroll
            for (int ms = 0; ms < 2; ms++) {
                LDSM4(as[ms][0], as[ms][1], as[ms][2], as[ms][3],
                      uAs + 2 * (aoff + ms * 16 * GPITCH + kk));
            }
#pragma unroll
            for (int g = 0; g < 4; g++) {
                const int off = (wn * 64 + g * 16) * GPITCH + bofflane + kk;
                uint32_t t0, t1, t2, t3;
                LDSM4(t0, t1, t2, t3, uBh + 2 * off);
                bh[2*g][0] = t0; bh[2*g][1] = t1; bh[2*g+1][0] = t2; bh[2*g+1][1] = t3;
                LDSM4(t0, t1, t2, t3, uBl + 2 * off);
                bl[2*g][0] = t0; bl[2*g][1] = t1; bl[2*g+1][0] = t2; bl[2*g+1][1] = t3;
            }
#pragma unroll
            for (int ms = 0; ms < 2; ms++)
#pragma unroll
                for (int ng = 0; ng < 8; ng++) {
                    MMA16816F(c[ms][ng], as[ms], bh[ng][0], bh[ng][1]);
                    MMA16816F(c[ms][ng], as[ms], bl[ng][0], bl[ng][1]);
                }
        }
        __syncthreads();
    }

#pragma unroll
    for (int ms = 0; ms < 2; ms++) {
        const int row = bm + wm * 32 + ms * 16 + (lane >> 2);
#pragma unroll
        for (int ng = 0; ng < 8; ng++) {
            const int col = bn + wn * 64 + ng * 8 + (lane & 3) * 2;
            *(float2*)(C + (size_t)row * N + col)       = make_float2(c[ms][ng][0], c[ms][ng][1]);
            *(float2*)(C + (size_t)(row + 8) * N + col) = make_float2(c[ms][ng][2], c[ms][ng][3]);
        }
    }
}

// ---------------------------------------------------------------------------
// Fused RoPE + fp16 conversion: Q -> single fp16 [b,h,s,d]; K -> fp16 hi/lo.
// ---------------------------------------------------------------------------
#define TQ_ITEMS (BATCH*SEQ*NHEADS*32)
#define TK_ITEMS (BATCH*SEQ*NKV*32)

__global__ void rope_all(const float* __restrict__ Qf, const float* __restrict__ Kf,
                         const float* __restrict__ cosv, const float* __restrict__ sinv,
                         __half* __restrict__ qs,
                         __half* __restrict__ kh, __half* __restrict__ kl)
{
    int i = blockIdx.x * blockDim.x + threadIdx.x;
    bool isQ;
    const float* buf; int nheads, j;
    if (i < TQ_ITEMS) { isQ = true;  buf = Qf; nheads = NHEADS; j = i; }
    else if (i < TQ_ITEMS + TK_ITEMS) { isQ = false; buf = Kf; nheads = NKV; j = i - TQ_ITEMS; }
    else return;

    int d = j & 31;
    int h = (j >> 5) % nheads;
    int s = (j / (32 * nheads)) % SEQ;
    int b = j / (32 * nheads * SEQ);

    const float* p = buf + (((size_t)b * SEQ + s) * nheads + h) * HDIM;
    float c0 = cosv[s * HDIM + d];
    float c1 = cosv[s * HDIM + d + 32];
    float s0 = sinv[s * HDIM + d];
    float s1 = sinv[s * HDIM + d + 32];
    float x0 = p[d];
    float x1 = p[d + 32];
    float y0 = x0 * c0 - x1 * s0;
    float y1 = x1 * c1 + x0 * s1;

    size_t o = (((size_t)b * nheads + h) * SEQ + s) * HDIM;
    if (isQ) {
        qs[o + d]      = __float2half_rn(y0);
        qs[o + d + 32] = __float2half_rn(y1);
    } else {
        __half h0 = __float2half_rn(y0);
        __half h1 = __float2half_rn(y1);
        kh[o + d]      = h0;
        kh[o + d + 32] = h1;
        kl[o + d]      = __float2half_rn(y0 - __half2float(h0));
        kl[o + d + 32] = __float2half_rn(y1 - __half2float(h1));
    }
}

// ---------------------------------------------------------------------------
// V fp32 [b,s,8,64] -> V^T single fp16 [b,kvh,d,s]
// ---------------------------------------------------------------------------
__global__ __launch_bounds__(256) void split_v_t(const float* __restrict__ V,
                                                 __half* __restrict__ vts)
{
    __shared__ __half th[64][68];
    const int s0  = blockIdx.x * 64;
    const int kvh = blockIdx.y;
    const int b   = blockIdx.z;

    {
        const int r  = threadIdx.x >> 2;
        const int cb = (threadIdx.x & 3) * 16;
        const float4* g = (const float4*)(V + (((size_t)b * SEQ + s0 + r) * NKV + kvh) * HDIM + cb);
#pragma unroll
        for (int i = 0; i < 4; i++) {
            float4 v = g[i];
            th[cb + i * 4 + 0][r] = __float2half_rn(v.x);
            th[cb + i * 4 + 1][r] = __float2half_rn(v.y);
            th[cb + i * 4 + 2][r] = __float2half_rn(v.z);
            th[cb + i * 4 + 3][r] = __float2half_rn(v.w);
        }
    }
    __syncthreads();
    {
        const int d  = threadIdx.x >> 2;
        const int sc = (threadIdx.x & 3) * 16;
        size_t obase = (((size_t)b * NKV + kvh) * HDIM + d) * SEQ + s0 + sc;
        uint2 a0 = *(uint2*)&th[d][sc];
        uint2 a1 = *(uint2*)&th[d][sc + 4];
        uint2 a2 = *(uint2*)&th[d][sc + 8];
        uint2 a3 = *(uint2*)&th[d][sc + 12];
        *(uint4*)(vts + obase)     = make_uint4(a0.x, a0.y, a1.x, a1.y);
        *(uint4*)(vts + obase + 8) = make_uint4(a2.x, a2.y, a3.x, a3.y);
    }
}

// ---------------------------------------------------------------------------
// Tensor-core causal flash attention: QK fp16 2-term, PV single fp16.
// ---------------------------------------------------------------------------
#define APITCH 72
#define A_ARR (64*APITCH)             // 4608 elems
#define A_STG_E (3*A_ARR)             // Kh, Kl, Vs
#define A_STG_B (A_STG_E*2)           // 27648 B
#define A_SMEM (2*A_STG_B)            // 55296 B
#define SCALE_LOG2 0.18033688011112042f   // log2(e)/8

__global__ __launch_bounds__(256, 1)
void attn_mma(const __half* __restrict__ Qs,
              const __half* __restrict__ Kh, const __half* __restrict__ Kl,
              const __half* __restrict__ Vts, __half* __restrict__ Os)
{
    extern __shared__ __align__(16) char dsm_raw[];
    const uint32_t sbase = smem_u32(dsm_raw);

    const int tid  = threadIdx.x;
    const int wid  = tid >> 5;
    const int lane = tid & 31;
    const int t = (int)gridDim.x - 1 - (int)blockIdx.x;
    const int h = blockIdx.y;
    const int b = blockIdx.z;
    const int kvh = h >> 2;

    // ---- stage Q (single fp16) and extract fragments ----
    {
        const size_t qbase = (((size_t)b * NHEADS + h) * SEQ + (size_t)t * 128) * HDIM;
#pragma unroll
        for (int q = 0; q < 4; q++) {
            int i = tid + q * 256;            // 0..1023
            int r = i >> 3;
            int cc = (i & 7) << 3;
            CP16(sbase + (r * APITCH + cc) * 2, Qs + qbase + (size_t)r * HDIM + cc);
        }
        CP_COMMIT();
        CP_WAIT0();
    }
    __syncthreads();

    uint32_t qs[4][4];
    {
        const int aoff = (wid * 16 + (lane & 15)) * APITCH + ((lane >> 4) << 3);
#pragma unroll
        for (int kk = 0; kk < 4; kk++) {
            LDSM4(qs[kk][0], qs[kk][1], qs[kk][2], qs[kk][3], sbase + 2 * (aoff + kk * 16));
        }
    }
    __syncthreads();

    const size_t kbase = ((size_t)b * NKV + kvh) * SEQ * HDIM;
    const size_t vbase = ((size_t)b * NKV + kvh) * HDIM * SEQ;

    auto load_kv = [&](int kb, int stage) {
        const uint32_t sb = sbase + stage * A_STG_B;
#pragma unroll
        for (int q = 0; q < 6; q++) {
            int i = tid + q * 256;            // 0..1535
            int a = i >> 9;                   // 0:Kh 1:Kl 2:Vs
            int j = i & 511;
            int r = j >> 3;
            int cc = (j & 7) << 3;
            uint32_t dst = sb + (a * A_ARR + r * APITCH + cc) * 2;
            if (a == 0)      CP16(dst, Kh  + kbase + (size_t)(kb * 64 + r) * HDIM + cc);
            else if (a == 1) CP16(dst, Kl  + kbase + (size_t)(kb * 64 + r) * HDIM + cc);
            else             CP16(dst, Vts + vbase + (size_t)r * SEQ + kb * 64 + cc);
        }
        CP_COMMIT();
    };

    float o[8][4];
#pragma unroll
    for (int nt = 0; nt < 8; nt++)
#pragma unroll
        for (int e = 0; e < 4; e++) o[nt][e] = 0.f;
    float mi0 = -1e30f, mi1 = -1e30f, li0 = 0.f, li1 = 0.f;

    const int row0 = t * 128 + wid * 16 + (lane >> 2);
    const int row1 = row0 + 8;

    const int nkb = 2 * t + 2;
    load_kv(0, 0);

#pragma unroll 1
    for (int kb = 0; kb < nkb; kb++) {
        if (kb + 1 < nkb) {
            load_kv(kb + 1, (kb + 1) & 1);
            CP_WAIT1();
        } else {
            CP_WAIT0();
        }
        __syncthreads();

        const uint32_t sb = sbase + (kb & 1) * A_STG_B;
        const uint32_t uKh = sb;
        const uint32_t uKl = sb + A_ARR * 2;
        const uint32_t uVs = sb + 2 * A_ARR * 2;

        // ---- S = Q K^T (fp16 2-term) ----
        float s[8][4];
#pragma unroll
        for (int nt = 0; nt < 8; nt++)
#pragma unroll
            for (int e = 0; e < 4; e++) s[nt][e] = 0.f;

#pragma unroll
        for (int kk = 0; kk < 4; kk++) {
            uint32_t bh[8][2], bl[8][2];
#pragma unroll
            for (int g = 0; g < 4; g++) {
                const int off = (g * 16 + ((lane >> 4) << 3) + (lane & 7)) * APITCH
                              + (((lane >> 3) & 1) << 3) + kk * 16;
                uint32_t t0, t1, t2, t3;
                LDSM4(t0, t1, t2, t3, uKh + 2 * off);
                bh[2*g][0] = t0; bh[2*g][1] = t1; bh[2*g+1][0] = t2; bh[2*g+1][1] = t3;
                LDSM4(t0, t1, t2, t3, uKl + 2 * off);
                bl[2*g][0] = t0; bl[2*g][1] = t1; bl[2*g+1][0] = t2; bl[2*g+1][1] = t3;
            }
#pragma unroll
            for (int nt = 0; nt < 8; nt++) {
                MMA16816F(s[nt], qs[kk], bh[nt][0], bh[nt][1]);
                MMA16816F(s[nt], qs[kk], bl[nt][0], bl[nt][1]);
            }
        }

        const bool diag = (kb >= 2 * t);
#pragma unroll
        for (int nt = 0; nt < 8; nt++) {
            const int col = kb * 64 + nt * 8 + (lane & 3) * 2;
            s[nt][0] *= SCALE_LOG2; s[nt][1] *= SCALE_LOG2;
            s[nt][2] *= SCALE_LOG2; s[nt][3] *= SCALE_LOG2;
            if (diag) {
                if (col > row0)     s[nt][0] = -1e30f;
                if (col + 1 > row0) s[nt][1] = -1e30f;
                if (col > row1)     s[nt][2] = -1e30f;
                if (col + 1 > row1) s[nt][3] = -1e30f;
            }
        }

        float bm0 = -1e30f, bm1 = -1e30f;
#pragma unroll
        for (int nt = 0; nt < 8; nt++) {
            bm0 = fmaxf(bm0, fmaxf(s[nt][0], s[nt][1]));
            bm1 = fmaxf(bm1, fmaxf(s[nt][2], s[nt][3]));
        }
        bm0 = fmaxf(bm0, __shfl_xor_sync(0xffffffffu, bm0, 1));
        bm0 = fmaxf(bm0, __shfl_xor_sync(0xffffffffu, bm0, 2));
        bm1 = fmaxf(bm1, __shfl_xor_sync(0xffffffffu, bm1, 1));
        bm1 = fmaxf(bm1, __shfl_xor_sync(0xffffffffu, bm1, 2));

        const float mn0 = fmaxf(mi0, bm0);
        const float mn1 = fmaxf(mi1, bm1);
        const float sc0 = exp2f(mi0 - mn0);
        const float sc1 = exp2f(mi1 - mn1);

        float ls0 = 0.f, ls1 = 0.f;
#pragma unroll
        for (int nt = 0; nt < 8; nt++) {
            s[nt][0] = exp2f(s[nt][0] - mn0);
            s[nt][1] = exp2f(s[nt][1] - mn0);
            s[nt][2] = exp2f(s[nt][2] - mn1);
            s[nt][3] = exp2f(s[nt][3] - mn1);
            ls0 += s[nt][0] + s[nt][1];
            ls1 += s[nt][2] + s[nt][3];
        }
        ls0 += __shfl_xor_sync(0xffffffffu, ls0, 1);
        ls0 += __shfl_xor_sync(0xffffffffu, ls0, 2);
        ls1 += __shfl_xor_sync(0xffffffffu, ls1, 1);
        ls1 += __shfl_xor_sync(0xffffffffu, ls1, 2);

        li0 = li0 * sc0 + ls0;
        li1 = li1 * sc1 + ls1;
        mi0 = mn0; mi1 = mn1;

#pragma unroll
        for (int nt = 0; nt < 8; nt++) {
            o[nt][0] *= sc0; o[nt][1] *= sc0;
            o[nt][2] *= sc1; o[nt][3] *= sc1;
        }

        // ---- pack P to single fp16 fragments ----
        uint32_t ps[8][2];
#pragma unroll
        for (int nt = 0; nt < 8; nt++) {
            ps[nt][0] = pack_f16x2(s[nt][0], s[nt][1]);
            ps[nt][1] = pack_f16x2(s[nt][2], s[nt][3]);
        }

        // ---- O += P V (single fp16 term) ----
#pragma unroll
        for (int kk = 0; kk < 4; kk++) {
            uint32_t vs[8][2];
#pragma unroll
            for (int g = 0; g < 4; g++) {
                const int off = (g * 16 + ((lane >> 4) << 3) + (lane & 7)) * APITCH
                              + (((lane >> 3) & 1) << 3) + kk * 16;
                uint32_t t0, t1, t2, t3;
                LDSM4(t0, t1, t2, t3, uVs + 2 * off);
                vs[2*g][0] = t0; vs[2*g][1] = t1; vs[2*g+1][0] = t2; vs[2*g+1][1] = t3;
            }
            uint32_t ap[4] = {ps[2*kk][0], ps[2*kk][1], ps[2*kk+1][0], ps[2*kk+1][1]};
#pragma unroll
            for (int nt = 0; nt < 8; nt++) {
                MMA16816F(o[nt], ap, vs[nt][0], vs[nt][1]);
            }
        }
        __syncthreads();
    }

    // ---- finalize: write fp16 single output ([b,s,h,d] = [M,2048]) ----
    const float inv0 = 1.f / li0;
    const float inv1 = 1.f / li1;
    const size_t o0 = (((size_t)b * SEQ + row0) * NHEADS + h) * HDIM;
    const size_t o1 = (((size_t)b * SEQ + row1) * NHEADS + h) * HDIM;
#pragma unroll
    for (int nt = 0; nt < 8; nt++) {
        const int col = nt * 8 + (lane & 3) * 2;
        *(uint32_t*)(Os + o0 + col) = pack_f16x2(o[nt][0] * inv0, o[nt][1] * inv0);
        *(uint32_t*)(Os + o1 + col) = pack_f16x2(o[nt][2] * inv1, o[nt][3] * inv1);
    }
}

// ---------------------------------------------------------------------------
extern "C" void kernel_launch(void* const* d_in, const int* in_sizes, int n_in,
                              void* d_out, int out_size)
{
    const float* x    = (const float*)d_in[0];
    const float* fcos = (const float*)d_in[1];
    const float* fsin = (const float*)d_in[2];
    const float* wq   = (const float*)d_in[3];
    const float* wk   = (const float*)d_in[4];
    const float* wv   = (const float*)d_in[5];
    const float* wo   = (const float*)d_in[6];
    float* out = (float*)d_out;

    float *Qp, *Kp, *Vp;
    __half *hf, *qs, *kh, *kl, *vts;
    cudaGetSymbolAddress((void**)&Qp, g_Q);
    cudaGetSymbolAddress((void**)&Kp, g_K);
    cudaGetSymbolAddress((void**)&Vp, g_V);
    cudaGetSymbolAddress((void**)&hf, g_hf);
    cudaGetSymbolAddress((void**)&qs, g_Qs);
    cudaGetSymbolAddress((void**)&kh, g_Kh);
    cudaGetSymbolAddress((void**)&kl, g_Kl);
    cudaGetSymbolAddress((void**)&vts, g_Vts);

    cudaFuncSetAttribute(gemm_mma, cudaFuncAttributeMaxDynamicSharedMemorySize, G_SMEM);
    cudaFuncSetAttribute(attn_mma, cudaFuncAttributeMaxDynamicSharedMemorySize, A_SMEM);

    const int M = BATCH * SEQ;

    // #0: prepass (x -> fp16 single; weights -> fp16 hi/lo)
    split_all<<<(Q_TOT + 255) / 256, 256>>>(x, wq, wk, wv, wo, hf);

    // #1: K and V projections fused
    gemm_mma<<<dim3(KVDIM / 128, M / 128, 2), 256, G_SMEM>>>(
        hf + OFF_XS, hf + OFF_WKH, hf + OFF_WKL,
        (size_t)(2 * N_WK), Kp, Vp, M, KVDIM, EMBED);

    // #2: V transpose (single fp16)
    split_v_t<<<dim3(SEQ / 64, NKV, BATCH), 256>>>(Vp, vts);

    // #3: Q projection  (ncu-profiled launch slot)
    gemm_mma<<<dim3(EMBED / 128, M / 128, 1), 256, G_SMEM>>>(
        hf + OFF_XS, hf + OFF_WQH, hf + OFF_WQL,
        (size_t)0, Qp, Qp, M, EMBED, EMBED);

    // #4: RoPE + fp16 conversion for Q and K
    rope_all<<<(TQ_ITEMS + TK_ITEMS + 255) / 256, 256>>>(Qp, Kp, fcos, fsin, qs, kh, kl);

    // #5: tensor-core causal GQA flash attention
    attn_mma<<<dim3(SEQ / 128, NHEADS, BATCH), 256, A_SMEM>>>(qs, kh, kl, vts,
                                                              hf + OFF_OS);

    // #6: output projection
    gemm_mma<<<dim3(EMBED / 128, M / 128, 1), 256, G_SMEM>>>(
        hf + OFF_OS, hf + OFF_WOH, hf + OFF_WOL,
        (size_t)0, out, out, M, EMBED, EMBED);
}

// round 13
// speedup vs baseline: 5.8857x; 1.2147x over previous
#include <cuda_runtime.h>
#include <cuda_bf16.h>
#include <cuda_fp16.h>
#include <cstdint>

#define BATCH 2
#define SEQ 2048
#define EMBED 2048
#define NHEADS 32
#define NKV 8
#define HDIM 64
#define KVDIM (NKV*HDIM)   // 512
#define NQKV 3072          // packed QKV output columns

// fp32 scratch: packed QKV gemm output [M, 3072] = [Q | K | V]
__device__ float g_QKV[(size_t)BATCH*SEQ*NQKV];

// fp16 pool: x single, Wqkv packed single, Wo hi/lo, attention output single
#define N_X    (size_t)8388608    // 2*2048*2048
#define N_WQKV (size_t)6291456    // 3072*2048
#define N_WO   (size_t)4194304
#define OFF_XS   (size_t)0
#define OFF_WQKV (OFF_XS + N_X)
#define OFF_WOH  (OFF_WQKV + N_WQKV)
#define OFF_WOL  (OFF_WOH + N_WO)
#define OFF_OS   (OFF_WOL + N_WO)
#define POOL_SZ  (OFF_OS + N_X)
__device__ __half g_hf[POOL_SZ];

// attention operands: all fp16. Q single, K hi/lo, V^T single.
__device__ __half g_Qs[(size_t)BATCH*NHEADS*SEQ*HDIM];
__device__ __half g_Kh[(size_t)BATCH*NKV*SEQ*HDIM];
__device__ __half g_Kl[(size_t)BATCH*NKV*SEQ*HDIM];
__device__ __half g_Vts[(size_t)BATCH*NKV*HDIM*SEQ];

// ============================ helpers ======================================
__device__ __forceinline__ uint32_t smem_u32(const void* p) {
    uint32_t a;
    asm("{ .reg .u64 t; cvta.to.shared.u64 t, %1; cvt.u32.u64 %0, t; }"
        : "=r"(a) : "l"(p));
    return a;
}

#define LDSM4(R0,R1,R2,R3,ADDR) \
    asm volatile("ldmatrix.sync.aligned.m8n8.x4.shared.b16 {%0,%1,%2,%3}, [%4];" \
                 : "=r"(R0), "=r"(R1), "=r"(R2), "=r"(R3) : "r"(ADDR))

#define MMA16816F(C, A, B0, B1) \
    asm volatile("mma.sync.aligned.m16n8k16.row.col.f32.f16.f16.f32 " \
                 "{%0,%1,%2,%3}, {%4,%5,%6,%7}, {%8,%9}, {%0,%1,%2,%3};" \
                 : "+f"((C)[0]), "+f"((C)[1]), "+f"((C)[2]), "+f"((C)[3]) \
                 : "r"((A)[0]), "r"((A)[1]), "r"((A)[2]), "r"((A)[3]), \
                   "r"(B0), "r"(B1))

#define CP16(DST, SRC) \
    asm volatile("cp.async.cg.shared.global [%0], [%1], 16;" :: "r"(DST), "l"(SRC))
#define CP_COMMIT() asm volatile("cp.async.commit_group;")
#define CP_WAIT0()  asm volatile("cp.async.wait_group 0;")
#define CP_WAIT1()  asm volatile("cp.async.wait_group 1;")

__device__ __forceinline__ uint32_t pack_f16x2(float lo, float hi) {
    uint32_t d;
    asm("cvt.rn.f16x2.f32 %0, %1, %2;" : "=r"(d) : "f"(hi), "f"(lo));
    return d;
}

// ---------------------------------------------------------------------------
// One-shot prepass: x,wq,wk,wv -> single fp16 (wq/wk/wv packed); wo -> hi/lo.
// ---------------------------------------------------------------------------
#define Q_X   (int)(N_X/4)
#define Q_WQ  1048576
#define Q_WK  262144
#define Q_WV  262144
#define Q_WO  1048576
#define Q_TOT (Q_X + Q_WQ + Q_WK + Q_WV + Q_WO)

__global__ void split_all(const float* __restrict__ x,  const float* __restrict__ wq,
                          const float* __restrict__ wk, const float* __restrict__ wv,
                          const float* __restrict__ wo, __half* __restrict__ hf)
{
    int i = blockIdx.x * blockDim.x + threadIdx.x;
    if (i >= Q_TOT) return;
    if (i < Q_X + Q_WQ + Q_WK + Q_WV) {
        // single-fp16 conversions: x, then packed Wqkv
        const float* src; size_t doff; int j;
        if (i < Q_X)             { src = x;  j = i;                  doff = OFF_XS; }
        else if (i < Q_X + Q_WQ) { src = wq; j = i - Q_X;            doff = OFF_WQKV; }
        else if (i < Q_X + Q_WQ + Q_WK)
                                 { src = wk; j = i - Q_X - Q_WQ;     doff = OFF_WQKV + (size_t)2048 * EMBED; }
        else                     { src = wv; j = i - Q_X - Q_WQ - Q_WK; doff = OFF_WQKV + (size_t)2560 * EMBED; }
        float4 v = ((const float4*)src)[j];
        uint2 u;
        u.x = pack_f16x2(v.x, v.y);
        u.y = pack_f16x2(v.z, v.w);
        ((uint2*)(hf + doff))[j] = u;
        return;
    }
    // Wo -> fp16 hi/lo
    int j = i - Q_X - Q_WQ - Q_WK - Q_WV;
    float4 v = ((const float4*)wo)[j];
    __half h0 = __float2half_rn(v.x);
    __half h1 = __float2half_rn(v.y);
    __half h2 = __float2half_rn(v.z);
    __half h3 = __float2half_rn(v.w);
    __half l0 = __float2half_rn(v.x - __half2float(h0));
    __half l1 = __float2half_rn(v.y - __half2float(h1));
    __half l2 = __float2half_rn(v.z - __half2float(h2));
    __half l3 = __float2half_rn(v.w - __half2float(h3));
    uint2 uh, ul;
    uh.x = (uint32_t)__half_as_ushort(h0) | ((uint32_t)__half_as_ushort(h1) << 16);
    uh.y = (uint32_t)__half_as_ushort(h2) | ((uint32_t)__half_as_ushort(h3) << 16);
    ul.x = (uint32_t)__half_as_ushort(l0) | ((uint32_t)__half_as_ushort(l1) << 16);
    ul.y = (uint32_t)__half_as_ushort(l2) | ((uint32_t)__half_as_ushort(l3) << 16);
    ((uint2*)(hf + OFF_WOH))[j] = uh;
    ((uint2*)(hf + OFF_WOL))[j] = ul;
}

// ---------------------------------------------------------------------------
// Single-term fp16 GEMM (QKV projection): C[M,N] = A * B^T.
// Block 128x128, BK=64, 256 threads, warp tile 32x64, 2-stage, 2 CTAs/SM.
// ---------------------------------------------------------------------------
#define GPITCH 72
#define G1A (128*GPITCH)              // 9216 elems per array
#define G1STG_B (2*G1A*2)             // 36864 B per stage
#define G1SMEM (2*G1STG_B)            // 73728 B

__global__ __launch_bounds__(256, 2)
void gemm_qkv(const __half* __restrict__ As, const __half* __restrict__ Bs,
              float* __restrict__ C, int M, int N, int K)
{
    extern __shared__ __align__(16) char dsm_raw[];
    const uint32_t sbase = smem_u32(dsm_raw);

    const int tid  = threadIdx.x;
    const int wid  = tid >> 5;
    const int lane = tid & 31;
    const int wm   = wid >> 1;      // 0..3
    const int wn   = wid & 1;       // 0..1

    const int bm = blockIdx.y * 128;
    const int bn = blockIdx.x * 128;

    const int aoff = (wm * 32 + (lane & 15)) * GPITCH + ((lane >> 4) << 3);
    const int bofflane = (((lane >> 4) << 3) + (lane & 7)) * GPITCH + (((lane >> 3) & 1) << 3);

    const int nk = K >> 6;

    auto load_stage = [&](int kt, int stage) {
        const int k0 = kt << 6;
        const uint32_t sb = sbase + stage * G1STG_B;
#pragma unroll
        for (int q = 0; q < 8; q++) {         // 2048 chunks
            int c = tid + q * 256;
            int arr = c >> 10;                // 0:A 1:B
            int j = c & 1023;
            int r = j >> 3;
            int col = (j & 7) << 3;
            const __half* g = (arr ? Bs + (size_t)(bn + r) * K
                                   : As + (size_t)(bm + r) * K) + k0 + col;
            CP16(sb + (arr * G1A + r * GPITCH + col) * 2, g);
        }
        CP_COMMIT();
    };

    float c[2][8][4];
#pragma unroll
    for (int a = 0; a < 2; a++)
#pragma unroll
        for (int b = 0; b < 8; b++)
#pragma unroll
            for (int d = 0; d < 4; d++) c[a][b][d] = 0.f;

    load_stage(0, 0);

#pragma unroll 1
    for (int kt = 0; kt < nk; kt++) {
        if (kt + 1 < nk) {
            load_stage(kt + 1, (kt + 1) & 1);
            CP_WAIT1();
        } else {
            CP_WAIT0();
        }
        __syncthreads();

        const uint32_t sb = sbase + (kt & 1) * G1STG_B;
        const uint32_t uAs = sb;
        const uint32_t uBs = sb + G1A * 2;

#pragma unroll
        for (int kk = 0; kk < 64; kk += 16) {
            uint32_t as[2][4], bs[8][2];
#pragma unroll
            for (int ms = 0; ms < 2; ms++) {
                LDSM4(as[ms][0], as[ms][1], as[ms][2], as[ms][3],
                      uAs + 2 * (aoff + ms * 16 * GPITCH + kk));
            }
#pragma unroll
            for (int g = 0; g < 4; g++) {
                const int off = (wn * 64 + g * 16) * GPITCH + bofflane + kk;
                uint32_t t0, t1, t2, t3;
                LDSM4(t0, t1, t2, t3, uBs + 2 * off);
                bs[2*g][0] = t0; bs[2*g][1] = t1; bs[2*g+1][0] = t2; bs[2*g+1][1] = t3;
            }
#pragma unroll
            for (int ms = 0; ms < 2; ms++)
#pragma unroll
                for (int ng = 0; ng < 8; ng++)
                    MMA16816F(c[ms][ng], as[ms], bs[ng][0], bs[ng][1]);
        }
        __syncthreads();
    }

#pragma unroll
    for (int ms = 0; ms < 2; ms++) {
        const int row = bm + wm * 32 + ms * 16 + (lane >> 2);
#pragma unroll
        for (int ng = 0; ng < 8; ng++) {
            const int col = bn + wn * 64 + ng * 8 + (lane & 3) * 2;
            *(float2*)(C + (size_t)row * N + col)       = make_float2(c[ms][ng][0], c[ms][ng][1]);
            *(float2*)(C + (size_t)(row + 8) * N + col) = make_float2(c[ms][ng][2], c[ms][ng][3]);
        }
    }
}

// ---------------------------------------------------------------------------
// 2-term fp16 GEMM (O projection): C = A * [Bh + Bl]^T. Same tiling.
// ---------------------------------------------------------------------------
#define G2STG_B (3*G1A*2)             // 55296 B per stage (A, Bh, Bl)
#define G2SMEM (2*G2STG_B)            // 110592 B

__global__ __launch_bounds__(256, 2)
void gemm_wo(const __half* __restrict__ As,
             const __half* __restrict__ Bh, const __half* __restrict__ Bl,
             float* __restrict__ C, int M, int N, int K)
{
    extern __shared__ __align__(16) char dsm_raw[];
    const uint32_t sbase = smem_u32(dsm_raw);

    const int tid  = threadIdx.x;
    const int wid  = tid >> 5;
    const int lane = tid & 31;
    const int wm   = wid >> 1;
    const int wn   = wid & 1;

    const int bm = blockIdx.y * 128;
    const int bn = blockIdx.x * 128;

    const int aoff = (wm * 32 + (lane & 15)) * GPITCH + ((lane >> 4) << 3);
    const int bofflane = (((lane >> 4) << 3) + (lane & 7)) * GPITCH + (((lane >> 3) & 1) << 3);

    const int nk = K >> 6;

    auto load_stage = [&](int kt, int stage) {
        const int k0 = kt << 6;
        const uint32_t sb = sbase + stage * G2STG_B;
#pragma unroll
        for (int q = 0; q < 12; q++) {        // 3072 chunks
            int c = tid + q * 256;
            int arr = c >> 10;                // 0:A 1:Bh 2:Bl
            int j = c & 1023;
            int r = j >> 3;
            int col = (j & 7) << 3;
            const __half* g;
            if (arr == 0)      g = As + (size_t)(bm + r) * K + k0 + col;
            else if (arr == 1) g = Bh + (size_t)(bn + r) * K + k0 + col;
            else               g = Bl + (size_t)(bn + r) * K + k0 + col;
            CP16(sb + (arr * G1A + r * GPITCH + col) * 2, g);
        }
        CP_COMMIT();
    };

    float c[2][8][4];
#pragma unroll
    for (int a = 0; a < 2; a++)
#pragma unroll
        for (int b = 0; b < 8; b++)
#pragma unroll
            for (int d = 0; d < 4; d++) c[a][b][d] = 0.f;

    load_stage(0, 0);

#pragma unroll 1
    for (int kt = 0; kt < nk; kt++) {
        if (kt + 1 < nk) {
            load_stage(kt + 1, (kt + 1) & 1);
            CP_WAIT1();
        } else {
            CP_WAIT0();
        }
        __syncthreads();

        const uint32_t sb = sbase + (kt & 1) * G2STG_B;
        const uint32_t uAs = sb;
        const uint32_t uBh = sb + G1A * 2;
        const uint32_t uBl = sb + 2 * G1A * 2;

#pragma unroll
        for (int kk = 0; kk < 64; kk += 16) {
            uint32_t as[2][4], bh[8][2], bl[8][2];
#pragma unroll
            for (int ms = 0; ms < 2; ms++) {
                LDSM4(as[ms][0], as[ms][1], as[ms][2], as[ms][3],
                      uAs + 2 * (aoff + ms * 16 * GPITCH + kk));
            }
#pragma unroll
            for (int g = 0; g < 4; g++) {
                const int off = (wn * 64 + g * 16) * GPITCH + bofflane + kk;
                uint32_t t0, t1, t2, t3;
                LDSM4(t0, t1, t2, t3, uBh + 2 * off);
                bh[2*g][0] = t0; bh[2*g][1] = t1; bh[2*g+1][0] = t2; bh[2*g+1][1] = t3;
                LDSM4(t0, t1, t2, t3, uBl + 2 * off);
                bl[2*g][0] = t0; bl[2*g][1] = t1; bl[2*g+1][0] = t2; bl[2*g+1][1] = t3;
            }
#pragma unroll
            for (int ms = 0; ms < 2; ms++)
#pragma unroll
                for (int ng = 0; ng < 8; ng++) {
                    MMA16816F(c[ms][ng], as[ms], bh[ng][0], bh[ng][1]);
                    MMA16816F(c[ms][ng], as[ms], bl[ng][0], bl[ng][1]);
                }
        }
        __syncthreads();
    }

#pragma unroll
    for (int ms = 0; ms < 2; ms++) {
        const int row = bm + wm * 32 + ms * 16 + (lane >> 2);
#pragma unroll
        for (int ng = 0; ng < 8; ng++) {
            const int col = bn + wn * 64 + ng * 8 + (lane & 3) * 2;
            *(float2*)(C + (size_t)row * N + col)       = make_float2(c[ms][ng][0], c[ms][ng][1]);
            *(float2*)(C + (size_t)(row + 8) * N + col) = make_float2(c[ms][ng][2], c[ms][ng][3]);
        }
    }
}

// ---------------------------------------------------------------------------
// Fused RoPE + fp16 conversion, reading from packed QKV [M, 3072].
// Q at cols [0,2048): -> single fp16 [b,h,s,d]
// K at cols [2048,2560): -> fp16 hi/lo [b,kvh,s,d]
// ---------------------------------------------------------------------------
#define TQ_ITEMS (BATCH*SEQ*NHEADS*32)
#define TK_ITEMS (BATCH*SEQ*NKV*32)

__global__ void rope_all(const float* __restrict__ QKV,
                         const float* __restrict__ cosv, const float* __restrict__ sinv,
                         __half* __restrict__ qs,
                         __half* __restrict__ kh, __half* __restrict__ kl)
{
    int i = blockIdx.x * blockDim.x + threadIdx.x;
    bool isQ;
    int nheads, coloff, j;
    if (i < TQ_ITEMS) { isQ = true;  nheads = NHEADS; coloff = 0;    j = i; }
    else if (i < TQ_ITEMS + TK_ITEMS) { isQ = false; nheads = NKV; coloff = 2048; j = i - TQ_ITEMS; }
    else return;

    int d = j & 31;
    int h = (j >> 5) % nheads;
    int s = (j / (32 * nheads)) % SEQ;
    int b = j / (32 * nheads * SEQ);

    const float* p = QKV + ((size_t)b * SEQ + s) * NQKV + coloff + h * HDIM;
    float c0 = cosv[s * HDIM + d];
    float c1 = cosv[s * HDIM + d + 32];
    float s0 = sinv[s * HDIM + d];
    float s1 = sinv[s * HDIM + d + 32];
    float x0 = p[d];
    float x1 = p[d + 32];
    float y0 = x0 * c0 - x1 * s0;
    float y1 = x1 * c1 + x0 * s1;

    size_t o = (((size_t)b * nheads + h) * SEQ + s) * HDIM;
    if (isQ) {
        qs[o + d]      = __float2half_rn(y0);
        qs[o + d + 32] = __float2half_rn(y1);
    } else {
        __half h0 = __float2half_rn(y0);
        __half h1 = __float2half_rn(y1);
        kh[o + d]      = h0;
        kh[o + d + 32] = h1;
        kl[o + d]      = __float2half_rn(y0 - __half2float(h0));
        kl[o + d + 32] = __float2half_rn(y1 - __half2float(h1));
    }
}

// ---------------------------------------------------------------------------
// V (cols [2560,3072) of QKV) -> V^T single fp16 [b,kvh,d,s]
// ---------------------------------------------------------------------------
__global__ __launch_bounds__(256) void split_v_t(const float* __restrict__ QKV,
                                                 __half* __restrict__ vts)
{
    __shared__ __half th[64][68];
    const int s0  = blockIdx.x * 64;
    const int kvh = blockIdx.y;
    const int b   = blockIdx.z;

    {
        const int r  = threadIdx.x >> 2;
        const int cb = (threadIdx.x & 3) * 16;
        const float4* g = (const float4*)(QKV + ((size_t)b * SEQ + s0 + r) * NQKV
                                          + 2560 + kvh * HDIM + cb);
#pragma unroll
        for (int i = 0; i < 4; i++) {
            float4 v = g[i];
            th[cb + i * 4 + 0][r] = __float2half_rn(v.x);
            th[cb + i * 4 + 1][r] = __float2half_rn(v.y);
            th[cb + i * 4 + 2][r] = __float2half_rn(v.z);
            th[cb + i * 4 + 3][r] = __float2half_rn(v.w);
        }
    }
    __syncthreads();
    {
        const int d  = threadIdx.x >> 2;
        const int sc = (threadIdx.x & 3) * 16;
        size_t obase = (((size_t)b * NKV + kvh) * HDIM + d) * SEQ + s0 + sc;
        uint2 a0 = *(uint2*)&th[d][sc];
        uint2 a1 = *(uint2*)&th[d][sc + 4];
        uint2 a2 = *(uint2*)&th[d][sc + 8];
        uint2 a3 = *(uint2*)&th[d][sc + 12];
        *(uint4*)(vts + obase)     = make_uint4(a0.x, a0.y, a1.x, a1.y);
        *(uint4*)(vts + obase + 8) = make_uint4(a2.x, a2.y, a3.x, a3.y);
    }
}

// ---------------------------------------------------------------------------
// Tensor-core causal flash attention: QK fp16 2-term, PV single fp16.
// ---------------------------------------------------------------------------
#define APITCH 72
#define A_ARR (64*APITCH)
#define A_STG_E (3*A_ARR)
#define A_STG_B (A_STG_E*2)           // 27648 B
#define A_SMEM (2*A_STG_B)            // 55296 B
#define SCALE_LOG2 0.18033688011112042f   // log2(e)/8

__global__ __launch_bounds__(256, 1)
void attn_mma(const __half* __restrict__ Qs,
              const __half* __restrict__ Kh, const __half* __restrict__ Kl,
              const __half* __restrict__ Vts, __half* __restrict__ Os)
{
    extern __shared__ __align__(16) char dsm_raw[];
    const uint32_t sbase = smem_u32(dsm_raw);

    const int tid  = threadIdx.x;
    const int wid  = tid >> 5;
    const int lane = tid & 31;
    const int t = (int)gridDim.x - 1 - (int)blockIdx.x;
    const int h = blockIdx.y;
    const int b = blockIdx.z;
    const int kvh = h >> 2;

    {
        const size_t qbase = (((size_t)b * NHEADS + h) * SEQ + (size_t)t * 128) * HDIM;
#pragma unroll
        for (int q = 0; q < 4; q++) {
            int i = tid + q * 256;
            int r = i >> 3;
            int cc = (i & 7) << 3;
            CP16(sbase + (r * APITCH + cc) * 2, Qs + qbase + (size_t)r * HDIM + cc);
        }
        CP_COMMIT();
        CP_WAIT0();
    }
    __syncthreads();

    uint32_t qs[4][4];
    {
        const int aoff = (wid * 16 + (lane & 15)) * APITCH + ((lane >> 4) << 3);
#pragma unroll
        for (int kk = 0; kk < 4; kk++) {
            LDSM4(qs[kk][0], qs[kk][1], qs[kk][2], qs[kk][3], sbase + 2 * (aoff + kk * 16));
        }
    }
    __syncthreads();

    const size_t kbase = ((size_t)b * NKV + kvh) * SEQ * HDIM;
    const size_t vbase = ((size_t)b * NKV + kvh) * HDIM * SEQ;

    auto load_kv = [&](int kb, int stage) {
        const uint32_t sb = sbase + stage * A_STG_B;
#pragma unroll
        for (int q = 0; q < 6; q++) {
            int i = tid + q * 256;
            int a = i >> 9;
            int j = i & 511;
            int r = j >> 3;
            int cc = (j & 7) << 3;
            uint32_t dst = sb + (a * A_ARR + r * APITCH + cc) * 2;
            if (a == 0)      CP16(dst, Kh  + kbase + (size_t)(kb * 64 + r) * HDIM + cc);
            else if (a == 1) CP16(dst, Kl  + kbase + (size_t)(kb * 64 + r) * HDIM + cc);
            else             CP16(dst, Vts + vbase + (size_t)r * SEQ + kb * 64 + cc);
        }
        CP_COMMIT();
    };

    float o[8][4];
#pragma unroll
    for (int nt = 0; nt < 8; nt++)
#pragma unroll
        for (int e = 0; e < 4; e++) o[nt][e] = 0.f;
    float mi0 = -1e30f, mi1 = -1e30f, li0 = 0.f, li1 = 0.f;

    const int row0 = t * 128 + wid * 16 + (lane >> 2);
    const int row1 = row0 + 8;

    const int nkb = 2 * t + 2;
    load_kv(0, 0);

#pragma unroll 1
    for (int kb = 0; kb < nkb; kb++) {
        if (kb + 1 < nkb) {
            load_kv(kb + 1, (kb + 1) & 1);
            CP_WAIT1();
        } else {
            CP_WAIT0();
        }
        __syncthreads();

        const uint32_t sb = sbase + (kb & 1) * A_STG_B;
        const uint32_t uKh = sb;
        const uint32_t uKl = sb + A_ARR * 2;
        const uint32_t uVs = sb + 2 * A_ARR * 2;

        float s[8][4];
#pragma unroll
        for (int nt = 0; nt < 8; nt++)
#pragma unroll
            for (int e = 0; e < 4; e++) s[nt][e] = 0.f;

#pragma unroll
        for (int kk = 0; kk < 4; kk++) {
            uint32_t bh[8][2], bl[8][2];
#pragma unroll
            for (int g = 0; g < 4; g++) {
                const int off = (g * 16 + ((lane >> 4) << 3) + (lane & 7)) * APITCH
                              + (((lane >> 3) & 1) << 3) + kk * 16;
                uint32_t t0, t1, t2, t3;
                LDSM4(t0, t1, t2, t3, uKh + 2 * off);
                bh[2*g][0] = t0; bh[2*g][1] = t1; bh[2*g+1][0] = t2; bh[2*g+1][1] = t3;
                LDSM4(t0, t1, t2, t3, uKl + 2 * off);
                bl[2*g][0] = t0; bl[2*g][1] = t1; bl[2*g+1][0] = t2; bl[2*g+1][1] = t3;
            }
#pragma unroll
            for (int nt = 0; nt < 8; nt++) {
                MMA16816F(s[nt], qs[kk], bh[nt][0], bh[nt][1]);
                MMA16816F(s[nt], qs[kk], bl[nt][0], bl[nt][1]);
            }
        }

        const bool diag = (kb >= 2 * t);
#pragma unroll
        for (int nt = 0; nt < 8; nt++) {
            const int col = kb * 64 + nt * 8 + (lane & 3) * 2;
            s[nt][0] *= SCALE_LOG2; s[nt][1] *= SCALE_LOG2;
            s[nt][2] *= SCALE_LOG2; s[nt][3] *= SCALE_LOG2;
            if (diag) {
                if (col > row0)     s[nt][0] = -1e30f;
                if (col + 1 > row0) s[nt][1] = -1e30f;
                if (col > row1)     s[nt][2] = -1e30f;
                if (col + 1 > row1) s[nt][3] = -1e30f;
            }
        }

        float bm0 = -1e30f, bm1 = -1e30f;
#pragma unroll
        for (int nt = 0; nt < 8; nt++) {
            bm0 = fmaxf(bm0, fmaxf(s[nt][0], s[nt][1]));
            bm1 = fmaxf(bm1, fmaxf(s[nt][2], s[nt][3]));
        }
        bm0 = fmaxf(bm0, __shfl_xor_sync(0xffffffffu, bm0, 1));
        bm0 = fmaxf(bm0, __shfl_xor_sync(0xffffffffu, bm0, 2));
        bm1 = fmaxf(bm1, __shfl_xor_sync(0xffffffffu, bm1, 1));
        bm1 = fmaxf(bm1, __shfl_xor_sync(0xffffffffu, bm1, 2));

        const float mn0 = fmaxf(mi0, bm0);
        const float mn1 = fmaxf(mi1, bm1);
        const float sc0 = exp2f(mi0 - mn0);
        const float sc1 = exp2f(mi1 - mn1);

        float ls0 = 0.f, ls1 = 0.f;
#pragma unroll
        for (int nt = 0; nt < 8; nt++) {
            s[nt][0] = exp2f(s[nt][0] - mn0);
            s[nt][1] = exp2f(s[nt][1] - mn0);
            s[nt][2] = exp2f(s[nt][2] - mn1);
            s[nt][3] = exp2f(s[nt][3] - mn1);
            ls0 += s[nt][0] + s[nt][1];
            ls1 += s[nt][2] + s[nt][3];
        }
        ls0 += __shfl_xor_sync(0xffffffffu, ls0, 1);
        ls0 += __shfl_xor_sync(0xffffffffu, ls0, 2);
        ls1 += __shfl_xor_sync(0xffffffffu, ls1, 1);
        ls1 += __shfl_xor_sync(0xffffffffu, ls1, 2);

        li0 = li0 * sc0 + ls0;
        li1 = li1 * sc1 + ls1;
        mi0 = mn0; mi1 = mn1;

#pragma unroll
        for (int nt = 0; nt < 8; nt++) {
            o[nt][0] *= sc0; o[nt][1] *= sc0;
            o[nt][2] *= sc1; o[nt][3] *= sc1;
        }

        uint32_t ps[8][2];
#pragma unroll
        for (int nt = 0; nt < 8; nt++) {
            ps[nt][0] = pack_f16x2(s[nt][0], s[nt][1]);
            ps[nt][1] = pack_f16x2(s[nt][2], s[nt][3]);
        }

#pragma unroll
        for (int kk = 0; kk < 4; kk++) {
            uint32_t vs[8][2];
#pragma unroll
            for (int g = 0; g < 4; g++) {
                const int off = (g * 16 + ((lane >> 4) << 3) + (lane & 7)) * APITCH
                              + (((lane >> 3) & 1) << 3) + kk * 16;
                uint32_t t0, t1, t2, t3;
                LDSM4(t0, t1, t2, t3, uVs + 2 * off);
                vs[2*g][0] = t0; vs[2*g][1] = t1; vs[2*g+1][0] = t2; vs[2*g+1][1] = t3;
            }
            uint32_t ap[4] = {ps[2*kk][0], ps[2*kk][1], ps[2*kk+1][0], ps[2*kk+1][1]};
#pragma unroll
            for (int nt = 0; nt < 8; nt++) {
                MMA16816F(o[nt], ap, vs[nt][0], vs[nt][1]);
            }
        }
        __syncthreads();
    }

    const float inv0 = 1.f / li0;
    const float inv1 = 1.f / li1;
    const size_t o0 = (((size_t)b * SEQ + row0) * NHEADS + h) * HDIM;
    const size_t o1 = (((size_t)b * SEQ + row1) * NHEADS + h) * HDIM;
#pragma unroll
    for (int nt = 0; nt < 8; nt++) {
        const int col = nt * 8 + (lane & 3) * 2;
        *(uint32_t*)(Os + o0 + col) = pack_f16x2(o[nt][0] * inv0, o[nt][1] * inv0);
        *(uint32_t*)(Os + o1 + col) = pack_f16x2(o[nt][2] * inv1, o[nt][3] * inv1);
    }
}

// ---------------------------------------------------------------------------
extern "C" void kernel_launch(void* const* d_in, const int* in_sizes, int n_in,
                              void* d_out, int out_size)
{
    const float* x    = (const float*)d_in[0];
    const float* fcos = (const float*)d_in[1];
    const float* fsin = (const float*)d_in[2];
    const float* wq   = (const float*)d_in[3];
    const float* wk   = (const float*)d_in[4];
    const float* wv   = (const float*)d_in[5];
    const float* wo   = (const float*)d_in[6];
    float* out = (float*)d_out;

    float* qkv;
    __half *hf, *qs, *kh, *kl, *vts;
    cudaGetSymbolAddress((void**)&qkv, g_QKV);
    cudaGetSymbolAddress((void**)&hf, g_hf);
    cudaGetSymbolAddress((void**)&qs, g_Qs);
    cudaGetSymbolAddress((void**)&kh, g_Kh);
    cudaGetSymbolAddress((void**)&kl, g_Kl);
    cudaGetSymbolAddress((void**)&vts, g_Vts);

    cudaFuncSetAttribute(gemm_qkv, cudaFuncAttributeMaxDynamicSharedMemorySize, G1SMEM);
    cudaFuncSetAttribute(gemm_wo, cudaFuncAttributeMaxDynamicSharedMemorySize, G2SMEM);
    cudaFuncSetAttribute(attn_mma, cudaFuncAttributeMaxDynamicSharedMemorySize, A_SMEM);

    const int M = BATCH * SEQ;

    // #0: prepass (x, Wqkv -> single fp16; Wo -> hi/lo)
    split_all<<<(Q_TOT + 255) / 256, 256>>>(x, wq, wk, wv, wo, hf);

    // #1: fused QKV projection (single-term fp16)
    gemm_qkv<<<dim3(NQKV / 128, M / 128), 256, G1SMEM>>>(
        hf + OFF_XS, hf + OFF_WQKV, qkv, M, NQKV, EMBED);

    // #2: V transpose (single fp16)
    split_v_t<<<dim3(SEQ / 64, NKV, BATCH), 256>>>(qkv, vts);

    // #3: RoPE + fp16 conversion for Q and K
    rope_all<<<(TQ_ITEMS + TK_ITEMS + 255) / 256, 256>>>(qkv, fcos, fsin, qs, kh, kl);

    // #4: tensor-core causal GQA flash attention
    attn_mma<<<dim3(SEQ / 128, NHEADS, BATCH), 256, A_SMEM>>>(qs, kh, kl, vts,
                                                              hf + OFF_OS);

    // #5: output projection (2-term weights)
    gemm_wo<<<dim3(EMBED / 128, M / 128), 256, G2SMEM>>>(
        hf + OFF_OS, hf + OFF_WOH, hf + OFF_WOL, out, M, EMBED, EMBED);
}

// round 14
// speedup vs baseline: 7.7587x; 1.3182x over previous
#include <cuda_runtime.h>
#include <cuda_fp16.h>
#include <cstdint>

#define BATCH 2
#define SEQ 2048
#define EMBED 2048
#define NHEADS 32
#define NKV 8
#define HDIM 64
#define NQKV 3072          // packed QKV output columns

// fp32 scratch: packed QKV gemm output [M, 3072] = [Q | K | V]
__device__ float g_QKV[(size_t)BATCH*SEQ*NQKV];

// fp16 pool: x, Wqkv packed, Wo, attention output — all single fp16
#define N_X    (size_t)8388608    // 2*2048*2048
#define N_WQKV (size_t)6291456    // 3072*2048
#define N_WO   (size_t)4194304
#define OFF_XS   (size_t)0
#define OFF_WQKV (OFF_XS + N_X)
#define OFF_WOS  (OFF_WQKV + N_WQKV)
#define OFF_OS   (OFF_WOS + N_WO)
#define POOL_SZ  (OFF_OS + N_X)
__device__ __half g_hf[POOL_SZ];

// attention operands: all single fp16
__device__ __half g_Qs[(size_t)BATCH*NHEADS*SEQ*HDIM];
__device__ __half g_Ks[(size_t)BATCH*NKV*SEQ*HDIM];
__device__ __half g_Vts[(size_t)BATCH*NKV*HDIM*SEQ];

// ============================ helpers ======================================
__device__ __forceinline__ uint32_t smem_u32(const void* p) {
    uint32_t a;
    asm("{ .reg .u64 t; cvta.to.shared.u64 t, %1; cvt.u32.u64 %0, t; }"
        : "=r"(a) : "l"(p));
    return a;
}

#define LDSM4(R0,R1,R2,R3,ADDR) \
    asm volatile("ldmatrix.sync.aligned.m8n8.x4.shared.b16 {%0,%1,%2,%3}, [%4];" \
                 : "=r"(R0), "=r"(R1), "=r"(R2), "=r"(R3) : "r"(ADDR))

#define MMA16816F(C, A, B0, B1) \
    asm volatile("mma.sync.aligned.m16n8k16.row.col.f32.f16.f16.f32 " \
                 "{%0,%1,%2,%3}, {%4,%5,%6,%7}, {%8,%9}, {%0,%1,%2,%3};" \
                 : "+f"((C)[0]), "+f"((C)[1]), "+f"((C)[2]), "+f"((C)[3]) \
                 : "r"((A)[0]), "r"((A)[1]), "r"((A)[2]), "r"((A)[3]), \
                   "r"(B0), "r"(B1))

#define CP16(DST, SRC) \
    asm volatile("cp.async.cg.shared.global [%0], [%1], 16;" :: "r"(DST), "l"(SRC))
#define CP_COMMIT() asm volatile("cp.async.commit_group;")
#define CP_WAIT0()  asm volatile("cp.async.wait_group 0;")
#define CP_WAIT1()  asm volatile("cp.async.wait_group 1;")

__device__ __forceinline__ uint32_t pack_f16x2(float lo, float hi) {
    uint32_t d;
    asm("cvt.rn.f16x2.f32 %0, %1, %2;" : "=r"(d) : "f"(hi), "f"(lo));
    return d;
}

// ---------------------------------------------------------------------------
// One-shot prepass: everything -> single fp16 (Wqkv packed [3072,2048]).
// ---------------------------------------------------------------------------
#define Q_X   (int)(N_X/4)
#define Q_WQ  1048576
#define Q_WK  262144
#define Q_WV  262144
#define Q_WO  1048576
#define Q_TOT (Q_X + Q_WQ + Q_WK + Q_WV + Q_WO)

__global__ void split_all(const float* __restrict__ x,  const float* __restrict__ wq,
                          const float* __restrict__ wk, const float* __restrict__ wv,
                          const float* __restrict__ wo, __half* __restrict__ hf)
{
    int i = blockIdx.x * blockDim.x + threadIdx.x;
    if (i >= Q_TOT) return;
    const float* src; size_t doff; int j;
    if (i < Q_X)                  { src = x;  j = i;                        doff = OFF_XS; }
    else if (i < Q_X + Q_WQ)      { src = wq; j = i - Q_X;                  doff = OFF_WQKV; }
    else if (i < Q_X + Q_WQ + Q_WK)
                                  { src = wk; j = i - Q_X - Q_WQ;           doff = OFF_WQKV + (size_t)2048 * EMBED; }
    else if (i < Q_X + Q_WQ + Q_WK + Q_WV)
                                  { src = wv; j = i - Q_X - Q_WQ - Q_WK;    doff = OFF_WQKV + (size_t)2560 * EMBED; }
    else                          { src = wo; j = i - Q_X - Q_WQ - Q_WK - Q_WV; doff = OFF_WOS; }
    float4 v = ((const float4*)src)[j];
    uint2 u;
    u.x = pack_f16x2(v.x, v.y);
    u.y = pack_f16x2(v.z, v.w);
    ((uint2*)(hf + doff))[j] = u;
}

// ---------------------------------------------------------------------------
// Single-term fp16 GEMM: C[M,N] = A * B^T.
// Block 128x128, BK=64, 256 threads, warp tile 32x64, 2-stage, 2 CTAs/SM.
// ---------------------------------------------------------------------------
#define GPITCH 72
#define G1A (128*GPITCH)              // 9216 elems per array
#define G1STG_B (2*G1A*2)             // 36864 B per stage
#define G1SMEM (2*G1STG_B)            // 73728 B

__global__ __launch_bounds__(256, 2)
void gemm_mma(const __half* __restrict__ As, const __half* __restrict__ Bs,
              float* __restrict__ C, int M, int N, int K)
{
    extern __shared__ __align__(16) char dsm_raw[];
    const uint32_t sbase = smem_u32(dsm_raw);

    const int tid  = threadIdx.x;
    const int wid  = tid >> 5;
    const int lane = tid & 31;
    const int wm   = wid >> 1;      // 0..3
    const int wn   = wid & 1;       // 0..1

    const int bm = blockIdx.y * 128;
    const int bn = blockIdx.x * 128;

    const int aoff = (wm * 32 + (lane & 15)) * GPITCH + ((lane >> 4) << 3);
    const int bofflane = (((lane >> 4) << 3) + (lane & 7)) * GPITCH + (((lane >> 3) & 1) << 3);

    const int nk = K >> 6;

    auto load_stage = [&](int kt, int stage) {
        const int k0 = kt << 6;
        const uint32_t sb = sbase + stage * G1STG_B;
#pragma unroll
        for (int q = 0; q < 8; q++) {         // 2048 chunks
            int c = tid + q * 256;
            int arr = c >> 10;                // 0:A 1:B
            int j = c & 1023;
            int r = j >> 3;
            int col = (j & 7) << 3;
            const __half* g = (arr ? Bs + (size_t)(bn + r) * K
                                   : As + (size_t)(bm + r) * K) + k0 + col;
            CP16(sb + (arr * G1A + r * GPITCH + col) * 2, g);
        }
        CP_COMMIT();
    };

    float c[2][8][4];
#pragma unroll
    for (int a = 0; a < 2; a++)
#pragma unroll
        for (int b = 0; b < 8; b++)
#pragma unroll
            for (int d = 0; d < 4; d++) c[a][b][d] = 0.f;

    load_stage(0, 0);

#pragma unroll 1
    for (int kt = 0; kt < nk; kt++) {
        if (kt + 1 < nk) {
            load_stage(kt + 1, (kt + 1) & 1);
            CP_WAIT1();
        } else {
            CP_WAIT0();
        }
        __syncthreads();

        const uint32_t sb = sbase + (kt & 1) * G1STG_B;
        const uint32_t uAs = sb;
        const uint32_t uBs = sb + G1A * 2;

#pragma unroll
        for (int kk = 0; kk < 64; kk += 16) {
            uint32_t as[2][4], bs[8][2];
#pragma unroll
            for (int ms = 0; ms < 2; ms++) {
                LDSM4(as[ms][0], as[ms][1], as[ms][2], as[ms][3],
                      uAs + 2 * (aoff + ms * 16 * GPITCH + kk));
            }
#pragma unroll
            for (int g = 0; g < 4; g++) {
                const int off = (wn * 64 + g * 16) * GPITCH + bofflane + kk;
                uint32_t t0, t1, t2, t3;
                LDSM4(t0, t1, t2, t3, uBs + 2 * off);
                bs[2*g][0] = t0; bs[2*g][1] = t1; bs[2*g+1][0] = t2; bs[2*g+1][1] = t3;
            }
#pragma unroll
            for (int ms = 0; ms < 2; ms++)
#pragma unroll
                for (int ng = 0; ng < 8; ng++)
                    MMA16816F(c[ms][ng], as[ms], bs[ng][0], bs[ng][1]);
        }
        __syncthreads();
    }

#pragma unroll
    for (int ms = 0; ms < 2; ms++) {
        const int row = bm + wm * 32 + ms * 16 + (lane >> 2);
#pragma unroll
        for (int ng = 0; ng < 8; ng++) {
            const int col = bn + wn * 64 + ng * 8 + (lane & 3) * 2;
            *(float2*)(C + (size_t)row * N + col)       = make_float2(c[ms][ng][0], c[ms][ng][1]);
            *(float2*)(C + (size_t)(row + 8) * N + col) = make_float2(c[ms][ng][2], c[ms][ng][3]);
        }
    }
}

// ---------------------------------------------------------------------------
// Fused RoPE + fp16 conversion, reading from packed QKV [M, 3072].
// Q at cols [0,2048) -> single fp16 [b,h,s,d]; K at [2048,2560) -> single fp16.
// ---------------------------------------------------------------------------
#define TQ_ITEMS (BATCH*SEQ*NHEADS*32)
#define TK_ITEMS (BATCH*SEQ*NKV*32)

__global__ void rope_all(const float* __restrict__ QKV,
                         const float* __restrict__ cosv, const float* __restrict__ sinv,
                         __half* __restrict__ qs, __half* __restrict__ ks)
{
    int i = blockIdx.x * blockDim.x + threadIdx.x;
    __half* dst;
    int nheads, coloff, j;
    if (i < TQ_ITEMS) { dst = qs; nheads = NHEADS; coloff = 0; j = i; }
    else if (i < TQ_ITEMS + TK_ITEMS) { dst = ks; nheads = NKV; coloff = 2048; j = i - TQ_ITEMS; }
    else return;

    int d = j & 31;
    int h = (j >> 5) % nheads;
    int s = (j / (32 * nheads)) % SEQ;
    int b = j / (32 * nheads * SEQ);

    const float* p = QKV + ((size_t)b * SEQ + s) * NQKV + coloff + h * HDIM;
    float c0 = cosv[s * HDIM + d];
    float c1 = cosv[s * HDIM + d + 32];
    float s0 = sinv[s * HDIM + d];
    float s1 = sinv[s * HDIM + d + 32];
    float x0 = p[d];
    float x1 = p[d + 32];

    size_t o = (((size_t)b * nheads + h) * SEQ + s) * HDIM;
    dst[o + d]      = __float2half_rn(x0 * c0 - x1 * s0);
    dst[o + d + 32] = __float2half_rn(x1 * c1 + x0 * s1);
}

// ---------------------------------------------------------------------------
// V (cols [2560,3072) of QKV) -> V^T single fp16 [b,kvh,d,s]
// ---------------------------------------------------------------------------
__global__ __launch_bounds__(256) void split_v_t(const float* __restrict__ QKV,
                                                 __half* __restrict__ vts)
{
    __shared__ __half th[64][68];
    const int s0  = blockIdx.x * 64;
    const int kvh = blockIdx.y;
    const int b   = blockIdx.z;

    {
        const int r  = threadIdx.x >> 2;
        const int cb = (threadIdx.x & 3) * 16;
        const float4* g = (const float4*)(QKV + ((size_t)b * SEQ + s0 + r) * NQKV
                                          + 2560 + kvh * HDIM + cb);
#pragma unroll
        for (int i = 0; i < 4; i++) {
            float4 v = g[i];
            th[cb + i * 4 + 0][r] = __float2half_rn(v.x);
            th[cb + i * 4 + 1][r] = __float2half_rn(v.y);
            th[cb + i * 4 + 2][r] = __float2half_rn(v.z);
            th[cb + i * 4 + 3][r] = __float2half_rn(v.w);
        }
    }
    __syncthreads();
    {
        const int d  = threadIdx.x >> 2;
        const int sc = (threadIdx.x & 3) * 16;
        size_t obase = (((size_t)b * NKV + kvh) * HDIM + d) * SEQ + s0 + sc;
        uint2 a0 = *(uint2*)&th[d][sc];
        uint2 a1 = *(uint2*)&th[d][sc + 4];
        uint2 a2 = *(uint2*)&th[d][sc + 8];
        uint2 a3 = *(uint2*)&th[d][sc + 12];
        *(uint4*)(vts + obase)     = make_uint4(a0.x, a0.y, a1.x, a1.y);
        *(uint4*)(vts + obase + 8) = make_uint4(a2.x, a2.y, a3.x, a3.y);
    }
}

// ---------------------------------------------------------------------------
// Tensor-core causal flash attention: all single fp16 operands.
// K + V^T staged via 2-stage cp.async; 2 CTAs/SM.
// ---------------------------------------------------------------------------
#define APITCH 72
#define A_ARR (64*APITCH)             // 4608 elems
#define A_STG_E (2*A_ARR)             // Ks, Vs
#define A_STG_B (A_STG_E*2)           // 18432 B
#define A_SMEM (2*A_STG_B)            // 36864 B (Q staging needs 18432 <= this)
#define SCALE_LOG2 0.18033688011112042f   // log2(e)/8

__global__ __launch_bounds__(256, 2)
void attn_mma(const __half* __restrict__ Qs, const __half* __restrict__ Ks,
              const __half* __restrict__ Vts, __half* __restrict__ Os)
{
    extern __shared__ __align__(16) char dsm_raw[];
    const uint32_t sbase = smem_u32(dsm_raw);

    const int tid  = threadIdx.x;
    const int wid  = tid >> 5;
    const int lane = tid & 31;
    const int t = (int)gridDim.x - 1 - (int)blockIdx.x;
    const int h = blockIdx.y;
    const int b = blockIdx.z;
    const int kvh = h >> 2;

    // ---- stage Q (single fp16) and extract fragments ----
    {
        const size_t qbase = (((size_t)b * NHEADS + h) * SEQ + (size_t)t * 128) * HDIM;
#pragma unroll
        for (int q = 0; q < 4; q++) {
            int i = tid + q * 256;            // 0..1023
            int r = i >> 3;
            int cc = (i & 7) << 3;
            CP16(sbase + (r * APITCH + cc) * 2, Qs + qbase + (size_t)r * HDIM + cc);
        }
        CP_COMMIT();
        CP_WAIT0();
    }
    __syncthreads();

    uint32_t qs[4][4];
    {
        const int aoff = (wid * 16 + (lane & 15)) * APITCH + ((lane >> 4) << 3);
#pragma unroll
        for (int kk = 0; kk < 4; kk++) {
            LDSM4(qs[kk][0], qs[kk][1], qs[kk][2], qs[kk][3], sbase + 2 * (aoff + kk * 16));
        }
    }
    __syncthreads();

    const size_t kbase = ((size_t)b * NKV + kvh) * SEQ * HDIM;
    const size_t vbase = ((size_t)b * NKV + kvh) * HDIM * SEQ;

    auto load_kv = [&](int kb, int stage) {
        const uint32_t sb = sbase + stage * A_STG_B;
#pragma unroll
        for (int q = 0; q < 4; q++) {
            int i = tid + q * 256;            // 0..1023
            int a = i >> 9;                   // 0:Ks 1:Vs
            int j = i & 511;
            int r = j >> 3;
            int cc = (j & 7) << 3;
            uint32_t dst = sb + (a * A_ARR + r * APITCH + cc) * 2;
            if (a == 0) CP16(dst, Ks  + kbase + (size_t)(kb * 64 + r) * HDIM + cc);
            else        CP16(dst, Vts + vbase + (size_t)r * SEQ + kb * 64 + cc);
        }
        CP_COMMIT();
    };

    float o[8][4];
#pragma unroll
    for (int nt = 0; nt < 8; nt++)
#pragma unroll
        for (int e = 0; e < 4; e++) o[nt][e] = 0.f;
    float mi0 = -1e30f, mi1 = -1e30f, li0 = 0.f, li1 = 0.f;

    const int row0 = t * 128 + wid * 16 + (lane >> 2);
    const int row1 = row0 + 8;

    const int nkb = 2 * t + 2;
    load_kv(0, 0);

#pragma unroll 1
    for (int kb = 0; kb < nkb; kb++) {
        if (kb + 1 < nkb) {
            load_kv(kb + 1, (kb + 1) & 1);
            CP_WAIT1();
        } else {
            CP_WAIT0();
        }
        __syncthreads();

        const uint32_t sb = sbase + (kb & 1) * A_STG_B;
        const uint32_t uKs = sb;
        const uint32_t uVs = sb + A_ARR * 2;

        // ---- S = Q K^T (single fp16) ----
        float s[8][4];
#pragma unroll
        for (int nt = 0; nt < 8; nt++)
#pragma unroll
            for (int e = 0; e < 4; e++) s[nt][e] = 0.f;

#pragma unroll
        for (int kk = 0; kk < 4; kk++) {
            uint32_t bs[8][2];
#pragma unroll
            for (int g = 0; g < 4; g++) {
                const int off = (g * 16 + ((lane >> 4) << 3) + (lane & 7)) * APITCH
                              + (((lane >> 3) & 1) << 3) + kk * 16;
                uint32_t t0, t1, t2, t3;
                LDSM4(t0, t1, t2, t3, uKs + 2 * off);
                bs[2*g][0] = t0; bs[2*g][1] = t1; bs[2*g+1][0] = t2; bs[2*g+1][1] = t3;
            }
#pragma unroll
            for (int nt = 0; nt < 8; nt++)
                MMA16816F(s[nt], qs[kk], bs[nt][0], bs[nt][1]);
        }

        const bool diag = (kb >= 2 * t);
#pragma unroll
        for (int nt = 0; nt < 8; nt++) {
            const int col = kb * 64 + nt * 8 + (lane & 3) * 2;
            s[nt][0] *= SCALE_LOG2; s[nt][1] *= SCALE_LOG2;
            s[nt][2] *= SCALE_LOG2; s[nt][3] *= SCALE_LOG2;
            if (diag) {
                if (col > row0)     s[nt][0] = -1e30f;
                if (col + 1 > row0) s[nt][1] = -1e30f;
                if (col > row1)     s[nt][2] = -1e30f;
                if (col + 1 > row1) s[nt][3] = -1e30f;
            }
        }

        float bm0 = -1e30f, bm1 = -1e30f;
#pragma unroll
        for (int nt = 0; nt < 8; nt++) {
            bm0 = fmaxf(bm0, fmaxf(s[nt][0], s[nt][1]));
            bm1 = fmaxf(bm1, fmaxf(s[nt][2], s[nt][3]));
        }
        bm0 = fmaxf(bm0, __shfl_xor_sync(0xffffffffu, bm0, 1));
        bm0 = fmaxf(bm0, __shfl_xor_sync(0xffffffffu, bm0, 2));
        bm1 = fmaxf(bm1, __shfl_xor_sync(0xffffffffu, bm1, 1));
        bm1 = fmaxf(bm1, __shfl_xor_sync(0xffffffffu, bm1, 2));

        const float mn0 = fmaxf(mi0, bm0);
        const float mn1 = fmaxf(mi1, bm1);
        const float sc0 = exp2f(mi0 - mn0);
        const float sc1 = exp2f(mi1 - mn1);

        float ls0 = 0.f, ls1 = 0.f;
#pragma unroll
        for (int nt = 0; nt < 8; nt++) {
            s[nt][0] = exp2f(s[nt][0] - mn0);
            s[nt][1] = exp2f(s[nt][1] - mn0);
            s[nt][2] = exp2f(s[nt][2] - mn1);
            s[nt][3] = exp2f(s[nt][3] - mn1);
            ls0 += s[nt][0] + s[nt][1];
            ls1 += s[nt][2] + s[nt][3];
        }
        ls0 += __shfl_xor_sync(0xffffffffu, ls0, 1);
        ls0 += __shfl_xor_sync(0xffffffffu, ls0, 2);
        ls1 += __shfl_xor_sync(0xffffffffu, ls1, 1);
        ls1 += __shfl_xor_sync(0xffffffffu, ls1, 2);

        li0 = li0 * sc0 + ls0;
        li1 = li1 * sc1 + ls1;
        mi0 = mn0; mi1 = mn1;

#pragma unroll
        for (int nt = 0; nt < 8; nt++) {
            o[nt][0] *= sc0; o[nt][1] *= sc0;
            o[nt][2] *= sc1; o[nt][3] *= sc1;
        }

        // ---- pack P to single fp16 fragments ----
        uint32_t ps[8][2];
#pragma unroll
        for (int nt = 0; nt < 8; nt++) {
            ps[nt][0] = pack_f16x2(s[nt][0], s[nt][1]);
            ps[nt][1] = pack_f16x2(s[nt][2], s[nt][3]);
        }

        // ---- O += P V ----
#pragma unroll
        for (int kk = 0; kk < 4; kk++) {
            uint32_t vs[8][2];
#pragma unroll
            for (int g = 0; g < 4; g++) {
                const int off = (g * 16 + ((lane >> 4) << 3) + (lane & 7)) * APITCH
                              + (((lane >> 3) & 1) << 3) + kk * 16;
                uint32_t t0, t1, t2, t3;
                LDSM4(t0, t1, t2, t3, uVs + 2 * off);
                vs[2*g][0] = t0; vs[2*g][1] = t1; vs[2*g+1][0] = t2; vs[2*g+1][1] = t3;
            }
            uint32_t ap[4] = {ps[2*kk][0], ps[2*kk][1], ps[2*kk+1][0], ps[2*kk+1][1]};
#pragma unroll
            for (int nt = 0; nt < 8; nt++)
                MMA16816F(o[nt], ap, vs[nt][0], vs[nt][1]);
        }
        __syncthreads();
    }

    // ---- finalize: write fp16 single output ([b,s,h,d] = [M,2048]) ----
    const float inv0 = 1.f / li0;
    const float inv1 = 1.f / li1;
    const size_t o0 = (((size_t)b * SEQ + row0) * NHEADS + h) * HDIM;
    const size_t o1 = (((size_t)b * SEQ + row1) * NHEADS + h) * HDIM;
#pragma unroll
    for (int nt = 0; nt < 8; nt++) {
        const int col = nt * 8 + (lane & 3) * 2;
        *(uint32_t*)(Os + o0 + col) = pack_f16x2(o[nt][0] * inv0, o[nt][1] * inv0);
        *(uint32_t*)(Os + o1 + col) = pack_f16x2(o[nt][2] * inv1, o[nt][3] * inv1);
    }
}

// ---------------------------------------------------------------------------
extern "C" void kernel_launch(void* const* d_in, const int* in_sizes, int n_in,
                              void* d_out, int out_size)
{
    const float* x    = (const float*)d_in[0];
    const float* fcos = (const float*)d_in[1];
    const float* fsin = (const float*)d_in[2];
    const float* wq   = (const float*)d_in[3];
    const float* wk   = (const float*)d_in[4];
    const float* wv   = (const float*)d_in[5];
    const float* wo   = (const float*)d_in[6];
    float* out = (float*)d_out;

    float* qkv;
    __half *hf, *qs, *ks, *vts;
    cudaGetSymbolAddress((void**)&qkv, g_QKV);
    cudaGetSymbolAddress((void**)&hf, g_hf);
    cudaGetSymbolAddress((void**)&qs, g_Qs);
    cudaGetSymbolAddress((void**)&ks, g_Ks);
    cudaGetSymbolAddress((void**)&vts, g_Vts);

    cudaFuncSetAttribute(gemm_mma, cudaFuncAttributeMaxDynamicSharedMemorySize, G1SMEM);
    cudaFuncSetAttribute(attn_mma, cudaFuncAttributeMaxDynamicSharedMemorySize, A_SMEM);

    const int M = BATCH * SEQ;

    // #0: prepass (everything -> single fp16)
    split_all<<<(Q_TOT + 255) / 256, 256>>>(x, wq, wk, wv, wo, hf);

    // #1: fused QKV projection
    gemm_mma<<<dim3(NQKV / 128, M / 128), 256, G1SMEM>>>(
        hf + OFF_XS, hf + OFF_WQKV, qkv, M, NQKV, EMBED);

    // #2: V transpose
    split_v_t<<<dim3(SEQ / 64, NKV, BATCH), 256>>>(qkv, vts);

    // #3: RoPE + fp16 conversion for Q and K
    rope_all<<<(TQ_ITEMS + TK_ITEMS + 255) / 256, 256>>>(qkv, fcos, fsin, qs, ks);

    // #4: tensor-core causal GQA flash attention
    attn_mma<<<dim3(SEQ / 128, NHEADS, BATCH), 256, A_SMEM>>>(qs, ks, vts, hf + OFF_OS);

    // #5: output projection
    gemm_mma<<<dim3(EMBED / 128, M / 128), 256, G1SMEM>>>(
        hf + OFF_OS, hf + OFF_WOS, out, M, EMBED, EMBED);
}

// round 15
// speedup vs baseline: 8.2669x; 1.0655x over previous
#include <cuda_runtime.h>
#include <cuda_fp16.h>
#include <cstdint>

#define BATCH 2
#define SEQ 2048
#define EMBED 2048
#define NHEADS 32
#define NKV 8
#define HDIM 64
#define NQKV 3072

// fp16 pool: x, Wqkv packed, Wo, attention output — all single fp16
#define N_X    (size_t)8388608    // 2*2048*2048
#define N_WQKV (size_t)6291456    // 3072*2048
#define N_WO   (size_t)4194304
#define OFF_XS   (size_t)0
#define OFF_WQKV (OFF_XS + N_X)
#define OFF_WOS  (OFF_WQKV + N_WQKV)
#define OFF_OS   (OFF_WOS + N_WO)
#define POOL_SZ  (OFF_OS + N_X)
__device__ __half g_hf[POOL_SZ];

// attention operands, single fp16: Q [b,h,s,d]; K,V [b,kvh,s,d]
__device__ __half g_Qs[(size_t)BATCH*NHEADS*SEQ*HDIM];
__device__ __half g_Ks[(size_t)BATCH*NKV*SEQ*HDIM];
__device__ __half g_Vs[(size_t)BATCH*NKV*SEQ*HDIM];

// ============================ helpers ======================================
__device__ __forceinline__ uint32_t smem_u32(const void* p) {
    uint32_t a;
    asm("{ .reg .u64 t; cvta.to.shared.u64 t, %1; cvt.u32.u64 %0, t; }"
        : "=r"(a) : "l"(p));
    return a;
}

#define LDSM4(R0,R1,R2,R3,ADDR) \
    asm volatile("ldmatrix.sync.aligned.m8n8.x4.shared.b16 {%0,%1,%2,%3}, [%4];" \
                 : "=r"(R0), "=r"(R1), "=r"(R2), "=r"(R3) : "r"(ADDR))

#define LDSM4T(R0,R1,R2,R3,ADDR) \
    asm volatile("ldmatrix.sync.aligned.m8n8.x4.trans.shared.b16 {%0,%1,%2,%3}, [%4];" \
                 : "=r"(R0), "=r"(R1), "=r"(R2), "=r"(R3) : "r"(ADDR))

#define MMA16816F(C, A, B0, B1) \
    asm volatile("mma.sync.aligned.m16n8k16.row.col.f32.f16.f16.f32 " \
                 "{%0,%1,%2,%3}, {%4,%5,%6,%7}, {%8,%9}, {%0,%1,%2,%3};" \
                 : "+f"((C)[0]), "+f"((C)[1]), "+f"((C)[2]), "+f"((C)[3]) \
                 : "r"((A)[0]), "r"((A)[1]), "r"((A)[2]), "r"((A)[3]), \
                   "r"(B0), "r"(B1))

#define CP16(DST, SRC) \
    asm volatile("cp.async.cg.shared.global [%0], [%1], 16;" :: "r"(DST), "l"(SRC))
#define CP_COMMIT() asm volatile("cp.async.commit_group;")
#define CP_WAIT0()  asm volatile("cp.async.wait_group 0;")
#define CP_WAIT1()  asm volatile("cp.async.wait_group 1;")

__device__ __forceinline__ uint32_t pack_f16x2(float lo, float hi) {
    uint32_t d;
    asm("cvt.rn.f16x2.f32 %0, %1, %2;" : "=r"(d) : "f"(hi), "f"(lo));
    return d;
}

// ---------------------------------------------------------------------------
// One-shot prepass: everything -> single fp16 (Wqkv packed [3072,2048]).
// ---------------------------------------------------------------------------
#define Q_X   (int)(N_X/4)
#define Q_WQ  1048576
#define Q_WK  262144
#define Q_WV  262144
#define Q_WO  1048576
#define Q_TOT (Q_X + Q_WQ + Q_WK + Q_WV + Q_WO)

__global__ void split_all(const float* __restrict__ x,  const float* __restrict__ wq,
                          const float* __restrict__ wk, const float* __restrict__ wv,
                          const float* __restrict__ wo, __half* __restrict__ hf)
{
    int i = blockIdx.x * blockDim.x + threadIdx.x;
    if (i >= Q_TOT) return;
    const float* src; size_t doff; int j;
    if (i < Q_X)                  { src = x;  j = i;                        doff = OFF_XS; }
    else if (i < Q_X + Q_WQ)      { src = wq; j = i - Q_X;                  doff = OFF_WQKV; }
    else if (i < Q_X + Q_WQ + Q_WK)
                                  { src = wk; j = i - Q_X - Q_WQ;           doff = OFF_WQKV + (size_t)2048 * EMBED; }
    else if (i < Q_X + Q_WQ + Q_WK + Q_WV)
                                  { src = wv; j = i - Q_X - Q_WQ - Q_WK;    doff = OFF_WQKV + (size_t)2560 * EMBED; }
    else                          { src = wo; j = i - Q_X - Q_WQ - Q_WK - Q_WV; doff = OFF_WOS; }
    float4 v = ((const float4*)src)[j];
    uint2 u;
    u.x = pack_f16x2(v.x, v.y);
    u.y = pack_f16x2(v.z, v.w);
    ((uint2*)(hf + doff))[j] = u;
}

// ---------------------------------------------------------------------------
// Single-term fp16 GEMM: block 128x128, BK=64, 256 thr, warp 32x64, 2-stage,
// 2 CTAs/SM. Two epilogues:
//   qkv_mode=1: apply RoPE (Q/K cols), convert fp16, scatter to qs/ks/vs.
//   qkv_mode=0: plain fp32 C store (O projection).
// ---------------------------------------------------------------------------
#define GPITCH 72
#define G1A (128*GPITCH)
#define G1STG_B (2*G1A*2)             // 36864 B per stage
#define G1SMEM (2*G1STG_B)            // 73728 B

__global__ __launch_bounds__(256, 2)
void gemm_mma(const __half* __restrict__ As, const __half* __restrict__ Bs,
              float* __restrict__ C, int M, int N, int K,
              int qkv_mode,
              const float* __restrict__ cosv, const float* __restrict__ sinv,
              __half* __restrict__ qs, __half* __restrict__ ks, __half* __restrict__ vs)
{
    extern __shared__ __align__(16) char dsm_raw[];
    const uint32_t sbase = smem_u32(dsm_raw);

    const int tid  = threadIdx.x;
    const int wid  = tid >> 5;
    const int lane = tid & 31;
    const int wm   = wid >> 1;      // 0..3
    const int wn   = wid & 1;       // 0..1

    const int bm = blockIdx.y * 128;
    const int bn = blockIdx.x * 128;

    const int aoff = (wm * 32 + (lane & 15)) * GPITCH + ((lane >> 4) << 3);
    const int bofflane = (((lane >> 4) << 3) + (lane & 7)) * GPITCH + (((lane >> 3) & 1) << 3);

    const int nk = K >> 6;

    auto load_stage = [&](int kt, int stage) {
        const int k0 = kt << 6;
        const uint32_t sb = sbase + stage * G1STG_B;
#pragma unroll
        for (int q = 0; q < 8; q++) {
            int c = tid + q * 256;
            int arr = c >> 10;
            int j = c & 1023;
            int r = j >> 3;
            int col = (j & 7) << 3;
            const __half* g = (arr ? Bs + (size_t)(bn + r) * K
                                   : As + (size_t)(bm + r) * K) + k0 + col;
            CP16(sb + (arr * G1A + r * GPITCH + col) * 2, g);
        }
        CP_COMMIT();
    };

    float c[2][8][4];
#pragma unroll
    for (int a = 0; a < 2; a++)
#pragma unroll
        for (int b = 0; b < 8; b++)
#pragma unroll
            for (int d = 0; d < 4; d++) c[a][b][d] = 0.f;

    load_stage(0, 0);

#pragma unroll 1
    for (int kt = 0; kt < nk; kt++) {
        if (kt + 1 < nk) {
            load_stage(kt + 1, (kt + 1) & 1);
            CP_WAIT1();
        } else {
            CP_WAIT0();
        }
        __syncthreads();

        const uint32_t sb = sbase + (kt & 1) * G1STG_B;
        const uint32_t uAs = sb;
        const uint32_t uBs = sb + G1A * 2;

#pragma unroll
        for (int kk = 0; kk < 64; kk += 16) {
            uint32_t as[2][4], bs[8][2];
#pragma unroll
            for (int ms = 0; ms < 2; ms++) {
                LDSM4(as[ms][0], as[ms][1], as[ms][2], as[ms][3],
                      uAs + 2 * (aoff + ms * 16 * GPITCH + kk));
            }
#pragma unroll
            for (int g = 0; g < 4; g++) {
                const int off = (wn * 64 + g * 16) * GPITCH + bofflane + kk;
                uint32_t t0, t1, t2, t3;
                LDSM4(t0, t1, t2, t3, uBs + 2 * off);
                bs[2*g][0] = t0; bs[2*g][1] = t1; bs[2*g+1][0] = t2; bs[2*g+1][1] = t3;
            }
#pragma unroll
            for (int ms = 0; ms < 2; ms++)
#pragma unroll
                for (int ng = 0; ng < 8; ng++)
                    MMA16816F(c[ms][ng], as[ms], bs[ng][0], bs[ng][1]);
        }
        __syncthreads();
    }

    if (!qkv_mode) {
        // fp32 epilogue (O projection)
#pragma unroll
        for (int ms = 0; ms < 2; ms++) {
            const int row = bm + wm * 32 + ms * 16 + (lane >> 2);
#pragma unroll
            for (int ng = 0; ng < 8; ng++) {
                const int col = bn + wn * 64 + ng * 8 + (lane & 3) * 2;
                *(float2*)(C + (size_t)row * N + col)       = make_float2(c[ms][ng][0], c[ms][ng][1]);
                *(float2*)(C + (size_t)(row + 8) * N + col) = make_float2(c[ms][ng][2], c[ms][ng][3]);
            }
        }
        return;
    }

    // ---- QKV epilogue: rope (Q/K) + fp16 scatter. Warp's 64-col span = 1 head.
    const int ccb = bn + wn * 64;        // region-uniform per warp
    __half* dst;
    int head, nheads;
    bool do_rope;
    if (ccb < 2048)      { dst = qs; head = ccb >> 6;          nheads = NHEADS; do_rope = true; }
    else if (ccb < 2560) { dst = ks; head = (ccb - 2048) >> 6; nheads = NKV;    do_rope = true; }
    else                 { dst = vs; head = (ccb - 2560) >> 6; nheads = NKV;    do_rope = false; }

#pragma unroll
    for (int ms = 0; ms < 2; ms++) {
        const int row = bm + wm * 32 + ms * 16 + (lane >> 2);
        const int bb = row >> 11;          // / SEQ
        const int ss = row & 2047;         // % SEQ  (row+8 stays in same batch)
        const size_t base0 = (((size_t)bb * nheads + head) * SEQ + ss) * HDIM;
        const size_t base1 = base0 + 8 * HDIM;
        if (do_rope) {
#pragma unroll
            for (int ng = 0; ng < 4; ng++) {
                const int d = ng * 8 + (lane & 3) * 2;
                // row
                {
                    float2 cl = *(const float2*)&cosv[ss * HDIM + d];
                    float2 sl = *(const float2*)&sinv[ss * HDIM + d];
                    float2 ch = *(const float2*)&cosv[ss * HDIM + d + 32];
                    float2 sh = *(const float2*)&sinv[ss * HDIM + d + 32];
                    float x0a = c[ms][ng][0],   x0b = c[ms][ng][1];
                    float x1a = c[ms][ng+4][0], x1b = c[ms][ng+4][1];
                    *(uint32_t*)(dst + base0 + d)      = pack_f16x2(x0a*cl.x - x1a*sl.x, x0b*cl.y - x1b*sl.y);
                    *(uint32_t*)(dst + base0 + d + 32) = pack_f16x2(x1a*ch.x + x0a*sh.x, x1b*ch.y + x0b*sh.y);
                }
                // row + 8
                {
                    const int s2 = ss + 8;
                    float2 cl = *(const float2*)&cosv[s2 * HDIM + d];
                    float2 sl = *(const float2*)&sinv[s2 * HDIM + d];
                    float2 ch = *(const float2*)&cosv[s2 * HDIM + d + 32];
                    float2 sh = *(const float2*)&sinv[s2 * HDIM + d + 32];
                    float x0a = c[ms][ng][2],   x0b = c[ms][ng][3];
                    float x1a = c[ms][ng+4][2], x1b = c[ms][ng+4][3];
                    *(uint32_t*)(dst + base1 + d)      = pack_f16x2(x0a*cl.x - x1a*sl.x, x0b*cl.y - x1b*sl.y);
                    *(uint32_t*)(dst + base1 + d + 32) = pack_f16x2(x1a*ch.x + x0a*sh.x, x1b*ch.y + x0b*sh.y);
                }
            }
        } else {
#pragma unroll
            for (int ng = 0; ng < 8; ng++) {
                const int d = ng * 8 + (lane & 3) * 2;
                *(uint32_t*)(dst + base0 + d) = pack_f16x2(c[ms][ng][0], c[ms][ng][1]);
                *(uint32_t*)(dst + base1 + d) = pack_f16x2(c[ms][ng][2], c[ms][ng][3]);
            }
        }
    }
}

// ---------------------------------------------------------------------------
// Tensor-core causal flash attention: all single fp16.
// K and V both [b,kvh,s,d]; PV uses ldmatrix.trans on the V tile.
// ---------------------------------------------------------------------------
#define APITCH 72
#define A_ARR (64*APITCH)
#define A_STG_E (2*A_ARR)             // Ks, Vs
#define A_STG_B (A_STG_E*2)           // 18432 B
#define A_SMEM (2*A_STG_B)            // 36864 B
#define SCALE_LOG2 0.18033688011112042f   // log2(e)/8

__global__ __launch_bounds__(256, 2)
void attn_mma(const __half* __restrict__ Qs, const __half* __restrict__ Ks,
              const __half* __restrict__ Vs, __half* __restrict__ Os)
{
    extern __shared__ __align__(16) char dsm_raw[];
    const uint32_t sbase = smem_u32(dsm_raw);

    const int tid  = threadIdx.x;
    const int wid  = tid >> 5;
    const int lane = tid & 31;
    const int t = (int)gridDim.x - 1 - (int)blockIdx.x;
    const int h = blockIdx.y;
    const int b = blockIdx.z;
    const int kvh = h >> 2;

    // ---- stage Q and extract fragments ----
    {
        const size_t qbase = (((size_t)b * NHEADS + h) * SEQ + (size_t)t * 128) * HDIM;
#pragma unroll
        for (int q = 0; q < 4; q++) {
            int i = tid + q * 256;
            int r = i >> 3;
            int cc = (i & 7) << 3;
            CP16(sbase + (r * APITCH + cc) * 2, Qs + qbase + (size_t)r * HDIM + cc);
        }
        CP_COMMIT();
        CP_WAIT0();
    }
    __syncthreads();

    uint32_t qs[4][4];
    {
        const int aoff = (wid * 16 + (lane & 15)) * APITCH + ((lane >> 4) << 3);
#pragma unroll
        for (int kk = 0; kk < 4; kk++) {
            LDSM4(qs[kk][0], qs[kk][1], qs[kk][2], qs[kk][3], sbase + 2 * (aoff + kk * 16));
        }
    }
    __syncthreads();

    const size_t kvbase = ((size_t)b * NKV + kvh) * SEQ * HDIM;

    auto load_kv = [&](int kb, int stage) {
        const uint32_t sb = sbase + stage * A_STG_B;
#pragma unroll
        for (int q = 0; q < 4; q++) {
            int i = tid + q * 256;
            int a = i >> 9;                   // 0:K 1:V
            int j = i & 511;
            int r = j >> 3;
            int cc = (j & 7) << 3;
            uint32_t dst = sb + (a * A_ARR + r * APITCH + cc) * 2;
            const __half* src = (a ? Vs : Ks) + kvbase + (size_t)(kb * 64 + r) * HDIM + cc;
            CP16(dst, src);
        }
        CP_COMMIT();
    };

    float o[8][4];
#pragma unroll
    for (int nt = 0; nt < 8; nt++)
#pragma unroll
        for (int e = 0; e < 4; e++) o[nt][e] = 0.f;
    float mi0 = -1e30f, mi1 = -1e30f, li0 = 0.f, li1 = 0.f;

    const int row0 = t * 128 + wid * 16 + (lane >> 2);
    const int row1 = row0 + 8;

    const int nkb = 2 * t + 2;
    load_kv(0, 0);

#pragma unroll 1
    for (int kb = 0; kb < nkb; kb++) {
        if (kb + 1 < nkb) {
            load_kv(kb + 1, (kb + 1) & 1);
            CP_WAIT1();
        } else {
            CP_WAIT0();
        }
        __syncthreads();

        const uint32_t sb = sbase + (kb & 1) * A_STG_B;
        const uint32_t uKs = sb;
        const uint32_t uVs = sb + A_ARR * 2;

        // ---- S = Q K^T ----
        float s[8][4];
#pragma unroll
        for (int nt = 0; nt < 8; nt++)
#pragma unroll
            for (int e = 0; e < 4; e++) s[nt][e] = 0.f;

#pragma unroll
        for (int kk = 0; kk < 4; kk++) {
            uint32_t bs[8][2];
#pragma unroll
            for (int g = 0; g < 4; g++) {
                const int off = (g * 16 + ((lane >> 4) << 3) + (lane & 7)) * APITCH
                              + (((lane >> 3) & 1) << 3) + kk * 16;
                uint32_t t0, t1, t2, t3;
                LDSM4(t0, t1, t2, t3, uKs + 2 * off);
                bs[2*g][0] = t0; bs[2*g][1] = t1; bs[2*g+1][0] = t2; bs[2*g+1][1] = t3;
            }
#pragma unroll
            for (int nt = 0; nt < 8; nt++)
                MMA16816F(s[nt], qs[kk], bs[nt][0], bs[nt][1]);
        }

        const bool diag = (kb >= 2 * t);
#pragma unroll
        for (int nt = 0; nt < 8; nt++) {
            const int col = kb * 64 + nt * 8 + (lane & 3) * 2;
            s[nt][0] *= SCALE_LOG2; s[nt][1] *= SCALE_LOG2;
            s[nt][2] *= SCALE_LOG2; s[nt][3] *= SCALE_LOG2;
            if (diag) {
                if (col > row0)     s[nt][0] = -1e30f;
                if (col + 1 > row0) s[nt][1] = -1e30f;
                if (col > row1)     s[nt][2] = -1e30f;
                if (col + 1 > row1) s[nt][3] = -1e30f;
            }
        }

        float bm0 = -1e30f, bm1 = -1e30f;
#pragma unroll
        for (int nt = 0; nt < 8; nt++) {
            bm0 = fmaxf(bm0, fmaxf(s[nt][0], s[nt][1]));
            bm1 = fmaxf(bm1, fmaxf(s[nt][2], s[nt][3]));
        }
        bm0 = fmaxf(bm0, __shfl_xor_sync(0xffffffffu, bm0, 1));
        bm0 = fmaxf(bm0, __shfl_xor_sync(0xffffffffu, bm0, 2));
        bm1 = fmaxf(bm1, __shfl_xor_sync(0xffffffffu, bm1, 1));
        bm1 = fmaxf(bm1, __shfl_xor_sync(0xffffffffu, bm1, 2));

        const float mn0 = fmaxf(mi0, bm0);
        const float mn1 = fmaxf(mi1, bm1);
        const float sc0 = exp2f(mi0 - mn0);
        const float sc1 = exp2f(mi1 - mn1);

        float ls0 = 0.f, ls1 = 0.f;
#pragma unroll
        for (int nt = 0; nt < 8; nt++) {
            s[nt][0] = exp2f(s[nt][0] - mn0);
            s[nt][1] = exp2f(s[nt][1] - mn0);
            s[nt][2] = exp2f(s[nt][2] - mn1);
            s[nt][3] = exp2f(s[nt][3] - mn1);
            ls0 += s[nt][0] + s[nt][1];
            ls1 += s[nt][2] + s[nt][3];
        }
        ls0 += __shfl_xor_sync(0xffffffffu, ls0, 1);
        ls0 += __shfl_xor_sync(0xffffffffu, ls0, 2);
        ls1 += __shfl_xor_sync(0xffffffffu, ls1, 1);
        ls1 += __shfl_xor_sync(0xffffffffu, ls1, 2);

        li0 = li0 * sc0 + ls0;
        li1 = li1 * sc1 + ls1;
        mi0 = mn0; mi1 = mn1;

#pragma unroll
        for (int nt = 0; nt < 8; nt++) {
            o[nt][0] *= sc0; o[nt][1] *= sc0;
            o[nt][2] *= sc1; o[nt][3] *= sc1;
        }

        // ---- pack P to fp16 fragments ----
        uint32_t ps[8][2];
#pragma unroll
        for (int nt = 0; nt < 8; nt++) {
            ps[nt][0] = pack_f16x2(s[nt][0], s[nt][1]);
            ps[nt][1] = pack_f16x2(s[nt][2], s[nt][3]);
        }

        // ---- O += P V: V tile [key,d], trans-ldmatrix gives V^T fragments ----
#pragma unroll
        for (int kk = 0; kk < 4; kk++) {
            uint32_t vs[8][2];
#pragma unroll
            for (int g = 0; g < 4; g++) {
                const int off = (kk * 16 + (lane & 15)) * APITCH
                              + g * 16 + ((lane >> 4) << 3);
                uint32_t t0, t1, t2, t3;
                LDSM4T(t0, t1, t2, t3, uVs + 2 * off);
                vs[2*g][0] = t0; vs[2*g][1] = t1; vs[2*g+1][0] = t2; vs[2*g+1][1] = t3;
            }
            uint32_t ap[4] = {ps[2*kk][0], ps[2*kk][1], ps[2*kk+1][0], ps[2*kk+1][1]};
#pragma unroll
            for (int nt = 0; nt < 8; nt++)
                MMA16816F(o[nt], ap, vs[nt][0], vs[nt][1]);
        }
        __syncthreads();
    }

    // ---- finalize ----
    const float inv0 = 1.f / li0;
    const float inv1 = 1.f / li1;
    const size_t o0 = (((size_t)b * SEQ + row0) * NHEADS + h) * HDIM;
    const size_t o1 = (((size_t)b * SEQ + row1) * NHEADS + h) * HDIM;
#pragma unroll
    for (int nt = 0; nt < 8; nt++) {
        const int col = nt * 8 + (lane & 3) * 2;
        *(uint32_t*)(Os + o0 + col) = pack_f16x2(o[nt][0] * inv0, o[nt][1] * inv0);
        *(uint32_t*)(Os + o1 + col) = pack_f16x2(o[nt][2] * inv1, o[nt][3] * inv1);
    }
}

// ---------------------------------------------------------------------------
extern "C" void kernel_launch(void* const* d_in, const int* in_sizes, int n_in,
                              void* d_out, int out_size)
{
    const float* x    = (const float*)d_in[0];
    const float* fcos = (const float*)d_in[1];
    const float* fsin = (const float*)d_in[2];
    const float* wq   = (const float*)d_in[3];
    const float* wk   = (const float*)d_in[4];
    const float* wv   = (const float*)d_in[5];
    const float* wo   = (const float*)d_in[6];
    float* out = (float*)d_out;

    __half *hf, *qs, *ks, *vs;
    cudaGetSymbolAddress((void**)&hf, g_hf);
    cudaGetSymbolAddress((void**)&qs, g_Qs);
    cudaGetSymbolAddress((void**)&ks, g_Ks);
    cudaGetSymbolAddress((void**)&vs, g_Vs);

    cudaFuncSetAttribute(gemm_mma, cudaFuncAttributeMaxDynamicSharedMemorySize, G1SMEM);
    cudaFuncSetAttribute(attn_mma, cudaFuncAttributeMaxDynamicSharedMemorySize, A_SMEM);

    const int M = BATCH * SEQ;

    // #0: prepass (everything -> single fp16)
    split_all<<<(Q_TOT + 255) / 256, 256>>>(x, wq, wk, wv, wo, hf);

    // #1: fused QKV projection + RoPE + fp16 scatter
    gemm_mma<<<dim3(NQKV / 128, M / 128), 256, G1SMEM>>>(
        hf + OFF_XS, hf + OFF_WQKV, nullptr, M, NQKV, EMBED,
        1, fcos, fsin, qs, ks, vs);

    // #2: tensor-core causal GQA flash attention
    attn_mma<<<dim3(SEQ / 128, NHEADS, BATCH), 256, A_SMEM>>>(qs, ks, vs, hf + OFF_OS);

    // #3: output projection (fp32 out)
    gemm_mma<<<dim3(EMBED / 128, M / 128), 256, G1SMEM>>>(
        hf + OFF_OS, hf + OFF_WOS, out, M, EMBED, EMBED,
        0, nullptr, nullptr, nullptr, nullptr, nullptr);
}

// round 16
// speedup vs baseline: 8.3995x; 1.0160x over previous
#include <cuda_runtime.h>
#include <cuda_fp16.h>
#include <cstdint>

#define BATCH 2
#define SEQ 2048
#define EMBED 2048
#define NHEADS 32
#define NKV 8
#define HDIM 64
#define NQKV 3072

// fp16 pool: x, Wqkv packed, Wo, attention output — all single fp16
#define N_X    (size_t)8388608    // 2*2048*2048
#define N_WQKV (size_t)6291456    // 3072*2048
#define N_WO   (size_t)4194304
#define OFF_XS   (size_t)0
#define OFF_WQKV (OFF_XS + N_X)
#define OFF_WOS  (OFF_WQKV + N_WQKV)
#define OFF_OS   (OFF_WOS + N_WO)
#define POOL_SZ  (OFF_OS + N_X)
__device__ __half g_hf[POOL_SZ];

// attention operands, single fp16: Q [b,h,s,d]; K,V [b,kvh,s,d]
__device__ __half g_Qs[(size_t)BATCH*NHEADS*SEQ*HDIM];
__device__ __half g_Ks[(size_t)BATCH*NKV*SEQ*HDIM];
__device__ __half g_Vs[(size_t)BATCH*NKV*SEQ*HDIM];

// ============================ helpers ======================================
__device__ __forceinline__ uint32_t smem_u32(const void* p) {
    uint32_t a;
    asm("{ .reg .u64 t; cvta.to.shared.u64 t, %1; cvt.u32.u64 %0, t; }"
        : "=r"(a) : "l"(p));
    return a;
}

#define LDSM4(R0,R1,R2,R3,ADDR) \
    asm volatile("ldmatrix.sync.aligned.m8n8.x4.shared.b16 {%0,%1,%2,%3}, [%4];" \
                 : "=r"(R0), "=r"(R1), "=r"(R2), "=r"(R3) : "r"(ADDR))

#define LDSM4T(R0,R1,R2,R3,ADDR) \
    asm volatile("ldmatrix.sync.aligned.m8n8.x4.trans.shared.b16 {%0,%1,%2,%3}, [%4];" \
                 : "=r"(R0), "=r"(R1), "=r"(R2), "=r"(R3) : "r"(ADDR))

#define MMA16816F(C, A, B0, B1) \
    asm volatile("mma.sync.aligned.m16n8k16.row.col.f32.f16.f16.f32 " \
                 "{%0,%1,%2,%3}, {%4,%5,%6,%7}, {%8,%9}, {%0,%1,%2,%3};" \
                 : "+f"((C)[0]), "+f"((C)[1]), "+f"((C)[2]), "+f"((C)[3]) \
                 : "r"((A)[0]), "r"((A)[1]), "r"((A)[2]), "r"((A)[3]), \
                   "r"(B0), "r"(B1))

#define CP16(DST, SRC) \
    asm volatile("cp.async.cg.shared.global [%0], [%1], 16;" :: "r"(DST), "l"(SRC))
#define CP_COMMIT() asm volatile("cp.async.commit_group;")
#define CP_WAIT0()  asm volatile("cp.async.wait_group 0;")

__device__ __forceinline__ uint32_t pack_f16x2(float lo, float hi) {
    uint32_t d;
    asm("cvt.rn.f16x2.f32 %0, %1, %2;" : "=r"(d) : "f"(hi), "f"(lo));
    return d;
}

// ---------------------------------------------------------------------------
// One-shot prepass: everything -> single fp16 (Wqkv packed [3072,2048]).
// ---------------------------------------------------------------------------
#define Q_X   (int)(N_X/4)
#define Q_WQ  1048576
#define Q_WK  262144
#define Q_WV  262144
#define Q_WO  1048576
#define Q_TOT (Q_X + Q_WQ + Q_WK + Q_WV + Q_WO)

__global__ void split_all(const float* __restrict__ x,  const float* __restrict__ wq,
                          const float* __restrict__ wk, const float* __restrict__ wv,
                          const float* __restrict__ wo, __half* __restrict__ hf)
{
    int i = blockIdx.x * blockDim.x + threadIdx.x;
    if (i >= Q_TOT) return;
    const float* src; size_t doff; int j;
    if (i < Q_X)                  { src = x;  j = i;                        doff = OFF_XS; }
    else if (i < Q_X + Q_WQ)      { src = wq; j = i - Q_X;                  doff = OFF_WQKV; }
    else if (i < Q_X + Q_WQ + Q_WK)
                                  { src = wk; j = i - Q_X - Q_WQ;           doff = OFF_WQKV + (size_t)2048 * EMBED; }
    else if (i < Q_X + Q_WQ + Q_WK + Q_WV)
                                  { src = wv; j = i - Q_X - Q_WQ - Q_WK;    doff = OFF_WQKV + (size_t)2560 * EMBED; }
    else                          { src = wo; j = i - Q_X - Q_WQ - Q_WK - Q_WV; doff = OFF_WOS; }
    float4 v = ((const float4*)src)[j];
    uint2 u;
    u.x = pack_f16x2(v.x, v.y);
    u.y = pack_f16x2(v.z, v.w);
    ((uint2*)(hf + doff))[j] = u;
}

// ---------------------------------------------------------------------------
// Single-term fp16 GEMM: block 128x128, BK=64, 256 thr, warp 32x64, 2-stage,
// single-sync mainloop, 2 CTAs/SM.
//   qkv_mode=1: apply RoPE (Q/K cols), convert fp16, scatter to qs/ks/vs.
//   qkv_mode=0: plain fp32 C store (O projection).
// ---------------------------------------------------------------------------
#define GPITCH 72
#define G1A (128*GPITCH)
#define G1STG_B (2*G1A*2)             // 36864 B per stage
#define G1SMEM (2*G1STG_B)            // 73728 B

__global__ __launch_bounds__(256, 2)
void gemm_mma(const __half* __restrict__ As, const __half* __restrict__ Bs,
              float* __restrict__ C, int M, int N, int K,
              int qkv_mode,
              const float* __restrict__ cosv, const float* __restrict__ sinv,
              __half* __restrict__ qs, __half* __restrict__ ks, __half* __restrict__ vs)
{
    extern __shared__ __align__(16) char dsm_raw[];
    const uint32_t sbase = smem_u32(dsm_raw);

    const int tid  = threadIdx.x;
    const int wid  = tid >> 5;
    const int lane = tid & 31;
    const int wm   = wid >> 1;      // 0..3
    const int wn   = wid & 1;       // 0..1

    const int bm = blockIdx.y * 128;
    const int bn = blockIdx.x * 128;

    const int aoff = (wm * 32 + (lane & 15)) * GPITCH + ((lane >> 4) << 3);
    const int bofflane = (((lane >> 4) << 3) + (lane & 7)) * GPITCH + (((lane >> 3) & 1) << 3);

    const int nk = K >> 6;

    auto load_stage = [&](int kt, int stage) {
        const int k0 = kt << 6;
        const uint32_t sb = sbase + stage * G1STG_B;
#pragma unroll
        for (int q = 0; q < 8; q++) {
            int c = tid + q * 256;
            int arr = c >> 10;
            int j = c & 1023;
            int r = j >> 3;
            int col = (j & 7) << 3;
            const __half* g = (arr ? Bs + (size_t)(bn + r) * K
                                   : As + (size_t)(bm + r) * K) + k0 + col;
            CP16(sb + (arr * G1A + r * GPITCH + col) * 2, g);
        }
        CP_COMMIT();
    };

    float c[2][8][4];
#pragma unroll
    for (int a = 0; a < 2; a++)
#pragma unroll
        for (int b = 0; b < 8; b++)
#pragma unroll
            for (int d = 0; d < 4; d++) c[a][b][d] = 0.f;

    load_stage(0, 0);

#pragma unroll 1
    for (int kt = 0; kt < nk; kt++) {
        CP_WAIT0();
        __syncthreads();
        // sync certifies compute(kt-1) done CTA-wide; safe to overwrite its stage
        if (kt + 1 < nk) load_stage(kt + 1, (kt + 1) & 1);

        const uint32_t sb = sbase + (kt & 1) * G1STG_B;
        const uint32_t uAs = sb;
        const uint32_t uBs = sb + G1A * 2;

#pragma unroll
        for (int kk = 0; kk < 64; kk += 16) {
            uint32_t as[2][4], bs[8][2];
#pragma unroll
            for (int ms = 0; ms < 2; ms++) {
                LDSM4(as[ms][0], as[ms][1], as[ms][2], as[ms][3],
                      uAs + 2 * (aoff + ms * 16 * GPITCH + kk));
            }
#pragma unroll
            for (int g = 0; g < 4; g++) {
                const int off = (wn * 64 + g * 16) * GPITCH + bofflane + kk;
                uint32_t t0, t1, t2, t3;
                LDSM4(t0, t1, t2, t3, uBs + 2 * off);
                bs[2*g][0] = t0; bs[2*g][1] = t1; bs[2*g+1][0] = t2; bs[2*g+1][1] = t3;
            }
#pragma unroll
            for (int ms = 0; ms < 2; ms++)
#pragma unroll
                for (int ng = 0; ng < 8; ng++)
                    MMA16816F(c[ms][ng], as[ms], bs[ng][0], bs[ng][1]);
        }
    }

    if (!qkv_mode) {
#pragma unroll
        for (int ms = 0; ms < 2; ms++) {
            const int row = bm + wm * 32 + ms * 16 + (lane >> 2);
#pragma unroll
            for (int ng = 0; ng < 8; ng++) {
                const int col = bn + wn * 64 + ng * 8 + (lane & 3) * 2;
                *(float2*)(C + (size_t)row * N + col)       = make_float2(c[ms][ng][0], c[ms][ng][1]);
                *(float2*)(C + (size_t)(row + 8) * N + col) = make_float2(c[ms][ng][2], c[ms][ng][3]);
            }
        }
        return;
    }

    // ---- QKV epilogue: rope (Q/K) + fp16 scatter. Warp's 64-col span = 1 head.
    const int ccb = bn + wn * 64;
    __half* dst;
    int head, nheads;
    bool do_rope;
    if (ccb < 2048)      { dst = qs; head = ccb >> 6;          nheads = NHEADS; do_rope = true; }
    else if (ccb < 2560) { dst = ks; head = (ccb - 2048) >> 6; nheads = NKV;    do_rope = true; }
    else                 { dst = vs; head = (ccb - 2560) >> 6; nheads = NKV;    do_rope = false; }

#pragma unroll
    for (int ms = 0; ms < 2; ms++) {
        const int row = bm + wm * 32 + ms * 16 + (lane >> 2);
        const int bb = row >> 11;
        const int ss = row & 2047;
        const size_t base0 = (((size_t)bb * nheads + head) * SEQ + ss) * HDIM;
        const size_t base1 = base0 + 8 * HDIM;
        if (do_rope) {
#pragma unroll
            for (int ng = 0; ng < 4; ng++) {
                const int d = ng * 8 + (lane & 3) * 2;
                {
                    float2 cl = *(const float2*)&cosv[ss * HDIM + d];
                    float2 sl = *(const float2*)&sinv[ss * HDIM + d];
                    float2 ch = *(const float2*)&cosv[ss * HDIM + d + 32];
                    float2 sh = *(const float2*)&sinv[ss * HDIM + d + 32];
                    float x0a = c[ms][ng][0],   x0b = c[ms][ng][1];
                    float x1a = c[ms][ng+4][0], x1b = c[ms][ng+4][1];
                    *(uint32_t*)(dst + base0 + d)      = pack_f16x2(x0a*cl.x - x1a*sl.x, x0b*cl.y - x1b*sl.y);
                    *(uint32_t*)(dst + base0 + d + 32) = pack_f16x2(x1a*ch.x + x0a*sh.x, x1b*ch.y + x0b*sh.y);
                }
                {
                    const int s2 = ss + 8;
                    float2 cl = *(const float2*)&cosv[s2 * HDIM + d];
                    float2 sl = *(const float2*)&sinv[s2 * HDIM + d];
                    float2 ch = *(const float2*)&cosv[s2 * HDIM + d + 32];
                    float2 sh = *(const float2*)&sinv[s2 * HDIM + d + 32];
                    float x0a = c[ms][ng][2],   x0b = c[ms][ng][3];
                    float x1a = c[ms][ng+4][2], x1b = c[ms][ng+4][3];
                    *(uint32_t*)(dst + base1 + d)      = pack_f16x2(x0a*cl.x - x1a*sl.x, x0b*cl.y - x1b*sl.y);
                    *(uint32_t*)(dst + base1 + d + 32) = pack_f16x2(x1a*ch.x + x0a*sh.x, x1b*ch.y + x0b*sh.y);
                }
            }
        } else {
#pragma unroll
            for (int ng = 0; ng < 8; ng++) {
                const int d = ng * 8 + (lane & 3) * 2;
                *(uint32_t*)(dst + base0 + d) = pack_f16x2(c[ms][ng][0], c[ms][ng][1]);
                *(uint32_t*)(dst + base1 + d) = pack_f16x2(c[ms][ng][2], c[ms][ng][3]);
            }
        }
    }
}

// ---------------------------------------------------------------------------
// Tensor-core causal flash attention: all single fp16, single-sync mainloop.
// K and V both [b,kvh,s,d]; PV uses ldmatrix.trans on the V tile.
// ---------------------------------------------------------------------------
#define APITCH 72
#define A_ARR (64*APITCH)
#define A_STG_E (2*A_ARR)
#define A_STG_B (A_STG_E*2)           // 18432 B
#define A_SMEM (2*A_STG_B)            // 36864 B
#define SCALE_LOG2 0.18033688011112042f   // log2(e)/8

__global__ __launch_bounds__(256, 2)
void attn_mma(const __half* __restrict__ Qs, const __half* __restrict__ Ks,
              const __half* __restrict__ Vs, __half* __restrict__ Os)
{
    extern __shared__ __align__(16) char dsm_raw[];
    const uint32_t sbase = smem_u32(dsm_raw);

    const int tid  = threadIdx.x;
    const int wid  = tid >> 5;
    const int lane = tid & 31;
    const int t = (int)gridDim.x - 1 - (int)blockIdx.x;
    const int h = blockIdx.y;
    const int b = blockIdx.z;
    const int kvh = h >> 2;

    // ---- stage Q and extract fragments ----
    {
        const size_t qbase = (((size_t)b * NHEADS + h) * SEQ + (size_t)t * 128) * HDIM;
#pragma unroll
        for (int q = 0; q < 4; q++) {
            int i = tid + q * 256;
            int r = i >> 3;
            int cc = (i & 7) << 3;
            CP16(sbase + (r * APITCH + cc) * 2, Qs + qbase + (size_t)r * HDIM + cc);
        }
        CP_COMMIT();
        CP_WAIT0();
    }
    __syncthreads();

    uint32_t qs[4][4];
    {
        const int aoff = (wid * 16 + (lane & 15)) * APITCH + ((lane >> 4) << 3);
#pragma unroll
        for (int kk = 0; kk < 4; kk++) {
            LDSM4(qs[kk][0], qs[kk][1], qs[kk][2], qs[kk][3], sbase + 2 * (aoff + kk * 16));
        }
    }
    __syncthreads();   // all warps done reading Q smem before K/V stage-0 overwrite

    const size_t kvbase = ((size_t)b * NKV + kvh) * SEQ * HDIM;

    auto load_kv = [&](int kb, int stage) {
        const uint32_t sb = sbase + stage * A_STG_B;
#pragma unroll
        for (int q = 0; q < 4; q++) {
            int i = tid + q * 256;
            int a = i >> 9;
            int j = i & 511;
            int r = j >> 3;
            int cc = (j & 7) << 3;
            uint32_t dst = sb + (a * A_ARR + r * APITCH + cc) * 2;
            const __half* src = (a ? Vs : Ks) + kvbase + (size_t)(kb * 64 + r) * HDIM + cc;
            CP16(dst, src);
        }
        CP_COMMIT();
    };

    float o[8][4];
#pragma unroll
    for (int nt = 0; nt < 8; nt++)
#pragma unroll
        for (int e = 0; e < 4; e++) o[nt][e] = 0.f;
    float mi0 = -1e30f, mi1 = -1e30f, li0 = 0.f, li1 = 0.f;

    const int row0 = t * 128 + wid * 16 + (lane >> 2);
    const int row1 = row0 + 8;

    const int nkb = 2 * t + 2;
    load_kv(0, 0);

#pragma unroll 1
    for (int kb = 0; kb < nkb; kb++) {
        CP_WAIT0();
        __syncthreads();
        if (kb + 1 < nkb) load_kv(kb + 1, (kb + 1) & 1);

        const uint32_t sb = sbase + (kb & 1) * A_STG_B;
        const uint32_t uKs = sb;
        const uint32_t uVs = sb + A_ARR * 2;

        // ---- S = Q K^T ----
        float s[8][4];
#pragma unroll
        for (int nt = 0; nt < 8; nt++)
#pragma unroll
            for (int e = 0; e < 4; e++) s[nt][e] = 0.f;

#pragma unroll
        for (int kk = 0; kk < 4; kk++) {
            uint32_t bs[8][2];
#pragma unroll
            for (int g = 0; g < 4; g++) {
                const int off = (g * 16 + ((lane >> 4) << 3) + (lane & 7)) * APITCH
                              + (((lane >> 3) & 1) << 3) + kk * 16;
                uint32_t t0, t1, t2, t3;
                LDSM4(t0, t1, t2, t3, uKs + 2 * off);
                bs[2*g][0] = t0; bs[2*g][1] = t1; bs[2*g+1][0] = t2; bs[2*g+1][1] = t3;
            }
#pragma unroll
            for (int nt = 0; nt < 8; nt++)
                MMA16816F(s[nt], qs[kk], bs[nt][0], bs[nt][1]);
        }

        const bool diag = (kb >= 2 * t);
#pragma unroll
        for (int nt = 0; nt < 8; nt++) {
            const int col = kb * 64 + nt * 8 + (lane & 3) * 2;
            s[nt][0] *= SCALE_LOG2; s[nt][1] *= SCALE_LOG2;
            s[nt][2] *= SCALE_LOG2; s[nt][3] *= SCALE_LOG2;
            if (diag) {
                if (col > row0)     s[nt][0] = -1e30f;
                if (col + 1 > row0) s[nt][1] = -1e30f;
                if (col > row1)     s[nt][2] = -1e30f;
                if (col + 1 > row1) s[nt][3] = -1e30f;
            }
        }

        float bm0 = -1e30f, bm1 = -1e30f;
#pragma unroll
        for (int nt = 0; nt < 8; nt++) {
            bm0 = fmaxf(bm0, fmaxf(s[nt][0], s[nt][1]));
            bm1 = fmaxf(bm1, fmaxf(s[nt][2], s[nt][3]));
        }
        bm0 = fmaxf(bm0, __shfl_xor_sync(0xffffffffu, bm0, 1));
        bm0 = fmaxf(bm0, __shfl_xor_sync(0xffffffffu, bm0, 2));
        bm1 = fmaxf(bm1, __shfl_xor_sync(0xffffffffu, bm1, 1));
        bm1 = fmaxf(bm1, __shfl_xor_sync(0xffffffffu, bm1, 2));

        const float mn0 = fmaxf(mi0, bm0);
        const float mn1 = fmaxf(mi1, bm1);
        const float sc0 = exp2f(mi0 - mn0);
        const float sc1 = exp2f(mi1 - mn1);

        float ls0 = 0.f, ls1 = 0.f;
#pragma unroll
        for (int nt = 0; nt < 8; nt++) {
            s[nt][0] = exp2f(s[nt][0] - mn0);
            s[nt][1] = exp2f(s[nt][1] - mn0);
            s[nt][2] = exp2f(s[nt][2] - mn1);
            s[nt][3] = exp2f(s[nt][3] - mn1);
            ls0 += s[nt][0] + s[nt][1];
            ls1 += s[nt][2] + s[nt][3];
        }
        ls0 += __shfl_xor_sync(0xffffffffu, ls0, 1);
        ls0 += __shfl_xor_sync(0xffffffffu, ls0, 2);
        ls1 += __shfl_xor_sync(0xffffffffu, ls1, 1);
        ls1 += __shfl_xor_sync(0xffffffffu, ls1, 2);

        li0 = li0 * sc0 + ls0;
        li1 = li1 * sc1 + ls1;
        mi0 = mn0; mi1 = mn1;

#pragma unroll
        for (int nt = 0; nt < 8; nt++) {
            o[nt][0] *= sc0; o[nt][1] *= sc0;
            o[nt][2] *= sc1; o[nt][3] *= sc1;
        }

        uint32_t ps[8][2];
#pragma unroll
        for (int nt = 0; nt < 8; nt++) {
            ps[nt][0] = pack_f16x2(s[nt][0], s[nt][1]);
            ps[nt][1] = pack_f16x2(s[nt][2], s[nt][3]);
        }

        // ---- O += P V (trans-ldmatrix on V tile) ----
#pragma unroll
        for (int kk = 0; kk < 4; kk++) {
            uint32_t vs[8][2];
#pragma unroll
            for (int g = 0; g < 4; g++) {
                const int off = (kk * 16 + (lane & 15)) * APITCH
                              + g * 16 + ((lane >> 4) << 3);
                uint32_t t0, t1, t2, t3;
                LDSM4T(t0, t1, t2, t3, uVs + 2 * off);
                vs[2*g][0] = t0; vs[2*g][1] = t1; vs[2*g+1][0] = t2; vs[2*g+1][1] = t3;
            }
            uint32_t ap[4] = {ps[2*kk][0], ps[2*kk][1], ps[2*kk+1][0], ps[2*kk+1][1]};
#pragma unroll
            for (int nt = 0; nt < 8; nt++)
                MMA16816F(o[nt], ap, vs[nt][0], vs[nt][1]);
        }
    }

    // ---- finalize ----
    const float inv0 = 1.f / li0;
    const float inv1 = 1.f / li1;
    const size_t o0 = (((size_t)b * SEQ + row0) * NHEADS + h) * HDIM;
    const size_t o1 = (((size_t)b * SEQ + row1) * NHEADS + h) * HDIM;
#pragma unroll
    for (int nt = 0; nt < 8; nt++) {
        const int col = nt * 8 + (lane & 3) * 2;
        *(uint32_t*)(Os + o0 + col) = pack_f16x2(o[nt][0] * inv0, o[nt][1] * inv0);
        *(uint32_t*)(Os + o1 + col) = pack_f16x2(o[nt][2] * inv1, o[nt][3] * inv1);
    }
}

// ---------------------------------------------------------------------------
extern "C" void kernel_launch(void* const* d_in, const int* in_sizes, int n_in,
                              void* d_out, int out_size)
{
    const float* x    = (const float*)d_in[0];
    const float* fcos = (const float*)d_in[1];
    const float* fsin = (const float*)d_in[2];
    const float* wq   = (const float*)d_in[3];
    const float* wk   = (const float*)d_in[4];
    const float* wv   = (const float*)d_in[5];
    const float* wo   = (const float*)d_in[6];
    float* out = (float*)d_out;

    __half *hf, *qs, *ks, *vs;
    cudaGetSymbolAddress((void**)&hf, g_hf);
    cudaGetSymbolAddress((void**)&qs, g_Qs);
    cudaGetSymbolAddress((void**)&ks, g_Ks);
    cudaGetSymbolAddress((void**)&vs, g_Vs);

    cudaFuncSetAttribute(gemm_mma, cudaFuncAttributeMaxDynamicSharedMemorySize, G1SMEM);
    cudaFuncSetAttribute(attn_mma, cudaFuncAttributeMaxDynamicSharedMemorySize, A_SMEM);

    const int M = BATCH * SEQ;

    // #0: prepass (everything -> single fp16)
    split_all<<<(Q_TOT + 255) / 256, 256>>>(x, wq, wk, wv, wo, hf);

    // #1: fused QKV projection + RoPE + fp16 scatter
    gemm_mma<<<dim3(NQKV / 128, M / 128), 256, G1SMEM>>>(
        hf + OFF_XS, hf + OFF_WQKV, nullptr, M, NQKV, EMBED,
        1, fcos, fsin, qs, ks, vs);

    // #2: tensor-core causal GQA flash attention
    attn_mma<<<dim3(SEQ / 128, NHEADS, BATCH), 256, A_SMEM>>>(qs, ks, vs, hf + OFF_OS);

    // #3: output projection (fp32 out)
    gemm_mma<<<dim3(EMBED / 128, M / 128), 256, G1SMEM>>>(
        hf + OFF_OS, hf + OFF_WOS, out, M, EMBED, EMBED,
        0, nullptr, nullptr, nullptr, nullptr, nullptr);
}

// round 17
// speedup vs baseline: 8.4754x; 1.0090x over previous
#include <cuda_runtime.h>
#include <cuda_fp16.h>
#include <cstdint>

#define BATCH 2
#define SEQ 2048
#define EMBED 2048
#define NHEADS 32
#define NKV 8
#define HDIM 64
#define NQKV 3072

// fp16 pool: x, Wqkv packed, Wo, attention output — all single fp16
#define N_X    (size_t)8388608    // 2*2048*2048
#define N_WQKV (size_t)6291456    // 3072*2048
#define N_WO   (size_t)4194304
#define OFF_XS   (size_t)0
#define OFF_WQKV (OFF_XS + N_X)
#define OFF_WOS  (OFF_WQKV + N_WQKV)
#define OFF_OS   (OFF_WOS + N_WO)
#define POOL_SZ  (OFF_OS + N_X)
__device__ __half g_hf[POOL_SZ];

// attention operands, single fp16: Q [b,h,s,d]; K,V [b,kvh,s,d]
__device__ __half g_Qs[(size_t)BATCH*NHEADS*SEQ*HDIM];
__device__ __half g_Ks[(size_t)BATCH*NKV*SEQ*HDIM];
__device__ __half g_Vs[(size_t)BATCH*NKV*SEQ*HDIM];

// ============================ helpers ======================================
__device__ __forceinline__ uint32_t smem_u32(const void* p) {
    uint32_t a;
    asm("{ .reg .u64 t; cvta.to.shared.u64 t, %1; cvt.u32.u64 %0, t; }"
        : "=r"(a) : "l"(p));
    return a;
}

#define LDSM4(R0,R1,R2,R3,ADDR) \
    asm volatile("ldmatrix.sync.aligned.m8n8.x4.shared.b16 {%0,%1,%2,%3}, [%4];" \
                 : "=r"(R0), "=r"(R1), "=r"(R2), "=r"(R3) : "r"(ADDR))

#define LDSM4T(R0,R1,R2,R3,ADDR) \
    asm volatile("ldmatrix.sync.aligned.m8n8.x4.trans.shared.b16 {%0,%1,%2,%3}, [%4];" \
                 : "=r"(R0), "=r"(R1), "=r"(R2), "=r"(R3) : "r"(ADDR))

#define MMA16816F(C, A, B0, B1) \
    asm volatile("mma.sync.aligned.m16n8k16.row.col.f32.f16.f16.f32 " \
                 "{%0,%1,%2,%3}, {%4,%5,%6,%7}, {%8,%9}, {%0,%1,%2,%3};" \
                 : "+f"((C)[0]), "+f"((C)[1]), "+f"((C)[2]), "+f"((C)[3]) \
                 : "r"((A)[0]), "r"((A)[1]), "r"((A)[2]), "r"((A)[3]), \
                   "r"(B0), "r"(B1))

#define CP16(DST, SRC) \
    asm volatile("cp.async.cg.shared.global [%0], [%1], 16;" :: "r"(DST), "l"(SRC))
#define CP_COMMIT() asm volatile("cp.async.commit_group;")
#define CP_WAIT0()  asm volatile("cp.async.wait_group 0;")

__device__ __forceinline__ uint32_t pack_f16x2(float lo, float hi) {
    uint32_t d;
    asm("cvt.rn.f16x2.f32 %0, %1, %2;" : "=r"(d) : "f"(hi), "f"(lo));
    return d;
}

// ---------------------------------------------------------------------------
// One-shot prepass: everything -> single fp16 (Wqkv packed [3072,2048]).
// 2 float4 per thread for ILP.
// ---------------------------------------------------------------------------
#define Q_X   (int)(N_X/4)
#define Q_WQ  1048576
#define Q_WK  262144
#define Q_WV  262144
#define Q_WO  1048576
#define Q_TOT (Q_X + Q_WQ + Q_WK + Q_WV + Q_WO)   // 4718592 quads

__device__ __forceinline__ void split_map(int i, const float* x, const float* wq,
                                          const float* wk, const float* wv,
                                          const float* wo,
                                          const float*& src, size_t& doff, int& j)
{
    if (i < Q_X)                  { src = x;  j = i;                        doff = OFF_XS; }
    else if (i < Q_X + Q_WQ)      { src = wq; j = i - Q_X;                  doff = OFF_WQKV; }
    else if (i < Q_X + Q_WQ + Q_WK)
                                  { src = wk; j = i - Q_X - Q_WQ;           doff = OFF_WQKV + (size_t)2048 * EMBED; }
    else if (i < Q_X + Q_WQ + Q_WK + Q_WV)
                                  { src = wv; j = i - Q_X - Q_WQ - Q_WK;    doff = OFF_WQKV + (size_t)2560 * EMBED; }
    else                          { src = wo; j = i - Q_X - Q_WQ - Q_WK - Q_WV; doff = OFF_WOS; }
}

__global__ void split_all(const float* __restrict__ x,  const float* __restrict__ wq,
                          const float* __restrict__ wk, const float* __restrict__ wv,
                          const float* __restrict__ wo, __half* __restrict__ hf)
{
    int base = blockIdx.x * (blockDim.x * 2) + threadIdx.x;
    int i0 = base;
    int i1 = base + blockDim.x;

    const float *s0 = nullptr, *s1 = nullptr;
    size_t d0 = 0, d1 = 0;
    int j0 = 0, j1 = 0;
    bool v0 = i0 < Q_TOT, v1 = i1 < Q_TOT;
    if (v0) split_map(i0, x, wq, wk, wv, wo, s0, d0, j0);
    if (v1) split_map(i1, x, wq, wk, wv, wo, s1, d1, j1);

    float4 a, b;
    if (v0) a = ((const float4*)s0)[j0];
    if (v1) b = ((const float4*)s1)[j1];
    if (v0) {
        uint2 u;
        u.x = pack_f16x2(a.x, a.y);
        u.y = pack_f16x2(a.z, a.w);
        ((uint2*)(hf + d0))[j0] = u;
    }
    if (v1) {
        uint2 u;
        u.x = pack_f16x2(b.x, b.y);
        u.y = pack_f16x2(b.z, b.w);
        ((uint2*)(hf + d1))[j1] = u;
    }
}

// ---------------------------------------------------------------------------
// Single-term fp16 GEMM: block 128x128, BK=64, 256 thr, warp 32x64, 2-stage,
// single-sync mainloop, A-fragments hoisted per kt, 2 CTAs/SM.
//   qkv_mode=1: apply RoPE (Q/K cols), convert fp16, scatter to qs/ks/vs.
//   qkv_mode=0: plain fp32 C store (O projection).
// ---------------------------------------------------------------------------
#define GPITCH 72
#define G1A (128*GPITCH)
#define G1STG_B (2*G1A*2)             // 36864 B per stage
#define G1SMEM (2*G1STG_B)            // 73728 B

__global__ __launch_bounds__(256, 2)
void gemm_mma(const __half* __restrict__ As, const __half* __restrict__ Bs,
              float* __restrict__ C, int M, int N, int K,
              int qkv_mode,
              const float* __restrict__ cosv, const float* __restrict__ sinv,
              __half* __restrict__ qs, __half* __restrict__ ks, __half* __restrict__ vs)
{
    extern __shared__ __align__(16) char dsm_raw[];
    const uint32_t sbase = smem_u32(dsm_raw);

    const int tid  = threadIdx.x;
    const int wid  = tid >> 5;
    const int lane = tid & 31;
    const int wm   = wid >> 1;      // 0..3
    const int wn   = wid & 1;       // 0..1

    const int bm = blockIdx.y * 128;
    const int bn = blockIdx.x * 128;

    const int aoff = (wm * 32 + (lane & 15)) * GPITCH + ((lane >> 4) << 3);
    const int bofflane = (((lane >> 4) << 3) + (lane & 7)) * GPITCH + (((lane >> 3) & 1) << 3);

    const int nk = K >> 6;

    auto load_stage = [&](int kt, int stage) {
        const int k0 = kt << 6;
        const uint32_t sb = sbase + stage * G1STG_B;
#pragma unroll
        for (int q = 0; q < 8; q++) {
            int c = tid + q * 256;
            int arr = c >> 10;
            int j = c & 1023;
            int r = j >> 3;
            int col = (j & 7) << 3;
            const __half* g = (arr ? Bs + (size_t)(bn + r) * K
                                   : As + (size_t)(bm + r) * K) + k0 + col;
            CP16(sb + (arr * G1A + r * GPITCH + col) * 2, g);
        }
        CP_COMMIT();
    };

    float c[2][8][4];
#pragma unroll
    for (int a = 0; a < 2; a++)
#pragma unroll
        for (int b = 0; b < 8; b++)
#pragma unroll
            for (int d = 0; d < 4; d++) c[a][b][d] = 0.f;

    load_stage(0, 0);

#pragma unroll 1
    for (int kt = 0; kt < nk; kt++) {
        CP_WAIT0();
        __syncthreads();
        if (kt + 1 < nk) load_stage(kt + 1, (kt + 1) & 1);

        const uint32_t sb = sbase + (kt & 1) * G1STG_B;
        const uint32_t uAs = sb;
        const uint32_t uBs = sb + G1A * 2;

        // hoist all A fragments for this kt
        uint32_t as[4][2][4];
#pragma unroll
        for (int kk4 = 0; kk4 < 4; kk4++)
#pragma unroll
            for (int ms = 0; ms < 2; ms++) {
                LDSM4(as[kk4][ms][0], as[kk4][ms][1], as[kk4][ms][2], as[kk4][ms][3],
                      uAs + 2 * (aoff + ms * 16 * GPITCH + kk4 * 16));
            }

#pragma unroll
        for (int kk4 = 0; kk4 < 4; kk4++) {
            uint32_t bs[8][2];
#pragma unroll
            for (int g = 0; g < 4; g++) {
                const int off = (wn * 64 + g * 16) * GPITCH + bofflane + kk4 * 16;
                uint32_t t0, t1, t2, t3;
                LDSM4(t0, t1, t2, t3, uBs + 2 * off);
                bs[2*g][0] = t0; bs[2*g][1] = t1; bs[2*g+1][0] = t2; bs[2*g+1][1] = t3;
            }
#pragma unroll
            for (int ms = 0; ms < 2; ms++)
#pragma unroll
                for (int ng = 0; ng < 8; ng++)
                    MMA16816F(c[ms][ng], as[kk4][ms], bs[ng][0], bs[ng][1]);
        }
    }

    if (!qkv_mode) {
#pragma unroll
        for (int ms = 0; ms < 2; ms++) {
            const int row = bm + wm * 32 + ms * 16 + (lane >> 2);
#pragma unroll
            for (int ng = 0; ng < 8; ng++) {
                const int col = bn + wn * 64 + ng * 8 + (lane & 3) * 2;
                *(float2*)(C + (size_t)row * N + col)       = make_float2(c[ms][ng][0], c[ms][ng][1]);
                *(float2*)(C + (size_t)(row + 8) * N + col) = make_float2(c[ms][ng][2], c[ms][ng][3]);
            }
        }
        return;
    }

    // ---- QKV epilogue: rope (Q/K) + fp16 scatter. Warp's 64-col span = 1 head.
    const int ccb = bn + wn * 64;
    __half* dst;
    int head, nheads;
    bool do_rope;
    if (ccb < 2048)      { dst = qs; head = ccb >> 6;          nheads = NHEADS; do_rope = true; }
    else if (ccb < 2560) { dst = ks; head = (ccb - 2048) >> 6; nheads = NKV;    do_rope = true; }
    else                 { dst = vs; head = (ccb - 2560) >> 6; nheads = NKV;    do_rope = false; }

#pragma unroll
    for (int ms = 0; ms < 2; ms++) {
        const int row = bm + wm * 32 + ms * 16 + (lane >> 2);
        const int bb = row >> 11;
        const int ss = row & 2047;
        const size_t base0 = (((size_t)bb * nheads + head) * SEQ + ss) * HDIM;
        const size_t base1 = base0 + 8 * HDIM;
        if (do_rope) {
#pragma unroll
            for (int ng = 0; ng < 4; ng++) {
                const int d = ng * 8 + (lane & 3) * 2;
                {
                    float2 cl = *(const float2*)&cosv[ss * HDIM + d];
                    float2 sl = *(const float2*)&sinv[ss * HDIM + d];
                    float2 ch = *(const float2*)&cosv[ss * HDIM + d + 32];
                    float2 sh = *(const float2*)&sinv[ss * HDIM + d + 32];
                    float x0a = c[ms][ng][0],   x0b = c[ms][ng][1];
                    float x1a = c[ms][ng+4][0], x1b = c[ms][ng+4][1];
                    *(uint32_t*)(dst + base0 + d)      = pack_f16x2(x0a*cl.x - x1a*sl.x, x0b*cl.y - x1b*sl.y);
                    *(uint32_t*)(dst + base0 + d + 32) = pack_f16x2(x1a*ch.x + x0a*sh.x, x1b*ch.y + x0b*sh.y);
                }
                {
                    const int s2 = ss + 8;
                    float2 cl = *(const float2*)&cosv[s2 * HDIM + d];
                    float2 sl = *(const float2*)&sinv[s2 * HDIM + d];
                    float2 ch = *(const float2*)&cosv[s2 * HDIM + d + 32];
                    float2 sh = *(const float2*)&sinv[s2 * HDIM + d + 32];
                    float x0a = c[ms][ng][2],   x0b = c[ms][ng][3];
                    float x1a = c[ms][ng+4][2], x1b = c[ms][ng+4][3];
                    *(uint32_t*)(dst + base1 + d)      = pack_f16x2(x0a*cl.x - x1a*sl.x, x0b*cl.y - x1b*sl.y);
                    *(uint32_t*)(dst + base1 + d + 32) = pack_f16x2(x1a*ch.x + x0a*sh.x, x1b*ch.y + x0b*sh.y);
                }
            }
        } else {
#pragma unroll
            for (int ng = 0; ng < 8; ng++) {
                const int d = ng * 8 + (lane & 3) * 2;
                *(uint32_t*)(dst + base0 + d) = pack_f16x2(c[ms][ng][0], c[ms][ng][1]);
                *(uint32_t*)(dst + base1 + d) = pack_f16x2(c[ms][ng][2], c[ms][ng][3]);
            }
        }
    }
}

// ---------------------------------------------------------------------------
// Tensor-core causal flash attention: all single fp16, single-sync mainloop.
// K and V both [b,kvh,s,d]; PV uses ldmatrix.trans on the V tile.
// ---------------------------------------------------------------------------
#define APITCH 72
#define A_ARR (64*APITCH)
#define A_STG_E (2*A_ARR)
#define A_STG_B (A_STG_E*2)           // 18432 B
#define A_SMEM (2*A_STG_B)            // 36864 B
#define SCALE_LOG2 0.18033688011112042f   // log2(e)/8

__global__ __launch_bounds__(256, 2)
void attn_mma(const __half* __restrict__ Qs, const __half* __restrict__ Ks,
              const __half* __restrict__ Vs, __half* __restrict__ Os)
{
    extern __shared__ __align__(16) char dsm_raw[];
    const uint32_t sbase = smem_u32(dsm_raw);

    const int tid  = threadIdx.x;
    const int wid  = tid >> 5;
    const int lane = tid & 31;
    const int t = (int)gridDim.x - 1 - (int)blockIdx.x;
    const int h = blockIdx.y;
    const int b = blockIdx.z;
    const int kvh = h >> 2;

    // ---- stage Q and extract fragments ----
    {
        const size_t qbase = (((size_t)b * NHEADS + h) * SEQ + (size_t)t * 128) * HDIM;
#pragma unroll
        for (int q = 0; q < 4; q++) {
            int i = tid + q * 256;
            int r = i >> 3;
            int cc = (i & 7) << 3;
            CP16(sbase + (r * APITCH + cc) * 2, Qs + qbase + (size_t)r * HDIM + cc);
        }
        CP_COMMIT();
        CP_WAIT0();
    }
    __syncthreads();

    uint32_t qs[4][4];
    {
        const int aoff = (wid * 16 + (lane & 15)) * APITCH + ((lane >> 4) << 3);
#pragma unroll
        for (int kk = 0; kk < 4; kk++) {
            LDSM4(qs[kk][0], qs[kk][1], qs[kk][2], qs[kk][3], sbase + 2 * (aoff + kk * 16));
        }
    }
    __syncthreads();

    const size_t kvbase = ((size_t)b * NKV + kvh) * SEQ * HDIM;

    auto load_kv = [&](int kb, int stage) {
        const uint32_t sb = sbase + stage * A_STG_B;
#pragma unroll
        for (int q = 0; q < 4; q++) {
            int i = tid + q * 256;
            int a = i >> 9;
            int j = i & 511;
            int r = j >> 3;
            int cc = (j & 7) << 3;
            uint32_t dst = sb + (a * A_ARR + r * APITCH + cc) * 2;
            const __half* src = (a ? Vs : Ks) + kvbase + (size_t)(kb * 64 + r) * HDIM + cc;
            CP16(dst, src);
        }
        CP_COMMIT();
    };

    float o[8][4];
#pragma unroll
    for (int nt = 0; nt < 8; nt++)
#pragma unroll
        for (int e = 0; e < 4; e++) o[nt][e] = 0.f;
    float mi0 = -1e30f, mi1 = -1e30f, li0 = 0.f, li1 = 0.f;

    const int row0 = t * 128 + wid * 16 + (lane >> 2);
    const int row1 = row0 + 8;

    const int nkb = 2 * t + 2;
    load_kv(0, 0);

#pragma unroll 1
    for (int kb = 0; kb < nkb; kb++) {
        CP_WAIT0();
        __syncthreads();
        if (kb + 1 < nkb) load_kv(kb + 1, (kb + 1) & 1);

        const uint32_t sb = sbase + (kb & 1) * A_STG_B;
        const uint32_t uKs = sb;
        const uint32_t uVs = sb + A_ARR * 2;

        float s[8][4];
#pragma unroll
        for (int nt = 0; nt < 8; nt++)
#pragma unroll
            for (int e = 0; e < 4; e++) s[nt][e] = 0.f;

#pragma unroll
        for (int kk = 0; kk < 4; kk++) {
            uint32_t bs[8][2];
#pragma unroll
            for (int g = 0; g < 4; g++) {
                const int off = (g * 16 + ((lane >> 4) << 3) + (lane & 7)) * APITCH
                              + (((lane >> 3) & 1) << 3) + kk * 16;
                uint32_t t0, t1, t2, t3;
                LDSM4(t0, t1, t2, t3, uKs + 2 * off);
                bs[2*g][0] = t0; bs[2*g][1] = t1; bs[2*g+1][0] = t2; bs[2*g+1][1] = t3;
            }
#pragma unroll
            for (int nt = 0; nt < 8; nt++)
                MMA16816F(s[nt], qs[kk], bs[nt][0], bs[nt][1]);
        }

        const bool diag = (kb >= 2 * t);
#pragma unroll
        for (int nt = 0; nt < 8; nt++) {
            const int col = kb * 64 + nt * 8 + (lane & 3) * 2;
            s[nt][0] *= SCALE_LOG2; s[nt][1] *= SCALE_LOG2;
            s[nt][2] *= SCALE_LOG2; s[nt][3] *= SCALE_LOG2;
            if (diag) {
                if (col > row0)     s[nt][0] = -1e30f;
                if (col + 1 > row0) s[nt][1] = -1e30f;
                if (col > row1)     s[nt][2] = -1e30f;
                if (col + 1 > row1) s[nt][3] = -1e30f;
            }
        }

        float bm0 = -1e30f, bm1 = -1e30f;
#pragma unroll
        for (int nt = 0; nt < 8; nt++) {
            bm0 = fmaxf(bm0, fmaxf(s[nt][0], s[nt][1]));
            bm1 = fmaxf(bm1, fmaxf(s[nt][2], s[nt][3]));
        }
        bm0 = fmaxf(bm0, __shfl_xor_sync(0xffffffffu, bm0, 1));
        bm0 = fmaxf(bm0, __shfl_xor_sync(0xffffffffu, bm0, 2));
        bm1 = fmaxf(bm1, __shfl_xor_sync(0xffffffffu, bm1, 1));
        bm1 = fmaxf(bm1, __shfl_xor_sync(0xffffffffu, bm1, 2));

        const float mn0 = fmaxf(mi0, bm0);
        const float mn1 = fmaxf(mi1, bm1);
        const float sc0 = exp2f(mi0 - mn0);
        const float sc1 = exp2f(mi1 - mn1);

        float ls0 = 0.f, ls1 = 0.f;
#pragma unroll
        for (int nt = 0; nt < 8; nt++) {
            s[nt][0] = exp2f(s[nt][0] - mn0);
            s[nt][1] = exp2f(s[nt][1] - mn0);
            s[nt][2] = exp2f(s[nt][2] - mn1);
            s[nt][3] = exp2f(s[nt][3] - mn1);
            ls0 += s[nt][0] + s[nt][1];
            ls1 += s[nt][2] + s[nt][3];
        }
        ls0 += __shfl_xor_sync(0xffffffffu, ls0, 1);
        ls0 += __shfl_xor_sync(0xffffffffu, ls0, 2);
        ls1 += __shfl_xor_sync(0xffffffffu, ls1, 1);
        ls1 += __shfl_xor_sync(0xffffffffu, ls1, 2);

        li0 = li0 * sc0 + ls0;
        li1 = li1 * sc1 + ls1;
        mi0 = mn0; mi1 = mn1;

#pragma unroll
        for (int nt = 0; nt < 8; nt++) {
            o[nt][0] *= sc0; o[nt][1] *= sc0;
            o[nt][2] *= sc1; o[nt][3] *= sc1;
        }

        uint32_t ps[8][2];
#pragma unroll
        for (int nt = 0; nt < 8; nt++) {
            ps[nt][0] = pack_f16x2(s[nt][0], s[nt][1]);
            ps[nt][1] = pack_f16x2(s[nt][2], s[nt][3]);
        }

#pragma unroll
        for (int kk = 0; kk < 4; kk++) {
            uint32_t vs[8][2];
#pragma unroll
            for (int g = 0; g < 4; g++) {
                const int off = (kk * 16 + (lane & 15)) * APITCH
                              + g * 16 + ((lane >> 4) << 3);
                uint32_t t0, t1, t2, t3;
                LDSM4T(t0, t1, t2, t3, uVs + 2 * off);
                vs[2*g][0] = t0; vs[2*g][1] = t1; vs[2*g+1][0] = t2; vs[2*g+1][1] = t3;
            }
            uint32_t ap[4] = {ps[2*kk][0], ps[2*kk][1], ps[2*kk+1][0], ps[2*kk+1][1]};
#pragma unroll
            for (int nt = 0; nt < 8; nt++)
                MMA16816F(o[nt], ap, vs[nt][0], vs[nt][1]);
        }
    }

    // ---- finalize ----
    const float inv0 = 1.f / li0;
    const float inv1 = 1.f / li1;
    const size_t o0 = (((size_t)b * SEQ + row0) * NHEADS + h) * HDIM;
    const size_t o1 = (((size_t)b * SEQ + row1) * NHEADS + h) * HDIM;
#pragma unroll
    for (int nt = 0; nt < 8; nt++) {
        const int col = nt * 8 + (lane & 3) * 2;
        *(uint32_t*)(Os + o0 + col) = pack_f16x2(o[nt][0] * inv0, o[nt][1] * inv0);
        *(uint32_t*)(Os + o1 + col) = pack_f16x2(o[nt][2] * inv1, o[nt][3] * inv1);
    }
}

// ---------------------------------------------------------------------------
extern "C" void kernel_launch(void* const* d_in, const int* in_sizes, int n_in,
                              void* d_out, int out_size)
{
    const float* x    = (const float*)d_in[0];
    const float* fcos = (const float*)d_in[1];
    const float* fsin = (const float*)d_in[2];
    const float* wq   = (const float*)d_in[3];
    const float* wk   = (const float*)d_in[4];
    const float* wv   = (const float*)d_in[5];
    const float* wo   = (const float*)d_in[6];
    float* out = (float*)d_out;

    __half *hf, *qs, *ks, *vs;
    cudaGetSymbolAddress((void**)&hf, g_hf);
    cudaGetSymbolAddress((void**)&qs, g_Qs);
    cudaGetSymbolAddress((void**)&ks, g_Ks);
    cudaGetSymbolAddress((void**)&vs, g_Vs);

    cudaFuncSetAttribute(gemm_mma, cudaFuncAttributeMaxDynamicSharedMemorySize, G1SMEM);
    cudaFuncSetAttribute(attn_mma, cudaFuncAttributeMaxDynamicSharedMemorySize, A_SMEM);

    const int M = BATCH * SEQ;

    // #0: prepass (everything -> single fp16), 2 quads/thread
    split_all<<<(Q_TOT + 511) / 512, 256>>>(x, wq, wk, wv, wo, hf);

    // #1: fused QKV projection + RoPE + fp16 scatter
    gemm_mma<<<dim3(NQKV / 128, M / 128), 256, G1SMEM>>>(
        hf + OFF_XS, hf + OFF_WQKV, nullptr, M, NQKV, EMBED,
        1, fcos, fsin, qs, ks, vs);

    // #2: tensor-core causal GQA flash attention
    attn_mma<<<dim3(SEQ / 128, NHEADS, BATCH), 256, A_SMEM>>>(qs, ks, vs, hf + OFF_OS);

    // #3: output projection (fp32 out)
    gemm_mma<<<dim3(EMBED / 128, M / 128), 256, G1SMEM>>>(
        hf + OFF_OS, hf + OFF_WOS, out, M, EMBED, EMBED,
        0, nullptr, nullptr, nullptr, nullptr, nullptr);
}